// round 1
// baseline (speedup 1.0000x reference)
#include <cuda_runtime.h>

#define B_   2
#define T_   4096
#define D_   1024
#define H_   16
#define DH_  64
#define MRF_ 256
#define FD_  512            // 2m
#define BH_  (B_*H_)

// ---------------- scratch (no cudaMalloc allowed) ----------------
#define SZ_BTD  ((size_t)B_*T_*D_)            // 8,388,608
#define SZ_F    ((size_t)BH_*T_*FD_)          // 67,108,864
#define OFF_Q    ((size_t)0)
#define OFF_K    (SZ_BTD)
#define OFF_V    (2*SZ_BTD)
#define OFF_ATTN (3*SZ_BTD)
#define OFF_QF   (4*SZ_BTD)
#define OFF_KF   (OFF_QF + SZ_F)
#define OFF_KV   (OFF_KF + SZ_F)
#define OFF_KS   (OFF_KV + (size_t)BH_*FD_*DH_)
#define OFF_Z    (OFF_KS + (size_t)BH_*FD_)
#define TOTAL_F  (OFF_Z + (size_t)BH_*T_)     // 168,968,192 floats (~676 MB)

__device__ float g_buf[168968192];

// ---------------- fast sincos on the FMA pipe ----------------
__device__ __forceinline__ void fast_sincos(float x, float& s, float& c) {
    float kf = rintf(x * 0.63661977f);            // 2/pi
    int   q  = (int)kf;
    float r  = fmaf(kf, -1.5707963705062866f, x); // x - k*pi/2 (hi)
    r        = fmaf(kf,  4.3711388286738e-8f, r); // correct lo part
    float r2 = r * r;
    float sp = fmaf(-1.98412698e-4f, r2, 8.33333333e-3f);
    sp       = fmaf(sp, r2, -1.66666667e-1f);
    sp      *= r2;
    float sr = fmaf(sp, r, r);
    float cp = fmaf(2.48015873e-5f, r2, -1.38888889e-3f);
    cp       = fmaf(cp, r2, 4.16666667e-2f);
    cp       = fmaf(cp, r2, -0.5f);
    float cr = fmaf(cp, r2, 1.0f);
    if (q & 1) { float t = sr; sr = cr; cr = -t; }
    if (q & 2) { sr = -sr; cr = -cr; }
    s = sr; c = cr;
}

// ---------------- SGEMM NT: C[M,N] = A[M,K] * B[N,K]^T ----------------
__global__ __launch_bounds__(256) void sgemm_nt(const float* __restrict__ A,
                                                const float* __restrict__ Bm,
                                                float* __restrict__ C,
                                                int M, int N, int K)
{
    __shared__ float As[16][132];
    __shared__ float Bs[16][132];
    const int tid = threadIdx.x;
    const int bm  = blockIdx.y << 7;
    const int bn  = blockIdx.x << 7;
    const int tm  = (tid >> 4) << 3;
    const int tn  = (tid & 15) << 3;

    float acc[8][8];
#pragma unroll
    for (int i = 0; i < 8; i++)
#pragma unroll
        for (int j = 0; j < 8; j++) acc[i][j] = 0.f;

    for (int k0 = 0; k0 < K; k0 += 16) {
#pragma unroll
        for (int i = 0; i < 2; i++) {
            int idx = tid + (i << 8);
            int r   = idx >> 2;
            int c4  = (idx & 3) << 2;
            float4 a = *(const float4*)&A[(size_t)(bm + r) * K + k0 + c4];
            As[c4+0][r] = a.x; As[c4+1][r] = a.y; As[c4+2][r] = a.z; As[c4+3][r] = a.w;
            float4 b = *(const float4*)&Bm[(size_t)(bn + r) * K + k0 + c4];
            Bs[c4+0][r] = b.x; Bs[c4+1][r] = b.y; Bs[c4+2][r] = b.z; Bs[c4+3][r] = b.w;
        }
        __syncthreads();
#pragma unroll
        for (int kk = 0; kk < 16; kk++) {
            float a[8], b[8];
            *(float4*)&a[0] = *(float4*)&As[kk][tm];
            *(float4*)&a[4] = *(float4*)&As[kk][tm + 4];
            *(float4*)&b[0] = *(float4*)&Bs[kk][tn];
            *(float4*)&b[4] = *(float4*)&Bs[kk][tn + 4];
#pragma unroll
            for (int i = 0; i < 8; i++)
#pragma unroll
                for (int j = 0; j < 8; j++)
                    acc[i][j] = fmaf(a[i], b[j], acc[i][j]);
        }
        __syncthreads();
    }
#pragma unroll
    for (int i = 0; i < 8; i++) {
        float* crow = &C[(size_t)(bm + tm + i) * N + bn + tn];
        *(float4*)&crow[0] = make_float4(acc[i][0], acc[i][1], acc[i][2], acc[i][3]);
        *(float4*)&crow[4] = make_float4(acc[i][4], acc[i][5], acc[i][6], acc[i][7]);
    }
}

// ---------------- phi: Qf/Kf = [cos(Q rf^T), sin(Q rf^T)] * exp(-|q|^2/2)/sqrt(m) ----------------
__global__ __launch_bounds__(256) void phi_kernel(const float* __restrict__ src, // [B,T,D]
                                                  const float* __restrict__ rf,  // [256,64]
                                                  float* __restrict__ dst)       // [BH,T,512]
{
    __shared__ float Qs[64][68];   // [t][d]
    __shared__ float Rs[64][68];   // [d][m]  (transposed rf tile)
    __shared__ float scaleS[64];
    const int tid = threadIdx.x;
    const int t0  = blockIdx.x << 6;
    const int m0  = blockIdx.y << 6;
    const int bh  = blockIdx.z;
    const int b   = bh >> 4, h = bh & 15;

#pragma unroll
    for (int i = 0; i < 4; i++) {
        int idx = tid + (i << 8);
        int r   = idx >> 4;
        int c4  = (idx & 15) << 2;
        float4 q = *(const float4*)&src[((size_t)(b * T_ + t0 + r)) * D_ + h * DH_ + c4];
        *(float4*)&Qs[r][c4] = q;
        float4 w = *(const float4*)&rf[(size_t)(m0 + r) * DH_ + c4];
        Rs[c4+0][r] = w.x; Rs[c4+1][r] = w.y; Rs[c4+2][r] = w.z; Rs[c4+3][r] = w.w;
    }
    __syncthreads();
    if (tid < 64) {
        float s = 0.f;
#pragma unroll
        for (int d = 0; d < 64; d++) { float q = Qs[tid][d]; s = fmaf(q, q, s); }
        scaleS[tid] = __expf(-0.5f * s) * 0.0625f;  // 1/sqrt(256)
    }
    __syncthreads();

    const int tt = (tid >> 4) << 2;
    const int tm = (tid & 15) << 2;
    float c[4][4];
#pragma unroll
    for (int i = 0; i < 4; i++)
#pragma unroll
        for (int j = 0; j < 4; j++) c[i][j] = 0.f;

#pragma unroll 16
    for (int d = 0; d < 64; d++) {
        float a0 = Qs[tt+0][d], a1 = Qs[tt+1][d], a2 = Qs[tt+2][d], a3 = Qs[tt+3][d];
        float4 bb = *(float4*)&Rs[d][tm];
        c[0][0] = fmaf(a0, bb.x, c[0][0]); c[0][1] = fmaf(a0, bb.y, c[0][1]);
        c[0][2] = fmaf(a0, bb.z, c[0][2]); c[0][3] = fmaf(a0, bb.w, c[0][3]);
        c[1][0] = fmaf(a1, bb.x, c[1][0]); c[1][1] = fmaf(a1, bb.y, c[1][1]);
        c[1][2] = fmaf(a1, bb.z, c[1][2]); c[1][3] = fmaf(a1, bb.w, c[1][3]);
        c[2][0] = fmaf(a2, bb.x, c[2][0]); c[2][1] = fmaf(a2, bb.y, c[2][1]);
        c[2][2] = fmaf(a2, bb.z, c[2][2]); c[2][3] = fmaf(a2, bb.w, c[2][3]);
        c[3][0] = fmaf(a3, bb.x, c[3][0]); c[3][1] = fmaf(a3, bb.y, c[3][1]);
        c[3][2] = fmaf(a3, bb.z, c[3][2]); c[3][3] = fmaf(a3, bb.w, c[3][3]);
    }

#pragma unroll
    for (int i = 0; i < 4; i++) {
        float sc = scaleS[tt + i];
        size_t rb = ((size_t)bh * T_ + t0 + tt + i) * FD_ + m0 + tm;
#pragma unroll
        for (int j = 0; j < 4; j++) {
            float s_, c_;
            fast_sincos(c[i][j], s_, c_);
            dst[rb + j]       = c_ * sc;
            dst[rb + 256 + j] = s_ * sc;
        }
    }
}

// ---------------- KV = Kf^T V  (+ K_sum) ----------------
__global__ __launch_bounds__(256) void kv_kernel(const float* __restrict__ Kf,  // [BH,T,512]
                                                 const float* __restrict__ V,   // [B,T,D]
                                                 float* __restrict__ KVo,       // [BH,512,64]
                                                 float* __restrict__ Ksum)      // [BH,512]
{
    __shared__ float Ks[64][68];  // [t][m]
    __shared__ float Vs[64][68];  // [t][v]
    __shared__ float red[256];
    const int tid = threadIdx.x;
    const int m0  = blockIdx.x << 6;
    const int bh  = blockIdx.y;
    const int b   = bh >> 4, h = bh & 15;
    const int ta  = (tid >> 4) << 2;
    const int tv  = (tid & 15) << 2;
    const int mk  = tid & 63;
    const int tg  = tid >> 6;

    float c[4][4];
#pragma unroll
    for (int i = 0; i < 4; i++)
#pragma unroll
        for (int j = 0; j < 4; j++) c[i][j] = 0.f;
    float ksum = 0.f;

    for (int t0 = 0; t0 < T_; t0 += 64) {
#pragma unroll
        for (int i = 0; i < 4; i++) {
            int idx = tid + (i << 8);
            int r   = idx >> 4;
            int c4  = (idx & 15) << 2;
            *(float4*)&Ks[r][c4] = *(const float4*)&Kf[((size_t)bh * T_ + t0 + r) * FD_ + m0 + c4];
            *(float4*)&Vs[r][c4] = *(const float4*)&V[((size_t)(b * T_ + t0 + r)) * D_ + h * DH_ + c4];
        }
        __syncthreads();
#pragma unroll 16
        for (int t = 0; t < 64; t++) {
            float4 a  = *(float4*)&Ks[t][ta];
            float4 bb = *(float4*)&Vs[t][tv];
            c[0][0] = fmaf(a.x, bb.x, c[0][0]); c[0][1] = fmaf(a.x, bb.y, c[0][1]);
            c[0][2] = fmaf(a.x, bb.z, c[0][2]); c[0][3] = fmaf(a.x, bb.w, c[0][3]);
            c[1][0] = fmaf(a.y, bb.x, c[1][0]); c[1][1] = fmaf(a.y, bb.y, c[1][1]);
            c[1][2] = fmaf(a.y, bb.z, c[1][2]); c[1][3] = fmaf(a.y, bb.w, c[1][3]);
            c[2][0] = fmaf(a.z, bb.x, c[2][0]); c[2][1] = fmaf(a.z, bb.y, c[2][1]);
            c[2][2] = fmaf(a.z, bb.z, c[2][2]); c[2][3] = fmaf(a.z, bb.w, c[2][3]);
            c[3][0] = fmaf(a.w, bb.x, c[3][0]); c[3][1] = fmaf(a.w, bb.y, c[3][1]);
            c[3][2] = fmaf(a.w, bb.z, c[3][2]); c[3][3] = fmaf(a.w, bb.w, c[3][3]);
        }
#pragma unroll
        for (int t = tg * 16; t < tg * 16 + 16; t++) ksum += Ks[t][mk];
        __syncthreads();
    }
#pragma unroll
    for (int i = 0; i < 4; i++) {
        *(float4*)&KVo[((size_t)bh * FD_ + m0 + ta + i) * DH_ + tv] =
            make_float4(c[i][0], c[i][1], c[i][2], c[i][3]);
    }
    red[tid] = ksum;
    __syncthreads();
    if (tid < 64)
        Ksum[(size_t)bh * FD_ + m0 + tid] = red[tid] + red[tid+64] + red[tid+128] + red[tid+192];
}

// ---------------- Z = Qf . K_sum ----------------
__global__ __launch_bounds__(256) void z_kernel(const float* __restrict__ Qf,
                                                const float* __restrict__ Ksum,
                                                float* __restrict__ Z)
{
    const int warp = threadIdx.x >> 5, lane = threadIdx.x & 31;
    const size_t row = (size_t)blockIdx.x * 8 + warp;  // < BH*T
    const int bh = (int)(row >> 12);                   // T = 4096
    const float* q  = Qf + row * FD_;
    const float* ks = Ksum + (size_t)bh * FD_;
    float s = 0.f;
#pragma unroll
    for (int i = lane * 4; i < FD_; i += 128) {
        float4 a = *(const float4*)&q[i];
        float4 b = *(const float4*)&ks[i];
        s = fmaf(a.x, b.x, s); s = fmaf(a.y, b.y, s);
        s = fmaf(a.z, b.z, s); s = fmaf(a.w, b.w, s);
    }
#pragma unroll
    for (int o = 16; o; o >>= 1) s += __shfl_xor_sync(0xffffffffu, s, o);
    if (lane == 0) Z[row] = s;
}

// ---------------- attn = (Qf KV) / max(Z,1e-6) ----------------
__global__ __launch_bounds__(256) void qkv_kernel(const float* __restrict__ Qf,  // [BH,T,512]
                                                  const float* __restrict__ KVi, // [BH,512,64]
                                                  const float* __restrict__ Z,   // [BH,T]
                                                  float* __restrict__ attn)      // [B,T,D]
{
    __shared__ float Qs[64][68];  // [t][m-chunk]
    __shared__ float Ws[64][68];  // [m][v]
    const int tid = threadIdx.x;
    const int t0  = blockIdx.x << 6;
    const int bh  = blockIdx.y;
    const int b   = bh >> 4, h = bh & 15;
    const int tt  = (tid >> 4) << 2;
    const int tv  = (tid & 15) << 2;

    float c[4][4];
#pragma unroll
    for (int i = 0; i < 4; i++)
#pragma unroll
        for (int j = 0; j < 4; j++) c[i][j] = 0.f;

    for (int m0 = 0; m0 < FD_; m0 += 64) {
#pragma unroll
        for (int i = 0; i < 4; i++) {
            int idx = tid + (i << 8);
            int r   = idx >> 4;
            int c4  = (idx & 15) << 2;
            *(float4*)&Qs[r][c4] = *(const float4*)&Qf[((size_t)bh * T_ + t0 + r) * FD_ + m0 + c4];
            *(float4*)&Ws[r][c4] = *(const float4*)&KVi[((size_t)bh * FD_ + m0 + r) * DH_ + c4];
        }
        __syncthreads();
#pragma unroll 16
        for (int m = 0; m < 64; m++) {
            float a0 = Qs[tt+0][m], a1 = Qs[tt+1][m], a2 = Qs[tt+2][m], a3 = Qs[tt+3][m];
            float4 bb = *(float4*)&Ws[m][tv];
            c[0][0] = fmaf(a0, bb.x, c[0][0]); c[0][1] = fmaf(a0, bb.y, c[0][1]);
            c[0][2] = fmaf(a0, bb.z, c[0][2]); c[0][3] = fmaf(a0, bb.w, c[0][3]);
            c[1][0] = fmaf(a1, bb.x, c[1][0]); c[1][1] = fmaf(a1, bb.y, c[1][1]);
            c[1][2] = fmaf(a1, bb.z, c[1][2]); c[1][3] = fmaf(a1, bb.w, c[1][3]);
            c[2][0] = fmaf(a2, bb.x, c[2][0]); c[2][1] = fmaf(a2, bb.y, c[2][1]);
            c[2][2] = fmaf(a2, bb.z, c[2][2]); c[2][3] = fmaf(a2, bb.w, c[2][3]);
            c[3][0] = fmaf(a3, bb.x, c[3][0]); c[3][1] = fmaf(a3, bb.y, c[3][1]);
            c[3][2] = fmaf(a3, bb.z, c[3][2]); c[3][3] = fmaf(a3, bb.w, c[3][3]);
        }
        __syncthreads();
    }
#pragma unroll
    for (int i = 0; i < 4; i++) {
        float z   = fmaxf(Z[(size_t)bh * T_ + t0 + tt + i], 1e-6f);
        float inv = 1.0f / z;
        *(float4*)&attn[((size_t)(b * T_ + t0 + tt + i)) * D_ + h * DH_ + tv] =
            make_float4(c[i][0]*inv, c[i][1]*inv, c[i][2]*inv, c[i][3]*inv);
    }
}

// ---------------- launch ----------------
extern "C" void kernel_launch(void* const* d_in, const int* in_sizes, int n_in,
                              void* d_out, int out_size)
{
    const float* x  = (const float*)d_in[0];
    const float* wq = (const float*)d_in[1];
    const float* wk = (const float*)d_in[2];
    const float* wv = (const float*)d_in[3];
    const float* wo = (const float*)d_in[4];
    const float* rf = (const float*)d_in[5];
    float* out = (float*)d_out;

    float* base = nullptr;
    cudaGetSymbolAddress((void**)&base, g_buf);
    float* Qp    = base + OFF_Q;
    float* Kp    = base + OFF_K;
    float* Vp    = base + OFF_V;
    float* attnp = base + OFF_ATTN;
    float* Qfp   = base + OFF_QF;
    float* Kfp   = base + OFF_KF;
    float* KVp   = base + OFF_KV;
    float* Ksp   = base + OFF_KS;
    float* Zp    = base + OFF_Z;

    dim3 gG(D_ / 128, (B_ * T_) / 128);  // (8, 64)
    sgemm_nt<<<gG, 256>>>(x, wq, Qp, B_ * T_, D_, D_);
    sgemm_nt<<<gG, 256>>>(x, wk, Kp, B_ * T_, D_, D_);
    sgemm_nt<<<gG, 256>>>(x, wv, Vp, B_ * T_, D_, D_);

    dim3 gPhi(T_ / 64, MRF_ / 64, BH_);  // (64, 4, 32)
    phi_kernel<<<gPhi, 256>>>(Qp, rf, Qfp);
    phi_kernel<<<gPhi, 256>>>(Kp, rf, Kfp);

    kv_kernel<<<dim3(FD_ / 64, BH_), 256>>>(Kfp, Vp, KVp, Ksp);
    z_kernel<<<(BH_ * T_) / 8, 256>>>(Qfp, Ksp, Zp);
    qkv_kernel<<<dim3(T_ / 64, BH_), 256>>>(Qfp, KVp, Zp, attnp);

    sgemm_nt<<<gG, 256>>>(attnp, wo, out, B_ * T_, D_, D_);
}

// round 3
// speedup vs baseline: 1.7357x; 1.7357x over previous
#include <cuda_runtime.h>
#include <cuda_bf16.h>
#include <cstdint>

#define B_   2
#define T_   4096
#define D_   1024
#define H_   16
#define DH_  64
#define MRF_ 256
#define FD_  512            // 2m
#define BH_  (B_*H_)

// ---------------- scratch (no cudaMalloc allowed) ----------------
#define SZ_BTD  ((size_t)B_*T_*D_)            // 8,388,608
#define SZ_F    ((size_t)BH_*T_*FD_)          // 67,108,864
#define OFF_Q    ((size_t)0)
#define OFF_K    (SZ_BTD)
#define OFF_V    (2*SZ_BTD)
#define OFF_QF   (3*SZ_BTD)
#define OFF_KF   (OFF_QF + SZ_F)
#define OFF_KV   (OFF_KF + SZ_F)
#define OFF_KS   (OFF_KV + (size_t)BH_*FD_*DH_)
#define OFF_Z    (OFF_KS + (size_t)BH_*FD_)
#define TOTAL_F  (OFF_Z + (size_t)BH_*T_)
__device__ float g_buf[TOTAL_F];

// bf16 scratch: x hi/lo, 4 weights hi/lo, attn hi/lo
#define BOFF_XH   ((size_t)0)
#define BOFF_XL   (SZ_BTD)
#define BOFF_W    (2*SZ_BTD)
#define BOFF_AH   (BOFF_W + 8*(size_t)D_*D_)
#define BOFF_AL   (BOFF_AH + SZ_BTD)
#define TOTAL_BF  (BOFF_AL + SZ_BTD)
__device__ __nv_bfloat16 g_bf[TOTAL_BF];

// ================= portable PTX helpers (compute_103-safe) =================
__device__ __forceinline__ uint32_t smem_to_u32(const void* p) {
    uint32_t a;
    asm("{ .reg .u64 t; cvta.to.shared.u64 t, %1; cvt.u32.u64 %0, t; }" : "=r"(a) : "l"(p));
    return a;
}
#define SWZ(o) ((o) ^ (((o) >> 3) & 0x70))

__device__ __forceinline__ void cp_async16(uint32_t saddr, const void* g) {
    asm volatile("cp.async.cg.shared.global [%0], [%1], 16;" :: "r"(saddr), "l"(g));
}
__device__ __forceinline__ void cp_commit() {
    asm volatile("cp.async.commit_group;" ::: "memory");
}
template <int N>
__device__ __forceinline__ void cp_wait() {
    asm volatile("cp.async.wait_group %0;" :: "n"(N) : "memory");
}

__device__ __forceinline__ void ldsm_x4(uint32_t& r0, uint32_t& r1, uint32_t& r2, uint32_t& r3,
                                        uint32_t a) {
    asm volatile("ldmatrix.sync.aligned.m8n8.x4.shared.b16 {%0,%1,%2,%3}, [%4];"
                 : "=r"(r0), "=r"(r1), "=r"(r2), "=r"(r3) : "r"(a));
}
__device__ __forceinline__ void ldsm_x2(uint32_t& r0, uint32_t& r1, uint32_t a) {
    asm volatile("ldmatrix.sync.aligned.m8n8.x2.shared.b16 {%0,%1}, [%2];"
                 : "=r"(r0), "=r"(r1) : "r"(a));
}
__device__ __forceinline__ void mma_bf16(float* c, const uint32_t* a, const uint32_t* b) {
    asm volatile("mma.sync.aligned.m16n8k16.row.col.f32.bf16.bf16.f32 "
                 "{%0,%1,%2,%3}, {%4,%5,%6,%7}, {%8,%9}, {%0,%1,%2,%3};"
                 : "+f"(c[0]), "+f"(c[1]), "+f"(c[2]), "+f"(c[3])
                 : "r"(a[0]), "r"(a[1]), "r"(a[2]), "r"(a[3]), "r"(b[0]), "r"(b[1]));
}

// ============ bf16x3 mma.sync GEMM: C[M,N] = A[M,K] * B[N,K]^T ============
#define TILE_B   16384                 // 128 rows x 128B
#define BUF_B    (4*TILE_B)            // Ah, Al, Bh, Bl
#define SMEM_TOTAL_MMA (2*BUF_B)       // double buffered: 128KB

__global__ void __launch_bounds__(256)
mma_gemm(const __nv_bfloat16* __restrict__ Ah, const __nv_bfloat16* __restrict__ Al,
         const __nv_bfloat16* __restrict__ Bh, const __nv_bfloat16* __restrict__ Bl,
         float* __restrict__ C, int M, int N, int K)
{
    extern __shared__ char smem[];
    const uint32_t sb = smem_to_u32(smem);
    const int tid  = threadIdx.x, wid = tid >> 5, lane = tid & 31;
    const int bn   = blockIdx.x << 7, bm = blockIdx.y << 7;
    const int wm   = (wid >> 2) << 6;   // warp m offset (0/64)
    const int wn   = (wid & 3) << 5;    // warp n offset (0/32/64/96)
    const int nchunk = K >> 6;

    float acc[4][4][4];
#pragma unroll
    for (int i = 0; i < 4; i++)
#pragma unroll
        for (int j = 0; j < 4; j++)
#pragma unroll
            for (int r = 0; r < 4; r++) acc[i][j][r] = 0.f;

    const __nv_bfloat16* gsrc[4] = {Ah, Al, Bh, Bl};
    const int rowbase[4] = {bm, bm, bn, bn};

    auto load_chunk = [&](int kc, int buf) {
        uint32_t base = sb + buf * BUF_B;
        const int kcE = kc << 6;
#pragma unroll
        for (int t = 0; t < 4; t++) {
#pragma unroll
            for (int i = 0; i < 4; i++) {
                int idx = tid + (i << 8);
                int r = idx >> 3, c = idx & 7;
                const void* g = gsrc[t] + (size_t)(rowbase[t] + r) * K + kcE + c * 8;
                cp_async16(base + t * TILE_B + SWZ(r * 128 + c * 16), g);
            }
        }
    };

    auto compute_chunk = [&](int buf) {
        uint32_t bAh = sb + buf * BUF_B;
        uint32_t bAl = bAh + TILE_B;
        uint32_t bBh = bAl + TILE_B;
        uint32_t bBl = bBh + TILE_B;
        const int lr = lane & 15, lc = lane >> 4;     // A ldmatrix addressing
        const int br = lane & 7,  bk = (lane >> 3) & 1; // B ldmatrix addressing
#pragma unroll
        for (int ks = 0; ks < 4; ks++) {
            uint32_t ah[4][4], al[4][4], bh[4][2], bl[4][2];
#pragma unroll
            for (int i = 0; i < 4; i++) {
                int off = SWZ((wm + i * 16 + lr) * 128 + ks * 32 + lc * 16);
                ldsm_x4(ah[i][0], ah[i][1], ah[i][2], ah[i][3], bAh + off);
                ldsm_x4(al[i][0], al[i][1], al[i][2], al[i][3], bAl + off);
            }
#pragma unroll
            for (int j = 0; j < 4; j++) {
                int off = SWZ((wn + j * 8 + br) * 128 + ks * 32 + bk * 16);
                ldsm_x2(bh[j][0], bh[j][1], bBh + off);
                ldsm_x2(bl[j][0], bl[j][1], bBl + off);
            }
#pragma unroll
            for (int i = 0; i < 4; i++)
#pragma unroll
                for (int j = 0; j < 4; j++) {
                    mma_bf16(acc[i][j], ah[i], bh[j]);
                    mma_bf16(acc[i][j], ah[i], bl[j]);
                    mma_bf16(acc[i][j], al[i], bh[j]);
                }
        }
    };

    load_chunk(0, 0);
    cp_commit();
    for (int kc = 0; kc < nchunk; kc++) {
        int cur = kc & 1;
        if (kc + 1 < nchunk) {
            load_chunk(kc + 1, cur ^ 1);
            cp_commit();
            cp_wait<1>();
        } else {
            cp_wait<0>();
        }
        __syncthreads();
        compute_chunk(cur);
        __syncthreads();
    }

    // epilogue: direct fragment stores (8B, aligned, coalesced within quads)
#pragma unroll
    for (int i = 0; i < 4; i++) {
        int row = bm + wm + i * 16 + (lane >> 2);
#pragma unroll
        for (int j = 0; j < 4; j++) {
            int col = bn + wn + j * 8 + ((lane & 3) << 1);
            *(float2*)&C[(size_t)row * N + col]       = make_float2(acc[i][j][0], acc[i][j][1]);
            *(float2*)&C[(size_t)(row + 8) * N + col] = make_float2(acc[i][j][2], acc[i][j][3]);
        }
    }
}

// ---------------- fp32 -> bf16 hi/lo split ----------------
__device__ __forceinline__ uint32_t pack_bf2(float a, float b) {
    __nv_bfloat162 t(__float2bfloat16(a), __float2bfloat16(b));
    return *(uint32_t*)&t;
}
__global__ void __launch_bounds__(256) split_kernel(const float* __restrict__ in,
                                                    __nv_bfloat16* __restrict__ hi,
                                                    __nv_bfloat16* __restrict__ lo, int n4)
{
    int i = blockIdx.x * 256 + threadIdx.x;
    if (i >= n4) return;
    float4 v = ((const float4*)in)[i];
    __nv_bfloat16 h0 = __float2bfloat16(v.x), h1 = __float2bfloat16(v.y);
    __nv_bfloat16 h2 = __float2bfloat16(v.z), h3 = __float2bfloat16(v.w);
    float l0 = v.x - __bfloat162float(h0), l1 = v.y - __bfloat162float(h1);
    float l2 = v.z - __bfloat162float(h2), l3 = v.w - __bfloat162float(h3);
    __nv_bfloat162 ph0(h0, h1), ph1(h2, h3);
    uint2 hp; hp.x = *(uint32_t*)&ph0; hp.y = *(uint32_t*)&ph1;
    ((uint2*)hi)[i] = hp;
    uint2 lp; lp.x = pack_bf2(l0, l1); lp.y = pack_bf2(l2, l3);
    ((uint2*)lo)[i] = lp;
}

// ---------------- fast sincos on the FMA pipe ----------------
__device__ __forceinline__ void fast_sincos(float x, float& s, float& c) {
    float kf = rintf(x * 0.63661977f);
    int   q  = (int)kf;
    float r  = fmaf(kf, -1.5707963705062866f, x);
    r        = fmaf(kf,  4.3711388286738e-8f, r);
    float r2 = r * r;
    float sp = fmaf(-1.98412698e-4f, r2, 8.33333333e-3f);
    sp       = fmaf(sp, r2, -1.66666667e-1f);
    sp      *= r2;
    float sr = fmaf(sp, r, r);
    float cp = fmaf(2.48015873e-5f, r2, -1.38888889e-3f);
    cp       = fmaf(cp, r2, 4.16666667e-2f);
    cp       = fmaf(cp, r2, -0.5f);
    float cr = fmaf(cp, r2, 1.0f);
    if (q & 1) { float t = sr; sr = cr; cr = -t; }
    if (q & 2) { sr = -sr; cr = -cr; }
    s = sr; c = cr;
}

// ---------------- phi ----------------
__global__ void __launch_bounds__(256) phi_kernel(const float* __restrict__ src,
                                                  const float* __restrict__ rf,
                                                  float* __restrict__ dst)
{
    __shared__ float Qs[64][68];
    __shared__ float Rs[64][68];
    __shared__ float scaleS[64];
    const int tid = threadIdx.x;
    const int t0  = blockIdx.x << 6;
    const int m0  = blockIdx.y << 6;
    const int bh  = blockIdx.z;
    const int b   = bh >> 4, h = bh & 15;

#pragma unroll
    for (int i = 0; i < 4; i++) {
        int idx = tid + (i << 8);
        int r   = idx >> 4;
        int c4  = (idx & 15) << 2;
        float4 q = *(const float4*)&src[((size_t)(b * T_ + t0 + r)) * D_ + h * DH_ + c4];
        *(float4*)&Qs[r][c4] = q;
        float4 w = *(const float4*)&rf[(size_t)(m0 + r) * DH_ + c4];
        Rs[c4+0][r] = w.x; Rs[c4+1][r] = w.y; Rs[c4+2][r] = w.z; Rs[c4+3][r] = w.w;
    }
    __syncthreads();
    if (tid < 64) {
        float s = 0.f;
#pragma unroll
        for (int d = 0; d < 64; d++) { float q = Qs[tid][d]; s = fmaf(q, q, s); }
        scaleS[tid] = __expf(-0.5f * s) * 0.0625f;
    }
    __syncthreads();

    const int tt = (tid >> 4) << 2;
    const int tm = (tid & 15) << 2;
    float c[4][4];
#pragma unroll
    for (int i = 0; i < 4; i++)
#pragma unroll
        for (int j = 0; j < 4; j++) c[i][j] = 0.f;

#pragma unroll 16
    for (int d = 0; d < 64; d++) {
        float a0 = Qs[tt+0][d], a1 = Qs[tt+1][d], a2 = Qs[tt+2][d], a3 = Qs[tt+3][d];
        float4 bb = *(float4*)&Rs[d][tm];
        c[0][0] = fmaf(a0, bb.x, c[0][0]); c[0][1] = fmaf(a0, bb.y, c[0][1]);
        c[0][2] = fmaf(a0, bb.z, c[0][2]); c[0][3] = fmaf(a0, bb.w, c[0][3]);
        c[1][0] = fmaf(a1, bb.x, c[1][0]); c[1][1] = fmaf(a1, bb.y, c[1][1]);
        c[1][2] = fmaf(a1, bb.z, c[1][2]); c[1][3] = fmaf(a1, bb.w, c[1][3]);
        c[2][0] = fmaf(a2, bb.x, c[2][0]); c[2][1] = fmaf(a2, bb.y, c[2][1]);
        c[2][2] = fmaf(a2, bb.z, c[2][2]); c[2][3] = fmaf(a2, bb.w, c[2][3]);
        c[3][0] = fmaf(a3, bb.x, c[3][0]); c[3][1] = fmaf(a3, bb.y, c[3][1]);
        c[3][2] = fmaf(a3, bb.z, c[3][2]); c[3][3] = fmaf(a3, bb.w, c[3][3]);
    }

#pragma unroll
    for (int i = 0; i < 4; i++) {
        float sc = scaleS[tt + i];
        size_t rb = ((size_t)bh * T_ + t0 + tt + i) * FD_ + m0 + tm;
#pragma unroll
        for (int j = 0; j < 4; j++) {
            float s_, c_;
            fast_sincos(c[i][j], s_, c_);
            dst[rb + j]       = c_ * sc;
            dst[rb + 256 + j] = s_ * sc;
        }
    }
}

// ---------------- KV = Kf^T V (+ K_sum) ----------------
__global__ void __launch_bounds__(256) kv_kernel(const float* __restrict__ Kf,
                                                 const float* __restrict__ V,
                                                 float* __restrict__ KVo,
                                                 float* __restrict__ Ksum)
{
    __shared__ float Ks[64][68];
    __shared__ float Vs[64][68];
    __shared__ float red[256];
    const int tid = threadIdx.x;
    const int m0  = blockIdx.x << 6;
    const int bh  = blockIdx.y;
    const int b   = bh >> 4, h = bh & 15;
    const int ta  = (tid >> 4) << 2;
    const int tv  = (tid & 15) << 2;
    const int mk  = tid & 63;
    const int tg  = tid >> 6;

    float c[4][4];
#pragma unroll
    for (int i = 0; i < 4; i++)
#pragma unroll
        for (int j = 0; j < 4; j++) c[i][j] = 0.f;
    float ksum = 0.f;

    for (int t0 = 0; t0 < T_; t0 += 64) {
#pragma unroll
        for (int i = 0; i < 4; i++) {
            int idx = tid + (i << 8);
            int r   = idx >> 4;
            int c4  = (idx & 15) << 2;
            *(float4*)&Ks[r][c4] = *(const float4*)&Kf[((size_t)bh * T_ + t0 + r) * FD_ + m0 + c4];
            *(float4*)&Vs[r][c4] = *(const float4*)&V[((size_t)(b * T_ + t0 + r)) * D_ + h * DH_ + c4];
        }
        __syncthreads();
#pragma unroll 16
        for (int t = 0; t < 64; t++) {
            float4 a  = *(float4*)&Ks[t][ta];
            float4 bb = *(float4*)&Vs[t][tv];
            c[0][0] = fmaf(a.x, bb.x, c[0][0]); c[0][1] = fmaf(a.x, bb.y, c[0][1]);
            c[0][2] = fmaf(a.x, bb.z, c[0][2]); c[0][3] = fmaf(a.x, bb.w, c[0][3]);
            c[1][0] = fmaf(a.y, bb.x, c[1][0]); c[1][1] = fmaf(a.y, bb.y, c[1][1]);
            c[1][2] = fmaf(a.y, bb.z, c[1][2]); c[1][3] = fmaf(a.y, bb.w, c[1][3]);
            c[2][0] = fmaf(a.z, bb.x, c[2][0]); c[2][1] = fmaf(a.z, bb.y, c[2][1]);
            c[2][2] = fmaf(a.z, bb.z, c[2][2]); c[2][3] = fmaf(a.z, bb.w, c[2][3]);
            c[3][0] = fmaf(a.w, bb.x, c[3][0]); c[3][1] = fmaf(a.w, bb.y, c[3][1]);
            c[3][2] = fmaf(a.w, bb.z, c[3][2]); c[3][3] = fmaf(a.w, bb.w, c[3][3]);
        }
#pragma unroll
        for (int t = tg * 16; t < tg * 16 + 16; t++) ksum += Ks[t][mk];
        __syncthreads();
    }
#pragma unroll
    for (int i = 0; i < 4; i++) {
        *(float4*)&KVo[((size_t)bh * FD_ + m0 + ta + i) * DH_ + tv] =
            make_float4(c[i][0], c[i][1], c[i][2], c[i][3]);
    }
    red[tid] = ksum;
    __syncthreads();
    if (tid < 64)
        Ksum[(size_t)bh * FD_ + m0 + tid] = red[tid] + red[tid+64] + red[tid+128] + red[tid+192];
}

// ---------------- Z = Qf . K_sum ----------------
__global__ void __launch_bounds__(256) z_kernel(const float* __restrict__ Qf,
                                                const float* __restrict__ Ksum,
                                                float* __restrict__ Z)
{
    const int warp = threadIdx.x >> 5, lane = threadIdx.x & 31;
    const size_t row = (size_t)blockIdx.x * 8 + warp;
    const int bh = (int)(row >> 12);
    const float* q  = Qf + row * FD_;
    const float* ks = Ksum + (size_t)bh * FD_;
    float s = 0.f;
#pragma unroll
    for (int i = lane * 4; i < FD_; i += 128) {
        float4 a = *(const float4*)&q[i];
        float4 b = *(const float4*)&ks[i];
        s = fmaf(a.x, b.x, s); s = fmaf(a.y, b.y, s);
        s = fmaf(a.z, b.z, s); s = fmaf(a.w, b.w, s);
    }
#pragma unroll
    for (int o = 16; o; o >>= 1) s += __shfl_xor_sync(0xffffffffu, s, o);
    if (lane == 0) Z[row] = s;
}

// ---------------- attn = (Qf KV)/max(Z,1e-6) -> bf16 hi/lo ----------------
__global__ void __launch_bounds__(256) qkv_kernel(const float* __restrict__ Qf,
                                                  const float* __restrict__ KVi,
                                                  const float* __restrict__ Z,
                                                  __nv_bfloat16* __restrict__ ah,
                                                  __nv_bfloat16* __restrict__ al)
{
    __shared__ float Qs[64][68];
    __shared__ float Ws[64][68];
    const int tid = threadIdx.x;
    const int t0  = blockIdx.x << 6;
    const int bh  = blockIdx.y;
    const int b   = bh >> 4, h = bh & 15;
    const int tt  = (tid >> 4) << 2;
    const int tv  = (tid & 15) << 2;

    float c[4][4];
#pragma unroll
    for (int i = 0; i < 4; i++)
#pragma unroll
        for (int j = 0; j < 4; j++) c[i][j] = 0.f;

    for (int m0 = 0; m0 < FD_; m0 += 64) {
#pragma unroll
        for (int i = 0; i < 4; i++) {
            int idx = tid + (i << 8);
            int r   = idx >> 4;
            int c4  = (idx & 15) << 2;
            *(float4*)&Qs[r][c4] = *(const float4*)&Qf[((size_t)bh * T_ + t0 + r) * FD_ + m0 + c4];
            *(float4*)&Ws[r][c4] = *(const float4*)&KVi[((size_t)bh * FD_ + m0 + r) * DH_ + c4];
        }
        __syncthreads();
#pragma unroll 16
        for (int m = 0; m < 64; m++) {
            float a0 = Qs[tt+0][m], a1 = Qs[tt+1][m], a2 = Qs[tt+2][m], a3 = Qs[tt+3][m];
            float4 bb = *(float4*)&Ws[m][tv];
            c[0][0] = fmaf(a0, bb.x, c[0][0]); c[0][1] = fmaf(a0, bb.y, c[0][1]);
            c[0][2] = fmaf(a0, bb.z, c[0][2]); c[0][3] = fmaf(a0, bb.w, c[0][3]);
            c[1][0] = fmaf(a1, bb.x, c[1][0]); c[1][1] = fmaf(a1, bb.y, c[1][1]);
            c[1][2] = fmaf(a1, bb.z, c[1][2]); c[1][3] = fmaf(a1, bb.w, c[1][3]);
            c[2][0] = fmaf(a2, bb.x, c[2][0]); c[2][1] = fmaf(a2, bb.y, c[2][1]);
            c[2][2] = fmaf(a2, bb.z, c[2][2]); c[2][3] = fmaf(a2, bb.w, c[2][3]);
            c[3][0] = fmaf(a3, bb.x, c[3][0]); c[3][1] = fmaf(a3, bb.y, c[3][1]);
            c[3][2] = fmaf(a3, bb.z, c[3][2]); c[3][3] = fmaf(a3, bb.w, c[3][3]);
        }
        __syncthreads();
    }
#pragma unroll
    for (int i = 0; i < 4; i++) {
        float z   = fmaxf(Z[(size_t)bh * T_ + t0 + tt + i], 1e-6f);
        float inv = 1.0f / z;
        size_t base = ((size_t)(b * T_ + t0 + tt + i)) * D_ + h * DH_ + tv;
        float v0 = c[i][0]*inv, v1 = c[i][1]*inv, v2 = c[i][2]*inv, v3 = c[i][3]*inv;
        __nv_bfloat16 h0 = __float2bfloat16(v0), h1 = __float2bfloat16(v1);
        __nv_bfloat16 h2 = __float2bfloat16(v2), h3 = __float2bfloat16(v3);
        __nv_bfloat162 hp0(h0, h1), hp1(h2, h3);
        uint2 hp; hp.x = *(uint32_t*)&hp0; hp.y = *(uint32_t*)&hp1;
        *(uint2*)&ah[base] = hp;
        uint2 lp;
        lp.x = pack_bf2(v0 - __bfloat162float(h0), v1 - __bfloat162float(h1));
        lp.y = pack_bf2(v2 - __bfloat162float(h2), v3 - __bfloat162float(h3));
        *(uint2*)&al[base] = lp;
    }
}

// ---------------- launch ----------------
extern "C" void kernel_launch(void* const* d_in, const int* in_sizes, int n_in,
                              void* d_out, int out_size)
{
    const float* x  = (const float*)d_in[0];
    const float* wq = (const float*)d_in[1];
    const float* wk = (const float*)d_in[2];
    const float* wv = (const float*)d_in[3];
    const float* wo = (const float*)d_in[4];
    const float* rf = (const float*)d_in[5];
    float* out = (float*)d_out;

    float* fbase = nullptr;
    cudaGetSymbolAddress((void**)&fbase, g_buf);
    __nv_bfloat16* bbase = nullptr;
    cudaGetSymbolAddress((void**)&bbase, g_bf);

    float* Qp  = fbase + OFF_Q;
    float* Kp  = fbase + OFF_K;
    float* Vp  = fbase + OFF_V;
    float* Qfp = fbase + OFF_QF;
    float* Kfp = fbase + OFF_KF;
    float* KVp = fbase + OFF_KV;
    float* Ksp = fbase + OFF_KS;
    float* Zp  = fbase + OFF_Z;

    __nv_bfloat16* xh  = bbase + BOFF_XH;
    __nv_bfloat16* xl  = bbase + BOFF_XL;
    __nv_bfloat16* wqh = bbase + BOFF_W + 0*(size_t)D_*D_;
    __nv_bfloat16* wql = bbase + BOFF_W + 1*(size_t)D_*D_;
    __nv_bfloat16* wkh = bbase + BOFF_W + 2*(size_t)D_*D_;
    __nv_bfloat16* wkl = bbase + BOFF_W + 3*(size_t)D_*D_;
    __nv_bfloat16* wvh = bbase + BOFF_W + 4*(size_t)D_*D_;
    __nv_bfloat16* wvl = bbase + BOFF_W + 5*(size_t)D_*D_;
    __nv_bfloat16* woh = bbase + BOFF_W + 6*(size_t)D_*D_;
    __nv_bfloat16* wol = bbase + BOFF_W + 7*(size_t)D_*D_;
    __nv_bfloat16* ah  = bbase + BOFF_AH;
    __nv_bfloat16* al  = bbase + BOFF_AL;

    cudaFuncSetAttribute(mma_gemm, cudaFuncAttributeMaxDynamicSharedMemorySize, SMEM_TOTAL_MMA);

    // splits
    split_kernel<<<(int)(SZ_BTD/4/256), 256>>>(x, xh, xl, (int)(SZ_BTD/4));
    int wn4 = D_*D_/4;
    split_kernel<<<wn4/256, 256>>>(wq, wqh, wql, wn4);
    split_kernel<<<wn4/256, 256>>>(wk, wkh, wkl, wn4);
    split_kernel<<<wn4/256, 256>>>(wv, wvh, wvl, wn4);
    split_kernel<<<wn4/256, 256>>>(wo, woh, wol, wn4);

    // projections via mma.sync bf16x3
    dim3 gG(D_ / 128, (B_ * T_) / 128);  // (8, 64)
    mma_gemm<<<gG, 256, SMEM_TOTAL_MMA>>>(xh, xl, wqh, wql, Qp, B_ * T_, D_, D_);
    mma_gemm<<<gG, 256, SMEM_TOTAL_MMA>>>(xh, xl, wkh, wkl, Kp, B_ * T_, D_, D_);
    mma_gemm<<<gG, 256, SMEM_TOTAL_MMA>>>(xh, xl, wvh, wvl, Vp, B_ * T_, D_, D_);

    dim3 gPhi(T_ / 64, MRF_ / 64, BH_);
    phi_kernel<<<gPhi, 256>>>(Qp, rf, Qfp);
    phi_kernel<<<gPhi, 256>>>(Kp, rf, Kfp);

    kv_kernel<<<dim3(FD_ / 64, BH_), 256>>>(Kfp, Vp, KVp, Ksp);
    z_kernel<<<(BH_ * T_) / 8, 256>>>(Qfp, Ksp, Zp);
    qkv_kernel<<<dim3(T_ / 64, BH_), 256>>>(Qfp, KVp, Zp, ah, al);

    mma_gemm<<<gG, 256, SMEM_TOTAL_MMA>>>(ah, al, woh, wol, out, B_ * T_, D_, D_);
}

// round 4
// speedup vs baseline: 1.7393x; 1.0021x over previous
#include <cuda_runtime.h>
#include <cuda_bf16.h>
#include <cstdint>

#define B_   2
#define T_   4096
#define D_   1024
#define H_   16
#define DH_  64
#define MRF_ 256
#define FD_  512            // 2m
#define BH_  (B_*H_)

// ---------------- scratch (no cudaMalloc allowed) ----------------
#define SZ_BTD  ((size_t)B_*T_*D_)            // 8,388,608
#define SZ_F    ((size_t)BH_*T_*FD_)          // 67,108,864
#define OFF_Q    ((size_t)0)
#define OFF_K    (SZ_BTD)
#define OFF_V    (2*SZ_BTD)
#define OFF_QF   (3*SZ_BTD)
#define OFF_KF   (OFF_QF + SZ_F)
#define OFF_KV   (OFF_KF + SZ_F)
#define OFF_KS   (OFF_KV + (size_t)BH_*FD_*DH_)
#define OFF_Z    (OFF_KS + (size_t)BH_*FD_)
#define TOTAL_F  (OFF_Z + (size_t)BH_*T_)
__device__ float g_buf[TOTAL_F];

// bf16 scratch: x hi/lo, 4 weights hi/lo, attn hi/lo
#define BOFF_XH   ((size_t)0)
#define BOFF_XL   (SZ_BTD)
#define BOFF_W    (2*SZ_BTD)
#define BOFF_AH   (BOFF_W + 8*(size_t)D_*D_)
#define BOFF_AL   (BOFF_AH + SZ_BTD)
#define TOTAL_BF  (BOFF_AL + SZ_BTD)
__device__ __nv_bfloat16 g_bf[TOTAL_BF];

// ================= portable PTX helpers (compute_103-safe) =================
__device__ __forceinline__ uint32_t smem_to_u32(const void* p) {
    uint32_t a;
    asm("{ .reg .u64 t; cvta.to.shared.u64 t, %1; cvt.u32.u64 %0, t; }" : "=r"(a) : "l"(p));
    return a;
}
#define SWZ(o) ((o) ^ (((o) >> 3) & 0x70))

__device__ __forceinline__ void cp_async16(uint32_t saddr, const void* g) {
    asm volatile("cp.async.cg.shared.global [%0], [%1], 16;" :: "r"(saddr), "l"(g));
}
__device__ __forceinline__ void cp_commit() {
    asm volatile("cp.async.commit_group;" ::: "memory");
}
template <int N>
__device__ __forceinline__ void cp_wait() {
    asm volatile("cp.async.wait_group %0;" :: "n"(N) : "memory");
}

__device__ __forceinline__ void ldsm_x4(uint32_t& r0, uint32_t& r1, uint32_t& r2, uint32_t& r3,
                                        uint32_t a) {
    asm volatile("ldmatrix.sync.aligned.m8n8.x4.shared.b16 {%0,%1,%2,%3}, [%4];"
                 : "=r"(r0), "=r"(r1), "=r"(r2), "=r"(r3) : "r"(a));
}
__device__ __forceinline__ void ldsm_x2(uint32_t& r0, uint32_t& r1, uint32_t a) {
    asm volatile("ldmatrix.sync.aligned.m8n8.x2.shared.b16 {%0,%1}, [%2];"
                 : "=r"(r0), "=r"(r1) : "r"(a));
}
__device__ __forceinline__ void mma_bf16(float* c, const uint32_t* a, const uint32_t* b) {
    asm volatile("mma.sync.aligned.m16n8k16.row.col.f32.bf16.bf16.f32 "
                 "{%0,%1,%2,%3}, {%4,%5,%6,%7}, {%8,%9}, {%0,%1,%2,%3};"
                 : "+f"(c[0]), "+f"(c[1]), "+f"(c[2]), "+f"(c[3])
                 : "r"(a[0]), "r"(a[1]), "r"(a[2]), "r"(a[3]), "r"(b[0]), "r"(b[1]));
}

// ============ bf16x3 mma.sync GEMM: C[M,N] = A[M,K] * B[N,K]^T ============
#define TILE_B   16384                 // 128 rows x 128B
#define BUF_B    (4*TILE_B)            // Ah, Al, Bh, Bl
#define SMEM_TOTAL_MMA (2*BUF_B)       // double buffered: 128KB

__global__ void __launch_bounds__(256)
mma_gemm(const __nv_bfloat16* __restrict__ Ah, const __nv_bfloat16* __restrict__ Al,
         const __nv_bfloat16* __restrict__ Bh, const __nv_bfloat16* __restrict__ Bl,
         float* __restrict__ C, int M, int N, int K)
{
    extern __shared__ char smem[];
    const uint32_t sb = smem_to_u32(smem);
    const int tid  = threadIdx.x, wid = tid >> 5, lane = tid & 31;
    const int bn   = blockIdx.x << 7, bm = blockIdx.y << 7;
    const int wm   = (wid >> 2) << 6;   // warp m offset (0/64)
    const int wn   = (wid & 3) << 5;    // warp n offset (0/32/64/96)
    const int nchunk = K >> 6;

    float acc[4][4][4];
#pragma unroll
    for (int i = 0; i < 4; i++)
#pragma unroll
        for (int j = 0; j < 4; j++)
#pragma unroll
            for (int r = 0; r < 4; r++) acc[i][j][r] = 0.f;

    const __nv_bfloat16* gsrc[4] = {Ah, Al, Bh, Bl};
    const int rowbase[4] = {bm, bm, bn, bn};

    auto load_chunk = [&](int kc, int buf) {
        uint32_t base = sb + buf * BUF_B;
        const int kcE = kc << 6;
#pragma unroll
        for (int t = 0; t < 4; t++) {
#pragma unroll
            for (int i = 0; i < 4; i++) {
                int idx = tid + (i << 8);
                int r = idx >> 3, c = idx & 7;
                const void* g = gsrc[t] + (size_t)(rowbase[t] + r) * K + kcE + c * 8;
                cp_async16(base + t * TILE_B + SWZ(r * 128 + c * 16), g);
            }
        }
    };

    auto compute_chunk = [&](int buf) {
        uint32_t bAh = sb + buf * BUF_B;
        uint32_t bAl = bAh + TILE_B;
        uint32_t bBh = bAl + TILE_B;
        uint32_t bBl = bBh + TILE_B;
        const int lr = lane & 15, lc = lane >> 4;     // A ldmatrix addressing
        const int br = lane & 7,  bk = (lane >> 3) & 1; // B ldmatrix addressing
#pragma unroll
        for (int ks = 0; ks < 4; ks++) {
            uint32_t ah[4][4], al[4][4], bh[4][2], bl[4][2];
#pragma unroll
            for (int i = 0; i < 4; i++) {
                int off = SWZ((wm + i * 16 + lr) * 128 + ks * 32 + lc * 16);
                ldsm_x4(ah[i][0], ah[i][1], ah[i][2], ah[i][3], bAh + off);
                ldsm_x4(al[i][0], al[i][1], al[i][2], al[i][3], bAl + off);
            }
#pragma unroll
            for (int j = 0; j < 4; j++) {
                int off = SWZ((wn + j * 8 + br) * 128 + ks * 32 + bk * 16);
                ldsm_x2(bh[j][0], bh[j][1], bBh + off);
                ldsm_x2(bl[j][0], bl[j][1], bBl + off);
            }
#pragma unroll
            for (int i = 0; i < 4; i++)
#pragma unroll
                for (int j = 0; j < 4; j++) {
                    mma_bf16(acc[i][j], ah[i], bh[j]);
                    mma_bf16(acc[i][j], ah[i], bl[j]);
                    mma_bf16(acc[i][j], al[i], bh[j]);
                }
        }
    };

    load_chunk(0, 0);
    cp_commit();
    for (int kc = 0; kc < nchunk; kc++) {
        int cur = kc & 1;
        if (kc + 1 < nchunk) {
            load_chunk(kc + 1, cur ^ 1);
            cp_commit();
            cp_wait<1>();
        } else {
            cp_wait<0>();
        }
        __syncthreads();
        compute_chunk(cur);
        __syncthreads();
    }

    // epilogue: direct fragment stores (8B, aligned, coalesced within quads)
#pragma unroll
    for (int i = 0; i < 4; i++) {
        int row = bm + wm + i * 16 + (lane >> 2);
#pragma unroll
        for (int j = 0; j < 4; j++) {
            int col = bn + wn + j * 8 + ((lane & 3) << 1);
            *(float2*)&C[(size_t)row * N + col]       = make_float2(acc[i][j][0], acc[i][j][1]);
            *(float2*)&C[(size_t)(row + 8) * N + col] = make_float2(acc[i][j][2], acc[i][j][3]);
        }
    }
}

// ---------------- fp32 -> bf16 hi/lo split ----------------
__device__ __forceinline__ uint32_t pack_bf2(float a, float b) {
    __nv_bfloat162 t(__float2bfloat16(a), __float2bfloat16(b));
    return *(uint32_t*)&t;
}
__global__ void __launch_bounds__(256) split_kernel(const float* __restrict__ in,
                                                    __nv_bfloat16* __restrict__ hi,
                                                    __nv_bfloat16* __restrict__ lo, int n4)
{
    int i = blockIdx.x * 256 + threadIdx.x;
    if (i >= n4) return;
    float4 v = ((const float4*)in)[i];
    __nv_bfloat16 h0 = __float2bfloat16(v.x), h1 = __float2bfloat16(v.y);
    __nv_bfloat16 h2 = __float2bfloat16(v.z), h3 = __float2bfloat16(v.w);
    float l0 = v.x - __bfloat162float(h0), l1 = v.y - __bfloat162float(h1);
    float l2 = v.z - __bfloat162float(h2), l3 = v.w - __bfloat162float(h3);
    __nv_bfloat162 ph0(h0, h1), ph1(h2, h3);
    uint2 hp; hp.x = *(uint32_t*)&ph0; hp.y = *(uint32_t*)&ph1;
    ((uint2*)hi)[i] = hp;
    uint2 lp; lp.x = pack_bf2(l0, l1); lp.y = pack_bf2(l2, l3);
    ((uint2*)lo)[i] = lp;
}

// ---------------- fast sincos on the FMA pipe ----------------
__device__ __forceinline__ void fast_sincos(float x, float& s, float& c) {
    float kf = rintf(x * 0.63661977f);
    int   q  = (int)kf;
    float r  = fmaf(kf, -1.5707963705062866f, x);
    r        = fmaf(kf,  4.3711388286738e-8f, r);
    float r2 = r * r;
    float sp = fmaf(-1.98412698e-4f, r2, 8.33333333e-3f);
    sp       = fmaf(sp, r2, -1.66666667e-1f);
    sp      *= r2;
    float sr = fmaf(sp, r, r);
    float cp = fmaf(2.48015873e-5f, r2, -1.38888889e-3f);
    cp       = fmaf(cp, r2, 4.16666667e-2f);
    cp       = fmaf(cp, r2, -0.5f);
    float cr = fmaf(cp, r2, 1.0f);
    if (q & 1) { float t = sr; sr = cr; cr = -t; }
    if (q & 2) { sr = -sr; cr = -cr; }
    s = sr; c = cr;
}

// ---------------- phi ----------------
__global__ void __launch_bounds__(256) phi_kernel(const float* __restrict__ src,
                                                  const float* __restrict__ rf,
                                                  float* __restrict__ dst)
{
    __shared__ float Qs[64][68];
    __shared__ float Rs[64][68];
    __shared__ float scaleS[64];
    const int tid = threadIdx.x;
    const int t0  = blockIdx.x << 6;
    const int m0  = blockIdx.y << 6;
    const int bh  = blockIdx.z;
    const int b   = bh >> 4, h = bh & 15;

#pragma unroll
    for (int i = 0; i < 4; i++) {
        int idx = tid + (i << 8);
        int r   = idx >> 4;
        int c4  = (idx & 15) << 2;
        float4 q = *(const float4*)&src[((size_t)(b * T_ + t0 + r)) * D_ + h * DH_ + c4];
        *(float4*)&Qs[r][c4] = q;
        float4 w = *(const float4*)&rf[(size_t)(m0 + r) * DH_ + c4];
        Rs[c4+0][r] = w.x; Rs[c4+1][r] = w.y; Rs[c4+2][r] = w.z; Rs[c4+3][r] = w.w;
    }
    __syncthreads();
    if (tid < 64) {
        float s = 0.f;
#pragma unroll
        for (int d = 0; d < 64; d++) { float q = Qs[tid][d]; s = fmaf(q, q, s); }
        scaleS[tid] = __expf(-0.5f * s) * 0.0625f;
    }
    __syncthreads();

    const int tt = (tid >> 4) << 2;
    const int tm = (tid & 15) << 2;
    float c[4][4];
#pragma unroll
    for (int i = 0; i < 4; i++)
#pragma unroll
        for (int j = 0; j < 4; j++) c[i][j] = 0.f;

#pragma unroll 16
    for (int d = 0; d < 64; d++) {
        float a0 = Qs[tt+0][d], a1 = Qs[tt+1][d], a2 = Qs[tt+2][d], a3 = Qs[tt+3][d];
        float4 bb = *(float4*)&Rs[d][tm];
        c[0][0] = fmaf(a0, bb.x, c[0][0]); c[0][1] = fmaf(a0, bb.y, c[0][1]);
        c[0][2] = fmaf(a0, bb.z, c[0][2]); c[0][3] = fmaf(a0, bb.w, c[0][3]);
        c[1][0] = fmaf(a1, bb.x, c[1][0]); c[1][1] = fmaf(a1, bb.y, c[1][1]);
        c[1][2] = fmaf(a1, bb.z, c[1][2]); c[1][3] = fmaf(a1, bb.w, c[1][3]);
        c[2][0] = fmaf(a2, bb.x, c[2][0]); c[2][1] = fmaf(a2, bb.y, c[2][1]);
        c[2][2] = fmaf(a2, bb.z, c[2][2]); c[2][3] = fmaf(a2, bb.w, c[2][3]);
        c[3][0] = fmaf(a3, bb.x, c[3][0]); c[3][1] = fmaf(a3, bb.y, c[3][1]);
        c[3][2] = fmaf(a3, bb.z, c[3][2]); c[3][3] = fmaf(a3, bb.w, c[3][3]);
    }

#pragma unroll
    for (int i = 0; i < 4; i++) {
        float sc = scaleS[tt + i];
        size_t rb = ((size_t)bh * T_ + t0 + tt + i) * FD_ + m0 + tm;
#pragma unroll
        for (int j = 0; j < 4; j++) {
            float s_, c_;
            fast_sincos(c[i][j], s_, c_);
            dst[rb + j]       = c_ * sc;
            dst[rb + 256 + j] = s_ * sc;
        }
    }
}

// ---------------- KV = Kf^T V (+ K_sum) ----------------
__global__ void __launch_bounds__(256) kv_kernel(const float* __restrict__ Kf,
                                                 const float* __restrict__ V,
                                                 float* __restrict__ KVo,
                                                 float* __restrict__ Ksum)
{
    __shared__ float Ks[64][68];
    __shared__ float Vs[64][68];
    __shared__ float red[256];
    const int tid = threadIdx.x;
    const int m0  = blockIdx.x << 6;
    const int bh  = blockIdx.y;
    const int b   = bh >> 4, h = bh & 15;
    const int ta  = (tid >> 4) << 2;
    const int tv  = (tid & 15) << 2;
    const int mk  = tid & 63;
    const int tg  = tid >> 6;

    float c[4][4];
#pragma unroll
    for (int i = 0; i < 4; i++)
#pragma unroll
        for (int j = 0; j < 4; j++) c[i][j] = 0.f;
    float ksum = 0.f;

    for (int t0 = 0; t0 < T_; t0 += 64) {
#pragma unroll
        for (int i = 0; i < 4; i++) {
            int idx = tid + (i << 8);
            int r   = idx >> 4;
            int c4  = (idx & 15) << 2;
            *(float4*)&Ks[r][c4] = *(const float4*)&Kf[((size_t)bh * T_ + t0 + r) * FD_ + m0 + c4];
            *(float4*)&Vs[r][c4] = *(const float4*)&V[((size_t)(b * T_ + t0 + r)) * D_ + h * DH_ + c4];
        }
        __syncthreads();
#pragma unroll 16
        for (int t = 0; t < 64; t++) {
            float4 a  = *(float4*)&Ks[t][ta];
            float4 bb = *(float4*)&Vs[t][tv];
            c[0][0] = fmaf(a.x, bb.x, c[0][0]); c[0][1] = fmaf(a.x, bb.y, c[0][1]);
            c[0][2] = fmaf(a.x, bb.z, c[0][2]); c[0][3] = fmaf(a.x, bb.w, c[0][3]);
            c[1][0] = fmaf(a.y, bb.x, c[1][0]); c[1][1] = fmaf(a.y, bb.y, c[1][1]);
            c[1][2] = fmaf(a.y, bb.z, c[1][2]); c[1][3] = fmaf(a.y, bb.w, c[1][3]);
            c[2][0] = fmaf(a.z, bb.x, c[2][0]); c[2][1] = fmaf(a.z, bb.y, c[2][1]);
            c[2][2] = fmaf(a.z, bb.z, c[2][2]); c[2][3] = fmaf(a.z, bb.w, c[2][3]);
            c[3][0] = fmaf(a.w, bb.x, c[3][0]); c[3][1] = fmaf(a.w, bb.y, c[3][1]);
            c[3][2] = fmaf(a.w, bb.z, c[3][2]); c[3][3] = fmaf(a.w, bb.w, c[3][3]);
        }
#pragma unroll
        for (int t = tg * 16; t < tg * 16 + 16; t++) ksum += Ks[t][mk];
        __syncthreads();
    }
#pragma unroll
    for (int i = 0; i < 4; i++) {
        *(float4*)&KVo[((size_t)bh * FD_ + m0 + ta + i) * DH_ + tv] =
            make_float4(c[i][0], c[i][1], c[i][2], c[i][3]);
    }
    red[tid] = ksum;
    __syncthreads();
    if (tid < 64)
        Ksum[(size_t)bh * FD_ + m0 + tid] = red[tid] + red[tid+64] + red[tid+128] + red[tid+192];
}

// ---------------- Z = Qf . K_sum ----------------
__global__ void __launch_bounds__(256) z_kernel(const float* __restrict__ Qf,
                                                const float* __restrict__ Ksum,
                                                float* __restrict__ Z)
{
    const int warp = threadIdx.x >> 5, lane = threadIdx.x & 31;
    const size_t row = (size_t)blockIdx.x * 8 + warp;
    const int bh = (int)(row >> 12);
    const float* q  = Qf + row * FD_;
    const float* ks = Ksum + (size_t)bh * FD_;
    float s = 0.f;
#pragma unroll
    for (int i = lane * 4; i < FD_; i += 128) {
        float4 a = *(const float4*)&q[i];
        float4 b = *(const float4*)&ks[i];
        s = fmaf(a.x, b.x, s); s = fmaf(a.y, b.y, s);
        s = fmaf(a.z, b.z, s); s = fmaf(a.w, b.w, s);
    }
#pragma unroll
    for (int o = 16; o; o >>= 1) s += __shfl_xor_sync(0xffffffffu, s, o);
    if (lane == 0) Z[row] = s;
}

// ---------------- attn = (Qf KV)/max(Z,1e-6) -> bf16 hi/lo ----------------
__global__ void __launch_bounds__(256) qkv_kernel(const float* __restrict__ Qf,
                                                  const float* __restrict__ KVi,
                                                  const float* __restrict__ Z,
                                                  __nv_bfloat16* __restrict__ ah,
                                                  __nv_bfloat16* __restrict__ al)
{
    __shared__ float Qs[64][68];
    __shared__ float Ws[64][68];
    const int tid = threadIdx.x;
    const int t0  = blockIdx.x << 6;
    const int bh  = blockIdx.y;
    const int b   = bh >> 4, h = bh & 15;
    const int tt  = (tid >> 4) << 2;
    const int tv  = (tid & 15) << 2;

    float c[4][4];
#pragma unroll
    for (int i = 0; i < 4; i++)
#pragma unroll
        for (int j = 0; j < 4; j++) c[i][j] = 0.f;

    for (int m0 = 0; m0 < FD_; m0 += 64) {
#pragma unroll
        for (int i = 0; i < 4; i++) {
            int idx = tid + (i << 8);
            int r   = idx >> 4;
            int c4  = (idx & 15) << 2;
            *(float4*)&Qs[r][c4] = *(const float4*)&Qf[((size_t)bh * T_ + t0 + r) * FD_ + m0 + c4];
            *(float4*)&Ws[r][c4] = *(const float4*)&KVi[((size_t)bh * FD_ + m0 + r) * DH_ + c4];
        }
        __syncthreads();
#pragma unroll 16
        for (int m = 0; m < 64; m++) {
            float a0 = Qs[tt+0][m], a1 = Qs[tt+1][m], a2 = Qs[tt+2][m], a3 = Qs[tt+3][m];
            float4 bb = *(float4*)&Ws[m][tv];
            c[0][0] = fmaf(a0, bb.x, c[0][0]); c[0][1] = fmaf(a0, bb.y, c[0][1]);
            c[0][2] = fmaf(a0, bb.z, c[0][2]); c[0][3] = fmaf(a0, bb.w, c[0][3]);
            c[1][0] = fmaf(a1, bb.x, c[1][0]); c[1][1] = fmaf(a1, bb.y, c[1][1]);
            c[1][2] = fmaf(a1, bb.z, c[1][2]); c[1][3] = fmaf(a1, bb.w, c[1][3]);
            c[2][0] = fmaf(a2, bb.x, c[2][0]); c[2][1] = fmaf(a2, bb.y, c[2][1]);
            c[2][2] = fmaf(a2, bb.z, c[2][2]); c[2][3] = fmaf(a2, bb.w, c[2][3]);
            c[3][0] = fmaf(a3, bb.x, c[3][0]); c[3][1] = fmaf(a3, bb.y, c[3][1]);
            c[3][2] = fmaf(a3, bb.z, c[3][2]); c[3][3] = fmaf(a3, bb.w, c[3][3]);
        }
        __syncthreads();
    }
#pragma unroll
    for (int i = 0; i < 4; i++) {
        float z   = fmaxf(Z[(size_t)bh * T_ + t0 + tt + i], 1e-6f);
        float inv = 1.0f / z;
        size_t base = ((size_t)(b * T_ + t0 + tt + i)) * D_ + h * DH_ + tv;
        float v0 = c[i][0]*inv, v1 = c[i][1]*inv, v2 = c[i][2]*inv, v3 = c[i][3]*inv;
        __nv_bfloat16 h0 = __float2bfloat16(v0), h1 = __float2bfloat16(v1);
        __nv_bfloat16 h2 = __float2bfloat16(v2), h3 = __float2bfloat16(v3);
        __nv_bfloat162 hp0(h0, h1), hp1(h2, h3);
        uint2 hp; hp.x = *(uint32_t*)&hp0; hp.y = *(uint32_t*)&hp1;
        *(uint2*)&ah[base] = hp;
        uint2 lp;
        lp.x = pack_bf2(v0 - __bfloat162float(h0), v1 - __bfloat162float(h1));
        lp.y = pack_bf2(v2 - __bfloat162float(h2), v3 - __bfloat162float(h3));
        *(uint2*)&al[base] = lp;
    }
}

// ---------------- launch ----------------
extern "C" void kernel_launch(void* const* d_in, const int* in_sizes, int n_in,
                              void* d_out, int out_size)
{
    const float* x  = (const float*)d_in[0];
    const float* wq = (const float*)d_in[1];
    const float* wk = (const float*)d_in[2];
    const float* wv = (const float*)d_in[3];
    const float* wo = (const float*)d_in[4];
    const float* rf = (const float*)d_in[5];
    float* out = (float*)d_out;

    float* fbase = nullptr;
    cudaGetSymbolAddress((void**)&fbase, g_buf);
    __nv_bfloat16* bbase = nullptr;
    cudaGetSymbolAddress((void**)&bbase, g_bf);

    float* Qp  = fbase + OFF_Q;
    float* Kp  = fbase + OFF_K;
    float* Vp  = fbase + OFF_V;
    float* Qfp = fbase + OFF_QF;
    float* Kfp = fbase + OFF_KF;
    float* KVp = fbase + OFF_KV;
    float* Ksp = fbase + OFF_KS;
    float* Zp  = fbase + OFF_Z;

    __nv_bfloat16* xh  = bbase + BOFF_XH;
    __nv_bfloat16* xl  = bbase + BOFF_XL;
    __nv_bfloat16* wqh = bbase + BOFF_W + 0*(size_t)D_*D_;
    __nv_bfloat16* wql = bbase + BOFF_W + 1*(size_t)D_*D_;
    __nv_bfloat16* wkh = bbase + BOFF_W + 2*(size_t)D_*D_;
    __nv_bfloat16* wkl = bbase + BOFF_W + 3*(size_t)D_*D_;
    __nv_bfloat16* wvh = bbase + BOFF_W + 4*(size_t)D_*D_;
    __nv_bfloat16* wvl = bbase + BOFF_W + 5*(size_t)D_*D_;
    __nv_bfloat16* woh = bbase + BOFF_W + 6*(size_t)D_*D_;
    __nv_bfloat16* wol = bbase + BOFF_W + 7*(size_t)D_*D_;
    __nv_bfloat16* ah  = bbase + BOFF_AH;
    __nv_bfloat16* al  = bbase + BOFF_AL;

    cudaFuncSetAttribute(mma_gemm, cudaFuncAttributeMaxDynamicSharedMemorySize, SMEM_TOTAL_MMA);

    // splits
    split_kernel<<<(int)(SZ_BTD/4/256), 256>>>(x, xh, xl, (int)(SZ_BTD/4));
    int wn4 = D_*D_/4;
    split_kernel<<<wn4/256, 256>>>(wq, wqh, wql, wn4);
    split_kernel<<<wn4/256, 256>>>(wk, wkh, wkl, wn4);
    split_kernel<<<wn4/256, 256>>>(wv, wvh, wvl, wn4);
    split_kernel<<<wn4/256, 256>>>(wo, woh, wol, wn4);

    // projections via mma.sync bf16x3
    dim3 gG(D_ / 128, (B_ * T_) / 128);  // (8, 64)
    mma_gemm<<<gG, 256, SMEM_TOTAL_MMA>>>(xh, xl, wqh, wql, Qp, B_ * T_, D_, D_);
    mma_gemm<<<gG, 256, SMEM_TOTAL_MMA>>>(xh, xl, wkh, wkl, Kp, B_ * T_, D_, D_);
    mma_gemm<<<gG, 256, SMEM_TOTAL_MMA>>>(xh, xl, wvh, wvl, Vp, B_ * T_, D_, D_);

    dim3 gPhi(T_ / 64, MRF_ / 64, BH_);
    phi_kernel<<<gPhi, 256>>>(Qp, rf, Qfp);
    phi_kernel<<<gPhi, 256>>>(Kp, rf, Kfp);

    kv_kernel<<<dim3(FD_ / 64, BH_), 256>>>(Kfp, Vp, KVp, Ksp);
    z_kernel<<<(BH_ * T_) / 8, 256>>>(Qfp, Ksp, Zp);
    qkv_kernel<<<dim3(T_ / 64, BH_), 256>>>(Qfp, KVp, Zp, ah, al);

    mma_gemm<<<gG, 256, SMEM_TOTAL_MMA>>>(ah, al, woh, wol, out, B_ * T_, D_, D_);
}

// round 6
// speedup vs baseline: 2.2523x; 1.2949x over previous
#include <cuda_runtime.h>
#include <cuda_bf16.h>
#include <cstdint>
typedef __nv_bfloat16 bf16;

#define B_   2
#define T_   4096
#define D_   1024
#define H_   16
#define DH_  64
#define FD_  512
#define BH_  (B_*H_)
#define SZ_BTD ((size_t)B_*T_*D_)
#define SZ_F   ((size_t)BH_*T_*FD_)

// fp32 scratch
#define OFF_Q   ((size_t)0)
#define OFF_K   (SZ_BTD)
#define OFF_V   (2*SZ_BTD)
#define OFF_KS  (3*SZ_BTD)
#define OFF_Z   (OFF_KS + (size_t)BH_*FD_)
__device__ float g_buf[OFF_Z + (size_t)BH_*T_];

// bf16 scratch
#define BO_XH   ((size_t)0)
#define BO_XL   (SZ_BTD)
#define BO_W    (2*SZ_BTD)
#define BO_RFH  (BO_W + 8*(size_t)D_*D_)
#define BO_RFL  (BO_RFH + 16384)
#define BO_QFH  (BO_RFL + 16384)
#define BO_QFL  (BO_QFH + SZ_F)
#define BO_KFTH (BO_QFL + SZ_F)
#define BO_KFTL (BO_KFTH + SZ_F)
#define BO_VTH  (BO_KFTL + SZ_F)
#define BO_VTL  (BO_VTH + SZ_BTD)
#define BO_KVTH (BO_VTL + SZ_BTD)
#define BO_KVTL (BO_KVTH + (size_t)BH_*DH_*FD_)
#define BO_AH   (BO_KVTL + (size_t)BH_*DH_*FD_)
#define BO_AL   (BO_AH + SZ_BTD)
__device__ bf16 g_bf[BO_AL + SZ_BTD];

__device__ __forceinline__ uint32_t smem_to_u32(const void* p) {
    uint32_t a;
    asm("{ .reg .u64 t; cvta.to.shared.u64 t, %1; cvt.u32.u64 %0, t; }" : "=r"(a) : "l"(p));
    return a;
}
#define SWZ(o) ((o) ^ (((o) >> 3) & 0x70))
__device__ __forceinline__ void cp_async16(uint32_t s, const void* g) {
    asm volatile("cp.async.cg.shared.global [%0], [%1], 16;" :: "r"(s), "l"(g));
}
__device__ __forceinline__ void cp_commit() { asm volatile("cp.async.commit_group;" ::: "memory"); }
template <int N> __device__ __forceinline__ void cp_wait() {
    asm volatile("cp.async.wait_group %0;" :: "n"(N) : "memory");
}
__device__ __forceinline__ void ldsm_x4(uint32_t& r0, uint32_t& r1, uint32_t& r2, uint32_t& r3, uint32_t a) {
    asm volatile("ldmatrix.sync.aligned.m8n8.x4.shared.b16 {%0,%1,%2,%3}, [%4];"
                 : "=r"(r0), "=r"(r1), "=r"(r2), "=r"(r3) : "r"(a));
}
__device__ __forceinline__ void ldsm_x2(uint32_t& r0, uint32_t& r1, uint32_t a) {
    asm volatile("ldmatrix.sync.aligned.m8n8.x2.shared.b16 {%0,%1}, [%2];"
                 : "=r"(r0), "=r"(r1) : "r"(a));
}
__device__ __forceinline__ void mma_bf16(float* c, const uint32_t* a, const uint32_t* b) {
    asm volatile("mma.sync.aligned.m16n8k16.row.col.f32.bf16.bf16.f32 "
                 "{%0,%1,%2,%3}, {%4,%5,%6,%7}, {%8,%9}, {%0,%1,%2,%3};"
                 : "+f"(c[0]), "+f"(c[1]), "+f"(c[2]), "+f"(c[3])
                 : "r"(a[0]), "r"(a[1]), "r"(a[2]), "r"(a[3]), "r"(b[0]), "r"(b[1]));
}
__device__ __forceinline__ void store_pair(bf16* ph, bf16* pl, size_t off, float x0, float x1) {
    bf16 h0 = __float2bfloat16(x0), h1 = __float2bfloat16(x1);
    __nv_bfloat162 hp(h0, h1);
    *(uint32_t*)(ph + off) = *(uint32_t*)&hp;
    __nv_bfloat162 lp(__float2bfloat16(x0 - __bfloat162float(h0)),
                      __float2bfloat16(x1 - __bfloat162float(h1)));
    *(uint32_t*)(pl + off) = *(uint32_t*)&lp;
}
__device__ __forceinline__ void fast_sincos(float x, float& s, float& c) {
    float kf = rintf(x * 0.63661977f);
    int q = (int)kf;
    float r = fmaf(kf, -1.5707963705062866f, x);
    r = fmaf(kf, 4.3711388286738e-8f, r);
    float r2 = r * r;
    float sp = fmaf(-1.98412698e-4f, r2, 8.33333333e-3f);
    sp = fmaf(sp, r2, -1.66666667e-1f) * r2;
    float sr = fmaf(sp, r, r);
    float cp = fmaf(2.48015873e-5f, r2, -1.38888889e-3f);
    cp = fmaf(cp, r2, 4.16666667e-2f);
    cp = fmaf(cp, r2, -0.5f);
    float cr = fmaf(cp, r2, 1.0f);
    if (q & 1) { float t = sr; sr = cr; cr = -t; }
    if (q & 2) { sr = -sr; cr = -cr; }
    s = sr; c = cr;
}

// ======== dense bf16x3 GEMM: C[M,N] = A[M,K] B[N,K]^T ========
#define TILE_B 16384
#define BUF_B  (4*TILE_B)
#define SMEM_G (2*BUF_B)
__global__ void __launch_bounds__(256)
mma_gemm(const bf16* __restrict__ Ah, const bf16* __restrict__ Al,
         const bf16* __restrict__ Bh, const bf16* __restrict__ Bl,
         float* __restrict__ C, int M, int N, int K)
{
    extern __shared__ char smem[];
    const uint32_t sb = smem_to_u32(smem);
    const int tid = threadIdx.x, wid = tid >> 5, lane = tid & 31;
    const int bn = blockIdx.x << 7, bm = blockIdx.y << 7;
    const int wm = (wid >> 2) << 6, wn = (wid & 3) << 5;
    const int nchunk = K >> 6;
    const int lr = lane & 15, lc = lane >> 4, br = lane & 7, bk = (lane >> 3) & 1;
    float acc[4][4][4];
#pragma unroll
    for (int i = 0; i < 4; i++)
#pragma unroll
        for (int j = 0; j < 4; j++)
#pragma unroll
            for (int r = 0; r < 4; r++) acc[i][j][r] = 0.f;
    const bf16* gs[4] = {Ah, Al, Bh, Bl};
    const int rb[4] = {bm, bm, bn, bn};
    auto load = [&](int kc, int buf) {
        uint32_t base = sb + buf * BUF_B;
        int ke = kc << 6;
#pragma unroll
        for (int t = 0; t < 4; t++)
#pragma unroll
            for (int i = 0; i < 4; i++) {
                int idx = tid + (i << 8), r = idx >> 3, c = idx & 7;
                cp_async16(base + t * TILE_B + SWZ(r * 128 + c * 16),
                           gs[t] + (size_t)(rb[t] + r) * K + ke + c * 8);
            }
    };
    load(0, 0); cp_commit();
    for (int kc = 0; kc < nchunk; kc++) {
        int cur = kc & 1;
        if (kc + 1 < nchunk) { load(kc + 1, cur ^ 1); cp_commit(); cp_wait<1>(); }
        else cp_wait<0>();
        __syncthreads();
        uint32_t bA = sb + cur * BUF_B;
#pragma unroll
        for (int ks = 0; ks < 4; ks++) {
            uint32_t a_h[4][4], a_l[4][4], b_h[4][2], b_l[4][2];
#pragma unroll
            for (int i = 0; i < 4; i++) {
                uint32_t o = SWZ((wm + i * 16 + lr) * 128 + ks * 32 + lc * 16);
                ldsm_x4(a_h[i][0], a_h[i][1], a_h[i][2], a_h[i][3], bA + o);
                ldsm_x4(a_l[i][0], a_l[i][1], a_l[i][2], a_l[i][3], bA + TILE_B + o);
            }
#pragma unroll
            for (int j = 0; j < 4; j++) {
                uint32_t o = SWZ((wn + j * 8 + br) * 128 + ks * 32 + bk * 16);
                ldsm_x2(b_h[j][0], b_h[j][1], bA + 2 * TILE_B + o);
                ldsm_x2(b_l[j][0], b_l[j][1], bA + 3 * TILE_B + o);
            }
#pragma unroll
            for (int i = 0; i < 4; i++)
#pragma unroll
                for (int j = 0; j < 4; j++) {
                    mma_bf16(acc[i][j], a_h[i], b_h[j]);
                    mma_bf16(acc[i][j], a_h[i], b_l[j]);
                    mma_bf16(acc[i][j], a_l[i], b_h[j]);
                }
        }
        __syncthreads();
    }
#pragma unroll
    for (int i = 0; i < 4; i++) {
        int row = bm + wm + i * 16 + (lane >> 2);
#pragma unroll
        for (int j = 0; j < 4; j++) {
            int col = bn + wn + j * 8 + ((lane & 3) << 1);
            *(float2*)&C[(size_t)row * N + col]       = make_float2(acc[i][j][0], acc[i][j][1]);
            *(float2*)&C[(size_t)(row + 8) * N + col] = make_float2(acc[i][j][2], acc[i][j][3]);
        }
    }
}

// ======== split fp32 -> hi/lo bf16 ========
__global__ void __launch_bounds__(256) split_kernel(const float* __restrict__ in,
                                                    bf16* __restrict__ hi, bf16* __restrict__ lo, int n4)
{
    int i = blockIdx.x * 256 + threadIdx.x;
    if (i >= n4) return;
    float4 v = ((const float4*)in)[i];
    store_pair(hi, lo, (size_t)i * 4, v.x, v.y);
    store_pair(hi, lo, (size_t)i * 4 + 2, v.z, v.w);
}

// ======== phi kernels ========
#define PA  0
#define PAL 16384
#define PB  32768
#define PBL 49152
#define PSC 65536
#define PNP 66048
#define SMEM_PHI 67072

__device__ __forceinline__ void conv_tile(const float* g, char* sm, int dstH, int dstL,
                                          float* np, int tid) {
    int r = tid >> 1, cb = (tid & 1) << 5;
    float s = 0.f;
    const float* gp = g + (size_t)r * D_ + cb;
#pragma unroll
    for (int k = 0; k < 8; k++) {
        float4 v = *(const float4*)(gp + k * 4);
        s = fmaf(v.x, v.x, s); s = fmaf(v.y, v.y, s);
        s = fmaf(v.z, v.z, s); s = fmaf(v.w, v.w, s);
        uint32_t sw = SWZ((uint32_t)(r * 128 + (cb + k * 4) * 2));
        bf16 h0 = __float2bfloat16(v.x), h1 = __float2bfloat16(v.y);
        bf16 h2 = __float2bfloat16(v.z), h3 = __float2bfloat16(v.w);
        __nv_bfloat162 hp0(h0, h1), hp1(h2, h3);
        *(uint32_t*)(sm + dstH + sw) = *(uint32_t*)&hp0;
        *(uint32_t*)(sm + dstH + sw + 4) = *(uint32_t*)&hp1;
        __nv_bfloat162 lp0(__float2bfloat16(v.x - __bfloat162float(h0)),
                           __float2bfloat16(v.y - __bfloat162float(h1)));
        __nv_bfloat162 lp1(__float2bfloat16(v.z - __bfloat162float(h2)),
                           __float2bfloat16(v.w - __bfloat162float(h3)));
        *(uint32_t*)(sm + dstL + sw) = *(uint32_t*)&lp0;
        *(uint32_t*)(sm + dstL + sw + 4) = *(uint32_t*)&lp1;
    }
    np[tid] = s;
}

__global__ void __launch_bounds__(256) phi_q_kernel(
    const float* __restrict__ Q, const bf16* __restrict__ rfh, const bf16* __restrict__ rfl,
    bf16* __restrict__ Qfh, bf16* __restrict__ Qfl)
{
    extern __shared__ char sm[];
    const uint32_t sb = smem_to_u32(sm);
    const int tid = threadIdx.x, wid = tid >> 5, lane = tid & 31;
    const int t0 = blockIdx.x << 7, m0c = blockIdx.y << 7, bh = blockIdx.z;
    const int b = bh >> 4, h = bh & 15;
    float* scale = (float*)(sm + PSC);
    float* np = (float*)(sm + PNP);
#pragma unroll
    for (int i = 0; i < 4; i++) {
        int idx = tid + (i << 8), r = idx >> 3, c = idx & 7;
        uint32_t so = SWZ(r * 128 + c * 16);
        size_t g = (size_t)(m0c + r) * DH_ + c * 8;
        cp_async16(sb + PB + so, rfh + g);
        cp_async16(sb + PBL + so, rfl + g);
    }
    cp_commit();
    conv_tile(&Q[((size_t)(b * T_ + t0)) * D_ + h * DH_], sm, PA, PAL, np, tid);
    __syncthreads();
    if (tid < 128) scale[tid] = __expf(-0.5f * (np[2 * tid] + np[2 * tid + 1])) * 0.0625f;
    cp_wait<0>();
    __syncthreads();
    const int wt = (wid >> 2) << 6, wm = (wid & 3) << 5;
    const int lr = lane & 15, lc = lane >> 4, br = lane & 7, bk = (lane >> 3) & 1;
    float acc[4][4][4];
#pragma unroll
    for (int i = 0; i < 4; i++)
#pragma unroll
        for (int j = 0; j < 4; j++)
#pragma unroll
            for (int r = 0; r < 4; r++) acc[i][j][r] = 0.f;
#pragma unroll
    for (int ks = 0; ks < 4; ks++) {
        uint32_t a_h[4][4], a_l[4][4], b_h[4][2], b_l[4][2];
#pragma unroll
        for (int i = 0; i < 4; i++) {
            uint32_t o = SWZ((wt + i * 16 + lr) * 128 + ks * 32 + lc * 16);
            ldsm_x4(a_h[i][0], a_h[i][1], a_h[i][2], a_h[i][3], sb + PA + o);
            ldsm_x4(a_l[i][0], a_l[i][1], a_l[i][2], a_l[i][3], sb + PAL + o);
        }
#pragma unroll
        for (int j = 0; j < 4; j++) {
            uint32_t o = SWZ((wm + j * 8 + br) * 128 + ks * 32 + bk * 16);
            ldsm_x2(b_h[j][0], b_h[j][1], sb + PB + o);
            ldsm_x2(b_l[j][0], b_l[j][1], sb + PBL + o);
        }
#pragma unroll
        for (int i = 0; i < 4; i++)
#pragma unroll
            for (int j = 0; j < 4; j++) {
                mma_bf16(acc[i][j], a_h[i], b_h[j]);
                mma_bf16(acc[i][j], a_h[i], b_l[j]);
                mma_bf16(acc[i][j], a_l[i], b_h[j]);
            }
    }
#pragma unroll
    for (int i = 0; i < 4; i++) {
        int r0 = wt + i * 16 + (lane >> 2);
        float sc0 = scale[r0], sc1 = scale[r0 + 8];
        size_t rb0 = ((size_t)bh * T_ + t0 + r0) * FD_ + m0c;
        size_t rb1 = rb0 + (size_t)8 * FD_;
#pragma unroll
        for (int j = 0; j < 4; j++) {
            int mc = wm + j * 8 + ((lane & 3) << 1);
            float sn0, cs0, sn1, cs1;
            fast_sincos(acc[i][j][0], sn0, cs0);
            fast_sincos(acc[i][j][1], sn1, cs1);
            store_pair(Qfh, Qfl, rb0 + mc, cs0 * sc0, cs1 * sc0);
            store_pair(Qfh, Qfl, rb0 + 256 + mc, sn0 * sc0, sn1 * sc0);
            fast_sincos(acc[i][j][2], sn0, cs0);
            fast_sincos(acc[i][j][3], sn1, cs1);
            store_pair(Qfh, Qfl, rb1 + mc, cs0 * sc1, cs1 * sc1);
            store_pair(Qfh, Qfl, rb1 + 256 + mc, sn0 * sc1, sn1 * sc1);
        }
    }
}

__global__ void __launch_bounds__(256) phi_k_kernel(
    const float* __restrict__ Kg, const bf16* __restrict__ rfh, const bf16* __restrict__ rfl,
    bf16* __restrict__ KfTh, bf16* __restrict__ KfTl)
{
    extern __shared__ char sm[];
    const uint32_t sb = smem_to_u32(sm);
    const int tid = threadIdx.x, wid = tid >> 5, lane = tid & 31;
    const int t0 = blockIdx.x << 7, m0c = blockIdx.y << 7, bh = blockIdx.z;
    const int b = bh >> 4, h = bh & 15;
    float* scale = (float*)(sm + PSC);
    float* np = (float*)(sm + PNP);
#pragma unroll
    for (int i = 0; i < 4; i++) {
        int idx = tid + (i << 8), r = idx >> 3, c = idx & 7;
        uint32_t so = SWZ(r * 128 + c * 16);
        size_t g = (size_t)(m0c + r) * DH_ + c * 8;
        cp_async16(sb + PA + so, rfh + g);
        cp_async16(sb + PAL + so, rfl + g);
    }
    cp_commit();
    conv_tile(&Kg[((size_t)(b * T_ + t0)) * D_ + h * DH_], sm, PB, PBL, np, tid);
    __syncthreads();
    if (tid < 128) scale[tid] = __expf(-0.5f * (np[2 * tid] + np[2 * tid + 1])) * 0.0625f;
    cp_wait<0>();
    __syncthreads();
    const int wm = (wid >> 2) << 6, wt = (wid & 3) << 5;
    const int lr = lane & 15, lc = lane >> 4, br = lane & 7, bk = (lane >> 3) & 1;
    float acc[4][4][4];
#pragma unroll
    for (int i = 0; i < 4; i++)
#pragma unroll
        for (int j = 0; j < 4; j++)
#pragma unroll
            for (int r = 0; r < 4; r++) acc[i][j][r] = 0.f;
#pragma unroll
    for (int ks = 0; ks < 4; ks++) {
        uint32_t a_h[4][4], a_l[4][4], b_h[4][2], b_l[4][2];
#pragma unroll
        for (int i = 0; i < 4; i++) {
            uint32_t o = SWZ((wm + i * 16 + lr) * 128 + ks * 32 + lc * 16);
            ldsm_x4(a_h[i][0], a_h[i][1], a_h[i][2], a_h[i][3], sb + PA + o);
            ldsm_x4(a_l[i][0], a_l[i][1], a_l[i][2], a_l[i][3], sb + PAL + o);
        }
#pragma unroll
        for (int j = 0; j < 4; j++) {
            uint32_t o = SWZ((wt + j * 8 + br) * 128 + ks * 32 + bk * 16);
            ldsm_x2(b_h[j][0], b_h[j][1], sb + PB + o);
            ldsm_x2(b_l[j][0], b_l[j][1], sb + PBL + o);
        }
#pragma unroll
        for (int i = 0; i < 4; i++)
#pragma unroll
            for (int j = 0; j < 4; j++) {
                mma_bf16(acc[i][j], a_h[i], b_h[j]);
                mma_bf16(acc[i][j], a_h[i], b_l[j]);
                mma_bf16(acc[i][j], a_l[i], b_h[j]);
            }
    }
#pragma unroll
    for (int i = 0; i < 4; i++) {
        int r0 = wm + i * 16 + (lane >> 2);
        size_t rc0 = ((size_t)bh * FD_ + m0c + r0) * T_ + t0;
        size_t rs0 = rc0 + (size_t)256 * T_;
        size_t rc1 = rc0 + (size_t)8 * T_, rs1 = rs0 + (size_t)8 * T_;
#pragma unroll
        for (int j = 0; j < 4; j++) {
            int tc = wt + j * 8 + ((lane & 3) << 1);
            float sc0 = scale[tc], sc1 = scale[tc + 1];
            float sn0, cs0, sn1, cs1;
            fast_sincos(acc[i][j][0], sn0, cs0);
            fast_sincos(acc[i][j][1], sn1, cs1);
            store_pair(KfTh, KfTl, rc0 + tc, cs0 * sc0, cs1 * sc1);
            store_pair(KfTh, KfTl, rs0 + tc, sn0 * sc0, sn1 * sc1);
            fast_sincos(acc[i][j][2], sn0, cs0);
            fast_sincos(acc[i][j][3], sn1, cs1);
            store_pair(KfTh, KfTl, rc1 + tc, cs0 * sc0, cs1 * sc1);
            store_pair(KfTh, KfTl, rs1 + tc, sn0 * sc0, sn1 * sc1);
        }
    }
}

// ======== V transpose: fp32 [B,T,D] -> VT hi/lo [bh][64][T] ========
__global__ void __launch_bounds__(256) vtrans_kernel(const float* __restrict__ V,
                                                     bf16* __restrict__ VTh, bf16* __restrict__ VTl)
{
    __shared__ float st[64][68];   // 68*4=272B row stride: float4 writes stay 16B-aligned
    const int tid = threadIdx.x;
    const int t0 = blockIdx.x << 6, bh = blockIdx.y;
    const int b = bh >> 4, h = bh & 15;
#pragma unroll
    for (int i = 0; i < 4; i++) {
        int idx = tid + (i << 8), r = idx >> 4, c4 = (idx & 15) << 2;
        *(float4*)&st[r][c4] = *(const float4*)&V[((size_t)(b * T_ + t0 + r)) * D_ + h * DH_ + c4];
    }
    __syncthreads();
    int v = tid >> 2, ts = (tid & 3) << 4;
#pragma unroll
    for (int p = 0; p < 8; p++) {
        int t = ts + p * 2;
        store_pair(VTh, VTl, ((size_t)bh * DH_ + v) * T_ + t0 + t, st[t][v], st[t + 1][v]);
    }
}

// ======== Ksum / Z ========
__global__ void __launch_bounds__(256) ksum_kernel(const bf16* __restrict__ KfTh,
                                                   const bf16* __restrict__ KfTl,
                                                   float* __restrict__ Ksum)
{
    const int wid = threadIdx.x >> 5, lane = threadIdx.x & 31;
    const int f = blockIdx.x * 8 + wid, bh = blockIdx.y;
    const bf16* ph = KfTh + ((size_t)bh * FD_ + f) * T_;
    const bf16* pl = KfTl + ((size_t)bh * FD_ + f) * T_;
    float s = 0.f;
    for (int i = lane * 2; i < T_; i += 64) {
        uint32_t hp = *(const uint32_t*)(ph + i), lp = *(const uint32_t*)(pl + i);
        __nv_bfloat162 h2 = *(__nv_bfloat162*)&hp, l2 = *(__nv_bfloat162*)&lp;
        s += __bfloat162float(h2.x) + __bfloat162float(l2.x)
           + __bfloat162float(h2.y) + __bfloat162float(l2.y);
    }
#pragma unroll
    for (int o = 16; o; o >>= 1) s += __shfl_xor_sync(0xffffffffu, s, o);
    if (lane == 0) Ksum[(size_t)bh * FD_ + f] = s;
}

__global__ void __launch_bounds__(256) z_kernel(const bf16* __restrict__ Qfh,
                                                const bf16* __restrict__ Qfl,
                                                const float* __restrict__ Ksum,
                                                float* __restrict__ Z)
{
    const int warp = threadIdx.x >> 5, lane = threadIdx.x & 31;
    const size_t row = (size_t)blockIdx.x * 8 + warp;
    const int bh = (int)(row >> 12);
    const bf16* qh = Qfh + row * FD_;
    const bf16* ql = Qfl + row * FD_;
    const float* ks = Ksum + (size_t)bh * FD_;
    float s = 0.f;
#pragma unroll
    for (int j = 0; j < 8; j++) {
        int f = lane * 2 + j * 64;
        uint32_t hp = *(const uint32_t*)(qh + f), lp = *(const uint32_t*)(ql + f);
        __nv_bfloat162 h2 = *(__nv_bfloat162*)&hp, l2 = *(__nv_bfloat162*)&lp;
        s = fmaf(__bfloat162float(h2.x) + __bfloat162float(l2.x), ks[f], s);
        s = fmaf(__bfloat162float(h2.y) + __bfloat162float(l2.y), ks[f + 1], s);
    }
#pragma unroll
    for (int o = 16; o; o >>= 1) s += __shfl_xor_sync(0xffffffffu, s, o);
    if (lane == 0) Z[row] = s;
}

// ======== kv / qkv tensor GEMMs (M=128, N=64) ========
#define KA   0
#define KAL  16384
#define KB   32768
#define KBL  40960
#define KBUF 49152
#define SMEM_KV (2*KBUF)

__global__ void __launch_bounds__(256) kv_gemm(
    const bf16* __restrict__ Ah, const bf16* __restrict__ Al,
    const bf16* __restrict__ Bh, const bf16* __restrict__ Bl,
    bf16* __restrict__ KVTh, bf16* __restrict__ KVTl)
{
    extern __shared__ char sm[];
    const uint32_t sb = smem_to_u32(sm);
    const int tid = threadIdx.x, wid = tid >> 5, lane = tid & 31;
    const int m0 = blockIdx.x << 7, bh = blockIdx.y;
    const size_t ab = (size_t)bh * FD_ + m0, bb = (size_t)bh * DH_;
    const int wm = (wid >> 1) << 5, wn = (wid & 1) << 5;
    const int lr = lane & 15, lc = lane >> 4, br = lane & 7, bk = (lane >> 3) & 1;
    float acc[2][4][4];
#pragma unroll
    for (int i = 0; i < 2; i++)
#pragma unroll
        for (int j = 0; j < 4; j++)
#pragma unroll
            for (int r = 0; r < 4; r++) acc[i][j][r] = 0.f;
    auto load = [&](int kc, int buf) {
        uint32_t base = sb + buf * KBUF;
        int ke = kc << 6;
#pragma unroll
        for (int i = 0; i < 4; i++) {
            int idx = tid + (i << 8), r = idx >> 3, c = idx & 7;
            uint32_t so = SWZ(r * 128 + c * 16);
            size_t g = (ab + r) * T_ + ke + c * 8;
            cp_async16(base + KA + so, Ah + g);
            cp_async16(base + KAL + so, Al + g);
        }
#pragma unroll
        for (int i = 0; i < 2; i++) {
            int idx = tid + (i << 8), r = idx >> 3, c = idx & 7;
            uint32_t so = SWZ(r * 128 + c * 16);
            size_t g = (bb + r) * T_ + ke + c * 8;
            cp_async16(base + KB + so, Bh + g);
            cp_async16(base + KBL + so, Bl + g);
        }
    };
    load(0, 0); cp_commit();
    for (int kc = 0; kc < T_ / 64; kc++) {
        int cur = kc & 1;
        if (kc + 1 < T_ / 64) { load(kc + 1, cur ^ 1); cp_commit(); cp_wait<1>(); }
        else cp_wait<0>();
        __syncthreads();
        uint32_t bA = sb + cur * KBUF;
#pragma unroll
        for (int ks = 0; ks < 4; ks++) {
            uint32_t a_h[2][4], a_l[2][4], b_h[4][2], b_l[4][2];
#pragma unroll
            for (int i = 0; i < 2; i++) {
                uint32_t o = SWZ((wm + i * 16 + lr) * 128 + ks * 32 + lc * 16);
                ldsm_x4(a_h[i][0], a_h[i][1], a_h[i][2], a_h[i][3], bA + KA + o);
                ldsm_x4(a_l[i][0], a_l[i][1], a_l[i][2], a_l[i][3], bA + KAL + o);
            }
#pragma unroll
            for (int j = 0; j < 4; j++) {
                uint32_t o = SWZ((wn + j * 8 + br) * 128 + ks * 32 + bk * 16);
                ldsm_x2(b_h[j][0], b_h[j][1], bA + KB + o);
                ldsm_x2(b_l[j][0], b_l[j][1], bA + KBL + o);
            }
#pragma unroll
            for (int i = 0; i < 2; i++)
#pragma unroll
                for (int j = 0; j < 4; j++) {
                    mma_bf16(acc[i][j], a_h[i], b_h[j]);
                    mma_bf16(acc[i][j], a_h[i], b_l[j]);
                    mma_bf16(acc[i][j], a_l[i], b_h[j]);
                }
        }
        __syncthreads();
    }
    float* stage = (float*)sm;  // [64 v][132]
#pragma unroll
    for (int i = 0; i < 2; i++) {
        int row = wm + i * 16 + (lane >> 2);
#pragma unroll
        for (int j = 0; j < 4; j++) {
            int col = wn + j * 8 + ((lane & 3) << 1);
            stage[col * 132 + row]           = acc[i][j][0];
            stage[(col + 1) * 132 + row]     = acc[i][j][1];
            stage[col * 132 + row + 8]       = acc[i][j][2];
            stage[(col + 1) * 132 + row + 8] = acc[i][j][3];
        }
    }
    __syncthreads();
    int v = tid >> 2, fs = (tid & 3) << 5;
#pragma unroll
    for (int p = 0; p < 16; p++) {
        int f = fs + p * 2;
        store_pair(KVTh, KVTl, ((size_t)bh * DH_ + v) * FD_ + m0 + f,
                   stage[v * 132 + f], stage[v * 132 + f + 1]);
    }
}

__global__ void __launch_bounds__(256) qkv_gemm(
    const bf16* __restrict__ Ah, const bf16* __restrict__ Al,
    const bf16* __restrict__ Bh, const bf16* __restrict__ Bl,
    const float* __restrict__ Z, bf16* __restrict__ oh, bf16* __restrict__ ol)
{
    extern __shared__ char sm[];
    __shared__ float ziv[128];
    const uint32_t sb = smem_to_u32(sm);
    const int tid = threadIdx.x, wid = tid >> 5, lane = tid & 31;
    const int t0 = blockIdx.x << 7, bh = blockIdx.y;
    const int b = bh >> 4, h = bh & 15;
    const size_t ab = (size_t)bh * T_ + t0, bb = (size_t)bh * DH_;
    const int wm = (wid >> 1) << 5, wn = (wid & 1) << 5;
    const int lr = lane & 15, lc = lane >> 4, br = lane & 7, bk = (lane >> 3) & 1;
    if (tid < 128) ziv[tid] = 1.f / fmaxf(Z[ab + tid], 1e-6f);
    float acc[2][4][4];
#pragma unroll
    for (int i = 0; i < 2; i++)
#pragma unroll
        for (int j = 0; j < 4; j++)
#pragma unroll
            for (int r = 0; r < 4; r++) acc[i][j][r] = 0.f;
    auto load = [&](int kc, int buf) {
        uint32_t base = sb + buf * KBUF;
        int ke = kc << 6;
#pragma unroll
        for (int i = 0; i < 4; i++) {
            int idx = tid + (i << 8), r = idx >> 3, c = idx & 7;
            uint32_t so = SWZ(r * 128 + c * 16);
            size_t g = (ab + r) * FD_ + ke + c * 8;
            cp_async16(base + KA + so, Ah + g);
            cp_async16(base + KAL + so, Al + g);
        }
#pragma unroll
        for (int i = 0; i < 2; i++) {
            int idx = tid + (i << 8), r = idx >> 3, c = idx & 7;
            uint32_t so = SWZ(r * 128 + c * 16);
            size_t g = (bb + r) * FD_ + ke + c * 8;
            cp_async16(base + KB + so, Bh + g);
            cp_async16(base + KBL + so, Bl + g);
        }
    };
    load(0, 0); cp_commit();
    for (int kc = 0; kc < 8; kc++) {
        int cur = kc & 1;
        if (kc + 1 < 8) { load(kc + 1, cur ^ 1); cp_commit(); cp_wait<1>(); }
        else cp_wait<0>();
        __syncthreads();
        uint32_t bA = sb + cur * KBUF;
#pragma unroll
        for (int ks = 0; ks < 4; ks++) {
            uint32_t a_h[2][4], a_l[2][4], b_h[4][2], b_l[4][2];
#pragma unroll
            for (int i = 0; i < 2; i++) {
                uint32_t o = SWZ((wm + i * 16 + lr) * 128 + ks * 32 + lc * 16);
                ldsm_x4(a_h[i][0], a_h[i][1], a_h[i][2], a_h[i][3], bA + KA + o);
                ldsm_x4(a_l[i][0], a_l[i][1], a_l[i][2], a_l[i][3], bA + KAL + o);
            }
#pragma unroll
            for (int j = 0; j < 4; j++) {
                uint32_t o = SWZ((wn + j * 8 + br) * 128 + ks * 32 + bk * 16);
                ldsm_x2(b_h[j][0], b_h[j][1], bA + KB + o);
                ldsm_x2(b_l[j][0], b_l[j][1], bA + KBL + o);
            }
#pragma unroll
            for (int i = 0; i < 2; i++)
#pragma unroll
                for (int j = 0; j < 4; j++) {
                    mma_bf16(acc[i][j], a_h[i], b_h[j]);
                    mma_bf16(acc[i][j], a_h[i], b_l[j]);
                    mma_bf16(acc[i][j], a_l[i], b_h[j]);
                }
        }
        __syncthreads();
    }
#pragma unroll
    for (int i = 0; i < 2; i++) {
        int row = wm + i * 16 + (lane >> 2);
        float iv0 = ziv[row], iv1 = ziv[row + 8];
#pragma unroll
        for (int j = 0; j < 4; j++) {
            int col = wn + j * 8 + ((lane & 3) << 1);
            size_t g0 = ((size_t)(b * T_ + t0 + row)) * D_ + h * DH_ + col;
            store_pair(oh, ol, g0, acc[i][j][0] * iv0, acc[i][j][1] * iv0);
            store_pair(oh, ol, g0 + (size_t)8 * D_, acc[i][j][2] * iv1, acc[i][j][3] * iv1);
        }
    }
}

// ======== launch ========
extern "C" void kernel_launch(void* const* d_in, const int* in_sizes, int n_in,
                              void* d_out, int out_size)
{
    const float* x  = (const float*)d_in[0];
    const float* wq = (const float*)d_in[1];
    const float* wk = (const float*)d_in[2];
    const float* wv = (const float*)d_in[3];
    const float* wo = (const float*)d_in[4];
    const float* rf = (const float*)d_in[5];
    float* out = (float*)d_out;

    float* fb = nullptr; cudaGetSymbolAddress((void**)&fb, g_buf);
    bf16*  bb = nullptr; cudaGetSymbolAddress((void**)&bb, g_bf);

    float *Qp = fb + OFF_Q, *Kp = fb + OFF_K, *Vp = fb + OFF_V;
    float *KSp = fb + OFF_KS, *Zp = fb + OFF_Z;
    bf16 *xh = bb + BO_XH, *xl = bb + BO_XL;
    bf16 *rfh = bb + BO_RFH, *rfl = bb + BO_RFL;
    bf16 *Qfh = bb + BO_QFH, *Qfl = bb + BO_QFL;
    bf16 *KfTh = bb + BO_KFTH, *KfTl = bb + BO_KFTL;
    bf16 *VTh = bb + BO_VTH, *VTl = bb + BO_VTL;
    bf16 *KVTh = bb + BO_KVTH, *KVTl = bb + BO_KVTL;
    bf16 *ah = bb + BO_AH, *al = bb + BO_AL;
    bf16 *W[8];
    for (int i = 0; i < 8; i++) W[i] = bb + BO_W + (size_t)i * D_ * D_;

    cudaFuncSetAttribute(mma_gemm, cudaFuncAttributeMaxDynamicSharedMemorySize, SMEM_G);
    cudaFuncSetAttribute(phi_q_kernel, cudaFuncAttributeMaxDynamicSharedMemorySize, SMEM_PHI);
    cudaFuncSetAttribute(phi_k_kernel, cudaFuncAttributeMaxDynamicSharedMemorySize, SMEM_PHI);
    cudaFuncSetAttribute(kv_gemm, cudaFuncAttributeMaxDynamicSharedMemorySize, SMEM_KV);
    cudaFuncSetAttribute(qkv_gemm, cudaFuncAttributeMaxDynamicSharedMemorySize, SMEM_KV);

    split_kernel<<<(int)(SZ_BTD / 4 / 256), 256>>>(x, xh, xl, (int)(SZ_BTD / 4));
    int wn4 = D_ * D_ / 4;
    split_kernel<<<wn4 / 256, 256>>>(wq, W[0], W[1], wn4);
    split_kernel<<<wn4 / 256, 256>>>(wk, W[2], W[3], wn4);
    split_kernel<<<wn4 / 256, 256>>>(wv, W[4], W[5], wn4);
    split_kernel<<<wn4 / 256, 256>>>(wo, W[6], W[7], wn4);
    split_kernel<<<16, 256>>>(rf, rfh, rfl, 4096);

    dim3 gG(D_ / 128, (B_ * T_) / 128);
    mma_gemm<<<gG, 256, SMEM_G>>>(xh, xl, W[0], W[1], Qp, B_ * T_, D_, D_);
    mma_gemm<<<gG, 256, SMEM_G>>>(xh, xl, W[2], W[3], Kp, B_ * T_, D_, D_);
    mma_gemm<<<gG, 256, SMEM_G>>>(xh, xl, W[4], W[5], Vp, B_ * T_, D_, D_);

    dim3 gPhi(T_ / 128, 2, BH_);
    phi_q_kernel<<<gPhi, 256, SMEM_PHI>>>(Qp, rfh, rfl, Qfh, Qfl);
    phi_k_kernel<<<gPhi, 256, SMEM_PHI>>>(Kp, rfh, rfl, KfTh, KfTl);
    vtrans_kernel<<<dim3(T_ / 64, BH_), 256>>>(Vp, VTh, VTl);
    ksum_kernel<<<dim3(FD_ / 8, BH_), 256>>>(KfTh, KfTl, KSp);
    z_kernel<<<(BH_ * T_) / 8, 256>>>(Qfh, Qfl, KSp, Zp);

    kv_gemm<<<dim3(FD_ / 128, BH_), 256, SMEM_KV>>>(KfTh, KfTl, VTh, VTl, KVTh, KVTl);
    qkv_gemm<<<dim3(T_ / 128, BH_), 256, SMEM_KV>>>(Qfh, Qfl, KVTh, KVTl, Zp, ah, al);

    mma_gemm<<<gG, 256, SMEM_G>>>(ah, al, W[6], W[7], out, B_ * T_, D_, D_);
}

// round 8
// speedup vs baseline: 2.4084x; 1.0693x over previous
#include <cuda_runtime.h>
#include <cuda_bf16.h>
#include <cuda_fp16.h>
#include <cstdint>
typedef __nv_bfloat16 bf16;
typedef __half f16;

#define B_   2
#define T_   4096
#define D_   1024
#define H_   16
#define DH_  64
#define FD_  512
#define BH_  (B_*H_)
#define SZ_BTD ((size_t)B_*T_*D_)
#define SZ_F   ((size_t)BH_*T_*FD_)

#define OFF_Q   ((size_t)0)
#define OFF_K   (SZ_BTD)
#define OFF_V   (2*SZ_BTD)
#define OFF_KS  (3*SZ_BTD)
#define OFF_Z   (OFF_KS + (size_t)BH_*FD_)
__device__ float g_buf[OFF_Z + (size_t)BH_*T_];

#define BO_XH   ((size_t)0)
#define BO_XL   (SZ_BTD)
#define BO_W    (2*SZ_BTD)
#define BO_RF   (BO_W + 8*(size_t)D_*D_)
#define BO_QFH  (BO_RF + 16384)
#define BO_QFL  (BO_QFH + SZ_F)
#define BO_KFTH (BO_QFL + SZ_F)
#define BO_KFTL (BO_KFTH + SZ_F)
#define BO_VTH  (BO_KFTL + SZ_F)
#define BO_VTL  (BO_VTH + SZ_BTD)
#define BO_KVTH (BO_VTL + SZ_BTD)
#define BO_KVTL (BO_KVTH + (size_t)BH_*DH_*FD_)
#define BO_AH   (BO_KVTL + (size_t)BH_*DH_*FD_)
#define BO_AL   (BO_AH + SZ_BTD)
__device__ bf16 g_bf[BO_AL + SZ_BTD];

__device__ __forceinline__ uint32_t smem_to_u32(const void* p) {
    uint32_t a;
    asm("{ .reg .u64 t; cvta.to.shared.u64 t, %1; cvt.u32.u64 %0, t; }" : "=r"(a) : "l"(p));
    return a;
}
#define SWZ(o) ((o) ^ (((o) >> 3) & 0x70))
__device__ __forceinline__ void cp_async16(uint32_t s, const void* g) {
    asm volatile("cp.async.cg.shared.global [%0], [%1], 16;" :: "r"(s), "l"(g));
}
__device__ __forceinline__ void cp_commit() { asm volatile("cp.async.commit_group;" ::: "memory"); }
template <int N> __device__ __forceinline__ void cp_wait() {
    asm volatile("cp.async.wait_group %0;" :: "n"(N) : "memory");
}
__device__ __forceinline__ void ldsm_x4(uint32_t& r0, uint32_t& r1, uint32_t& r2, uint32_t& r3, uint32_t a) {
    asm volatile("ldmatrix.sync.aligned.m8n8.x4.shared.b16 {%0,%1,%2,%3}, [%4];"
                 : "=r"(r0), "=r"(r1), "=r"(r2), "=r"(r3) : "r"(a));
}
__device__ __forceinline__ void ldsm_x2(uint32_t& r0, uint32_t& r1, uint32_t a) {
    asm volatile("ldmatrix.sync.aligned.m8n8.x2.shared.b16 {%0,%1}, [%2];"
                 : "=r"(r0), "=r"(r1) : "r"(a));
}
__device__ __forceinline__ void mma_bf16(float* c, const uint32_t* a, const uint32_t* b) {
    asm volatile("mma.sync.aligned.m16n8k16.row.col.f32.bf16.bf16.f32 "
                 "{%0,%1,%2,%3}, {%4,%5,%6,%7}, {%8,%9}, {%0,%1,%2,%3};"
                 : "+f"(c[0]), "+f"(c[1]), "+f"(c[2]), "+f"(c[3])
                 : "r"(a[0]), "r"(a[1]), "r"(a[2]), "r"(a[3]), "r"(b[0]), "r"(b[1]));
}
__device__ __forceinline__ void mma_f16(float* c, const uint32_t* a, const uint32_t* b) {
    asm volatile("mma.sync.aligned.m16n8k16.row.col.f32.f16.f16.f32 "
                 "{%0,%1,%2,%3}, {%4,%5,%6,%7}, {%8,%9}, {%0,%1,%2,%3};"
                 : "+f"(c[0]), "+f"(c[1]), "+f"(c[2]), "+f"(c[3])
                 : "r"(a[0]), "r"(a[1]), "r"(a[2]), "r"(a[3]), "r"(b[0]), "r"(b[1]));
}
__device__ __forceinline__ void store_pair(bf16* ph, bf16* pl, size_t off, float x0, float x1) {
    bf16 h0 = __float2bfloat16(x0), h1 = __float2bfloat16(x1);
    __nv_bfloat162 hp(h0, h1);
    *(uint32_t*)(ph + off) = *(uint32_t*)&hp;
    __nv_bfloat162 lp(__float2bfloat16(x0 - __bfloat162float(h0)),
                      __float2bfloat16(x1 - __bfloat162float(h1)));
    *(uint32_t*)(pl + off) = *(uint32_t*)&lp;
}
__device__ __forceinline__ void store_pair_h(f16* ph, f16* pl, size_t off, float x0, float x1) {
    f16 h0 = __float2half_rn(x0), h1 = __float2half_rn(x1);
    __half2 hp = __halves2half2(h0, h1);
    *(uint32_t*)(ph + off) = *(uint32_t*)&hp;
    __half2 lp = __halves2half2(__float2half_rn(x0 - __half2float(h0)),
                                __float2half_rn(x1 - __half2float(h1)));
    *(uint32_t*)(pl + off) = *(uint32_t*)&lp;
}
__device__ __forceinline__ void fast_sincos(float x, float& s, float& c) {
    float kf = rintf(x * 0.63661977f);
    int q = (int)kf;
    float r = fmaf(kf, -1.5707963705062866f, x);
    r = fmaf(kf, 4.3711388286738e-8f, r);
    float r2 = r * r;
    float sp = fmaf(-1.98412698e-4f, r2, 8.33333333e-3f);
    sp = fmaf(sp, r2, -1.66666667e-1f) * r2;
    float sr = fmaf(sp, r, r);
    float cp = fmaf(2.48015873e-5f, r2, -1.38888889e-3f);
    cp = fmaf(cp, r2, 4.16666667e-2f);
    cp = fmaf(cp, r2, -0.5f);
    float cr = fmaf(cp, r2, 1.0f);
    if (q & 1) { float t = sr; sr = cr; cr = -t; }
    if (q & 2) { sr = -sr; cr = -cr; }
    s = sr; c = cr;
}

#define TILE_B 16384

// ======== 3-pass GEMM (templated mma op by flag): C = A(hi/lo) B(hi/lo)^T ========
#define BUF3   (4*TILE_B)
#define SMEM_G3 (2*BUF3)
template <int USE_F16>
__global__ void __launch_bounds__(256)
gemm3t(const uint32_t* __restrict__ Ah_, const uint32_t* __restrict__ Al_,
       const uint32_t* __restrict__ Bh_, const uint32_t* __restrict__ Bl_,
       float* __restrict__ C, int M, int N, int K)
{
    extern __shared__ char smem[];
    const uint32_t sb = smem_to_u32(smem);
    const int tid = threadIdx.x, wid = tid >> 5, lane = tid & 31;
    const int bn = blockIdx.x << 7, bm = blockIdx.y << 7;
    const int wm = (wid >> 2) << 6, wn = (wid & 3) << 5;
    const int nchunk = K >> 6;
    const int lr = lane & 15, lc = lane >> 4, br = lane & 7, bk = (lane >> 3) & 1;
    float acc[4][4][4];
#pragma unroll
    for (int i = 0; i < 4; i++)
#pragma unroll
        for (int j = 0; j < 4; j++)
#pragma unroll
            for (int r = 0; r < 4; r++) acc[i][j][r] = 0.f;
    const char* gs[4] = {(const char*)Ah_, (const char*)Al_, (const char*)Bh_, (const char*)Bl_};
    const int rb[4] = {bm, bm, bn, bn};
    auto load = [&](int kc, int buf) {
        uint32_t base = sb + buf * BUF3;
        int ke = kc << 6;
#pragma unroll
        for (int t = 0; t < 4; t++)
#pragma unroll
            for (int i = 0; i < 4; i++) {
                int idx = tid + (i << 8), r = idx >> 3, c = idx & 7;
                cp_async16(base + t * TILE_B + SWZ(r * 128 + c * 16),
                           gs[t] + ((size_t)(rb[t] + r) * K + ke) * 2 + c * 16);
            }
    };
    load(0, 0); cp_commit();
    for (int kc = 0; kc < nchunk; kc++) {
        int cur = kc & 1;
        if (kc + 1 < nchunk) { load(kc + 1, cur ^ 1); cp_commit(); cp_wait<1>(); }
        else cp_wait<0>();
        __syncthreads();
        uint32_t bA = sb + cur * BUF3;
#pragma unroll
        for (int ks = 0; ks < 4; ks++) {
            uint32_t a_h[4][4], a_l[4][4], b_h[4][2], b_l[4][2];
#pragma unroll
            for (int i = 0; i < 4; i++) {
                uint32_t o = SWZ((wm + i * 16 + lr) * 128 + ks * 32 + lc * 16);
                ldsm_x4(a_h[i][0], a_h[i][1], a_h[i][2], a_h[i][3], bA + o);
                ldsm_x4(a_l[i][0], a_l[i][1], a_l[i][2], a_l[i][3], bA + TILE_B + o);
            }
#pragma unroll
            for (int j = 0; j < 4; j++) {
                uint32_t o = SWZ((wn + j * 8 + br) * 128 + ks * 32 + bk * 16);
                ldsm_x2(b_h[j][0], b_h[j][1], bA + 2 * TILE_B + o);
                ldsm_x2(b_l[j][0], b_l[j][1], bA + 3 * TILE_B + o);
            }
#pragma unroll
            for (int i = 0; i < 4; i++)
#pragma unroll
                for (int j = 0; j < 4; j++) {
                    if (USE_F16) {
                        mma_f16(acc[i][j], a_h[i], b_h[j]);
                        mma_f16(acc[i][j], a_h[i], b_l[j]);
                        mma_f16(acc[i][j], a_l[i], b_h[j]);
                    } else {
                        mma_bf16(acc[i][j], a_h[i], b_h[j]);
                        mma_bf16(acc[i][j], a_h[i], b_l[j]);
                        mma_bf16(acc[i][j], a_l[i], b_h[j]);
                    }
                }
        }
        __syncthreads();
    }
#pragma unroll
    for (int i = 0; i < 4; i++) {
        int row = bm + wm + i * 16 + (lane >> 2);
#pragma unroll
        for (int j = 0; j < 4; j++) {
            int col = bn + wn + j * 8 + ((lane & 3) << 1);
            *(float2*)&C[(size_t)row * N + col]       = make_float2(acc[i][j][0], acc[i][j][1]);
            *(float2*)&C[(size_t)(row + 8) * N + col] = make_float2(acc[i][j][2], acc[i][j][3]);
        }
    }
}

// ======== fp16 2-pass GEMM (V): C = (Ah+Al) B^T ========
#define BUF2   (3*TILE_B)
#define SMEM_G2 (2*BUF2)
__global__ void __launch_bounds__(256)
gemm2(const f16* __restrict__ Ah, const f16* __restrict__ Al,
      const f16* __restrict__ Bm, float* __restrict__ C, int M, int N, int K)
{
    extern __shared__ char smem[];
    const uint32_t sb = smem_to_u32(smem);
    const int tid = threadIdx.x, wid = tid >> 5, lane = tid & 31;
    const int bn = blockIdx.x << 7, bm = blockIdx.y << 7;
    const int wm = (wid >> 2) << 6, wn = (wid & 3) << 5;
    const int nchunk = K >> 6;
    const int lr = lane & 15, lc = lane >> 4, br = lane & 7, bk = (lane >> 3) & 1;
    float acc[4][4][4];
#pragma unroll
    for (int i = 0; i < 4; i++)
#pragma unroll
        for (int j = 0; j < 4; j++)
#pragma unroll
            for (int r = 0; r < 4; r++) acc[i][j][r] = 0.f;
    auto load = [&](int kc, int buf) {
        uint32_t base = sb + buf * BUF2;
        int ke = kc << 6;
#pragma unroll
        for (int i = 0; i < 4; i++) {
            int idx = tid + (i << 8), r = idx >> 3, c = idx & 7;
            uint32_t so = SWZ(r * 128 + c * 16);
            cp_async16(base + so,              Ah + (size_t)(bm + r) * K + ke + c * 8);
            cp_async16(base + TILE_B + so,     Al + (size_t)(bm + r) * K + ke + c * 8);
            cp_async16(base + 2 * TILE_B + so, Bm + (size_t)(bn + r) * K + ke + c * 8);
        }
    };
    load(0, 0); cp_commit();
    for (int kc = 0; kc < nchunk; kc++) {
        int cur = kc & 1;
        if (kc + 1 < nchunk) { load(kc + 1, cur ^ 1); cp_commit(); cp_wait<1>(); }
        else cp_wait<0>();
        __syncthreads();
        uint32_t bA = sb + cur * BUF2;
#pragma unroll
        for (int ks = 0; ks < 4; ks++) {
            uint32_t a_h[4][4], a_l[4][4], b_[4][2];
#pragma unroll
            for (int i = 0; i < 4; i++) {
                uint32_t o = SWZ((wm + i * 16 + lr) * 128 + ks * 32 + lc * 16);
                ldsm_x4(a_h[i][0], a_h[i][1], a_h[i][2], a_h[i][3], bA + o);
                ldsm_x4(a_l[i][0], a_l[i][1], a_l[i][2], a_l[i][3], bA + TILE_B + o);
            }
#pragma unroll
            for (int j = 0; j < 4; j++) {
                uint32_t o = SWZ((wn + j * 8 + br) * 128 + ks * 32 + bk * 16);
                ldsm_x2(b_[j][0], b_[j][1], bA + 2 * TILE_B + o);
            }
#pragma unroll
            for (int i = 0; i < 4; i++)
#pragma unroll
                for (int j = 0; j < 4; j++) {
                    mma_f16(acc[i][j], a_h[i], b_[j]);
                    mma_f16(acc[i][j], a_l[i], b_[j]);
                }
        }
        __syncthreads();
    }
#pragma unroll
    for (int i = 0; i < 4; i++) {
        int row = bm + wm + i * 16 + (lane >> 2);
#pragma unroll
        for (int j = 0; j < 4; j++) {
            int col = bn + wn + j * 8 + ((lane & 3) << 1);
            *(float2*)&C[(size_t)row * N + col]       = make_float2(acc[i][j][0], acc[i][j][1]);
            *(float2*)&C[(size_t)(row + 8) * N + col] = make_float2(acc[i][j][2], acc[i][j][3]);
        }
    }
}

// ======== conversions ========
__global__ void __launch_bounds__(256) split16_kernel(const float* __restrict__ in,
                                                      f16* __restrict__ hi, f16* __restrict__ lo, int n4)
{
    int i = blockIdx.x * 256 + threadIdx.x;
    if (i >= n4) return;
    float4 v = ((const float4*)in)[i];
    store_pair_h(hi, lo, (size_t)i * 4, v.x, v.y);
    store_pair_h(hi, lo, (size_t)i * 4 + 2, v.z, v.w);
}
__global__ void __launch_bounds__(256) splitbf_kernel(const float* __restrict__ in,
                                                      bf16* __restrict__ hi, bf16* __restrict__ lo, int n4)
{
    int i = blockIdx.x * 256 + threadIdx.x;
    if (i >= n4) return;
    float4 v = ((const float4*)in)[i];
    store_pair(hi, lo, (size_t)i * 4, v.x, v.y);
    store_pair(hi, lo, (size_t)i * 4 + 2, v.z, v.w);
}
__global__ void __launch_bounds__(256) conv16_kernel(const float* __restrict__ in,
                                                     f16* __restrict__ out, int n4)
{
    int i = blockIdx.x * 256 + threadIdx.x;
    if (i >= n4) return;
    float4 v = ((const float4*)in)[i];
    __half2 p0 = __halves2half2(__float2half_rn(v.x), __float2half_rn(v.y));
    __half2 p1 = __halves2half2(__float2half_rn(v.z), __float2half_rn(v.w));
    uint2 o; o.x = *(uint32_t*)&p0; o.y = *(uint32_t*)&p1;
    ((uint2*)out)[i] = o;
}

// ======== phi kernels (fp16 proj, 2 MMAs) ========
#define PA  0
#define PAL 16384
#define PB  32768
#define PBL 49152
#define PSC 65536
#define PNP 66048
#define SMEM_PHI 67072

__device__ __forceinline__ void conv_tile_h(const float* g, char* sm, int dstH, int dstL,
                                            float* np, int tid) {
    int r = tid >> 1, cb = (tid & 1) << 5;
    float s = 0.f;
    const float* gp = g + (size_t)r * D_ + cb;
#pragma unroll
    for (int k = 0; k < 8; k++) {
        float4 v = *(const float4*)(gp + k * 4);
        s = fmaf(v.x, v.x, s); s = fmaf(v.y, v.y, s);
        s = fmaf(v.z, v.z, s); s = fmaf(v.w, v.w, s);
        uint32_t sw = SWZ((uint32_t)(r * 128 + (cb + k * 4) * 2));
        f16 h0 = __float2half_rn(v.x), h1 = __float2half_rn(v.y);
        f16 h2 = __float2half_rn(v.z), h3 = __float2half_rn(v.w);
        __half2 hp0 = __halves2half2(h0, h1), hp1 = __halves2half2(h2, h3);
        *(uint32_t*)(sm + dstH + sw) = *(uint32_t*)&hp0;
        *(uint32_t*)(sm + dstH + sw + 4) = *(uint32_t*)&hp1;
        __half2 lp0 = __halves2half2(__float2half_rn(v.x - __half2float(h0)),
                                     __float2half_rn(v.y - __half2float(h1)));
        __half2 lp1 = __halves2half2(__float2half_rn(v.z - __half2float(h2)),
                                     __float2half_rn(v.w - __half2float(h3)));
        *(uint32_t*)(sm + dstL + sw) = *(uint32_t*)&lp0;
        *(uint32_t*)(sm + dstL + sw + 4) = *(uint32_t*)&lp1;
    }
    np[tid] = s;
}

__global__ void __launch_bounds__(256) phi_q_kernel(
    const float* __restrict__ Q, const f16* __restrict__ rf16,
    bf16* __restrict__ Qfh, bf16* __restrict__ Qfl)
{
    extern __shared__ char sm[];
    const uint32_t sb = smem_to_u32(sm);
    const int tid = threadIdx.x, wid = tid >> 5, lane = tid & 31;
    const int t0 = blockIdx.x << 7, m0c = blockIdx.y << 7, bh = blockIdx.z;
    const int b = bh >> 4, h = bh & 15;
    float* scale = (float*)(sm + PSC);
    float* np = (float*)(sm + PNP);
#pragma unroll
    for (int i = 0; i < 4; i++) {
        int idx = tid + (i << 8), r = idx >> 3, c = idx & 7;
        cp_async16(sb + PB + SWZ(r * 128 + c * 16), rf16 + (size_t)(m0c + r) * DH_ + c * 8);
    }
    cp_commit();
    conv_tile_h(&Q[((size_t)(b * T_ + t0)) * D_ + h * DH_], sm, PA, PAL, np, tid);
    __syncthreads();
    if (tid < 128) scale[tid] = __expf(-0.5f * (np[2 * tid] + np[2 * tid + 1])) * 0.0625f;
    cp_wait<0>();
    __syncthreads();
    const int wt = (wid >> 2) << 6, wm = (wid & 3) << 5;
    const int lr = lane & 15, lc = lane >> 4, br = lane & 7, bk = (lane >> 3) & 1;
    float acc[4][4][4];
#pragma unroll
    for (int i = 0; i < 4; i++)
#pragma unroll
        for (int j = 0; j < 4; j++)
#pragma unroll
            for (int r = 0; r < 4; r++) acc[i][j][r] = 0.f;
#pragma unroll
    for (int ks = 0; ks < 4; ks++) {
        uint32_t a_h[4][4], a_l[4][4], b_[4][2];
#pragma unroll
        for (int i = 0; i < 4; i++) {
            uint32_t o = SWZ((wt + i * 16 + lr) * 128 + ks * 32 + lc * 16);
            ldsm_x4(a_h[i][0], a_h[i][1], a_h[i][2], a_h[i][3], sb + PA + o);
            ldsm_x4(a_l[i][0], a_l[i][1], a_l[i][2], a_l[i][3], sb + PAL + o);
        }
#pragma unroll
        for (int j = 0; j < 4; j++) {
            uint32_t o = SWZ((wm + j * 8 + br) * 128 + ks * 32 + bk * 16);
            ldsm_x2(b_[j][0], b_[j][1], sb + PB + o);
        }
#pragma unroll
        for (int i = 0; i < 4; i++)
#pragma unroll
            for (int j = 0; j < 4; j++) {
                mma_f16(acc[i][j], a_h[i], b_[j]);
                mma_f16(acc[i][j], a_l[i], b_[j]);
            }
    }
#pragma unroll
    for (int i = 0; i < 4; i++) {
        int r0 = wt + i * 16 + (lane >> 2);
        float sc0 = scale[r0], sc1 = scale[r0 + 8];
        size_t rb0 = ((size_t)bh * T_ + t0 + r0) * FD_ + m0c;
        size_t rb1 = rb0 + (size_t)8 * FD_;
#pragma unroll
        for (int j = 0; j < 4; j++) {
            int mc = wm + j * 8 + ((lane & 3) << 1);
            float sn0, cs0, sn1, cs1;
            fast_sincos(acc[i][j][0], sn0, cs0);
            fast_sincos(acc[i][j][1], sn1, cs1);
            store_pair(Qfh, Qfl, rb0 + mc, cs0 * sc0, cs1 * sc0);
            store_pair(Qfh, Qfl, rb0 + 256 + mc, sn0 * sc0, sn1 * sc0);
            fast_sincos(acc[i][j][2], sn0, cs0);
            fast_sincos(acc[i][j][3], sn1, cs1);
            store_pair(Qfh, Qfl, rb1 + mc, cs0 * sc1, cs1 * sc1);
            store_pair(Qfh, Qfl, rb1 + 256 + mc, sn0 * sc1, sn1 * sc1);
        }
    }
}

__global__ void __launch_bounds__(256) phi_k_kernel(
    const float* __restrict__ Kg, const f16* __restrict__ rf16,
    bf16* __restrict__ KfTh, bf16* __restrict__ KfTl)
{
    extern __shared__ char sm[];
    const uint32_t sb = smem_to_u32(sm);
    const int tid = threadIdx.x, wid = tid >> 5, lane = tid & 31;
    const int t0 = blockIdx.x << 7, m0c = blockIdx.y << 7, bh = blockIdx.z;
    const int b = bh >> 4, h = bh & 15;
    float* scale = (float*)(sm + PSC);
    float* np = (float*)(sm + PNP);
#pragma unroll
    for (int i = 0; i < 4; i++) {
        int idx = tid + (i << 8), r = idx >> 3, c = idx & 7;
        cp_async16(sb + PA + SWZ(r * 128 + c * 16), rf16 + (size_t)(m0c + r) * DH_ + c * 8);
    }
    cp_commit();
    conv_tile_h(&Kg[((size_t)(b * T_ + t0)) * D_ + h * DH_], sm, PB, PBL, np, tid);
    __syncthreads();
    if (tid < 128) scale[tid] = __expf(-0.5f * (np[2 * tid] + np[2 * tid + 1])) * 0.0625f;
    cp_wait<0>();
    __syncthreads();
    const int wm = (wid >> 2) << 6, wt = (wid & 3) << 5;
    const int lr = lane & 15, lc = lane >> 4, br = lane & 7, bk = (lane >> 3) & 1;
    float acc[4][4][4];
#pragma unroll
    for (int i = 0; i < 4; i++)
#pragma unroll
        for (int j = 0; j < 4; j++)
#pragma unroll
            for (int r = 0; r < 4; r++) acc[i][j][r] = 0.f;
#pragma unroll
    for (int ks = 0; ks < 4; ks++) {
        uint32_t a_[4][4], b_h[4][2], b_l[4][2];
#pragma unroll
        for (int i = 0; i < 4; i++) {
            uint32_t o = SWZ((wm + i * 16 + lr) * 128 + ks * 32 + lc * 16);
            ldsm_x4(a_[i][0], a_[i][1], a_[i][2], a_[i][3], sb + PA + o);
        }
#pragma unroll
        for (int j = 0; j < 4; j++) {
            uint32_t o = SWZ((wt + j * 8 + br) * 128 + ks * 32 + bk * 16);
            ldsm_x2(b_h[j][0], b_h[j][1], sb + PB + o);
            ldsm_x2(b_l[j][0], b_l[j][1], sb + PBL + o);
        }
#pragma unroll
        for (int i = 0; i < 4; i++)
#pragma unroll
            for (int j = 0; j < 4; j++) {
                mma_f16(acc[i][j], a_[i], b_h[j]);
                mma_f16(acc[i][j], a_[i], b_l[j]);
            }
    }
#pragma unroll
    for (int i = 0; i < 4; i++) {
        int r0 = wm + i * 16 + (lane >> 2);
        size_t rc0 = ((size_t)bh * FD_ + m0c + r0) * T_ + t0;
        size_t rs0 = rc0 + (size_t)256 * T_;
        size_t rc1 = rc0 + (size_t)8 * T_, rs1 = rs0 + (size_t)8 * T_;
#pragma unroll
        for (int j = 0; j < 4; j++) {
            int tc = wt + j * 8 + ((lane & 3) << 1);
            float sc0 = scale[tc], sc1 = scale[tc + 1];
            float sn0, cs0, sn1, cs1;
            fast_sincos(acc[i][j][0], sn0, cs0);
            fast_sincos(acc[i][j][1], sn1, cs1);
            store_pair(KfTh, KfTl, rc0 + tc, cs0 * sc0, cs1 * sc1);
            store_pair(KfTh, KfTl, rs0 + tc, sn0 * sc0, sn1 * sc1);
            fast_sincos(acc[i][j][2], sn0, cs0);
            fast_sincos(acc[i][j][3], sn1, cs1);
            store_pair(KfTh, KfTl, rc1 + tc, cs0 * sc0, cs1 * sc1);
            store_pair(KfTh, KfTl, rs1 + tc, sn0 * sc0, sn1 * sc1);
        }
    }
}

// ======== V transpose ========
__global__ void __launch_bounds__(256) vtrans_kernel(const float* __restrict__ V,
                                                     bf16* __restrict__ VTh, bf16* __restrict__ VTl)
{
    __shared__ float st[64][68];
    const int tid = threadIdx.x;
    const int t0 = blockIdx.x << 6, bh = blockIdx.y;
    const int b = bh >> 4, h = bh & 15;
#pragma unroll
    for (int i = 0; i < 4; i++) {
        int idx = tid + (i << 8), r = idx >> 4, c4 = (idx & 15) << 2;
        *(float4*)&st[r][c4] = *(const float4*)&V[((size_t)(b * T_ + t0 + r)) * D_ + h * DH_ + c4];
    }
    __syncthreads();
    int v = tid >> 2, ts = (tid & 3) << 4;
#pragma unroll
    for (int p = 0; p < 8; p++) {
        int t = ts + p * 2;
        store_pair(VTh, VTl, ((size_t)bh * DH_ + v) * T_ + t0 + t, st[t][v], st[t + 1][v]);
    }
}

// ======== Ksum / Z ========
__global__ void __launch_bounds__(256) ksum_kernel(const bf16* __restrict__ KfTh,
                                                   const bf16* __restrict__ KfTl,
                                                   float* __restrict__ Ksum)
{
    const int wid = threadIdx.x >> 5, lane = threadIdx.x & 31;
    const int f = blockIdx.x * 8 + wid, bh = blockIdx.y;
    const bf16* ph = KfTh + ((size_t)bh * FD_ + f) * T_;
    const bf16* pl = KfTl + ((size_t)bh * FD_ + f) * T_;
    float s = 0.f;
    for (int i = lane * 2; i < T_; i += 64) {
        uint32_t hp = *(const uint32_t*)(ph + i), lp = *(const uint32_t*)(pl + i);
        __nv_bfloat162 h2 = *(__nv_bfloat162*)&hp, l2 = *(__nv_bfloat162*)&lp;
        s += __bfloat162float(h2.x) + __bfloat162float(l2.x)
           + __bfloat162float(h2.y) + __bfloat162float(l2.y);
    }
#pragma unroll
    for (int o = 16; o; o >>= 1) s += __shfl_xor_sync(0xffffffffu, s, o);
    if (lane == 0) Ksum[(size_t)bh * FD_ + f] = s;
}

__global__ void __launch_bounds__(256) z_kernel(const bf16* __restrict__ Qfh,
                                                const bf16* __restrict__ Qfl,
                                                const float* __restrict__ Ksum,
                                                float* __restrict__ Z)
{
    const int warp = threadIdx.x >> 5, lane = threadIdx.x & 31;
    const size_t row = (size_t)blockIdx.x * 8 + warp;
    const int bh = (int)(row >> 12);
    const bf16* qh = Qfh + row * FD_;
    const bf16* ql = Qfl + row * FD_;
    const float* ks = Ksum + (size_t)bh * FD_;
    float s = 0.f;
#pragma unroll
    for (int j = 0; j < 8; j++) {
        int f = lane * 2 + j * 64;
        uint32_t hp = *(const uint32_t*)(qh + f), lp = *(const uint32_t*)(ql + f);
        __nv_bfloat162 h2 = *(__nv_bfloat162*)&hp, l2 = *(__nv_bfloat162*)&lp;
        s = fmaf(__bfloat162float(h2.x) + __bfloat162float(l2.x), ks[f], s);
        s = fmaf(__bfloat162float(h2.y) + __bfloat162float(l2.y), ks[f + 1], s);
    }
#pragma unroll
    for (int o = 16; o; o >>= 1) s += __shfl_xor_sync(0xffffffffu, s, o);
    if (lane == 0) Z[row] = s;
}

// ======== kv / qkv tensor GEMMs (bf16x3, M=128, N=64) ========
#define KA   0
#define KAL  16384
#define KB   32768
#define KBL  40960
#define KBUF 49152
#define SMEM_KV (2*KBUF)

__global__ void __launch_bounds__(256) kv_gemm(
    const bf16* __restrict__ Ah, const bf16* __restrict__ Al,
    const bf16* __restrict__ Bh, const bf16* __restrict__ Bl,
    bf16* __restrict__ KVTh, bf16* __restrict__ KVTl)
{
    extern __shared__ char sm[];
    const uint32_t sb = smem_to_u32(sm);
    const int tid = threadIdx.x, wid = tid >> 5, lane = tid & 31;
    const int m0 = blockIdx.x << 7, bh = blockIdx.y;
    const size_t ab = (size_t)bh * FD_ + m0, bb = (size_t)bh * DH_;
    const int wm = (wid >> 1) << 5, wn = (wid & 1) << 5;
    const int lr = lane & 15, lc = lane >> 4, br = lane & 7, bk = (lane >> 3) & 1;
    float acc[2][4][4];
#pragma unroll
    for (int i = 0; i < 2; i++)
#pragma unroll
        for (int j = 0; j < 4; j++)
#pragma unroll
            for (int r = 0; r < 4; r++) acc[i][j][r] = 0.f;
    auto load = [&](int kc, int buf) {
        uint32_t base = sb + buf * KBUF;
        int ke = kc << 6;
#pragma unroll
        for (int i = 0; i < 4; i++) {
            int idx = tid + (i << 8), r = idx >> 3, c = idx & 7;
            uint32_t so = SWZ(r * 128 + c * 16);
            size_t g = (ab + r) * T_ + ke + c * 8;
            cp_async16(base + KA + so, Ah + g);
            cp_async16(base + KAL + so, Al + g);
        }
#pragma unroll
        for (int i = 0; i < 2; i++) {
            int idx = tid + (i << 8), r = idx >> 3, c = idx & 7;
            uint32_t so = SWZ(r * 128 + c * 16);
            size_t g = (bb + r) * T_ + ke + c * 8;
            cp_async16(base + KB + so, Bh + g);
            cp_async16(base + KBL + so, Bl + g);
        }
    };
    load(0, 0); cp_commit();
    for (int kc = 0; kc < T_ / 64; kc++) {
        int cur = kc & 1;
        if (kc + 1 < T_ / 64) { load(kc + 1, cur ^ 1); cp_commit(); cp_wait<1>(); }
        else cp_wait<0>();
        __syncthreads();
        uint32_t bA = sb + cur * KBUF;
#pragma unroll
        for (int ks = 0; ks < 4; ks++) {
            uint32_t a_h[2][4], a_l[2][4], b_h[4][2], b_l[4][2];
#pragma unroll
            for (int i = 0; i < 2; i++) {
                uint32_t o = SWZ((wm + i * 16 + lr) * 128 + ks * 32 + lc * 16);
                ldsm_x4(a_h[i][0], a_h[i][1], a_h[i][2], a_h[i][3], bA + KA + o);
                ldsm_x4(a_l[i][0], a_l[i][1], a_l[i][2], a_l[i][3], bA + KAL + o);
            }
#pragma unroll
            for (int j = 0; j < 4; j++) {
                uint32_t o = SWZ((wn + j * 8 + br) * 128 + ks * 32 + bk * 16);
                ldsm_x2(b_h[j][0], b_h[j][1], bA + KB + o);
                ldsm_x2(b_l[j][0], b_l[j][1], bA + KBL + o);
            }
#pragma unroll
            for (int i = 0; i < 2; i++)
#pragma unroll
                for (int j = 0; j < 4; j++) {
                    mma_bf16(acc[i][j], a_h[i], b_h[j]);
                    mma_bf16(acc[i][j], a_h[i], b_l[j]);
                    mma_bf16(acc[i][j], a_l[i], b_h[j]);
                }
        }
        __syncthreads();
    }
    float* stage = (float*)sm;
#pragma unroll
    for (int i = 0; i < 2; i++) {
        int row = wm + i * 16 + (lane >> 2);
#pragma unroll
        for (int j = 0; j < 4; j++) {
            int col = wn + j * 8 + ((lane & 3) << 1);
            stage[col * 132 + row]           = acc[i][j][0];
            stage[(col + 1) * 132 + row]     = acc[i][j][1];
            stage[col * 132 + row + 8]       = acc[i][j][2];
            stage[(col + 1) * 132 + row + 8] = acc[i][j][3];
        }
    }
    __syncthreads();
    int v = tid >> 2, fs = (tid & 3) << 5;
#pragma unroll
    for (int p = 0; p < 16; p++) {
        int f = fs + p * 2;
        store_pair(KVTh, KVTl, ((size_t)bh * DH_ + v) * FD_ + m0 + f,
                   stage[v * 132 + f], stage[v * 132 + f + 1]);
    }
}

__global__ void __launch_bounds__(256) qkv_gemm(
    const bf16* __restrict__ Ah, const bf16* __restrict__ Al,
    const bf16* __restrict__ Bh, const bf16* __restrict__ Bl,
    const float* __restrict__ Z, bf16* __restrict__ oh, bf16* __restrict__ ol)
{
    extern __shared__ char sm[];
    __shared__ float ziv[128];
    const uint32_t sb = smem_to_u32(sm);
    const int tid = threadIdx.x, wid = tid >> 5, lane = tid & 31;
    const int t0 = blockIdx.x << 7, bh = blockIdx.y;
    const int b = bh >> 4, h = bh & 15;
    const size_t ab = (size_t)bh * T_ + t0, bb = (size_t)bh * DH_;
    const int wm = (wid >> 1) << 5, wn = (wid & 1) << 5;
    const int lr = lane & 15, lc = lane >> 4, br = lane & 7, bk = (lane >> 3) & 1;
    if (tid < 128) ziv[tid] = 1.f / fmaxf(Z[ab + tid], 1e-6f);
    float acc[2][4][4];
#pragma unroll
    for (int i = 0; i < 2; i++)
#pragma unroll
        for (int j = 0; j < 4; j++)
#pragma unroll
            for (int r = 0; r < 4; r++) acc[i][j][r] = 0.f;
    auto load = [&](int kc, int buf) {
        uint32_t base = sb + buf * KBUF;
        int ke = kc << 6;
#pragma unroll
        for (int i = 0; i < 4; i++) {
            int idx = tid + (i << 8), r = idx >> 3, c = idx & 7;
            uint32_t so = SWZ(r * 128 + c * 16);
            size_t g = (ab + r) * FD_ + ke + c * 8;
            cp_async16(base + KA + so, Ah + g);
            cp_async16(base + KAL + so, Al + g);
        }
#pragma unroll
        for (int i = 0; i < 2; i++) {
            int idx = tid + (i << 8), r = idx >> 3, c = idx & 7;
            uint32_t so = SWZ(r * 128 + c * 16);
            size_t g = (bb + r) * FD_ + ke + c * 8;
            cp_async16(base + KB + so, Bh + g);
            cp_async16(base + KBL + so, Bl + g);
        }
    };
    load(0, 0); cp_commit();
    for (int kc = 0; kc < 8; kc++) {
        int cur = kc & 1;
        if (kc + 1 < 8) { load(kc + 1, cur ^ 1); cp_commit(); cp_wait<1>(); }
        else cp_wait<0>();
        __syncthreads();
        uint32_t bA = sb + cur * KBUF;
#pragma unroll
        for (int ks = 0; ks < 4; ks++) {
            uint32_t a_h[2][4], a_l[2][4], b_h[4][2], b_l[4][2];
#pragma unroll
            for (int i = 0; i < 2; i++) {
                uint32_t o = SWZ((wm + i * 16 + lr) * 128 + ks * 32 + lc * 16);
                ldsm_x4(a_h[i][0], a_h[i][1], a_h[i][2], a_h[i][3], bA + KA + o);
                ldsm_x4(a_l[i][0], a_l[i][1], a_l[i][2], a_l[i][3], bA + KAL + o);
            }
#pragma unroll
            for (int j = 0; j < 4; j++) {
                uint32_t o = SWZ((wn + j * 8 + br) * 128 + ks * 32 + bk * 16);
                ldsm_x2(b_h[j][0], b_h[j][1], bA + KB + o);
                ldsm_x2(b_l[j][0], b_l[j][1], bA + KBL + o);
            }
#pragma unroll
            for (int i = 0; i < 2; i++)
#pragma unroll
                for (int j = 0; j < 4; j++) {
                    mma_bf16(acc[i][j], a_h[i], b_h[j]);
                    mma_bf16(acc[i][j], a_h[i], b_l[j]);
                    mma_bf16(acc[i][j], a_l[i], b_h[j]);
                }
        }
        __syncthreads();
    }
#pragma unroll
    for (int i = 0; i < 2; i++) {
        int row = wm + i * 16 + (lane >> 2);
        float iv0 = ziv[row], iv1 = ziv[row + 8];
#pragma unroll
        for (int j = 0; j < 4; j++) {
            int col = wn + j * 8 + ((lane & 3) << 1);
            size_t g0 = ((size_t)(b * T_ + t0 + row)) * D_ + h * DH_ + col;
            store_pair(oh, ol, g0, acc[i][j][0] * iv0, acc[i][j][1] * iv0);
            store_pair(oh, ol, g0 + (size_t)8 * D_, acc[i][j][2] * iv1, acc[i][j][3] * iv1);
        }
    }
}

// ======== launch ========
extern "C" void kernel_launch(void* const* d_in, const int* in_sizes, int n_in,
                              void* d_out, int out_size)
{
    const float* x  = (const float*)d_in[0];
    const float* wq = (const float*)d_in[1];
    const float* wk = (const float*)d_in[2];
    const float* wv = (const float*)d_in[3];
    const float* wo = (const float*)d_in[4];
    const float* rf = (const float*)d_in[5];
    float* out = (float*)d_out;

    float* fb = nullptr; cudaGetSymbolAddress((void**)&fb, g_buf);
    bf16*  bb = nullptr; cudaGetSymbolAddress((void**)&bb, g_bf);

    float *Qp = fb + OFF_Q, *Kp = fb + OFF_K, *Vp = fb + OFF_V;
    float *KSp = fb + OFF_KS, *Zp = fb + OFF_Z;
    f16 *xh = (f16*)(bb + BO_XH), *xl = (f16*)(bb + BO_XL);
    f16 *wqh = (f16*)(bb + BO_W + 0*(size_t)D_*D_);
    f16 *wql = (f16*)(bb + BO_W + 1*(size_t)D_*D_);
    f16 *wkh = (f16*)(bb + BO_W + 2*(size_t)D_*D_);
    f16 *wkl = (f16*)(bb + BO_W + 3*(size_t)D_*D_);
    f16 *wv16 = (f16*)(bb + BO_W + 4*(size_t)D_*D_);
    bf16 *woh = bb + BO_W + 5*(size_t)D_*D_;
    bf16 *wol = bb + BO_W + 6*(size_t)D_*D_;
    f16 *rf16 = (f16*)(bb + BO_RF);
    bf16 *Qfh = bb + BO_QFH, *Qfl = bb + BO_QFL;
    bf16 *KfTh = bb + BO_KFTH, *KfTl = bb + BO_KFTL;
    bf16 *VTh = bb + BO_VTH, *VTl = bb + BO_VTL;
    bf16 *KVTh = bb + BO_KVTH, *KVTl = bb + BO_KVTL;
    bf16 *ah = bb + BO_AH, *al = bb + BO_AL;

    cudaFuncSetAttribute(gemm3t<1>, cudaFuncAttributeMaxDynamicSharedMemorySize, SMEM_G3);
    cudaFuncSetAttribute(gemm3t<0>, cudaFuncAttributeMaxDynamicSharedMemorySize, SMEM_G3);
    cudaFuncSetAttribute(gemm2, cudaFuncAttributeMaxDynamicSharedMemorySize, SMEM_G2);
    cudaFuncSetAttribute(phi_q_kernel, cudaFuncAttributeMaxDynamicSharedMemorySize, SMEM_PHI);
    cudaFuncSetAttribute(phi_k_kernel, cudaFuncAttributeMaxDynamicSharedMemorySize, SMEM_PHI);
    cudaFuncSetAttribute(kv_gemm, cudaFuncAttributeMaxDynamicSharedMemorySize, SMEM_KV);
    cudaFuncSetAttribute(qkv_gemm, cudaFuncAttributeMaxDynamicSharedMemorySize, SMEM_KV);

    int wn4 = D_ * D_ / 4;
    split16_kernel<<<(int)(SZ_BTD / 4 / 256), 256>>>(x, xh, xl, (int)(SZ_BTD / 4));
    split16_kernel<<<wn4 / 256, 256>>>(wq, wqh, wql, wn4);
    split16_kernel<<<wn4 / 256, 256>>>(wk, wkh, wkl, wn4);
    conv16_kernel<<<wn4 / 256, 256>>>(wv, wv16, wn4);
    splitbf_kernel<<<wn4 / 256, 256>>>(wo, woh, wol, wn4);
    conv16_kernel<<<16, 256>>>(rf, rf16, 4096);

    dim3 gG(D_ / 128, (B_ * T_) / 128);
    gemm3t<1><<<gG, 256, SMEM_G3>>>((uint32_t*)xh, (uint32_t*)xl, (uint32_t*)wqh, (uint32_t*)wql,
                                    Qp, B_ * T_, D_, D_);
    gemm3t<1><<<gG, 256, SMEM_G3>>>((uint32_t*)xh, (uint32_t*)xl, (uint32_t*)wkh, (uint32_t*)wkl,
                                    Kp, B_ * T_, D_, D_);
    gemm2<<<gG, 256, SMEM_G2>>>(xh, xl, wv16, Vp, B_ * T_, D_, D_);

    dim3 gPhi(T_ / 128, 2, BH_);
    phi_q_kernel<<<gPhi, 256, SMEM_PHI>>>(Qp, rf16, Qfh, Qfl);
    phi_k_kernel<<<gPhi, 256, SMEM_PHI>>>(Kp, rf16, KfTh, KfTl);
    vtrans_kernel<<<dim3(T_ / 64, BH_), 256>>>(Vp, VTh, VTl);
    ksum_kernel<<<dim3(FD_ / 8, BH_), 256>>>(KfTh, KfTl, KSp);
    z_kernel<<<(BH_ * T_) / 8, 256>>>(Qfh, Qfl, KSp, Zp);

    kv_gemm<<<dim3(FD_ / 128, BH_), 256, SMEM_KV>>>(KfTh, KfTl, VTh, VTl, KVTh, KVTl);
    qkv_gemm<<<dim3(T_ / 128, BH_), 256, SMEM_KV>>>(Qfh, Qfl, KVTh, KVTl, Zp, ah, al);

    gemm3t<0><<<gG, 256, SMEM_G3>>>((uint32_t*)ah, (uint32_t*)al, (uint32_t*)woh, (uint32_t*)wol,
                                    out, B_ * T_, D_, D_);
}

// round 9
// speedup vs baseline: 2.5719x; 1.0679x over previous
#include <cuda_runtime.h>
#include <cuda_bf16.h>
#include <cuda_fp16.h>
#include <cstdint>
typedef __nv_bfloat16 bf16;
typedef __half f16;

#define B_   2
#define T_   4096
#define D_   1024
#define H_   16
#define DH_  64
#define FD_  512
#define BH_  (B_*H_)
#define SZ_BTD ((size_t)B_*T_*D_)
#define SZ_F   ((size_t)BH_*T_*FD_)

#define OFF_Q   ((size_t)0)
#define OFF_K   (SZ_BTD)
#define OFF_V   (2*SZ_BTD)
#define OFF_SCQ (3*SZ_BTD)
#define OFF_SCK (OFF_SCQ + (size_t)BH_*T_)
#define OFF_AL  (OFF_SCK + (size_t)BH_*T_)
#define OFF_SR  (OFF_AL + BH_)
__device__ float g_buf[OFF_SR + (size_t)B_*T_];

#define BO_XH   ((size_t)0)
#define BO_XL   (SZ_BTD)
#define BO_W    (2*SZ_BTD)
#define BO_RF   (BO_W + 6*(size_t)D_*D_)
#define BO_QFH  (BO_RF + 16384)
#define BO_QFL  (BO_QFH + SZ_F)
#define BO_KFTH (BO_QFL + SZ_F)
#define BO_KFTL (BO_KFTH + SZ_F)
#define BO_VTH  (BO_KFTL + SZ_F)
#define BO_VTL  (BO_VTH + SZ_BTD)
#define BO_KVT  (BO_VTL + SZ_BTD)
#define BO_AH   (BO_KVT + (size_t)BH_*80*FD_)
#define BO_ALO  (BO_AH + SZ_BTD)
__device__ bf16 g_bf[BO_ALO + SZ_BTD];

__device__ __forceinline__ uint32_t smem_to_u32(const void* p) {
    uint32_t a;
    asm("{ .reg .u64 t; cvta.to.shared.u64 t, %1; cvt.u32.u64 %0, t; }" : "=r"(a) : "l"(p));
    return a;
}
#define SWZ(o) ((o) ^ (((o) >> 3) & 0x70))
__device__ __forceinline__ void cp_async16(uint32_t s, const void* g) {
    asm volatile("cp.async.cg.shared.global [%0], [%1], 16;" :: "r"(s), "l"(g));
}
__device__ __forceinline__ void cp_commit() { asm volatile("cp.async.commit_group;" ::: "memory"); }
template <int N> __device__ __forceinline__ void cp_wait() {
    asm volatile("cp.async.wait_group %0;" :: "n"(N) : "memory");
}
__device__ __forceinline__ void ldsm_x4(uint32_t& r0, uint32_t& r1, uint32_t& r2, uint32_t& r3, uint32_t a) {
    asm volatile("ldmatrix.sync.aligned.m8n8.x4.shared.b16 {%0,%1,%2,%3}, [%4];"
                 : "=r"(r0), "=r"(r1), "=r"(r2), "=r"(r3) : "r"(a));
}
__device__ __forceinline__ void ldsm_x2(uint32_t& r0, uint32_t& r1, uint32_t a) {
    asm volatile("ldmatrix.sync.aligned.m8n8.x2.shared.b16 {%0,%1}, [%2];"
                 : "=r"(r0), "=r"(r1) : "r"(a));
}
__device__ __forceinline__ void mma_bf16(float* c, const uint32_t* a, const uint32_t* b) {
    asm volatile("mma.sync.aligned.m16n8k16.row.col.f32.bf16.bf16.f32 "
                 "{%0,%1,%2,%3}, {%4,%5,%6,%7}, {%8,%9}, {%0,%1,%2,%3};"
                 : "+f"(c[0]), "+f"(c[1]), "+f"(c[2]), "+f"(c[3])
                 : "r"(a[0]), "r"(a[1]), "r"(a[2]), "r"(a[3]), "r"(b[0]), "r"(b[1]));
}
__device__ __forceinline__ void mma_f16(float* c, const uint32_t* a, const uint32_t* b) {
    asm volatile("mma.sync.aligned.m16n8k16.row.col.f32.f16.f16.f32 "
                 "{%0,%1,%2,%3}, {%4,%5,%6,%7}, {%8,%9}, {%0,%1,%2,%3};"
                 : "+f"(c[0]), "+f"(c[1]), "+f"(c[2]), "+f"(c[3])
                 : "r"(a[0]), "r"(a[1]), "r"(a[2]), "r"(a[3]), "r"(b[0]), "r"(b[1]));
}
__device__ __forceinline__ void store_pair(bf16* ph, bf16* pl, size_t off, float x0, float x1) {
    bf16 h0 = __float2bfloat16(x0), h1 = __float2bfloat16(x1);
    __nv_bfloat162 hp(h0, h1);
    *(uint32_t*)(ph + off) = *(uint32_t*)&hp;
    __nv_bfloat162 lp(__float2bfloat16(x0 - __bfloat162float(h0)),
                      __float2bfloat16(x1 - __bfloat162float(h1)));
    *(uint32_t*)(pl + off) = *(uint32_t*)&lp;
}
__device__ __forceinline__ void store_pair_h(f16* ph, f16* pl, size_t off, float x0, float x1) {
    f16 h0 = __float2half_rn(x0), h1 = __float2half_rn(x1);
    __half2 hp = __halves2half2(h0, h1);
    *(uint32_t*)(ph + off) = *(uint32_t*)&hp;
    __half2 lp = __halves2half2(__float2half_rn(x0 - __half2float(h0)),
                                __float2half_rn(x1 - __half2float(h1)));
    *(uint32_t*)(pl + off) = *(uint32_t*)&lp;
}
__device__ __forceinline__ void fast_sincos(float x, float& s, float& c) {
    float kf = rintf(x * 0.63661977f);
    int q = (int)kf;
    float r = fmaf(kf, -1.5707963705062866f, x);
    r = fmaf(kf, 4.3711388286738e-8f, r);
    float r2 = r * r;
    float sp = fmaf(-1.98412698e-4f, r2, 8.33333333e-3f);
    sp = fmaf(sp, r2, -1.66666667e-1f) * r2;
    float sr = fmaf(sp, r, r);
    float cp = fmaf(2.48015873e-5f, r2, -1.38888889e-3f);
    cp = fmaf(cp, r2, 4.16666667e-2f);
    cp = fmaf(cp, r2, -0.5f);
    float cr = fmaf(cp, r2, 1.0f);
    if (q & 1) { float t = sr; sr = cr; cr = -t; }
    if (q & 2) { sr = -sr; cr = -cr; }
    s = sr; c = cr;
}

#define TILE_B 16384

// ======== fp16 3-pass GEMM: C = A(hi/lo) B(hi/lo)^T ========
#define BUF3   (4*TILE_B)
#define SMEM_G3 (2*BUF3)
__global__ void __launch_bounds__(256)
gemm3(const f16* __restrict__ Ah, const f16* __restrict__ Al,
      const f16* __restrict__ Bh, const f16* __restrict__ Bl,
      float* __restrict__ C, int M, int N, int K)
{
    extern __shared__ char smem[];
    const uint32_t sb = smem_to_u32(smem);
    const int tid = threadIdx.x, wid = tid >> 5, lane = tid & 31;
    const int bn = blockIdx.x << 7, bm = blockIdx.y << 7;
    const int wm = (wid >> 2) << 6, wn = (wid & 3) << 5;
    const int nchunk = K >> 6;
    const int lr = lane & 15, lc = lane >> 4, br = lane & 7, bk = (lane >> 3) & 1;
    float acc[4][4][4];
#pragma unroll
    for (int i = 0; i < 4; i++)
#pragma unroll
        for (int j = 0; j < 4; j++)
#pragma unroll
            for (int r = 0; r < 4; r++) acc[i][j][r] = 0.f;
    const f16* gs[4] = {Ah, Al, Bh, Bl};
    const int rb[4] = {bm, bm, bn, bn};
    auto load = [&](int kc, int buf) {
        uint32_t base = sb + buf * BUF3;
        int ke = kc << 6;
#pragma unroll
        for (int t = 0; t < 4; t++)
#pragma unroll
            for (int i = 0; i < 4; i++) {
                int idx = tid + (i << 8), r = idx >> 3, c = idx & 7;
                cp_async16(base + t * TILE_B + SWZ(r * 128 + c * 16),
                           gs[t] + (size_t)(rb[t] + r) * K + ke + c * 8);
            }
    };
    load(0, 0); cp_commit();
    for (int kc = 0; kc < nchunk; kc++) {
        int cur = kc & 1;
        if (kc + 1 < nchunk) { load(kc + 1, cur ^ 1); cp_commit(); cp_wait<1>(); }
        else cp_wait<0>();
        __syncthreads();
        uint32_t bA = sb + cur * BUF3;
#pragma unroll
        for (int ks = 0; ks < 4; ks++) {
            uint32_t a_h[4][4], a_l[4][4], b_h[4][2], b_l[4][2];
#pragma unroll
            for (int i = 0; i < 4; i++) {
                uint32_t o = SWZ((wm + i * 16 + lr) * 128 + ks * 32 + lc * 16);
                ldsm_x4(a_h[i][0], a_h[i][1], a_h[i][2], a_h[i][3], bA + o);
                ldsm_x4(a_l[i][0], a_l[i][1], a_l[i][2], a_l[i][3], bA + TILE_B + o);
            }
#pragma unroll
            for (int j = 0; j < 4; j++) {
                uint32_t o = SWZ((wn + j * 8 + br) * 128 + ks * 32 + bk * 16);
                ldsm_x2(b_h[j][0], b_h[j][1], bA + 2 * TILE_B + o);
                ldsm_x2(b_l[j][0], b_l[j][1], bA + 3 * TILE_B + o);
            }
#pragma unroll
            for (int i = 0; i < 4; i++)
#pragma unroll
                for (int j = 0; j < 4; j++) {
                    mma_f16(acc[i][j], a_h[i], b_h[j]);
                    mma_f16(acc[i][j], a_h[i], b_l[j]);
                    mma_f16(acc[i][j], a_l[i], b_h[j]);
                }
        }
        __syncthreads();
    }
#pragma unroll
    for (int i = 0; i < 4; i++) {
        int row = bm + wm + i * 16 + (lane >> 2);
#pragma unroll
        for (int j = 0; j < 4; j++) {
            int col = bn + wn + j * 8 + ((lane & 3) << 1);
            *(float2*)&C[(size_t)row * N + col]       = make_float2(acc[i][j][0], acc[i][j][1]);
            *(float2*)&C[(size_t)(row + 8) * N + col] = make_float2(acc[i][j][2], acc[i][j][3]);
        }
    }
}

// ======== fp16 2-pass GEMM: C = (Ah+Al) B^T ; optional row scale (fp32 C or f16 n/a) ========
#define BUF2   (3*TILE_B)
#define SMEM_G2 (2*BUF2)
template <int ROWSCALE>
__global__ void __launch_bounds__(256)
gemm2t(const f16* __restrict__ Ah, const f16* __restrict__ Al,
       const f16* __restrict__ Bm, const float* __restrict__ S,
       float* __restrict__ C, int M, int N, int K)
{
    extern __shared__ char smem[];
    const uint32_t sb = smem_to_u32(smem);
    const int tid = threadIdx.x, wid = tid >> 5, lane = tid & 31;
    const int bn = blockIdx.x << 7, bm = blockIdx.y << 7;
    const int wm = (wid >> 2) << 6, wn = (wid & 3) << 5;
    const int nchunk = K >> 6;
    const int lr = lane & 15, lc = lane >> 4, br = lane & 7, bk = (lane >> 3) & 1;
    float acc[4][4][4];
#pragma unroll
    for (int i = 0; i < 4; i++)
#pragma unroll
        for (int j = 0; j < 4; j++)
#pragma unroll
            for (int r = 0; r < 4; r++) acc[i][j][r] = 0.f;
    auto load = [&](int kc, int buf) {
        uint32_t base = sb + buf * BUF2;
        int ke = kc << 6;
#pragma unroll
        for (int i = 0; i < 4; i++) {
            int idx = tid + (i << 8), r = idx >> 3, c = idx & 7;
            uint32_t so = SWZ(r * 128 + c * 16);
            cp_async16(base + so,              Ah + (size_t)(bm + r) * K + ke + c * 8);
            cp_async16(base + TILE_B + so,     Al + (size_t)(bm + r) * K + ke + c * 8);
            cp_async16(base + 2 * TILE_B + so, Bm + (size_t)(bn + r) * K + ke + c * 8);
        }
    };
    load(0, 0); cp_commit();
    for (int kc = 0; kc < nchunk; kc++) {
        int cur = kc & 1;
        if (kc + 1 < nchunk) { load(kc + 1, cur ^ 1); cp_commit(); cp_wait<1>(); }
        else cp_wait<0>();
        __syncthreads();
        uint32_t bA = sb + cur * BUF2;
#pragma unroll
        for (int ks = 0; ks < 4; ks++) {
            uint32_t a_h[4][4], a_l[4][4], b_[4][2];
#pragma unroll
            for (int i = 0; i < 4; i++) {
                uint32_t o = SWZ((wm + i * 16 + lr) * 128 + ks * 32 + lc * 16);
                ldsm_x4(a_h[i][0], a_h[i][1], a_h[i][2], a_h[i][3], bA + o);
                ldsm_x4(a_l[i][0], a_l[i][1], a_l[i][2], a_l[i][3], bA + TILE_B + o);
            }
#pragma unroll
            for (int j = 0; j < 4; j++) {
                uint32_t o = SWZ((wn + j * 8 + br) * 128 + ks * 32 + bk * 16);
                ldsm_x2(b_[j][0], b_[j][1], bA + 2 * TILE_B + o);
            }
#pragma unroll
            for (int i = 0; i < 4; i++)
#pragma unroll
                for (int j = 0; j < 4; j++) {
                    mma_f16(acc[i][j], a_h[i], b_[j]);
                    mma_f16(acc[i][j], a_l[i], b_[j]);
                }
        }
        __syncthreads();
    }
#pragma unroll
    for (int i = 0; i < 4; i++) {
        int row = bm + wm + i * 16 + (lane >> 2);
        float s0 = ROWSCALE ? S[row] : 1.f;
        float s1 = ROWSCALE ? S[row + 8] : 1.f;
#pragma unroll
        for (int j = 0; j < 4; j++) {
            int col = bn + wn + j * 8 + ((lane & 3) << 1);
            *(float2*)&C[(size_t)row * N + col]       = make_float2(acc[i][j][0] * s0, acc[i][j][1] * s0);
            *(float2*)&C[(size_t)(row + 8) * N + col] = make_float2(acc[i][j][2] * s1, acc[i][j][3] * s1);
        }
    }
}

// ======== conversions ========
__global__ void __launch_bounds__(256) split16_kernel(const float* __restrict__ in,
                                                      f16* __restrict__ hi, f16* __restrict__ lo, int n4)
{
    int i = blockIdx.x * 256 + threadIdx.x;
    if (i >= n4) return;
    float4 v = ((const float4*)in)[i];
    store_pair_h(hi, lo, (size_t)i * 4, v.x, v.y);
    store_pair_h(hi, lo, (size_t)i * 4 + 2, v.z, v.w);
}
__global__ void __launch_bounds__(256) conv16_kernel(const float* __restrict__ in,
                                                     f16* __restrict__ out, int n4)
{
    int i = blockIdx.x * 256 + threadIdx.x;
    if (i >= n4) return;
    float4 v = ((const float4*)in)[i];
    __half2 p0 = __halves2half2(__float2half_rn(v.x), __float2half_rn(v.y));
    __half2 p1 = __halves2half2(__float2half_rn(v.z), __float2half_rn(v.w));
    uint2 o; o.x = *(uint32_t*)&p0; o.y = *(uint32_t*)&p1;
    ((uint2*)out)[i] = o;
}

// ======== phi kernels (fp16 proj, 2 MMAs) ========
#define PA  0
#define PAL 16384
#define PB  32768
#define PBL 49152
#define PSC 65536
#define PNP 66048
#define SMEM_PHI 67072

__device__ __forceinline__ void conv_tile_h(const float* g, char* sm, int dstH, int dstL,
                                            float* np, int tid) {
    int r = tid >> 1, cb = (tid & 1) << 5;
    float s = 0.f;
    const float* gp = g + (size_t)r * D_ + cb;
#pragma unroll
    for (int k = 0; k < 8; k++) {
        float4 v = *(const float4*)(gp + k * 4);
        s = fmaf(v.x, v.x, s); s = fmaf(v.y, v.y, s);
        s = fmaf(v.z, v.z, s); s = fmaf(v.w, v.w, s);
        uint32_t sw = SWZ((uint32_t)(r * 128 + (cb + k * 4) * 2));
        f16 h0 = __float2half_rn(v.x), h1 = __float2half_rn(v.y);
        f16 h2 = __float2half_rn(v.z), h3 = __float2half_rn(v.w);
        __half2 hp0 = __halves2half2(h0, h1), hp1 = __halves2half2(h2, h3);
        *(uint32_t*)(sm + dstH + sw) = *(uint32_t*)&hp0;
        *(uint32_t*)(sm + dstH + sw + 4) = *(uint32_t*)&hp1;
        __half2 lp0 = __halves2half2(__float2half_rn(v.x - __half2float(h0)),
                                     __float2half_rn(v.y - __half2float(h1)));
        __half2 lp1 = __halves2half2(__float2half_rn(v.z - __half2float(h2)),
                                     __float2half_rn(v.w - __half2float(h3)));
        *(uint32_t*)(sm + dstL + sw) = *(uint32_t*)&lp0;
        *(uint32_t*)(sm + dstL + sw + 4) = *(uint32_t*)&lp1;
    }
    np[tid] = s;
}

// phi_q: Qf^ = [cos,sin] UNSCALED -> fp16 hi/lo; scq[bh][t] = exp(-|q|^2/2)/16
__global__ void __launch_bounds__(256) phi_q_kernel(
    const float* __restrict__ Q, const f16* __restrict__ rf16,
    f16* __restrict__ Qfh, f16* __restrict__ Qfl, float* __restrict__ scq)
{
    extern __shared__ char sm[];
    const uint32_t sb = smem_to_u32(sm);
    const int tid = threadIdx.x, wid = tid >> 5, lane = tid & 31;
    const int t0 = blockIdx.x << 7, m0c = blockIdx.y << 7, bh = blockIdx.z;
    const int b = bh >> 4, h = bh & 15;
    float* np = (float*)(sm + PNP);
#pragma unroll
    for (int i = 0; i < 4; i++) {
        int idx = tid + (i << 8), r = idx >> 3, c = idx & 7;
        cp_async16(sb + PB + SWZ(r * 128 + c * 16), rf16 + (size_t)(m0c + r) * DH_ + c * 8);
    }
    cp_commit();
    conv_tile_h(&Q[((size_t)(b * T_ + t0)) * D_ + h * DH_], sm, PA, PAL, np, tid);
    __syncthreads();
    if (tid < 128 && blockIdx.y == 0)
        scq[(size_t)bh * T_ + t0 + tid] = __expf(-0.5f * (np[2 * tid] + np[2 * tid + 1])) * 0.0625f;
    cp_wait<0>();
    __syncthreads();
    const int wt = (wid >> 2) << 6, wm = (wid & 3) << 5;
    const int lr = lane & 15, lc = lane >> 4, br = lane & 7, bk = (lane >> 3) & 1;
    float acc[4][4][4];
#pragma unroll
    for (int i = 0; i < 4; i++)
#pragma unroll
        for (int j = 0; j < 4; j++)
#pragma unroll
            for (int r = 0; r < 4; r++) acc[i][j][r] = 0.f;
#pragma unroll
    for (int ks = 0; ks < 4; ks++) {
        uint32_t a_h[4][4], a_l[4][4], b_[4][2];
#pragma unroll
        for (int i = 0; i < 4; i++) {
            uint32_t o = SWZ((wt + i * 16 + lr) * 128 + ks * 32 + lc * 16);
            ldsm_x4(a_h[i][0], a_h[i][1], a_h[i][2], a_h[i][3], sb + PA + o);
            ldsm_x4(a_l[i][0], a_l[i][1], a_l[i][2], a_l[i][3], sb + PAL + o);
        }
#pragma unroll
        for (int j = 0; j < 4; j++) {
            uint32_t o = SWZ((wm + j * 8 + br) * 128 + ks * 32 + bk * 16);
            ldsm_x2(b_[j][0], b_[j][1], sb + PB + o);
        }
#pragma unroll
        for (int i = 0; i < 4; i++)
#pragma unroll
            for (int j = 0; j < 4; j++) {
                mma_f16(acc[i][j], a_h[i], b_[j]);
                mma_f16(acc[i][j], a_l[i], b_[j]);
            }
    }
#pragma unroll
    for (int i = 0; i < 4; i++) {
        int r0 = wt + i * 16 + (lane >> 2);
        size_t rb0 = ((size_t)bh * T_ + t0 + r0) * FD_ + m0c;
        size_t rb1 = rb0 + (size_t)8 * FD_;
#pragma unroll
        for (int j = 0; j < 4; j++) {
            int mc = wm + j * 8 + ((lane & 3) << 1);
            float sn0, cs0, sn1, cs1;
            fast_sincos(acc[i][j][0], sn0, cs0);
            fast_sincos(acc[i][j][1], sn1, cs1);
            store_pair_h(Qfh, Qfl, rb0 + mc, cs0, cs1);
            store_pair_h(Qfh, Qfl, rb0 + 256 + mc, sn0, sn1);
            fast_sincos(acc[i][j][2], sn0, cs0);
            fast_sincos(acc[i][j][3], sn1, cs1);
            store_pair_h(Qfh, Qfl, rb1 + mc, cs0, cs1);
            store_pair_h(Qfh, Qfl, rb1 + 256 + mc, sn0, sn1);
        }
    }
}

// phi_k: KfT (WITH scale) bf16 hi/lo; sck[bh][t]
__global__ void __launch_bounds__(256) phi_k_kernel(
    const float* __restrict__ Kg, const f16* __restrict__ rf16,
    bf16* __restrict__ KfTh, bf16* __restrict__ KfTl, float* __restrict__ sck)
{
    extern __shared__ char sm[];
    const uint32_t sb = smem_to_u32(sm);
    const int tid = threadIdx.x, wid = tid >> 5, lane = tid & 31;
    const int t0 = blockIdx.x << 7, m0c = blockIdx.y << 7, bh = blockIdx.z;
    const int b = bh >> 4, h = bh & 15;
    float* scale = (float*)(sm + PSC);
    float* np = (float*)(sm + PNP);
#pragma unroll
    for (int i = 0; i < 4; i++) {
        int idx = tid + (i << 8), r = idx >> 3, c = idx & 7;
        cp_async16(sb + PA + SWZ(r * 128 + c * 16), rf16 + (size_t)(m0c + r) * DH_ + c * 8);
    }
    cp_commit();
    conv_tile_h(&Kg[((size_t)(b * T_ + t0)) * D_ + h * DH_], sm, PB, PBL, np, tid);
    __syncthreads();
    if (tid < 128) {
        float sc = __expf(-0.5f * (np[2 * tid] + np[2 * tid + 1])) * 0.0625f;
        scale[tid] = sc;
        if (blockIdx.y == 0) sck[(size_t)bh * T_ + t0 + tid] = sc;
    }
    cp_wait<0>();
    __syncthreads();
    const int wm = (wid >> 2) << 6, wt = (wid & 3) << 5;
    const int lr = lane & 15, lc = lane >> 4, br = lane & 7, bk = (lane >> 3) & 1;
    float acc[4][4][4];
#pragma unroll
    for (int i = 0; i < 4; i++)
#pragma unroll
        for (int j = 0; j < 4; j++)
#pragma unroll
            for (int r = 0; r < 4; r++) acc[i][j][r] = 0.f;
#pragma unroll
    for (int ks = 0; ks < 4; ks++) {
        uint32_t a_[4][4], b_h[4][2], b_l[4][2];
#pragma unroll
        for (int i = 0; i < 4; i++) {
            uint32_t o = SWZ((wm + i * 16 + lr) * 128 + ks * 32 + lc * 16);
            ldsm_x4(a_[i][0], a_[i][1], a_[i][2], a_[i][3], sb + PA + o);
        }
#pragma unroll
        for (int j = 0; j < 4; j++) {
            uint32_t o = SWZ((wt + j * 8 + br) * 128 + ks * 32 + bk * 16);
            ldsm_x2(b_h[j][0], b_h[j][1], sb + PB + o);
            ldsm_x2(b_l[j][0], b_l[j][1], sb + PBL + o);
        }
#pragma unroll
        for (int i = 0; i < 4; i++)
#pragma unroll
            for (int j = 0; j < 4; j++) {
                mma_f16(acc[i][j], a_[i], b_h[j]);
                mma_f16(acc[i][j], a_[i], b_l[j]);
            }
    }
#pragma unroll
    for (int i = 0; i < 4; i++) {
        int r0 = wm + i * 16 + (lane >> 2);
        size_t rc0 = ((size_t)bh * FD_ + m0c + r0) * T_ + t0;
        size_t rs0 = rc0 + (size_t)256 * T_;
        size_t rc1 = rc0 + (size_t)8 * T_, rs1 = rs0 + (size_t)8 * T_;
#pragma unroll
        for (int j = 0; j < 4; j++) {
            int tc = wt + j * 8 + ((lane & 3) << 1);
            float sc0 = scale[tc], sc1 = scale[tc + 1];
            float sn0, cs0, sn1, cs1;
            fast_sincos(acc[i][j][0], sn0, cs0);
            fast_sincos(acc[i][j][1], sn1, cs1);
            store_pair(KfTh, KfTl, rc0 + tc, cs0 * sc0, cs1 * sc1);
            store_pair(KfTh, KfTl, rs0 + tc, sn0 * sc0, sn1 * sc1);
            fast_sincos(acc[i][j][2], sn0, cs0);
            fast_sincos(acc[i][j][3], sn1, cs1);
            store_pair(KfTh, KfTl, rc1 + tc, cs0 * sc0, cs1 * sc1);
            store_pair(KfTh, KfTl, rs1 + tc, sn0 * sc0, sn1 * sc1);
        }
    }
}

// ======== V transpose ========
__global__ void __launch_bounds__(256) vtrans_kernel(const float* __restrict__ V,
                                                     bf16* __restrict__ VTh, bf16* __restrict__ VTl)
{
    __shared__ float st[64][68];
    const int tid = threadIdx.x;
    const int t0 = blockIdx.x << 6, bh = blockIdx.y;
    const int b = bh >> 4, h = bh & 15;
#pragma unroll
    for (int i = 0; i < 4; i++) {
        int idx = tid + (i << 8), r = idx >> 4, c4 = (idx & 15) << 2;
        *(float4*)&st[r][c4] = *(const float4*)&V[((size_t)(b * T_ + t0 + r)) * D_ + h * DH_ + c4];
    }
    __syncthreads();
    int v = tid >> 2, ts = (tid & 3) << 4;
#pragma unroll
    for (int p = 0; p < 8; p++) {
        int t = ts + p * 2;
        store_pair(VTh, VTl, ((size_t)bh * DH_ + v) * T_ + t0 + t, st[t][v], st[t + 1][v]);
    }
}

// ======== alpha / ksum / zero / srow ========
__global__ void __launch_bounds__(256) alpha_kernel(const float* __restrict__ sck,
                                                    float* __restrict__ alpha)
{
    __shared__ float red[256];
    const int bh = blockIdx.x, tid = threadIdx.x;
    float s = 0.f;
    for (int i = tid; i < T_; i += 256) s += sck[(size_t)bh * T_ + i];
    red[tid] = s;
    __syncthreads();
    for (int o = 128; o; o >>= 1) { if (tid < o) red[tid] += red[tid + o]; __syncthreads(); }
    if (tid == 0) alpha[bh] = 1.f / fmaxf(red[0], 1e-30f);
}

__global__ void __launch_bounds__(256) ksum_kernel(const bf16* __restrict__ KfTh,
                                                   const bf16* __restrict__ KfTl,
                                                   const float* __restrict__ alpha,
                                                   f16* __restrict__ kvt)
{
    const int wid = threadIdx.x >> 5, lane = threadIdx.x & 31;
    const int f = blockIdx.x * 8 + wid, bh = blockIdx.y;
    const bf16* ph = KfTh + ((size_t)bh * FD_ + f) * T_;
    const bf16* pl = KfTl + ((size_t)bh * FD_ + f) * T_;
    float s = 0.f;
    for (int i = lane * 2; i < T_; i += 64) {
        uint32_t hp = *(const uint32_t*)(ph + i), lp = *(const uint32_t*)(pl + i);
        __nv_bfloat162 h2 = *(__nv_bfloat162*)&hp, l2 = *(__nv_bfloat162*)&lp;
        s += __bfloat162float(h2.x) + __bfloat162float(l2.x)
           + __bfloat162float(h2.y) + __bfloat162float(l2.y);
    }
#pragma unroll
    for (int o = 16; o; o >>= 1) s += __shfl_xor_sync(0xffffffffu, s, o);
    if (lane == 0) kvt[((size_t)bh * 80 + 64) * FD_ + f] = __float2half_rn(s * alpha[bh]);
}

__global__ void __launch_bounds__(256) zero_kvt_kernel(f16* __restrict__ kvt)
{
    const int bh = blockIdx.x;
    for (int i = threadIdx.x; i < 15 * FD_; i += 256)
        kvt[((size_t)bh * 80 + 65) * FD_ + i] = __float2half_rn(0.f);
}

__global__ void __launch_bounds__(256) srow_kernel(const float* __restrict__ scq,
                                                   const float* __restrict__ alpha,
                                                   float* __restrict__ srow)
{
    int row = blockIdx.x * 256 + threadIdx.x;   // b*T + t
    int b = row >> 12, t = row & 4095;
    float m = 0.f;
#pragma unroll
    for (int h = 0; h < H_; h++) {
        int bh = b * H_ + h;
        m = fmaxf(m, scq[(size_t)bh * T_ + t] / alpha[bh]);
    }
    srow[row] = fmaxf(m * 1e6f, 1e-30f);
}

// ======== kv: KfT x VT^T (bf16x3), KVT' = alpha*KV fp16 ========
#define KA   0
#define KAL  16384
#define KB   32768
#define KBL  40960
#define KBUF 49152
#define SMEM_KV (2*KBUF)

__global__ void __launch_bounds__(256) kv_gemm(
    const bf16* __restrict__ Ah, const bf16* __restrict__ Al,
    const bf16* __restrict__ Bh, const bf16* __restrict__ Bl,
    const float* __restrict__ alpha, f16* __restrict__ kvt)
{
    extern __shared__ char sm[];
    const uint32_t sb = smem_to_u32(sm);
    const int tid = threadIdx.x, wid = tid >> 5, lane = tid & 31;
    const int m0 = blockIdx.x << 7, bh = blockIdx.y;
    const size_t ab = (size_t)bh * FD_ + m0, bb = (size_t)bh * DH_;
    const int wm = (wid >> 1) << 5, wn = (wid & 1) << 5;
    const int lr = lane & 15, lc = lane >> 4, br = lane & 7, bk = (lane >> 3) & 1;
    float acc[2][4][4];
#pragma unroll
    for (int i = 0; i < 2; i++)
#pragma unroll
        for (int j = 0; j < 4; j++)
#pragma unroll
            for (int r = 0; r < 4; r++) acc[i][j][r] = 0.f;
    auto load = [&](int kc, int buf) {
        uint32_t base = sb + buf * KBUF;
        int ke = kc << 6;
#pragma unroll
        for (int i = 0; i < 4; i++) {
            int idx = tid + (i << 8), r = idx >> 3, c = idx & 7;
            uint32_t so = SWZ(r * 128 + c * 16);
            size_t g = (ab + r) * T_ + ke + c * 8;
            cp_async16(base + KA + so, Ah + g);
            cp_async16(base + KAL + so, Al + g);
        }
#pragma unroll
        for (int i = 0; i < 2; i++) {
            int idx = tid + (i << 8), r = idx >> 3, c = idx & 7;
            uint32_t so = SWZ(r * 128 + c * 16);
            size_t g = (bb + r) * T_ + ke + c * 8;
            cp_async16(base + KB + so, Bh + g);
            cp_async16(base + KBL + so, Bl + g);
        }
    };
    load(0, 0); cp_commit();
    for (int kc = 0; kc < T_ / 64; kc++) {
        int cur = kc & 1;
        if (kc + 1 < T_ / 64) { load(kc + 1, cur ^ 1); cp_commit(); cp_wait<1>(); }
        else cp_wait<0>();
        __syncthreads();
        uint32_t bA = sb + cur * KBUF;
#pragma unroll
        for (int ks = 0; ks < 4; ks++) {
            uint32_t a_h[2][4], a_l[2][4], b_h[4][2], b_l[4][2];
#pragma unroll
            for (int i = 0; i < 2; i++) {
                uint32_t o = SWZ((wm + i * 16 + lr) * 128 + ks * 32 + lc * 16);
                ldsm_x4(a_h[i][0], a_h[i][1], a_h[i][2], a_h[i][3], bA + KA + o);
                ldsm_x4(a_l[i][0], a_l[i][1], a_l[i][2], a_l[i][3], bA + KAL + o);
            }
#pragma unroll
            for (int j = 0; j < 4; j++) {
                uint32_t o = SWZ((wn + j * 8 + br) * 128 + ks * 32 + bk * 16);
                ldsm_x2(b_h[j][0], b_h[j][1], bA + KB + o);
                ldsm_x2(b_l[j][0], b_l[j][1], bA + KBL + o);
            }
#pragma unroll
            for (int i = 0; i < 2; i++)
#pragma unroll
                for (int j = 0; j < 4; j++) {
                    mma_bf16(acc[i][j], a_h[i], b_h[j]);
                    mma_bf16(acc[i][j], a_h[i], b_l[j]);
                    mma_bf16(acc[i][j], a_l[i], b_h[j]);
                }
        }
        __syncthreads();
    }
    float* stage = (float*)sm;
#pragma unroll
    for (int i = 0; i < 2; i++) {
        int row = wm + i * 16 + (lane >> 2);
#pragma unroll
        for (int j = 0; j < 4; j++) {
            int col = wn + j * 8 + ((lane & 3) << 1);
            stage[col * 132 + row]           = acc[i][j][0];
            stage[(col + 1) * 132 + row]     = acc[i][j][1];
            stage[col * 132 + row + 8]       = acc[i][j][2];
            stage[(col + 1) * 132 + row + 8] = acc[i][j][3];
        }
    }
    __syncthreads();
    float av = alpha[bh];
    int v = tid >> 2, fs = (tid & 3) << 5;
#pragma unroll
    for (int p = 0; p < 16; p++) {
        int f = fs + p * 2;
        __half2 hp = __halves2half2(__float2half_rn(stage[v * 132 + f] * av),
                                    __float2half_rn(stage[v * 132 + f + 1] * av));
        *(uint32_t*)&kvt[((size_t)bh * 80 + v) * FD_ + m0 + f] = *(uint32_t*)&hp;
    }
}

// ======== qkv: Qf^ (fp16 h/l) x KVT'[80 rows] (fp16), 2-pass; epilogue Z + scales ========
#define QA   0
#define QAL  16384
#define QB   32768
#define QBUF 43008
#define SMEM_QKV (2*QBUF)

__global__ void __launch_bounds__(256) qkv_gemm(
    const f16* __restrict__ Ah, const f16* __restrict__ Al,
    const f16* __restrict__ Bm, const float* __restrict__ scq,
    const float* __restrict__ alpha, const float* __restrict__ srow,
    f16* __restrict__ oh, f16* __restrict__ ol)
{
    extern __shared__ char sm[];
    __shared__ float zsm[128];
    const uint32_t sb = smem_to_u32(sm);
    const int tid = threadIdx.x, wid = tid >> 5, lane = tid & 31;
    const int t0 = blockIdx.x << 7, bh = blockIdx.y;
    const int b = bh >> 4, h = bh & 15;
    const size_t ab = (size_t)bh * T_ + t0, bb = (size_t)bh * 80;
    const int wm = (wid >> 1) << 5, wn = (wid & 1) * 40;
    const int lr = lane & 15, lc = lane >> 4, br = lane & 7, bk = (lane >> 3) & 1;
    float acc[2][5][4];
#pragma unroll
    for (int i = 0; i < 2; i++)
#pragma unroll
        for (int j = 0; j < 5; j++)
#pragma unroll
            for (int r = 0; r < 4; r++) acc[i][j][r] = 0.f;
    auto load = [&](int kc, int buf) {
        uint32_t base = sb + buf * QBUF;
        int ke = kc << 6;
#pragma unroll
        for (int i = 0; i < 4; i++) {
            int idx = tid + (i << 8), r = idx >> 3, c = idx & 7;
            uint32_t so = SWZ(r * 128 + c * 16);
            size_t g = (ab + r) * FD_ + ke + c * 8;
            cp_async16(base + QA + so, Ah + g);
            cp_async16(base + QAL + so, Al + g);
        }
#pragma unroll
        for (int i = 0; i < 3; i++) {
            int idx = tid + (i << 8);
            if (idx < 640) {
                int r = idx >> 3, c = idx & 7;
                cp_async16(base + QB + SWZ(r * 128 + c * 16), Bm + (bb + r) * FD_ + ke + c * 8);
            }
        }
    };
    load(0, 0); cp_commit();
    for (int kc = 0; kc < 8; kc++) {
        int cur = kc & 1;
        if (kc + 1 < 8) { load(kc + 1, cur ^ 1); cp_commit(); cp_wait<1>(); }
        else cp_wait<0>();
        __syncthreads();
        uint32_t bA = sb + cur * QBUF;
#pragma unroll
        for (int ks = 0; ks < 4; ks++) {
            uint32_t a_h[2][4], a_l[2][4], b_[5][2];
#pragma unroll
            for (int i = 0; i < 2; i++) {
                uint32_t o = SWZ((wm + i * 16 + lr) * 128 + ks * 32 + lc * 16);
                ldsm_x4(a_h[i][0], a_h[i][1], a_h[i][2], a_h[i][3], bA + QA + o);
                ldsm_x4(a_l[i][0], a_l[i][1], a_l[i][2], a_l[i][3], bA + QAL + o);
            }
#pragma unroll
            for (int j = 0; j < 5; j++) {
                uint32_t o = SWZ((wn + j * 8 + br) * 128 + ks * 32 + bk * 16);
                ldsm_x2(b_[j][0], b_[j][1], bA + QB + o);
            }
#pragma unroll
            for (int i = 0; i < 2; i++)
#pragma unroll
                for (int j = 0; j < 5; j++) {
                    mma_f16(acc[i][j], a_h[i], b_[j]);
                    mma_f16(acc[i][j], a_l[i], b_[j]);
                }
        }
        __syncthreads();
    }
    // col 64 (= alpha*Z/scq) lives in warp-group wn==40, j=3, (lane&3)==0
    if (wn == 40 && (lane & 3) == 0) {
#pragma unroll
        for (int i = 0; i < 2; i++) {
            int row = wm + i * 16 + (lane >> 2);
            zsm[row] = acc[i][3][0];
            zsm[row + 8] = acc[i][3][2];
        }
    }
    __syncthreads();
    float av = alpha[bh];
#pragma unroll
    for (int i = 0; i < 2; i++) {
#pragma unroll
        for (int half = 0; half < 2; half++) {
            int row = wm + i * 16 + (lane >> 2) + half * 8;
            float sq = scq[ab + row];
            float Zt = sq * zsm[row] / av;
            float d = fmaxf(Zt, 1e-6f);
            float mult = sq / (av * d * srow[(size_t)b * T_ + t0 + row]);
#pragma unroll
            for (int j = 0; j < 5; j++) {
                int col = wn + j * 8 + ((lane & 3) << 1);
                if (col < 64) {
                    size_t g0 = ((size_t)(b * T_ + t0 + row)) * D_ + h * DH_ + col;
                    store_pair_h(oh, ol, g0, acc[i][j][half * 2] * mult, acc[i][j][half * 2 + 1] * mult);
                }
            }
        }
    }
}

// ======== launch ========
extern "C" void kernel_launch(void* const* d_in, const int* in_sizes, int n_in,
                              void* d_out, int out_size)
{
    const float* x  = (const float*)d_in[0];
    const float* wq = (const float*)d_in[1];
    const float* wk = (const float*)d_in[2];
    const float* wv = (const float*)d_in[3];
    const float* wo = (const float*)d_in[4];
    const float* rf = (const float*)d_in[5];
    float* out = (float*)d_out;

    float* fb = nullptr; cudaGetSymbolAddress((void**)&fb, g_buf);
    bf16*  bb = nullptr; cudaGetSymbolAddress((void**)&bb, g_bf);

    float *Qp = fb + OFF_Q, *Kp = fb + OFF_K, *Vp = fb + OFF_V;
    float *SCQ = fb + OFF_SCQ, *SCK = fb + OFF_SCK, *ALP = fb + OFF_AL, *SR = fb + OFF_SR;
    f16 *xh = (f16*)(bb + BO_XH), *xl = (f16*)(bb + BO_XL);
    f16 *wqh = (f16*)(bb + BO_W + 0*(size_t)D_*D_);
    f16 *wql = (f16*)(bb + BO_W + 1*(size_t)D_*D_);
    f16 *wkh = (f16*)(bb + BO_W + 2*(size_t)D_*D_);
    f16 *wkl = (f16*)(bb + BO_W + 3*(size_t)D_*D_);
    f16 *wv16 = (f16*)(bb + BO_W + 4*(size_t)D_*D_);
    f16 *wo16 = (f16*)(bb + BO_W + 5*(size_t)D_*D_);
    f16 *rf16 = (f16*)(bb + BO_RF);
    f16 *Qfh = (f16*)(bb + BO_QFH), *Qfl = (f16*)(bb + BO_QFL);
    bf16 *KfTh = bb + BO_KFTH, *KfTl = bb + BO_KFTL;
    bf16 *VTh = bb + BO_VTH, *VTl = bb + BO_VTL;
    f16 *KVT = (f16*)(bb + BO_KVT);
    f16 *ah = (f16*)(bb + BO_AH), *al = (f16*)(bb + BO_ALO);

    cudaFuncSetAttribute(gemm3, cudaFuncAttributeMaxDynamicSharedMemorySize, SMEM_G3);
    cudaFuncSetAttribute(gemm2t<0>, cudaFuncAttributeMaxDynamicSharedMemorySize, SMEM_G2);
    cudaFuncSetAttribute(gemm2t<1>, cudaFuncAttributeMaxDynamicSharedMemorySize, SMEM_G2);
    cudaFuncSetAttribute(phi_q_kernel, cudaFuncAttributeMaxDynamicSharedMemorySize, SMEM_PHI);
    cudaFuncSetAttribute(phi_k_kernel, cudaFuncAttributeMaxDynamicSharedMemorySize, SMEM_PHI);
    cudaFuncSetAttribute(kv_gemm, cudaFuncAttributeMaxDynamicSharedMemorySize, SMEM_KV);
    cudaFuncSetAttribute(qkv_gemm, cudaFuncAttributeMaxDynamicSharedMemorySize, SMEM_QKV);

    int wn4 = D_ * D_ / 4;
    split16_kernel<<<(int)(SZ_BTD / 4 / 256), 256>>>(x, xh, xl, (int)(SZ_BTD / 4));
    split16_kernel<<<wn4 / 256, 256>>>(wq, wqh, wql, wn4);
    split16_kernel<<<wn4 / 256, 256>>>(wk, wkh, wkl, wn4);
    conv16_kernel<<<wn4 / 256, 256>>>(wv, wv16, wn4);
    conv16_kernel<<<wn4 / 256, 256>>>(wo, wo16, wn4);
    conv16_kernel<<<16, 256>>>(rf, rf16, 4096);

    dim3 gG(D_ / 128, (B_ * T_) / 128);
    gemm3<<<gG, 256, SMEM_G3>>>(xh, xl, wqh, wql, Qp, B_ * T_, D_, D_);
    gemm3<<<gG, 256, SMEM_G3>>>(xh, xl, wkh, wkl, Kp, B_ * T_, D_, D_);
    gemm2t<0><<<gG, 256, SMEM_G2>>>(xh, xl, wv16, nullptr, Vp, B_ * T_, D_, D_);

    dim3 gPhi(T_ / 128, 2, BH_);
    phi_q_kernel<<<gPhi, 256, SMEM_PHI>>>(Qp, rf16, Qfh, Qfl, SCQ);
    phi_k_kernel<<<gPhi, 256, SMEM_PHI>>>(Kp, rf16, KfTh, KfTl, SCK);
    vtrans_kernel<<<dim3(T_ / 64, BH_), 256>>>(Vp, VTh, VTl);

    alpha_kernel<<<BH_, 256>>>(SCK, ALP);
    ksum_kernel<<<dim3(FD_ / 8, BH_), 256>>>(KfTh, KfTl, ALP, KVT);
    zero_kvt_kernel<<<BH_, 256>>>(KVT);
    kv_gemm<<<dim3(FD_ / 128, BH_), 256, SMEM_KV>>>(KfTh, KfTl, VTh, VTl, ALP, KVT);
    srow_kernel<<<(B_ * T_) / 256, 256>>>(SCQ, ALP, SR);

    qkv_gemm<<<dim3(T_ / 128, BH_), 256, SMEM_QKV>>>(Qfh, Qfl, KVT, SCQ, ALP, SR, ah, al);

    gemm2t<1><<<gG, 256, SMEM_G2>>>(ah, al, wo16, SR, out, B_ * T_, D_, D_);
}

// round 11
// speedup vs baseline: 2.6521x; 1.0312x over previous
#include <cuda_runtime.h>
#include <cuda_bf16.h>
#include <cuda_fp16.h>
#include <cstdint>
typedef __nv_bfloat16 bf16;
typedef __half f16;

#define B_   2
#define T_   4096
#define D_   1024
#define H_   16
#define DH_  64
#define FD_  512
#define BH_  (B_*H_)
#define SZ_BTD ((size_t)B_*T_*D_)
#define SZ_F   ((size_t)BH_*T_*FD_)

// fp32 scratch
#define OFF_QK  ((size_t)0)                       // [8192, 2048]: cols 0-1023 Q, 1024-2047 K
#define OFF_V   (2*SZ_BTD)
#define OFF_SCQ (3*SZ_BTD)
#define OFF_SCK (OFF_SCQ + (size_t)BH_*T_)
#define OFF_AL  (OFF_SCK + (size_t)BH_*T_)
#define OFF_BE  (OFF_AL + BH_)
#define OFF_SR  (OFF_BE + BH_)
__device__ float g_buf[OFF_SR + (size_t)B_*T_];

// 2-byte scratch
#define BO_XH    ((size_t)0)
#define BO_XL    (SZ_BTD)
#define BO_WQKH  (2*SZ_BTD)
#define BO_WQKL  (BO_WQKH + 2*(size_t)D_*D_)
#define BO_WV    (BO_WQKL + 2*(size_t)D_*D_)
#define BO_WO    (BO_WV + (size_t)D_*D_)
#define BO_RF    (BO_WO + (size_t)D_*D_)
#define BO_QFH   (BO_RF + 16384)
#define BO_QFL   (BO_QFH + SZ_F)
#define BO_KFTH  (BO_QFL + SZ_F)
#define BO_KFTL  (BO_KFTH + SZ_F)
#define BO_VT    (BO_KFTL + SZ_F)
#define BO_KVT   (BO_VT + SZ_BTD)
#define BO_AH    (BO_KVT + (size_t)BH_*80*FD_)
#define BO_ALO   (BO_AH + SZ_BTD)
__device__ bf16 g_bf[BO_ALO + SZ_BTD];

__device__ __forceinline__ uint32_t smem_to_u32(const void* p) {
    uint32_t a;
    asm("{ .reg .u64 t; cvta.to.shared.u64 t, %1; cvt.u32.u64 %0, t; }" : "=r"(a) : "l"(p));
    return a;
}
#define SWZ(o) ((o) ^ (((o) >> 3) & 0x70))
__device__ __forceinline__ void cp_async16(uint32_t s, const void* g) {
    asm volatile("cp.async.cg.shared.global [%0], [%1], 16;" :: "r"(s), "l"(g));
}
__device__ __forceinline__ void cp_commit() { asm volatile("cp.async.commit_group;" ::: "memory"); }
template <int N> __device__ __forceinline__ void cp_wait() {
    asm volatile("cp.async.wait_group %0;" :: "n"(N) : "memory");
}
__device__ __forceinline__ void ldsm_x4(uint32_t& r0, uint32_t& r1, uint32_t& r2, uint32_t& r3, uint32_t a) {
    asm volatile("ldmatrix.sync.aligned.m8n8.x4.shared.b16 {%0,%1,%2,%3}, [%4];"
                 : "=r"(r0), "=r"(r1), "=r"(r2), "=r"(r3) : "r"(a));
}
__device__ __forceinline__ void ldsm_x2(uint32_t& r0, uint32_t& r1, uint32_t a) {
    asm volatile("ldmatrix.sync.aligned.m8n8.x2.shared.b16 {%0,%1}, [%2];"
                 : "=r"(r0), "=r"(r1) : "r"(a));
}
__device__ __forceinline__ void mma_f16(float* c, const uint32_t* a, const uint32_t* b) {
    asm volatile("mma.sync.aligned.m16n8k16.row.col.f32.f16.f16.f32 "
                 "{%0,%1,%2,%3}, {%4,%5,%6,%7}, {%8,%9}, {%0,%1,%2,%3};"
                 : "+f"(c[0]), "+f"(c[1]), "+f"(c[2]), "+f"(c[3])
                 : "r"(a[0]), "r"(a[1]), "r"(a[2]), "r"(a[3]), "r"(b[0]), "r"(b[1]));
}
__device__ __forceinline__ void store_pair_h(f16* ph, f16* pl, size_t off, float x0, float x1) {
    f16 h0 = __float2half_rn(x0), h1 = __float2half_rn(x1);
    __half2 hp = __halves2half2(h0, h1);
    *(uint32_t*)(ph + off) = *(uint32_t*)&hp;
    __half2 lp = __halves2half2(__float2half_rn(x0 - __half2float(h0)),
                                __float2half_rn(x1 - __half2float(h1)));
    *(uint32_t*)(pl + off) = *(uint32_t*)&lp;
}
__device__ __forceinline__ void fast_sincos(float x, float& s, float& c) {
    float kf = rintf(x * 0.63661977f);
    int q = (int)kf;
    float r = fmaf(kf, -1.5707963705062866f, x);
    r = fmaf(kf, 4.3711388286738e-8f, r);
    float r2 = r * r;
    float sp = fmaf(-1.98412698e-4f, r2, 8.33333333e-3f);
    sp = fmaf(sp, r2, -1.66666667e-1f) * r2;
    float sr = fmaf(sp, r, r);
    float cp = fmaf(2.48015873e-5f, r2, -1.38888889e-3f);
    cp = fmaf(cp, r2, 4.16666667e-2f);
    cp = fmaf(cp, r2, -0.5f);
    float cr = fmaf(cp, r2, 1.0f);
    if (q & 1) { float t = sr; sr = cr; cr = -t; }
    if (q & 2) { sr = -sr; cr = -cr; }
    s = sr; c = cr;
}

#define TILE_B 16384

// ======== fp16 3-pass GEMM: C = A(hi/lo) B(hi/lo)^T ========
#define BUF3   (4*TILE_B)
#define SMEM_G3 (2*BUF3)
__global__ void __launch_bounds__(256)
gemm3(const f16* __restrict__ Ah, const f16* __restrict__ Al,
      const f16* __restrict__ Bh, const f16* __restrict__ Bl,
      float* __restrict__ C, int M, int N, int K)
{
    extern __shared__ char smem[];
    const uint32_t sb = smem_to_u32(smem);
    const int tid = threadIdx.x, wid = tid >> 5, lane = tid & 31;
    const int bn = blockIdx.x << 7, bm = blockIdx.y << 7;
    const int wm = (wid >> 2) << 6, wn = (wid & 3) << 5;
    const int nchunk = K >> 6;
    const int lr = lane & 15, lc = lane >> 4, br = lane & 7, bk = (lane >> 3) & 1;
    float acc[4][4][4];
#pragma unroll
    for (int i = 0; i < 4; i++)
#pragma unroll
        for (int j = 0; j < 4; j++)
#pragma unroll
            for (int r = 0; r < 4; r++) acc[i][j][r] = 0.f;
    const f16* gs[4] = {Ah, Al, Bh, Bl};
    const int rb[4] = {bm, bm, bn, bn};
    auto load = [&](int kc, int buf) {
        uint32_t base = sb + buf * BUF3;
        int ke = kc << 6;
#pragma unroll
        for (int t = 0; t < 4; t++)
#pragma unroll
            for (int i = 0; i < 4; i++) {
                int idx = tid + (i << 8), r = idx >> 3, c = idx & 7;
                cp_async16(base + t * TILE_B + SWZ(r * 128 + c * 16),
                           gs[t] + (size_t)(rb[t] + r) * K + ke + c * 8);
            }
    };
    load(0, 0); cp_commit();
    for (int kc = 0; kc < nchunk; kc++) {
        int cur = kc & 1;
        if (kc + 1 < nchunk) { load(kc + 1, cur ^ 1); cp_commit(); cp_wait<1>(); }
        else cp_wait<0>();
        __syncthreads();
        uint32_t bA = sb + cur * BUF3;
#pragma unroll
        for (int ks = 0; ks < 4; ks++) {
            uint32_t a_h[4][4], a_l[4][4], b_h[4][2], b_l[4][2];
#pragma unroll
            for (int i = 0; i < 4; i++) {
                uint32_t o = SWZ((wm + i * 16 + lr) * 128 + ks * 32 + lc * 16);
                ldsm_x4(a_h[i][0], a_h[i][1], a_h[i][2], a_h[i][3], bA + o);
                ldsm_x4(a_l[i][0], a_l[i][1], a_l[i][2], a_l[i][3], bA + TILE_B + o);
            }
#pragma unroll
            for (int j = 0; j < 4; j++) {
                uint32_t o = SWZ((wn + j * 8 + br) * 128 + ks * 32 + bk * 16);
                ldsm_x2(b_h[j][0], b_h[j][1], bA + 2 * TILE_B + o);
                ldsm_x2(b_l[j][0], b_l[j][1], bA + 3 * TILE_B + o);
            }
#pragma unroll
            for (int i = 0; i < 4; i++)
#pragma unroll
                for (int j = 0; j < 4; j++) {
                    mma_f16(acc[i][j], a_h[i], b_h[j]);
                    mma_f16(acc[i][j], a_h[i], b_l[j]);
                    mma_f16(acc[i][j], a_l[i], b_h[j]);
                }
        }
        __syncthreads();
    }
#pragma unroll
    for (int i = 0; i < 4; i++) {
        int row = bm + wm + i * 16 + (lane >> 2);
#pragma unroll
        for (int j = 0; j < 4; j++) {
            int col = bn + wn + j * 8 + ((lane & 3) << 1);
            *(float2*)&C[(size_t)row * N + col]       = make_float2(acc[i][j][0], acc[i][j][1]);
            *(float2*)&C[(size_t)(row + 8) * N + col] = make_float2(acc[i][j][2], acc[i][j][3]);
        }
    }
}

// ======== fp16 2-pass GEMM: C = (Ah+Al) B^T ; optional fp32 row scale ========
#define BUF2   (3*TILE_B)
#define SMEM_G2 (2*BUF2)
template <int ROWSCALE>
__global__ void __launch_bounds__(256)
gemm2t(const f16* __restrict__ Ah, const f16* __restrict__ Al,
       const f16* __restrict__ Bm, const float* __restrict__ S,
       float* __restrict__ C, int M, int N, int K)
{
    extern __shared__ char smem[];
    const uint32_t sb = smem_to_u32(smem);
    const int tid = threadIdx.x, wid = tid >> 5, lane = tid & 31;
    const int bn = blockIdx.x << 7, bm = blockIdx.y << 7;
    const int wm = (wid >> 2) << 6, wn = (wid & 3) << 5;
    const int nchunk = K >> 6;
    const int lr = lane & 15, lc = lane >> 4, br = lane & 7, bk = (lane >> 3) & 1;
    float acc[4][4][4];
#pragma unroll
    for (int i = 0; i < 4; i++)
#pragma unroll
        for (int j = 0; j < 4; j++)
#pragma unroll
            for (int r = 0; r < 4; r++) acc[i][j][r] = 0.f;
    auto load = [&](int kc, int buf) {
        uint32_t base = sb + buf * BUF2;
        int ke = kc << 6;
#pragma unroll
        for (int i = 0; i < 4; i++) {
            int idx = tid + (i << 8), r = idx >> 3, c = idx & 7;
            uint32_t so = SWZ(r * 128 + c * 16);
            cp_async16(base + so,              Ah + (size_t)(bm + r) * K + ke + c * 8);
            cp_async16(base + TILE_B + so,     Al + (size_t)(bm + r) * K + ke + c * 8);
            cp_async16(base + 2 * TILE_B + so, Bm + (size_t)(bn + r) * K + ke + c * 8);
        }
    };
    load(0, 0); cp_commit();
    for (int kc = 0; kc < nchunk; kc++) {
        int cur = kc & 1;
        if (kc + 1 < nchunk) { load(kc + 1, cur ^ 1); cp_commit(); cp_wait<1>(); }
        else cp_wait<0>();
        __syncthreads();
        uint32_t bA = sb + cur * BUF2;
#pragma unroll
        for (int ks = 0; ks < 4; ks++) {
            uint32_t a_h[4][4], a_l[4][4], b_[4][2];
#pragma unroll
            for (int i = 0; i < 4; i++) {
                uint32_t o = SWZ((wm + i * 16 + lr) * 128 + ks * 32 + lc * 16);
                ldsm_x4(a_h[i][0], a_h[i][1], a_h[i][2], a_h[i][3], bA + o);
                ldsm_x4(a_l[i][0], a_l[i][1], a_l[i][2], a_l[i][3], bA + TILE_B + o);
            }
#pragma unroll
            for (int j = 0; j < 4; j++) {
                uint32_t o = SWZ((wn + j * 8 + br) * 128 + ks * 32 + bk * 16);
                ldsm_x2(b_[j][0], b_[j][1], bA + 2 * TILE_B + o);
            }
#pragma unroll
            for (int i = 0; i < 4; i++)
#pragma unroll
                for (int j = 0; j < 4; j++) {
                    mma_f16(acc[i][j], a_h[i], b_[j]);
                    mma_f16(acc[i][j], a_l[i], b_[j]);
                }
        }
        __syncthreads();
    }
#pragma unroll
    for (int i = 0; i < 4; i++) {
        int row = bm + wm + i * 16 + (lane >> 2);
        float s0 = ROWSCALE ? S[row] : 1.f;
        float s1 = ROWSCALE ? S[row + 8] : 1.f;
#pragma unroll
        for (int j = 0; j < 4; j++) {
            int col = bn + wn + j * 8 + ((lane & 3) << 1);
            *(float2*)&C[(size_t)row * N + col]       = make_float2(acc[i][j][0] * s0, acc[i][j][1] * s0);
            *(float2*)&C[(size_t)(row + 8) * N + col] = make_float2(acc[i][j][2] * s1, acc[i][j][3] * s1);
        }
    }
}

// ======== conversions ========
__global__ void __launch_bounds__(256) split16_kernel(const float* __restrict__ in,
                                                      f16* __restrict__ hi, f16* __restrict__ lo, int n4)
{
    int i = blockIdx.x * 256 + threadIdx.x;
    if (i >= n4) return;
    float4 v = ((const float4*)in)[i];
    store_pair_h(hi, lo, (size_t)i * 4, v.x, v.y);
    store_pair_h(hi, lo, (size_t)i * 4 + 2, v.z, v.w);
}
__global__ void __launch_bounds__(256) conv16_kernel(const float* __restrict__ in,
                                                     f16* __restrict__ out, int n4)
{
    int i = blockIdx.x * 256 + threadIdx.x;
    if (i >= n4) return;
    float4 v = ((const float4*)in)[i];
    __half2 p0 = __halves2half2(__float2half_rn(v.x), __float2half_rn(v.y));
    __half2 p1 = __halves2half2(__float2half_rn(v.z), __float2half_rn(v.w));
    uint2 o; o.x = *(uint32_t*)&p0; o.y = *(uint32_t*)&p1;
    ((uint2*)out)[i] = o;
}

// ======== phi kernels (3x16KB tiles + scale + np) ========
#define PA  0
#define PAL 16384
#define PB  32768
#define PSC 49152
#define PNP 49664
#define SMEM_PHI 50688

__device__ __forceinline__ void conv_tile_h(const float* g, int ld, char* sm, int dstH, int dstL,
                                            float* np, int tid) {
    int r = tid >> 1, cb = (tid & 1) << 5;
    float s = 0.f;
    const float* gp = g + (size_t)r * ld + cb;
#pragma unroll
    for (int k = 0; k < 8; k++) {
        float4 v = *(const float4*)(gp + k * 4);
        s = fmaf(v.x, v.x, s); s = fmaf(v.y, v.y, s);
        s = fmaf(v.z, v.z, s); s = fmaf(v.w, v.w, s);
        uint32_t sw = SWZ((uint32_t)(r * 128 + (cb + k * 4) * 2));
        f16 h0 = __float2half_rn(v.x), h1 = __float2half_rn(v.y);
        f16 h2 = __float2half_rn(v.z), h3 = __float2half_rn(v.w);
        __half2 hp0 = __halves2half2(h0, h1), hp1 = __halves2half2(h2, h3);
        *(uint32_t*)(sm + dstH + sw) = *(uint32_t*)&hp0;
        *(uint32_t*)(sm + dstH + sw + 4) = *(uint32_t*)&hp1;
        __half2 lp0 = __halves2half2(__float2half_rn(v.x - __half2float(h0)),
                                     __float2half_rn(v.y - __half2float(h1)));
        __half2 lp1 = __halves2half2(__float2half_rn(v.z - __half2float(h2)),
                                     __float2half_rn(v.w - __half2float(h3)));
        *(uint32_t*)(sm + dstL + sw) = *(uint32_t*)&lp0;
        *(uint32_t*)(sm + dstL + sw + 4) = *(uint32_t*)&lp1;
    }
    np[tid] = s;
}

// phi_q: Qf^ unscaled fp16 hi/lo; scq = exp(-|q|^2/2)/16
__global__ void __launch_bounds__(256) phi_q_kernel(
    const float* __restrict__ QK, const f16* __restrict__ rf16,
    f16* __restrict__ Qfh, f16* __restrict__ Qfl, float* __restrict__ scq)
{
    extern __shared__ char sm[];
    const uint32_t sb = smem_to_u32(sm);
    const int tid = threadIdx.x, wid = tid >> 5, lane = tid & 31;
    const int t0 = blockIdx.x << 7, m0c = blockIdx.y << 7, bh = blockIdx.z;
    const int b = bh >> 4, h = bh & 15;
    float* np = (float*)(sm + PNP);
#pragma unroll
    for (int i = 0; i < 4; i++) {
        int idx = tid + (i << 8), r = idx >> 3, c = idx & 7;
        cp_async16(sb + PB + SWZ(r * 128 + c * 16), rf16 + (size_t)(m0c + r) * DH_ + c * 8);
    }
    cp_commit();
    conv_tile_h(&QK[((size_t)(b * T_ + t0)) * 2048 + h * DH_], 2048, sm, PA, PAL, np, tid);
    __syncthreads();
    if (tid < 128 && blockIdx.y == 0)
        scq[(size_t)bh * T_ + t0 + tid] = __expf(-0.5f * (np[2 * tid] + np[2 * tid + 1])) * 0.0625f;
    cp_wait<0>();
    __syncthreads();
    const int wt = (wid >> 2) << 6, wm = (wid & 3) << 5;
    const int lr = lane & 15, lc = lane >> 4, br = lane & 7, bk = (lane >> 3) & 1;
    float acc[4][4][4];
#pragma unroll
    for (int i = 0; i < 4; i++)
#pragma unroll
        for (int j = 0; j < 4; j++)
#pragma unroll
            for (int r = 0; r < 4; r++) acc[i][j][r] = 0.f;
#pragma unroll
    for (int ks = 0; ks < 4; ks++) {
        uint32_t a_h[4][4], a_l[4][4], b_[4][2];
#pragma unroll
        for (int i = 0; i < 4; i++) {
            uint32_t o = SWZ((wt + i * 16 + lr) * 128 + ks * 32 + lc * 16);
            ldsm_x4(a_h[i][0], a_h[i][1], a_h[i][2], a_h[i][3], sb + PA + o);
            ldsm_x4(a_l[i][0], a_l[i][1], a_l[i][2], a_l[i][3], sb + PAL + o);
        }
#pragma unroll
        for (int j = 0; j < 4; j++) {
            uint32_t o = SWZ((wm + j * 8 + br) * 128 + ks * 32 + bk * 16);
            ldsm_x2(b_[j][0], b_[j][1], sb + PB + o);
        }
#pragma unroll
        for (int i = 0; i < 4; i++)
#pragma unroll
            for (int j = 0; j < 4; j++) {
                mma_f16(acc[i][j], a_h[i], b_[j]);
                mma_f16(acc[i][j], a_l[i], b_[j]);
            }
    }
#pragma unroll
    for (int i = 0; i < 4; i++) {
        int r0 = wt + i * 16 + (lane >> 2);
        size_t rb0 = ((size_t)bh * T_ + t0 + r0) * FD_ + m0c;
        size_t rb1 = rb0 + (size_t)8 * FD_;
#pragma unroll
        for (int j = 0; j < 4; j++) {
            int mc = wm + j * 8 + ((lane & 3) << 1);
            float sn0, cs0, sn1, cs1;
            fast_sincos(acc[i][j][0], sn0, cs0);
            fast_sincos(acc[i][j][1], sn1, cs1);
            store_pair_h(Qfh, Qfl, rb0 + mc, cs0, cs1);
            store_pair_h(Qfh, Qfl, rb0 + 256 + mc, sn0, sn1);
            fast_sincos(acc[i][j][2], sn0, cs0);
            fast_sincos(acc[i][j][3], sn1, cs1);
            store_pair_h(Qfh, Qfl, rb1 + mc, cs0, cs1);
            store_pair_h(Qfh, Qfl, rb1 + 256 + mc, sn0, sn1);
        }
    }
}

// phi_k: KfT' = phi_k / beta (fp16 hi/lo). rf at PA; K hi at PAL; K lo at PB.
__global__ void __launch_bounds__(256) phi_k_kernel(
    const float* __restrict__ QK, const f16* __restrict__ rf16,
    const float* __restrict__ beta,
    f16* __restrict__ KfTh, f16* __restrict__ KfTl)
{
    extern __shared__ char sm[];
    const uint32_t sb = smem_to_u32(sm);
    const int tid = threadIdx.x, wid = tid >> 5, lane = tid & 31;
    const int t0 = blockIdx.x << 7, m0c = blockIdx.y << 7, bh = blockIdx.z;
    const int b = bh >> 4, h = bh & 15;
    float* scale = (float*)(sm + PSC);
    float* np = (float*)(sm + PNP);
    const float gamma = 1.f / beta[bh];
#pragma unroll
    for (int i = 0; i < 4; i++) {
        int idx = tid + (i << 8), r = idx >> 3, c = idx & 7;
        cp_async16(sb + PA + SWZ(r * 128 + c * 16), rf16 + (size_t)(m0c + r) * DH_ + c * 8);
    }
    cp_commit();
    conv_tile_h(&QK[((size_t)(b * T_ + t0)) * 2048 + 1024 + h * DH_], 2048, sm, PAL, PB, np, tid);
    __syncthreads();
    if (tid < 128)
        scale[tid] = __expf(-0.5f * (np[2 * tid] + np[2 * tid + 1])) * 0.0625f * gamma;
    cp_wait<0>();
    __syncthreads();
    const int wm = (wid >> 2) << 6, wt = (wid & 3) << 5;
    const int lr = lane & 15, lc = lane >> 4, br = lane & 7, bk = (lane >> 3) & 1;
    float acc[4][4][4];
#pragma unroll
    for (int i = 0; i < 4; i++)
#pragma unroll
        for (int j = 0; j < 4; j++)
#pragma unroll
            for (int r = 0; r < 4; r++) acc[i][j][r] = 0.f;
#pragma unroll
    for (int ks = 0; ks < 4; ks++) {
        uint32_t a_[4][4], b_h[4][2], b_l[4][2];
#pragma unroll
        for (int i = 0; i < 4; i++) {
            uint32_t o = SWZ((wm + i * 16 + lr) * 128 + ks * 32 + lc * 16);
            ldsm_x4(a_[i][0], a_[i][1], a_[i][2], a_[i][3], sb + PA + o);
        }
#pragma unroll
        for (int j = 0; j < 4; j++) {
            uint32_t o = SWZ((wt + j * 8 + br) * 128 + ks * 32 + bk * 16);
            ldsm_x2(b_h[j][0], b_h[j][1], sb + PAL + o);
            ldsm_x2(b_l[j][0], b_l[j][1], sb + PB + o);
        }
#pragma unroll
        for (int i = 0; i < 4; i++)
#pragma unroll
            for (int j = 0; j < 4; j++) {
                mma_f16(acc[i][j], a_[i], b_h[j]);
                mma_f16(acc[i][j], a_[i], b_l[j]);
            }
    }
#pragma unroll
    for (int i = 0; i < 4; i++) {
        int r0 = wm + i * 16 + (lane >> 2);
        size_t rc0 = ((size_t)bh * FD_ + m0c + r0) * T_ + t0;
        size_t rs0 = rc0 + (size_t)256 * T_;
        size_t rc1 = rc0 + (size_t)8 * T_, rs1 = rs0 + (size_t)8 * T_;
#pragma unroll
        for (int j = 0; j < 4; j++) {
            int tc = wt + j * 8 + ((lane & 3) << 1);
            float sc0 = scale[tc], sc1 = scale[tc + 1];
            float sn0, cs0, sn1, cs1;
            fast_sincos(acc[i][j][0], sn0, cs0);
            fast_sincos(acc[i][j][1], sn1, cs1);
            store_pair_h(KfTh, KfTl, rc0 + tc, cs0 * sc0, cs1 * sc1);
            store_pair_h(KfTh, KfTl, rs0 + tc, sn0 * sc0, sn1 * sc1);
            fast_sincos(acc[i][j][2], sn0, cs0);
            fast_sincos(acc[i][j][3], sn1, cs1);
            store_pair_h(KfTh, KfTl, rc1 + tc, cs0 * sc0, cs1 * sc1);
            store_pair_h(KfTh, KfTl, rs1 + tc, sn0 * sc0, sn1 * sc1);
        }
    }
}

// ======== knorm: sck from QK buffer (K half) ========
__global__ void __launch_bounds__(256) knorm_kernel(const float* __restrict__ QK,
                                                    float* __restrict__ sck)
{
    __shared__ float np[256];
    const int tid = threadIdx.x;
    const int t0 = blockIdx.x << 7, bh = blockIdx.y;
    const int b = bh >> 4, h = bh & 15;
    int r = tid >> 1, cb = (tid & 1) << 5;
    const float* gp = QK + ((size_t)(b * T_ + t0 + r)) * 2048 + 1024 + h * DH_ + cb;
    float s = 0.f;
#pragma unroll
    for (int k = 0; k < 8; k++) {
        float4 v = *(const float4*)(gp + k * 4);
        s = fmaf(v.x, v.x, s); s = fmaf(v.y, v.y, s);
        s = fmaf(v.z, v.z, s); s = fmaf(v.w, v.w, s);
    }
    np[tid] = s;
    __syncthreads();
    if (tid < 128)
        sck[(size_t)bh * T_ + t0 + tid] = __expf(-0.5f * (np[2 * tid] + np[2 * tid + 1])) * 0.0625f;
}

// ======== alpha/beta, ksum, zero, srow ========
__global__ void __launch_bounds__(256) alphabeta_kernel(const float* __restrict__ sck,
                                                        float* __restrict__ alpha,
                                                        float* __restrict__ beta)
{
    __shared__ float rs[256], rm[256];
    const int bh = blockIdx.x, tid = threadIdx.x;
    float s = 0.f, m = 0.f;
    for (int i = tid; i < T_; i += 256) {
        float v = sck[(size_t)bh * T_ + i];
        s += v; m = fmaxf(m, v);
    }
    rs[tid] = s; rm[tid] = m;
    __syncthreads();
    for (int o = 128; o; o >>= 1) {
        if (tid < o) { rs[tid] += rs[tid + o]; rm[tid] = fmaxf(rm[tid], rm[tid + o]); }
        __syncthreads();
    }
    if (tid == 0) {
        alpha[bh] = 1.f / fmaxf(rs[0], 1e-30f);
        beta[bh]  = fmaxf(rm[0], 1e-37f);
    }
}

__global__ void __launch_bounds__(256) ksum_kernel(const f16* __restrict__ KfTh,
                                                   const f16* __restrict__ KfTl,
                                                   const float* __restrict__ alpha,
                                                   const float* __restrict__ beta,
                                                   f16* __restrict__ kvt)
{
    const int wid = threadIdx.x >> 5, lane = threadIdx.x & 31;
    const int f = blockIdx.x * 8 + wid, bh = blockIdx.y;
    const f16* ph = KfTh + ((size_t)bh * FD_ + f) * T_;
    const f16* pl = KfTl + ((size_t)bh * FD_ + f) * T_;
    float s = 0.f;
    for (int i = lane * 2; i < T_; i += 64) {
        uint32_t hp = *(const uint32_t*)(ph + i), lp = *(const uint32_t*)(pl + i);
        __half2 h2 = *(__half2*)&hp, l2 = *(__half2*)&lp;
        s += __half2float(h2.x) + __half2float(l2.x)
           + __half2float(h2.y) + __half2float(l2.y);
    }
#pragma unroll
    for (int o = 16; o; o >>= 1) s += __shfl_xor_sync(0xffffffffu, s, o);
    if (lane == 0) kvt[((size_t)bh * 80 + 64) * FD_ + f] = __float2half_rn(s * alpha[bh] * beta[bh]);
}

__global__ void __launch_bounds__(256) zero_kvt_kernel(f16* __restrict__ kvt)
{
    const int bh = blockIdx.x;
    for (int i = threadIdx.x; i < 15 * FD_; i += 256)
        kvt[((size_t)bh * 80 + 65) * FD_ + i] = __float2half_rn(0.f);
}

__global__ void __launch_bounds__(256) srow_kernel(const float* __restrict__ scq,
                                                   const float* __restrict__ alpha,
                                                   float* __restrict__ srow)
{
    int row = blockIdx.x * 256 + threadIdx.x;
    int b = row >> 12, t = row & 4095;
    float m = 0.f;
#pragma unroll
    for (int h = 0; h < H_; h++) {
        int bh = b * H_ + h;
        m = fmaxf(m, scq[(size_t)bh * T_ + t] / alpha[bh]);
    }
    srow[row] = fmaxf(m * 1e6f, 1e-30f);
}

// ======== V transpose (fp16 single) ========
__global__ void __launch_bounds__(256) vtrans_kernel(const float* __restrict__ V,
                                                     f16* __restrict__ VT)
{
    __shared__ float st[64][68];
    const int tid = threadIdx.x;
    const int t0 = blockIdx.x << 6, bh = blockIdx.y;
    const int b = bh >> 4, h = bh & 15;
#pragma unroll
    for (int i = 0; i < 4; i++) {
        int idx = tid + (i << 8), r = idx >> 4, c4 = (idx & 15) << 2;
        *(float4*)&st[r][c4] = *(const float4*)&V[((size_t)(b * T_ + t0 + r)) * D_ + h * DH_ + c4];
    }
    __syncthreads();
    int v = tid >> 2, ts = (tid & 3) << 4;
#pragma unroll
    for (int p = 0; p < 8; p++) {
        int t = ts + p * 2;
        __half2 hp = __halves2half2(__float2half_rn(st[t][v]), __float2half_rn(st[t + 1][v]));
        *(uint32_t*)&VT[((size_t)bh * DH_ + v) * T_ + t0 + t] = *(uint32_t*)&hp;
    }
}

// ======== kv: KfT'(fp16 h/l) x VT(fp16)^T, 2-pass; kvt = alpha*beta*acc ========
#define KA   0
#define KAL  16384
#define KB   32768
#define KBUF 40960
#define SMEM_KV (2*KBUF)

__global__ void __launch_bounds__(256) kv_gemm(
    const f16* __restrict__ Ah, const f16* __restrict__ Al,
    const f16* __restrict__ Bm,
    const float* __restrict__ alpha, const float* __restrict__ beta,
    f16* __restrict__ kvt)
{
    extern __shared__ char sm[];
    const uint32_t sb = smem_to_u32(sm);
    const int tid = threadIdx.x, wid = tid >> 5, lane = tid & 31;
    const int m0 = blockIdx.x << 7, bh = blockIdx.y;
    const size_t ab = (size_t)bh * FD_ + m0, bb = (size_t)bh * DH_;
    const int wm = (wid >> 1) << 5, wn = (wid & 1) << 5;
    const int lr = lane & 15, lc = lane >> 4, br = lane & 7, bk = (lane >> 3) & 1;
    float acc[2][4][4];
#pragma unroll
    for (int i = 0; i < 2; i++)
#pragma unroll
        for (int j = 0; j < 4; j++)
#pragma unroll
            for (int r = 0; r < 4; r++) acc[i][j][r] = 0.f;
    auto load = [&](int kc, int buf) {
        uint32_t base = sb + buf * KBUF;
        int ke = kc << 6;
#pragma unroll
        for (int i = 0; i < 4; i++) {
            int idx = tid + (i << 8), r = idx >> 3, c = idx & 7;
            uint32_t so = SWZ(r * 128 + c * 16);
            size_t g = (ab + r) * T_ + ke + c * 8;
            cp_async16(base + KA + so, Ah + g);
            cp_async16(base + KAL + so, Al + g);
        }
#pragma unroll
        for (int i = 0; i < 2; i++) {
            int idx = tid + (i << 8);
            if (idx < 512) {
                int r = idx >> 3, c = idx & 7;
                cp_async16(base + KB + SWZ(r * 128 + c * 16), Bm + (bb + r) * T_ + ke + c * 8);
            }
        }
    };
    load(0, 0); cp_commit();
    for (int kc = 0; kc < T_ / 64; kc++) {
        int cur = kc & 1;
        if (kc + 1 < T_ / 64) { load(kc + 1, cur ^ 1); cp_commit(); cp_wait<1>(); }
        else cp_wait<0>();
        __syncthreads();
        uint32_t bA = sb + cur * KBUF;
#pragma unroll
        for (int ks = 0; ks < 4; ks++) {
            uint32_t a_h[2][4], a_l[2][4], b_[4][2];
#pragma unroll
            for (int i = 0; i < 2; i++) {
                uint32_t o = SWZ((wm + i * 16 + lr) * 128 + ks * 32 + lc * 16);
                ldsm_x4(a_h[i][0], a_h[i][1], a_h[i][2], a_h[i][3], bA + KA + o);
                ldsm_x4(a_l[i][0], a_l[i][1], a_l[i][2], a_l[i][3], bA + KAL + o);
            }
#pragma unroll
            for (int j = 0; j < 4; j++) {
                uint32_t o = SWZ((wn + j * 8 + br) * 128 + ks * 32 + bk * 16);
                ldsm_x2(b_[j][0], b_[j][1], bA + KB + o);
            }
#pragma unroll
            for (int i = 0; i < 2; i++)
#pragma unroll
                for (int j = 0; j < 4; j++) {
                    mma_f16(acc[i][j], a_h[i], b_[j]);
                    mma_f16(acc[i][j], a_l[i], b_[j]);
                }
        }
        __syncthreads();
    }
    float* stage = (float*)sm;
#pragma unroll
    for (int i = 0; i < 2; i++) {
        int row = wm + i * 16 + (lane >> 2);
#pragma unroll
        for (int j = 0; j < 4; j++) {
            int col = wn + j * 8 + ((lane & 3) << 1);
            stage[col * 132 + row]           = acc[i][j][0];
            stage[(col + 1) * 132 + row]     = acc[i][j][1];
            stage[col * 132 + row + 8]       = acc[i][j][2];
            stage[(col + 1) * 132 + row + 8] = acc[i][j][3];
        }
    }
    __syncthreads();
    float av = alpha[bh] * beta[bh];
    int v = tid >> 2, fs = (tid & 3) << 5;
#pragma unroll
    for (int p = 0; p < 16; p++) {
        int f = fs + p * 2;
        __half2 hp = __halves2half2(__float2half_rn(stage[v * 132 + f] * av),
                                    __float2half_rn(stage[v * 132 + f + 1] * av));
        *(uint32_t*)&kvt[((size_t)bh * 80 + v) * FD_ + m0 + f] = *(uint32_t*)&hp;
    }
}

// ======== qkv: Qf^ x KVT'[80], 2-pass; epilogue Z + scales ========
#define QA   0
#define QAL  16384
#define QB   32768
#define QBUF 43008
#define SMEM_QKV (2*QBUF)

__global__ void __launch_bounds__(256) qkv_gemm(
    const f16* __restrict__ Ah, const f16* __restrict__ Al,
    const f16* __restrict__ Bm, const float* __restrict__ scq,
    const float* __restrict__ alpha, const float* __restrict__ srow,
    f16* __restrict__ oh, f16* __restrict__ ol)
{
    extern __shared__ char sm[];
    __shared__ float zsm[128];
    const uint32_t sb = smem_to_u32(sm);
    const int tid = threadIdx.x, wid = tid >> 5, lane = tid & 31;
    const int t0 = blockIdx.x << 7, bh = blockIdx.y;
    const int b = bh >> 4, h = bh & 15;
    const size_t ab = (size_t)bh * T_ + t0, bb = (size_t)bh * 80;
    const int wm = (wid >> 1) << 5, wn = (wid & 1) * 40;
    const int lr = lane & 15, lc = lane >> 4, br = lane & 7, bk = (lane >> 3) & 1;
    float acc[2][5][4];
#pragma unroll
    for (int i = 0; i < 2; i++)
#pragma unroll
        for (int j = 0; j < 5; j++)
#pragma unroll
            for (int r = 0; r < 4; r++) acc[i][j][r] = 0.f;
    auto load = [&](int kc, int buf) {
        uint32_t base = sb + buf * QBUF;
        int ke = kc << 6;
#pragma unroll
        for (int i = 0; i < 4; i++) {
            int idx = tid + (i << 8), r = idx >> 3, c = idx & 7;
            uint32_t so = SWZ(r * 128 + c * 16);
            size_t g = (ab + r) * FD_ + ke + c * 8;
            cp_async16(base + QA + so, Ah + g);
            cp_async16(base + QAL + so, Al + g);
        }
#pragma unroll
        for (int i = 0; i < 3; i++) {
            int idx = tid + (i << 8);
            if (idx < 640) {
                int r = idx >> 3, c = idx & 7;
                cp_async16(base + QB + SWZ(r * 128 + c * 16), Bm + (bb + r) * FD_ + ke + c * 8);
            }
        }
    };
    load(0, 0); cp_commit();
    for (int kc = 0; kc < 8; kc++) {
        int cur = kc & 1;
        if (kc + 1 < 8) { load(kc + 1, cur ^ 1); cp_commit(); cp_wait<1>(); }
        else cp_wait<0>();
        __syncthreads();
        uint32_t bA = sb + cur * QBUF;
#pragma unroll
        for (int ks = 0; ks < 4; ks++) {
            uint32_t a_h[2][4], a_l[2][4], b_[5][2];
#pragma unroll
            for (int i = 0; i < 2; i++) {
                uint32_t o = SWZ((wm + i * 16 + lr) * 128 + ks * 32 + lc * 16);
                ldsm_x4(a_h[i][0], a_h[i][1], a_h[i][2], a_h[i][3], bA + QA + o);
                ldsm_x4(a_l[i][0], a_l[i][1], a_l[i][2], a_l[i][3], bA + QAL + o);
            }
#pragma unroll
            for (int j = 0; j < 5; j++) {
                uint32_t o = SWZ((wn + j * 8 + br) * 128 + ks * 32 + bk * 16);
                ldsm_x2(b_[j][0], b_[j][1], bA + QB + o);
            }
#pragma unroll
            for (int i = 0; i < 2; i++)
#pragma unroll
                for (int j = 0; j < 5; j++) {
                    mma_f16(acc[i][j], a_h[i], b_[j]);
                    mma_f16(acc[i][j], a_l[i], b_[j]);
                }
        }
        __syncthreads();
    }
    if (wn == 40 && (lane & 3) == 0) {
#pragma unroll
        for (int i = 0; i < 2; i++) {
            int row = wm + i * 16 + (lane >> 2);
            zsm[row] = acc[i][3][0];
            zsm[row + 8] = acc[i][3][2];
        }
    }
    __syncthreads();
    float av = alpha[bh];
#pragma unroll
    for (int i = 0; i < 2; i++) {
#pragma unroll
        for (int half = 0; half < 2; half++) {
            int row = wm + i * 16 + (lane >> 2) + half * 8;
            float sq = scq[ab + row];
            float Zt = sq * zsm[row] / av;
            float d = fmaxf(Zt, 1e-6f);
            float mult = sq / (av * d * srow[(size_t)b * T_ + t0 + row]);
#pragma unroll
            for (int j = 0; j < 5; j++) {
                int col = wn + j * 8 + ((lane & 3) << 1);
                if (col < 64) {
                    size_t g0 = ((size_t)(b * T_ + t0 + row)) * D_ + h * DH_ + col;
                    store_pair_h(oh, ol, g0, acc[i][j][half * 2] * mult, acc[i][j][half * 2 + 1] * mult);
                }
            }
        }
    }
}

// ======== launch ========
extern "C" void kernel_launch(void* const* d_in, const int* in_sizes, int n_in,
                              void* d_out, int out_size)
{
    const float* x  = (const float*)d_in[0];
    const float* wq = (const float*)d_in[1];
    const float* wk = (const float*)d_in[2];
    const float* wv = (const float*)d_in[3];
    const float* wo = (const float*)d_in[4];
    const float* rf = (const float*)d_in[5];
    float* out = (float*)d_out;

    float* fb = nullptr; cudaGetSymbolAddress((void**)&fb, g_buf);
    bf16*  bb = nullptr; cudaGetSymbolAddress((void**)&bb, g_bf);

    float *QKp = fb + OFF_QK, *Vp = fb + OFF_V;
    float *SCQ = fb + OFF_SCQ, *SCK = fb + OFF_SCK;
    float *ALP = fb + OFF_AL, *BET = fb + OFF_BE, *SR = fb + OFF_SR;
    f16 *xh = (f16*)(bb + BO_XH), *xl = (f16*)(bb + BO_XL);
    f16 *wqkh = (f16*)(bb + BO_WQKH), *wqkl = (f16*)(bb + BO_WQKL);
    f16 *wv16 = (f16*)(bb + BO_WV), *wo16 = (f16*)(bb + BO_WO);
    f16 *rf16 = (f16*)(bb + BO_RF);
    f16 *Qfh = (f16*)(bb + BO_QFH), *Qfl = (f16*)(bb + BO_QFL);
    f16 *KfTh = (f16*)(bb + BO_KFTH), *KfTl = (f16*)(bb + BO_KFTL);
    f16 *VT = (f16*)(bb + BO_VT);
    f16 *KVT = (f16*)(bb + BO_KVT);
    f16 *ah = (f16*)(bb + BO_AH), *al = (f16*)(bb + BO_ALO);

    cudaFuncSetAttribute(gemm3, cudaFuncAttributeMaxDynamicSharedMemorySize, SMEM_G3);
    cudaFuncSetAttribute(gemm2t<0>, cudaFuncAttributeMaxDynamicSharedMemorySize, SMEM_G2);
    cudaFuncSetAttribute(gemm2t<1>, cudaFuncAttributeMaxDynamicSharedMemorySize, SMEM_G2);
    cudaFuncSetAttribute(phi_q_kernel, cudaFuncAttributeMaxDynamicSharedMemorySize, SMEM_PHI);
    cudaFuncSetAttribute(phi_k_kernel, cudaFuncAttributeMaxDynamicSharedMemorySize, SMEM_PHI);
    cudaFuncSetAttribute(kv_gemm, cudaFuncAttributeMaxDynamicSharedMemorySize, SMEM_KV);
    cudaFuncSetAttribute(qkv_gemm, cudaFuncAttributeMaxDynamicSharedMemorySize, SMEM_QKV);

    int wn4 = D_ * D_ / 4;
    split16_kernel<<<(int)(SZ_BTD / 4 / 256), 256>>>(x, xh, xl, (int)(SZ_BTD / 4));
    split16_kernel<<<wn4 / 256, 256>>>(wq, wqkh, wqkl, wn4);
    split16_kernel<<<wn4 / 256, 256>>>(wk, wqkh + (size_t)D_ * D_, wqkl + (size_t)D_ * D_, wn4);
    conv16_kernel<<<wn4 / 256, 256>>>(wv, wv16, wn4);
    conv16_kernel<<<wn4 / 256, 256>>>(wo, wo16, wn4);
    conv16_kernel<<<16, 256>>>(rf, rf16, 4096);

    // merged Q+K projection: [8192, 2048]
    gemm3<<<dim3(16, 64), 256, SMEM_G3>>>(xh, xl, wqkh, wqkl, QKp, B_ * T_, 2048, D_);
    gemm2t<0><<<dim3(8, 64), 256, SMEM_G2>>>(xh, xl, wv16, nullptr, Vp, B_ * T_, D_, D_);

    dim3 gPhi(T_ / 128, 2, BH_);
    phi_q_kernel<<<gPhi, 256, SMEM_PHI>>>(QKp, rf16, Qfh, Qfl, SCQ);
    knorm_kernel<<<dim3(T_ / 128, BH_), 256>>>(QKp, SCK);
    alphabeta_kernel<<<BH_, 256>>>(SCK, ALP, BET);
    phi_k_kernel<<<gPhi, 256, SMEM_PHI>>>(QKp, rf16, BET, KfTh, KfTl);
    vtrans_kernel<<<dim3(T_ / 64, BH_), 256>>>(Vp, VT);

    ksum_kernel<<<dim3(FD_ / 8, BH_), 256>>>(KfTh, KfTl, ALP, BET, KVT);
    zero_kvt_kernel<<<BH_, 256>>>(KVT);
    kv_gemm<<<dim3(FD_ / 128, BH_), 256, SMEM_KV>>>(KfTh, KfTl, VT, ALP, BET, KVT);
    srow_kernel<<<(B_ * T_) / 256, 256>>>(SCQ, ALP, SR);

    qkv_gemm<<<dim3(T_ / 128, BH_), 256, SMEM_QKV>>>(Qfh, Qfl, KVT, SCQ, ALP, SR, ah, al);

    gemm2t<1><<<dim3(8, 64), 256, SMEM_G2>>>(ah, al, wo16, SR, out, B_ * T_, D_, D_);
}

// round 12
// speedup vs baseline: 2.7603x; 1.0408x over previous
#include <cuda_runtime.h>
#include <cuda_bf16.h>
#include <cuda_fp16.h>
#include <cstdint>
typedef __nv_bfloat16 bf16;
typedef __half f16;

#define B_   2
#define T_   4096
#define D_   1024
#define H_   16
#define DH_  64
#define FD_  512
#define BH_  (B_*H_)
#define SZ_BTD ((size_t)B_*T_*D_)
#define SZ_F   ((size_t)BH_*T_*FD_)

// fp32 scratch
#define OFF_QK  ((size_t)0)                       // [8192, 2048]
#define OFF_SCQ (2*SZ_BTD)
#define OFF_SCK (OFF_SCQ + (size_t)BH_*T_)
#define OFF_AL  (OFF_SCK + (size_t)BH_*T_)
#define OFF_BE  (OFF_AL + BH_)
#define OFF_SR  (OFF_BE + BH_)
__device__ float g_buf[OFF_SR + (size_t)B_*T_];

// 2-byte scratch
#define BO_XH    ((size_t)0)
#define BO_XL    (SZ_BTD)
#define BO_WQKH  (2*SZ_BTD)
#define BO_WQKL  (BO_WQKH + 2*(size_t)D_*D_)
#define BO_WV    (BO_WQKL + 2*(size_t)D_*D_)
#define BO_WO    (BO_WV + (size_t)D_*D_)
#define BO_RF    (BO_WO + (size_t)D_*D_)
#define BO_QFH   (BO_RF + 16384)
#define BO_QFL   (BO_QFH + SZ_F)
#define BO_KFTH  (BO_QFL + SZ_F)
#define BO_KFTL  (BO_KFTH + SZ_F)
#define BO_VT    (BO_KFTL + SZ_F)                 // [bh][80][T] fp16; row64=ones
#define BO_KVT   (BO_VT + (size_t)BH_*80*T_)
#define BO_AH    (BO_KVT + (size_t)BH_*80*FD_)
#define BO_ALO   (BO_AH + SZ_BTD)
__device__ bf16 g_bf[BO_ALO + SZ_BTD];

__device__ __forceinline__ uint32_t smem_to_u32(const void* p) {
    uint32_t a;
    asm("{ .reg .u64 t; cvta.to.shared.u64 t, %1; cvt.u32.u64 %0, t; }" : "=r"(a) : "l"(p));
    return a;
}
#define SWZ(o) ((o) ^ (((o) >> 3) & 0x70))
__device__ __forceinline__ void cp_async16(uint32_t s, const void* g) {
    asm volatile("cp.async.cg.shared.global [%0], [%1], 16;" :: "r"(s), "l"(g));
}
__device__ __forceinline__ void cp_commit() { asm volatile("cp.async.commit_group;" ::: "memory"); }
template <int N> __device__ __forceinline__ void cp_wait() {
    asm volatile("cp.async.wait_group %0;" :: "n"(N) : "memory");
}
__device__ __forceinline__ void ldsm_x4(uint32_t& r0, uint32_t& r1, uint32_t& r2, uint32_t& r3, uint32_t a) {
    asm volatile("ldmatrix.sync.aligned.m8n8.x4.shared.b16 {%0,%1,%2,%3}, [%4];"
                 : "=r"(r0), "=r"(r1), "=r"(r2), "=r"(r3) : "r"(a));
}
__device__ __forceinline__ void ldsm_x2(uint32_t& r0, uint32_t& r1, uint32_t a) {
    asm volatile("ldmatrix.sync.aligned.m8n8.x2.shared.b16 {%0,%1}, [%2];"
                 : "=r"(r0), "=r"(r1) : "r"(a));
}
__device__ __forceinline__ void mma_f16(float* c, const uint32_t* a, const uint32_t* b) {
    asm volatile("mma.sync.aligned.m16n8k16.row.col.f32.f16.f16.f32 "
                 "{%0,%1,%2,%3}, {%4,%5,%6,%7}, {%8,%9}, {%0,%1,%2,%3};"
                 : "+f"(c[0]), "+f"(c[1]), "+f"(c[2]), "+f"(c[3])
                 : "r"(a[0]), "r"(a[1]), "r"(a[2]), "r"(a[3]), "r"(b[0]), "r"(b[1]));
}
__device__ __forceinline__ void store_pair_h(f16* ph, f16* pl, size_t off, float x0, float x1) {
    f16 h0 = __float2half_rn(x0), h1 = __float2half_rn(x1);
    __half2 hp = __halves2half2(h0, h1);
    *(uint32_t*)(ph + off) = *(uint32_t*)&hp;
    __half2 lp = __halves2half2(__float2half_rn(x0 - __half2float(h0)),
                                __float2half_rn(x1 - __half2float(h1)));
    *(uint32_t*)(pl + off) = *(uint32_t*)&lp;
}
__device__ __forceinline__ void fast_sincos(float x, float& s, float& c) {
    float kf = rintf(x * 0.63661977f);
    int q = (int)kf;
    float r = fmaf(kf, -1.5707963705062866f, x);
    r = fmaf(kf, 4.3711388286738e-8f, r);
    float r2 = r * r;
    float sp = fmaf(-1.98412698e-4f, r2, 8.33333333e-3f);
    sp = fmaf(sp, r2, -1.66666667e-1f) * r2;
    float sr = fmaf(sp, r, r);
    float cp = fmaf(2.48015873e-5f, r2, -1.38888889e-3f);
    cp = fmaf(cp, r2, 4.16666667e-2f);
    cp = fmaf(cp, r2, -0.5f);
    float cr = fmaf(cp, r2, 1.0f);
    if (q & 1) { float t = sr; sr = cr; cr = -t; }
    if (q & 2) { sr = -sr; cr = -cr; }
    s = sr; c = cr;
}

#define TILE_B 16384

// ======== fp16 3-pass GEMM: C = A(hi/lo) B(hi/lo)^T ========
#define BUF3   (4*TILE_B)
#define SMEM_G3 (2*BUF3)
__global__ void __launch_bounds__(256)
gemm3(const f16* __restrict__ Ah, const f16* __restrict__ Al,
      const f16* __restrict__ Bh, const f16* __restrict__ Bl,
      float* __restrict__ C, int M, int N, int K)
{
    extern __shared__ char smem[];
    const uint32_t sb = smem_to_u32(smem);
    const int tid = threadIdx.x, wid = tid >> 5, lane = tid & 31;
    const int bn = blockIdx.x << 7, bm = blockIdx.y << 7;
    const int wm = (wid >> 2) << 6, wn = (wid & 3) << 5;
    const int nchunk = K >> 6;
    const int lr = lane & 15, lc = lane >> 4, br = lane & 7, bk = (lane >> 3) & 1;
    float acc[4][4][4];
#pragma unroll
    for (int i = 0; i < 4; i++)
#pragma unroll
        for (int j = 0; j < 4; j++)
#pragma unroll
            for (int r = 0; r < 4; r++) acc[i][j][r] = 0.f;
    const f16* gs[4] = {Ah, Al, Bh, Bl};
    const int rb[4] = {bm, bm, bn, bn};
    auto load = [&](int kc, int buf) {
        uint32_t base = sb + buf * BUF3;
        int ke = kc << 6;
#pragma unroll
        for (int t = 0; t < 4; t++)
#pragma unroll
            for (int i = 0; i < 4; i++) {
                int idx = tid + (i << 8), r = idx >> 3, c = idx & 7;
                cp_async16(base + t * TILE_B + SWZ(r * 128 + c * 16),
                           gs[t] + (size_t)(rb[t] + r) * K + ke + c * 8);
            }
    };
    load(0, 0); cp_commit();
    for (int kc = 0; kc < nchunk; kc++) {
        int cur = kc & 1;
        if (kc + 1 < nchunk) { load(kc + 1, cur ^ 1); cp_commit(); cp_wait<1>(); }
        else cp_wait<0>();
        __syncthreads();
        uint32_t bA = sb + cur * BUF3;
#pragma unroll
        for (int ks = 0; ks < 4; ks++) {
            uint32_t a_h[4][4], a_l[4][4], b_h[4][2], b_l[4][2];
#pragma unroll
            for (int i = 0; i < 4; i++) {
                uint32_t o = SWZ((wm + i * 16 + lr) * 128 + ks * 32 + lc * 16);
                ldsm_x4(a_h[i][0], a_h[i][1], a_h[i][2], a_h[i][3], bA + o);
                ldsm_x4(a_l[i][0], a_l[i][1], a_l[i][2], a_l[i][3], bA + TILE_B + o);
            }
#pragma unroll
            for (int j = 0; j < 4; j++) {
                uint32_t o = SWZ((wn + j * 8 + br) * 128 + ks * 32 + bk * 16);
                ldsm_x2(b_h[j][0], b_h[j][1], bA + 2 * TILE_B + o);
                ldsm_x2(b_l[j][0], b_l[j][1], bA + 3 * TILE_B + o);
            }
#pragma unroll
            for (int i = 0; i < 4; i++)
#pragma unroll
                for (int j = 0; j < 4; j++) {
                    mma_f16(acc[i][j], a_h[i], b_h[j]);
                    mma_f16(acc[i][j], a_h[i], b_l[j]);
                    mma_f16(acc[i][j], a_l[i], b_h[j]);
                }
        }
        __syncthreads();
    }
#pragma unroll
    for (int i = 0; i < 4; i++) {
        int row = bm + wm + i * 16 + (lane >> 2);
#pragma unroll
        for (int j = 0; j < 4; j++) {
            int col = bn + wn + j * 8 + ((lane & 3) << 1);
            *(float2*)&C[(size_t)row * N + col]       = make_float2(acc[i][j][0], acc[i][j][1]);
            *(float2*)&C[(size_t)(row + 8) * N + col] = make_float2(acc[i][j][2], acc[i][j][3]);
        }
    }
}

// ======== fp16 2-pass GEMM core + two epilogues ========
#define BUF2   (3*TILE_B)
#define SMEM_G2 (2*BUF2)

// MODE 0: fp32 C, no scale (unused now)  MODE 1: fp32 C with row scale  MODE 2: VT fp16 transposed
template <int MODE>
__global__ void __launch_bounds__(256)
gemm2t(const f16* __restrict__ Ah, const f16* __restrict__ Al,
       const f16* __restrict__ Bm, const float* __restrict__ S,
       float* __restrict__ C, f16* __restrict__ VT, int M, int N, int K)
{
    extern __shared__ char smem[];
    const uint32_t sb = smem_to_u32(smem);
    const int tid = threadIdx.x, wid = tid >> 5, lane = tid & 31;
    const int bn = blockIdx.x << 7, bm = blockIdx.y << 7;
    const int wm = (wid >> 2) << 6, wn = (wid & 3) << 5;
    const int nchunk = K >> 6;
    const int lr = lane & 15, lc = lane >> 4, br = lane & 7, bk = (lane >> 3) & 1;
    float acc[4][4][4];
#pragma unroll
    for (int i = 0; i < 4; i++)
#pragma unroll
        for (int j = 0; j < 4; j++)
#pragma unroll
            for (int r = 0; r < 4; r++) acc[i][j][r] = 0.f;
    auto load = [&](int kc, int buf) {
        uint32_t base = sb + buf * BUF2;
        int ke = kc << 6;
#pragma unroll
        for (int i = 0; i < 4; i++) {
            int idx = tid + (i << 8), r = idx >> 3, c = idx & 7;
            uint32_t so = SWZ(r * 128 + c * 16);
            cp_async16(base + so,              Ah + (size_t)(bm + r) * K + ke + c * 8);
            cp_async16(base + TILE_B + so,     Al + (size_t)(bm + r) * K + ke + c * 8);
            cp_async16(base + 2 * TILE_B + so, Bm + (size_t)(bn + r) * K + ke + c * 8);
        }
    };
    load(0, 0); cp_commit();
    for (int kc = 0; kc < nchunk; kc++) {
        int cur = kc & 1;
        if (kc + 1 < nchunk) { load(kc + 1, cur ^ 1); cp_commit(); cp_wait<1>(); }
        else cp_wait<0>();
        __syncthreads();
        uint32_t bA = sb + cur * BUF2;
#pragma unroll
        for (int ks = 0; ks < 4; ks++) {
            uint32_t a_h[4][4], a_l[4][4], b_[4][2];
#pragma unroll
            for (int i = 0; i < 4; i++) {
                uint32_t o = SWZ((wm + i * 16 + lr) * 128 + ks * 32 + lc * 16);
                ldsm_x4(a_h[i][0], a_h[i][1], a_h[i][2], a_h[i][3], bA + o);
                ldsm_x4(a_l[i][0], a_l[i][1], a_l[i][2], a_l[i][3], bA + TILE_B + o);
            }
#pragma unroll
            for (int j = 0; j < 4; j++) {
                uint32_t o = SWZ((wn + j * 8 + br) * 128 + ks * 32 + bk * 16);
                ldsm_x2(b_[j][0], b_[j][1], bA + 2 * TILE_B + o);
            }
#pragma unroll
            for (int i = 0; i < 4; i++)
#pragma unroll
                for (int j = 0; j < 4; j++) {
                    mma_f16(acc[i][j], a_h[i], b_[j]);
                    mma_f16(acc[i][j], a_l[i], b_[j]);
                }
        }
        __syncthreads();
    }
    if (MODE == 2) {
        // stage fp32 [d_local 128][t_local 132] then write VT fp16 [bh][80][T]
        float* stage = (float*)smem;
#pragma unroll
        for (int i = 0; i < 4; i++) {
            int row = wm + i * 16 + (lane >> 2);
#pragma unroll
            for (int j = 0; j < 4; j++) {
                int col = wn + j * 8 + ((lane & 3) << 1);
                stage[col * 132 + row]           = acc[i][j][0];
                stage[(col + 1) * 132 + row]     = acc[i][j][1];
                stage[col * 132 + row + 8]       = acc[i][j][2];
                stage[(col + 1) * 132 + row + 8] = acc[i][j][3];
            }
        }
        __syncthreads();
        int b = bm >> 12;
        int dl = tid >> 1, ts = (tid & 1) << 6;
        int h = (bn + dl) >> 6, v = (bn + dl) & 63;
        size_t base = ((size_t)(b * H_ + h) * 80 + v) * T_ + (bm & 4095) + ts;
#pragma unroll
        for (int p = 0; p < 32; p++) {
            __half2 hp = __halves2half2(__float2half_rn(stage[dl * 132 + ts + p * 2]),
                                        __float2half_rn(stage[dl * 132 + ts + p * 2 + 1]));
            *(uint32_t*)&VT[base + p * 2] = *(uint32_t*)&hp;
        }
    } else {
#pragma unroll
        for (int i = 0; i < 4; i++) {
            int row = bm + wm + i * 16 + (lane >> 2);
            float s0 = (MODE == 1) ? S[row] : 1.f;
            float s1 = (MODE == 1) ? S[row + 8] : 1.f;
#pragma unroll
            for (int j = 0; j < 4; j++) {
                int col = bn + wn + j * 8 + ((lane & 3) << 1);
                *(float2*)&C[(size_t)row * N + col]       = make_float2(acc[i][j][0] * s0, acc[i][j][1] * s0);
                *(float2*)&C[(size_t)(row + 8) * N + col] = make_float2(acc[i][j][2] * s1, acc[i][j][3] * s1);
            }
        }
    }
}

// ======== conversions ========
__global__ void __launch_bounds__(256) split16_kernel(const float* __restrict__ in,
                                                      f16* __restrict__ hi, f16* __restrict__ lo, int n4)
{
    int i = blockIdx.x * 256 + threadIdx.x;
    if (i >= n4) return;
    float4 v = ((const float4*)in)[i];
    store_pair_h(hi, lo, (size_t)i * 4, v.x, v.y);
    store_pair_h(hi, lo, (size_t)i * 4 + 2, v.z, v.w);
}
__global__ void __launch_bounds__(256) conv16_kernel(const float* __restrict__ in,
                                                     f16* __restrict__ out, int n4)
{
    int i = blockIdx.x * 256 + threadIdx.x;
    if (i >= n4) return;
    float4 v = ((const float4*)in)[i];
    __half2 p0 = __halves2half2(__float2half_rn(v.x), __float2half_rn(v.y));
    __half2 p1 = __halves2half2(__float2half_rn(v.z), __float2half_rn(v.w));
    uint2 o; o.x = *(uint32_t*)&p0; o.y = *(uint32_t*)&p1;
    ((uint2*)out)[i] = o;
}

// ======== phi kernels ========
#define PA  0
#define PAL 16384
#define PB  32768
#define PSC 49152
#define PNP 49664
#define SMEM_PHI 50688

__device__ __forceinline__ void conv_tile_h(const float* g, int ld, char* sm, int dstH, int dstL,
                                            float* np, int tid) {
    int r = tid >> 1, cb = (tid & 1) << 5;
    float s = 0.f;
    const float* gp = g + (size_t)r * ld + cb;
#pragma unroll
    for (int k = 0; k < 8; k++) {
        float4 v = *(const float4*)(gp + k * 4);
        s = fmaf(v.x, v.x, s); s = fmaf(v.y, v.y, s);
        s = fmaf(v.z, v.z, s); s = fmaf(v.w, v.w, s);
        uint32_t sw = SWZ((uint32_t)(r * 128 + (cb + k * 4) * 2));
        f16 h0 = __float2half_rn(v.x), h1 = __float2half_rn(v.y);
        f16 h2 = __float2half_rn(v.z), h3 = __float2half_rn(v.w);
        __half2 hp0 = __halves2half2(h0, h1), hp1 = __halves2half2(h2, h3);
        *(uint32_t*)(sm + dstH + sw) = *(uint32_t*)&hp0;
        *(uint32_t*)(sm + dstH + sw + 4) = *(uint32_t*)&hp1;
        __half2 lp0 = __halves2half2(__float2half_rn(v.x - __half2float(h0)),
                                     __float2half_rn(v.y - __half2float(h1)));
        __half2 lp1 = __halves2half2(__float2half_rn(v.z - __half2float(h2)),
                                     __float2half_rn(v.w - __half2float(h3)));
        *(uint32_t*)(sm + dstL + sw) = *(uint32_t*)&lp0;
        *(uint32_t*)(sm + dstL + sw + 4) = *(uint32_t*)&lp1;
    }
    np[tid] = s;
}

__global__ void __launch_bounds__(256) phi_q_kernel(
    const float* __restrict__ QK, const f16* __restrict__ rf16,
    f16* __restrict__ Qfh, f16* __restrict__ Qfl, float* __restrict__ scq)
{
    extern __shared__ char sm[];
    const uint32_t sb = smem_to_u32(sm);
    const int tid = threadIdx.x, wid = tid >> 5, lane = tid & 31;
    const int t0 = blockIdx.x << 7, m0c = blockIdx.y << 7, bh = blockIdx.z;
    const int b = bh >> 4, h = bh & 15;
    float* np = (float*)(sm + PNP);
#pragma unroll
    for (int i = 0; i < 4; i++) {
        int idx = tid + (i << 8), r = idx >> 3, c = idx & 7;
        cp_async16(sb + PB + SWZ(r * 128 + c * 16), rf16 + (size_t)(m0c + r) * DH_ + c * 8);
    }
    cp_commit();
    conv_tile_h(&QK[((size_t)(b * T_ + t0)) * 2048 + h * DH_], 2048, sm, PA, PAL, np, tid);
    __syncthreads();
    if (tid < 128 && blockIdx.y == 0)
        scq[(size_t)bh * T_ + t0 + tid] = __expf(-0.5f * (np[2 * tid] + np[2 * tid + 1])) * 0.0625f;
    cp_wait<0>();
    __syncthreads();
    const int wt = (wid >> 2) << 6, wm = (wid & 3) << 5;
    const int lr = lane & 15, lc = lane >> 4, br = lane & 7, bk = (lane >> 3) & 1;
    float acc[4][4][4];
#pragma unroll
    for (int i = 0; i < 4; i++)
#pragma unroll
        for (int j = 0; j < 4; j++)
#pragma unroll
            for (int r = 0; r < 4; r++) acc[i][j][r] = 0.f;
#pragma unroll
    for (int ks = 0; ks < 4; ks++) {
        uint32_t a_h[4][4], a_l[4][4], b_[4][2];
#pragma unroll
        for (int i = 0; i < 4; i++) {
            uint32_t o = SWZ((wt + i * 16 + lr) * 128 + ks * 32 + lc * 16);
            ldsm_x4(a_h[i][0], a_h[i][1], a_h[i][2], a_h[i][3], sb + PA + o);
            ldsm_x4(a_l[i][0], a_l[i][1], a_l[i][2], a_l[i][3], sb + PAL + o);
        }
#pragma unroll
        for (int j = 0; j < 4; j++) {
            uint32_t o = SWZ((wm + j * 8 + br) * 128 + ks * 32 + bk * 16);
            ldsm_x2(b_[j][0], b_[j][1], sb + PB + o);
        }
#pragma unroll
        for (int i = 0; i < 4; i++)
#pragma unroll
            for (int j = 0; j < 4; j++) {
                mma_f16(acc[i][j], a_h[i], b_[j]);
                mma_f16(acc[i][j], a_l[i], b_[j]);
            }
    }
#pragma unroll
    for (int i = 0; i < 4; i++) {
        int r0 = wt + i * 16 + (lane >> 2);
        size_t rb0 = ((size_t)bh * T_ + t0 + r0) * FD_ + m0c;
        size_t rb1 = rb0 + (size_t)8 * FD_;
#pragma unroll
        for (int j = 0; j < 4; j++) {
            int mc = wm + j * 8 + ((lane & 3) << 1);
            float sn0, cs0, sn1, cs1;
            fast_sincos(acc[i][j][0], sn0, cs0);
            fast_sincos(acc[i][j][1], sn1, cs1);
            store_pair_h(Qfh, Qfl, rb0 + mc, cs0, cs1);
            store_pair_h(Qfh, Qfl, rb0 + 256 + mc, sn0, sn1);
            fast_sincos(acc[i][j][2], sn0, cs0);
            fast_sincos(acc[i][j][3], sn1, cs1);
            store_pair_h(Qfh, Qfl, rb1 + mc, cs0, cs1);
            store_pair_h(Qfh, Qfl, rb1 + 256 + mc, sn0, sn1);
        }
    }
}

__global__ void __launch_bounds__(256) phi_k_kernel(
    const float* __restrict__ QK, const f16* __restrict__ rf16,
    const float* __restrict__ beta,
    f16* __restrict__ KfTh, f16* __restrict__ KfTl)
{
    extern __shared__ char sm[];
    const uint32_t sb = smem_to_u32(sm);
    const int tid = threadIdx.x, wid = tid >> 5, lane = tid & 31;
    const int t0 = blockIdx.x << 7, m0c = blockIdx.y << 7, bh = blockIdx.z;
    const int b = bh >> 4, h = bh & 15;
    float* scale = (float*)(sm + PSC);
    float* np = (float*)(sm + PNP);
    const float gamma = 1.f / beta[bh];
#pragma unroll
    for (int i = 0; i < 4; i++) {
        int idx = tid + (i << 8), r = idx >> 3, c = idx & 7;
        cp_async16(sb + PA + SWZ(r * 128 + c * 16), rf16 + (size_t)(m0c + r) * DH_ + c * 8);
    }
    cp_commit();
    conv_tile_h(&QK[((size_t)(b * T_ + t0)) * 2048 + 1024 + h * DH_], 2048, sm, PAL, PB, np, tid);
    __syncthreads();
    if (tid < 128)
        scale[tid] = __expf(-0.5f * (np[2 * tid] + np[2 * tid + 1])) * 0.0625f * gamma;
    cp_wait<0>();
    __syncthreads();
    const int wm = (wid >> 2) << 6, wt = (wid & 3) << 5;
    const int lr = lane & 15, lc = lane >> 4, br = lane & 7, bk = (lane >> 3) & 1;
    float acc[4][4][4];
#pragma unroll
    for (int i = 0; i < 4; i++)
#pragma unroll
        for (int j = 0; j < 4; j++)
#pragma unroll
            for (int r = 0; r < 4; r++) acc[i][j][r] = 0.f;
#pragma unroll
    for (int ks = 0; ks < 4; ks++) {
        uint32_t a_[4][4], b_h[4][2], b_l[4][2];
#pragma unroll
        for (int i = 0; i < 4; i++) {
            uint32_t o = SWZ((wm + i * 16 + lr) * 128 + ks * 32 + lc * 16);
            ldsm_x4(a_[i][0], a_[i][1], a_[i][2], a_[i][3], sb + PA + o);
        }
#pragma unroll
        for (int j = 0; j < 4; j++) {
            uint32_t o = SWZ((wt + j * 8 + br) * 128 + ks * 32 + bk * 16);
            ldsm_x2(b_h[j][0], b_h[j][1], sb + PAL + o);
            ldsm_x2(b_l[j][0], b_l[j][1], sb + PB + o);
        }
#pragma unroll
        for (int i = 0; i < 4; i++)
#pragma unroll
            for (int j = 0; j < 4; j++) {
                mma_f16(acc[i][j], a_[i], b_h[j]);
                mma_f16(acc[i][j], a_[i], b_l[j]);
            }
    }
#pragma unroll
    for (int i = 0; i < 4; i++) {
        int r0 = wm + i * 16 + (lane >> 2);
        size_t rc0 = ((size_t)bh * FD_ + m0c + r0) * T_ + t0;
        size_t rs0 = rc0 + (size_t)256 * T_;
        size_t rc1 = rc0 + (size_t)8 * T_, rs1 = rs0 + (size_t)8 * T_;
#pragma unroll
        for (int j = 0; j < 4; j++) {
            int tc = wt + j * 8 + ((lane & 3) << 1);
            float sc0 = scale[tc], sc1 = scale[tc + 1];
            float sn0, cs0, sn1, cs1;
            fast_sincos(acc[i][j][0], sn0, cs0);
            fast_sincos(acc[i][j][1], sn1, cs1);
            store_pair_h(KfTh, KfTl, rc0 + tc, cs0 * sc0, cs1 * sc1);
            store_pair_h(KfTh, KfTl, rs0 + tc, sn0 * sc0, sn1 * sc1);
            fast_sincos(acc[i][j][2], sn0, cs0);
            fast_sincos(acc[i][j][3], sn1, cs1);
            store_pair_h(KfTh, KfTl, rc1 + tc, cs0 * sc0, cs1 * sc1);
            store_pair_h(KfTh, KfTl, rs1 + tc, sn0 * sc0, sn1 * sc1);
        }
    }
}

// ======== knorm / alphabeta / srow / vt_ones / zero_kvt ========
__global__ void __launch_bounds__(256) knorm_kernel(const float* __restrict__ QK,
                                                    float* __restrict__ sck)
{
    __shared__ float np[256];
    const int tid = threadIdx.x;
    const int t0 = blockIdx.x << 7, bh = blockIdx.y;
    const int b = bh >> 4, h = bh & 15;
    int r = tid >> 1, cb = (tid & 1) << 5;
    const float* gp = QK + ((size_t)(b * T_ + t0 + r)) * 2048 + 1024 + h * DH_ + cb;
    float s = 0.f;
#pragma unroll
    for (int k = 0; k < 8; k++) {
        float4 v = *(const float4*)(gp + k * 4);
        s = fmaf(v.x, v.x, s); s = fmaf(v.y, v.y, s);
        s = fmaf(v.z, v.z, s); s = fmaf(v.w, v.w, s);
    }
    np[tid] = s;
    __syncthreads();
    if (tid < 128)
        sck[(size_t)bh * T_ + t0 + tid] = __expf(-0.5f * (np[2 * tid] + np[2 * tid + 1])) * 0.0625f;
}

__global__ void __launch_bounds__(256) alphabeta_kernel(const float* __restrict__ sck,
                                                        float* __restrict__ alpha,
                                                        float* __restrict__ beta)
{
    __shared__ float rs[256], rm[256];
    const int bh = blockIdx.x, tid = threadIdx.x;
    float s = 0.f, m = 0.f;
    for (int i = tid; i < T_; i += 256) {
        float v = sck[(size_t)bh * T_ + i];
        s += v; m = fmaxf(m, v);
    }
    rs[tid] = s; rm[tid] = m;
    __syncthreads();
    for (int o = 128; o; o >>= 1) {
        if (tid < o) { rs[tid] += rs[tid + o]; rm[tid] = fmaxf(rm[tid], rm[tid + o]); }
        __syncthreads();
    }
    if (tid == 0) {
        alpha[bh] = 1.f / fmaxf(rs[0], 1e-30f);
        beta[bh]  = fmaxf(rm[0], 1e-37f);
    }
}

__global__ void __launch_bounds__(256) srow_kernel(const float* __restrict__ scq,
                                                   const float* __restrict__ alpha,
                                                   float* __restrict__ srow)
{
    int row = blockIdx.x * 256 + threadIdx.x;
    int b = row >> 12, t = row & 4095;
    float m = 0.f;
#pragma unroll
    for (int h = 0; h < H_; h++) {
        int bh = b * H_ + h;
        m = fmaxf(m, scq[(size_t)bh * T_ + t] / alpha[bh]);
    }
    srow[row] = fmaxf(m * 1e6f, 1e-30f);
}

// fill VT row 64 with ones, rows 65-71 with zeros (B operand rows for kv ksum trick)
__global__ void __launch_bounds__(256) vt_ones_kernel(f16* __restrict__ VT)
{
    const int bh = blockIdx.x;
    const f16 one = __float2half_rn(1.f), zero = __float2half_rn(0.f);
    for (int i = threadIdx.x; i < 8 * T_; i += 256) {
        int r = i >> 12, t = i & 4095;   // r 0..7 -> rows 64..71
        VT[((size_t)bh * 80 + 64 + r) * T_ + t] = (r == 0) ? one : zero;
    }
}

__global__ void __launch_bounds__(256) zero_kvt_kernel(f16* __restrict__ kvt)
{
    const int bh = blockIdx.x;
    for (int i = threadIdx.x; i < 15 * FD_; i += 256)
        kvt[((size_t)bh * 80 + 65) * FD_ + i] = __float2half_rn(0.f);
}

// ======== kv: KfT'(fp16 h/l) x VT(fp16, 72 rows incl. ones row)^T, fused Ksum ========
#define KA   0
#define KAL  16384
#define KB   32768
#define KBUF 43008          // 16K + 16K + 80*128B (only 72 loaded)
#define SMEM_KV (2*KBUF)

__global__ void __launch_bounds__(256) kv_gemm(
    const f16* __restrict__ Ah, const f16* __restrict__ Al,
    const f16* __restrict__ Bm,
    const float* __restrict__ alpha, const float* __restrict__ beta,
    f16* __restrict__ kvt)
{
    extern __shared__ char sm[];
    const uint32_t sb = smem_to_u32(sm);
    const int tid = threadIdx.x, wid = tid >> 5, lane = tid & 31;
    const int m0 = blockIdx.x << 7, bh = blockIdx.y;
    const size_t ab = (size_t)bh * FD_ + m0, bb = (size_t)bh * 80;
    const int wm = (wid >> 1) << 5, wn = (wid & 1) * 40;
    const int lr = lane & 15, lc = lane >> 4, br = lane & 7, bk = (lane >> 3) & 1;
    float acc[2][5][4];
#pragma unroll
    for (int i = 0; i < 2; i++)
#pragma unroll
        for (int j = 0; j < 5; j++)
#pragma unroll
            for (int r = 0; r < 4; r++) acc[i][j][r] = 0.f;
    auto load = [&](int kc, int buf) {
        uint32_t base = sb + buf * KBUF;
        int ke = kc << 6;
#pragma unroll
        for (int i = 0; i < 4; i++) {
            int idx = tid + (i << 8), r = idx >> 3, c = idx & 7;
            uint32_t so = SWZ(r * 128 + c * 16);
            size_t g = (ab + r) * T_ + ke + c * 8;
            cp_async16(base + KA + so, Ah + g);
            cp_async16(base + KAL + so, Al + g);
        }
#pragma unroll
        for (int i = 0; i < 3; i++) {
            int idx = tid + (i << 8);
            if (idx < 576) {                 // 72 rows x 8 chunks
                int r = idx >> 3, c = idx & 7;
                cp_async16(base + KB + SWZ(r * 128 + c * 16), Bm + (bb + r) * T_ + ke + c * 8);
            }
        }
    };
    load(0, 0); cp_commit();
    for (int kc = 0; kc < T_ / 64; kc++) {
        int cur = kc & 1;
        if (kc + 1 < T_ / 64) { load(kc + 1, cur ^ 1); cp_commit(); cp_wait<1>(); }
        else cp_wait<0>();
        __syncthreads();
        uint32_t bA = sb + cur * KBUF;
#pragma unroll
        for (int ks = 0; ks < 4; ks++) {
            uint32_t a_h[2][4], a_l[2][4], b_[5][2];
#pragma unroll
            for (int i = 0; i < 2; i++) {
                uint32_t o = SWZ((wm + i * 16 + lr) * 128 + ks * 32 + lc * 16);
                ldsm_x4(a_h[i][0], a_h[i][1], a_h[i][2], a_h[i][3], bA + KA + o);
                ldsm_x4(a_l[i][0], a_l[i][1], a_l[i][2], a_l[i][3], bA + KAL + o);
            }
#pragma unroll
            for (int j = 0; j < 5; j++) {
                uint32_t o = SWZ((wn + j * 8 + br) * 128 + ks * 32 + bk * 16);
                ldsm_x2(b_[j][0], b_[j][1], bA + KB + o);
            }
#pragma unroll
            for (int i = 0; i < 2; i++)
#pragma unroll
                for (int j = 0; j < 5; j++) {
                    mma_f16(acc[i][j], a_h[i], b_[j]);
                    mma_f16(acc[i][j], a_l[i], b_[j]);
                }
        }
        __syncthreads();
    }
    // stage cols 0..79 (only 0..64 stored) then write kvt rows 0..64
    float* stage = (float*)sm;
#pragma unroll
    for (int i = 0; i < 2; i++) {
        int row = wm + i * 16 + (lane >> 2);
#pragma unroll
        for (int j = 0; j < 5; j++) {
            int col = wn + j * 8 + ((lane & 3) << 1);
            stage[col * 132 + row]           = acc[i][j][0];
            stage[(col + 1) * 132 + row]     = acc[i][j][1];
            stage[col * 132 + row + 8]       = acc[i][j][2];
            stage[(col + 1) * 132 + row + 8] = acc[i][j][3];
        }
    }
    __syncthreads();
    float av = alpha[bh] * beta[bh];
    int v = tid >> 2, fs = (tid & 3) << 5;
#pragma unroll
    for (int p = 0; p < 16; p++) {
        int f = fs + p * 2;
        __half2 hp = __halves2half2(__float2half_rn(stage[v * 132 + f] * av),
                                    __float2half_rn(stage[v * 132 + f + 1] * av));
        *(uint32_t*)&kvt[((size_t)bh * 80 + v) * FD_ + m0 + f] = *(uint32_t*)&hp;
    }
    if (tid < 64) {
        int f = tid * 2;
        __half2 hp = __halves2half2(__float2half_rn(stage[64 * 132 + f] * av),
                                    __float2half_rn(stage[64 * 132 + f + 1] * av));
        *(uint32_t*)&kvt[((size_t)bh * 80 + 64) * FD_ + m0 + f] = *(uint32_t*)&hp;
    }
}

// ======== qkv: Qf^ x KVT'[80], 2-pass; epilogue Z + scales ========
#define QA   0
#define QAL  16384
#define QB   32768
#define QBUF 43008
#define SMEM_QKV (2*QBUF)

__global__ void __launch_bounds__(256) qkv_gemm(
    const f16* __restrict__ Ah, const f16* __restrict__ Al,
    const f16* __restrict__ Bm, const float* __restrict__ scq,
    const float* __restrict__ alpha, const float* __restrict__ srow,
    f16* __restrict__ oh, f16* __restrict__ ol)
{
    extern __shared__ char sm[];
    __shared__ float zsm[128];
    const uint32_t sb = smem_to_u32(sm);
    const int tid = threadIdx.x, wid = tid >> 5, lane = tid & 31;
    const int t0 = blockIdx.x << 7, bh = blockIdx.y;
    const int b = bh >> 4, h = bh & 15;
    const size_t ab = (size_t)bh * T_ + t0, bb = (size_t)bh * 80;
    const int wm = (wid >> 1) << 5, wn = (wid & 1) * 40;
    const int lr = lane & 15, lc = lane >> 4, br = lane & 7, bk = (lane >> 3) & 1;
    float acc[2][5][4];
#pragma unroll
    for (int i = 0; i < 2; i++)
#pragma unroll
        for (int j = 0; j < 5; j++)
#pragma unroll
            for (int r = 0; r < 4; r++) acc[i][j][r] = 0.f;
    auto load = [&](int kc, int buf) {
        uint32_t base = sb + buf * QBUF;
        int ke = kc << 6;
#pragma unroll
        for (int i = 0; i < 4; i++) {
            int idx = tid + (i << 8), r = idx >> 3, c = idx & 7;
            uint32_t so = SWZ(r * 128 + c * 16);
            size_t g = (ab + r) * FD_ + ke + c * 8;
            cp_async16(base + QA + so, Ah + g);
            cp_async16(base + QAL + so, Al + g);
        }
#pragma unroll
        for (int i = 0; i < 3; i++) {
            int idx = tid + (i << 8);
            if (idx < 640) {
                int r = idx >> 3, c = idx & 7;
                cp_async16(base + QB + SWZ(r * 128 + c * 16), Bm + (bb + r) * FD_ + ke + c * 8);
            }
        }
    };
    load(0, 0); cp_commit();
    for (int kc = 0; kc < 8; kc++) {
        int cur = kc & 1;
        if (kc + 1 < 8) { load(kc + 1, cur ^ 1); cp_commit(); cp_wait<1>(); }
        else cp_wait<0>();
        __syncthreads();
        uint32_t bA = sb + cur * QBUF;
#pragma unroll
        for (int ks = 0; ks < 4; ks++) {
            uint32_t a_h[2][4], a_l[2][4], b_[5][2];
#pragma unroll
            for (int i = 0; i < 2; i++) {
                uint32_t o = SWZ((wm + i * 16 + lr) * 128 + ks * 32 + lc * 16);
                ldsm_x4(a_h[i][0], a_h[i][1], a_h[i][2], a_h[i][3], bA + QA + o);
                ldsm_x4(a_l[i][0], a_l[i][1], a_l[i][2], a_l[i][3], bA + QAL + o);
            }
#pragma unroll
            for (int j = 0; j < 5; j++) {
                uint32_t o = SWZ((wn + j * 8 + br) * 128 + ks * 32 + bk * 16);
                ldsm_x2(b_[j][0], b_[j][1], bA + QB + o);
            }
#pragma unroll
            for (int i = 0; i < 2; i++)
#pragma unroll
                for (int j = 0; j < 5; j++) {
                    mma_f16(acc[i][j], a_h[i], b_[j]);
                    mma_f16(acc[i][j], a_l[i], b_[j]);
                }
        }
        __syncthreads();
    }
    if (wn == 40 && (lane & 3) == 0) {
#pragma unroll
        for (int i = 0; i < 2; i++) {
            int row = wm + i * 16 + (lane >> 2);
            zsm[row] = acc[i][3][0];
            zsm[row + 8] = acc[i][3][2];
        }
    }
    __syncthreads();
    float av = alpha[bh];
#pragma unroll
    for (int i = 0; i < 2; i++) {
#pragma unroll
        for (int half = 0; half < 2; half++) {
            int row = wm + i * 16 + (lane >> 2) + half * 8;
            float sq = scq[ab + row];
            float Zt = sq * zsm[row] / av;
            float d = fmaxf(Zt, 1e-6f);
            float mult = sq / (av * d * srow[(size_t)b * T_ + t0 + row]);
#pragma unroll
            for (int j = 0; j < 5; j++) {
                int col = wn + j * 8 + ((lane & 3) << 1);
                if (col < 64) {
                    size_t g0 = ((size_t)(b * T_ + t0 + row)) * D_ + h * DH_ + col;
                    store_pair_h(oh, ol, g0, acc[i][j][half * 2] * mult, acc[i][j][half * 2 + 1] * mult);
                }
            }
        }
    }
}

// ======== launch ========
extern "C" void kernel_launch(void* const* d_in, const int* in_sizes, int n_in,
                              void* d_out, int out_size)
{
    const float* x  = (const float*)d_in[0];
    const float* wq = (const float*)d_in[1];
    const float* wk = (const float*)d_in[2];
    const float* wv = (const float*)d_in[3];
    const float* wo = (const float*)d_in[4];
    const float* rf = (const float*)d_in[5];
    float* out = (float*)d_out;

    float* fb = nullptr; cudaGetSymbolAddress((void**)&fb, g_buf);
    bf16*  bb = nullptr; cudaGetSymbolAddress((void**)&bb, g_bf);

    float *QKp = fb + OFF_QK;
    float *SCQ = fb + OFF_SCQ, *SCK = fb + OFF_SCK;
    float *ALP = fb + OFF_AL, *BET = fb + OFF_BE, *SR = fb + OFF_SR;
    f16 *xh = (f16*)(bb + BO_XH), *xl = (f16*)(bb + BO_XL);
    f16 *wqkh = (f16*)(bb + BO_WQKH), *wqkl = (f16*)(bb + BO_WQKL);
    f16 *wv16 = (f16*)(bb + BO_WV), *wo16 = (f16*)(bb + BO_WO);
    f16 *rf16 = (f16*)(bb + BO_RF);
    f16 *Qfh = (f16*)(bb + BO_QFH), *Qfl = (f16*)(bb + BO_QFL);
    f16 *KfTh = (f16*)(bb + BO_KFTH), *KfTl = (f16*)(bb + BO_KFTL);
    f16 *VT = (f16*)(bb + BO_VT);
    f16 *KVT = (f16*)(bb + BO_KVT);
    f16 *ah = (f16*)(bb + BO_AH), *al = (f16*)(bb + BO_ALO);

    cudaFuncSetAttribute(gemm3, cudaFuncAttributeMaxDynamicSharedMemorySize, SMEM_G3);
    cudaFuncSetAttribute(gemm2t<1>, cudaFuncAttributeMaxDynamicSharedMemorySize, SMEM_G2);
    cudaFuncSetAttribute(gemm2t<2>, cudaFuncAttributeMaxDynamicSharedMemorySize, SMEM_G2);
    cudaFuncSetAttribute(phi_q_kernel, cudaFuncAttributeMaxDynamicSharedMemorySize, SMEM_PHI);
    cudaFuncSetAttribute(phi_k_kernel, cudaFuncAttributeMaxDynamicSharedMemorySize, SMEM_PHI);
    cudaFuncSetAttribute(kv_gemm, cudaFuncAttributeMaxDynamicSharedMemorySize, SMEM_KV);
    cudaFuncSetAttribute(qkv_gemm, cudaFuncAttributeMaxDynamicSharedMemorySize, SMEM_QKV);

    int wn4 = D_ * D_ / 4;
    split16_kernel<<<(int)(SZ_BTD / 4 / 256), 256>>>(x, xh, xl, (int)(SZ_BTD / 4));
    split16_kernel<<<wn4 / 256, 256>>>(wq, wqkh, wqkl, wn4);
    split16_kernel<<<wn4 / 256, 256>>>(wk, wqkh + (size_t)D_ * D_, wqkl + (size_t)D_ * D_, wn4);
    conv16_kernel<<<wn4 / 256, 256>>>(wv, wv16, wn4);
    conv16_kernel<<<wn4 / 256, 256>>>(wo, wo16, wn4);
    conv16_kernel<<<16, 256>>>(rf, rf16, 4096);

    // merged Q+K projection: [8192, 2048]
    gemm3<<<dim3(16, 64), 256, SMEM_G3>>>(xh, xl, wqkh, wqkl, QKp, B_ * T_, 2048, D_);
    // V projection with fused transpose -> VT fp16 [bh][80][T]
    gemm2t<2><<<dim3(8, 64), 256, SMEM_G2>>>(xh, xl, wv16, nullptr, nullptr, VT, B_ * T_, D_, D_);
    vt_ones_kernel<<<BH_, 256>>>(VT);

    dim3 gPhi(T_ / 128, 2, BH_);
    phi_q_kernel<<<gPhi, 256, SMEM_PHI>>>(QKp, rf16, Qfh, Qfl, SCQ);
    knorm_kernel<<<dim3(T_ / 128, BH_), 256>>>(QKp, SCK);
    alphabeta_kernel<<<BH_, 256>>>(SCK, ALP, BET);
    phi_k_kernel<<<gPhi, 256, SMEM_PHI>>>(QKp, rf16, BET, KfTh, KfTl);

    zero_kvt_kernel<<<BH_, 256>>>(KVT);
    kv_gemm<<<dim3(FD_ / 128, BH_), 256, SMEM_KV>>>(KfTh, KfTl, VT, ALP, BET, KVT);
    srow_kernel<<<(B_ * T_) / 256, 256>>>(SCQ, ALP, SR);

    qkv_gemm<<<dim3(T_ / 128, BH_), 256, SMEM_QKV>>>(Qfh, Qfl, KVT, SCQ, ALP, SR, ah, al);

    gemm2t<1><<<dim3(8, 64), 256, SMEM_G2>>>(ah, al, wo16, SR, out, nullptr, B_ * T_, D_, D_);
}

// round 13
// speedup vs baseline: 3.1356x; 1.1360x over previous
#include <cuda_runtime.h>
#include <cuda_bf16.h>
#include <cuda_fp16.h>
#include <cstdint>
typedef __nv_bfloat16 bf16;
typedef __half f16;

#define B_   2
#define T_   4096
#define D_   1024
#define H_   16
#define DH_  64
#define FD_  512
#define BH_  (B_*H_)
#define SZ_BTD ((size_t)B_*T_*D_)
#define SZ_F   ((size_t)BH_*T_*FD_)

// fp32 scratch
#define OFF_QK  ((size_t)0)
#define OFF_SCQ (2*SZ_BTD)
#define OFF_SCK (OFF_SCQ + (size_t)BH_*T_)
#define OFF_AL  (OFF_SCK + (size_t)BH_*T_)
#define OFF_BE  (OFF_AL + BH_)
#define OFF_SR  (OFF_BE + BH_)
__device__ float g_buf[OFF_SR + (size_t)B_*T_];

// 2-byte scratch
#define BO_XH    ((size_t)0)
#define BO_XL    (SZ_BTD)
#define BO_WQKH  (2*SZ_BTD)
#define BO_WQKL  (BO_WQKH + 2*(size_t)D_*D_)
#define BO_WV    (BO_WQKL + 2*(size_t)D_*D_)
#define BO_WO    (BO_WV + (size_t)D_*D_)
#define BO_RF    (BO_WO + (size_t)D_*D_)
#define BO_QFH   (BO_RF + 16384)
#define BO_QFL   (BO_QFH + SZ_F)
#define BO_KFT   (BO_QFL + SZ_F)
#define BO_VT    (BO_KFT + SZ_F)                  // [bh][80][T] fp16; row64=ones
#define BO_KVT   (BO_VT + (size_t)BH_*80*T_)
#define BO_AH    (BO_KVT + (size_t)BH_*80*FD_)
__device__ bf16 g_bf[BO_AH + SZ_BTD];

__device__ __forceinline__ uint32_t smem_to_u32(const void* p) {
    uint32_t a;
    asm("{ .reg .u64 t; cvta.to.shared.u64 t, %1; cvt.u32.u64 %0, t; }" : "=r"(a) : "l"(p));
    return a;
}
#define SWZ(o) ((o) ^ (((o) >> 3) & 0x70))
__device__ __forceinline__ void cp_async16(uint32_t s, const void* g) {
    asm volatile("cp.async.cg.shared.global [%0], [%1], 16;" :: "r"(s), "l"(g));
}
__device__ __forceinline__ void cp_commit() { asm volatile("cp.async.commit_group;" ::: "memory"); }
template <int N> __device__ __forceinline__ void cp_wait() {
    asm volatile("cp.async.wait_group %0;" :: "n"(N) : "memory");
}
__device__ __forceinline__ void ldsm_x4(uint32_t& r0, uint32_t& r1, uint32_t& r2, uint32_t& r3, uint32_t a) {
    asm volatile("ldmatrix.sync.aligned.m8n8.x4.shared.b16 {%0,%1,%2,%3}, [%4];"
                 : "=r"(r0), "=r"(r1), "=r"(r2), "=r"(r3) : "r"(a));
}
__device__ __forceinline__ void ldsm_x2(uint32_t& r0, uint32_t& r1, uint32_t a) {
    asm volatile("ldmatrix.sync.aligned.m8n8.x2.shared.b16 {%0,%1}, [%2];"
                 : "=r"(r0), "=r"(r1) : "r"(a));
}
__device__ __forceinline__ void mma_f16(float* c, const uint32_t* a, const uint32_t* b) {
    asm volatile("mma.sync.aligned.m16n8k16.row.col.f32.f16.f16.f32 "
                 "{%0,%1,%2,%3}, {%4,%5,%6,%7}, {%8,%9}, {%0,%1,%2,%3};"
                 : "+f"(c[0]), "+f"(c[1]), "+f"(c[2]), "+f"(c[3])
                 : "r"(a[0]), "r"(a[1]), "r"(a[2]), "r"(a[3]), "r"(b[0]), "r"(b[1]));
}
__device__ __forceinline__ void store_pair_h(f16* ph, f16* pl, size_t off, float x0, float x1) {
    f16 h0 = __float2half_rn(x0), h1 = __float2half_rn(x1);
    __half2 hp = __halves2half2(h0, h1);
    *(uint32_t*)(ph + off) = *(uint32_t*)&hp;
    __half2 lp = __halves2half2(__float2half_rn(x0 - __half2float(h0)),
                                __float2half_rn(x1 - __half2float(h1)));
    *(uint32_t*)(pl + off) = *(uint32_t*)&lp;
}
__device__ __forceinline__ void store_h2(f16* p, size_t off, float x0, float x1) {
    __half2 hp = __halves2half2(__float2half_rn(x0), __float2half_rn(x1));
    *(uint32_t*)(p + off) = *(uint32_t*)&hp;
}
__device__ __forceinline__ void fast_sincos(float x, float& s, float& c) {
    float kf = rintf(x * 0.63661977f);
    int q = (int)kf;
    float r = fmaf(kf, -1.5707963705062866f, x);
    r = fmaf(kf, 4.3711388286738e-8f, r);
    float r2 = r * r;
    float sp = fmaf(-1.98412698e-4f, r2, 8.33333333e-3f);
    sp = fmaf(sp, r2, -1.66666667e-1f) * r2;
    float sr = fmaf(sp, r, r);
    float cp = fmaf(2.48015873e-5f, r2, -1.38888889e-3f);
    cp = fmaf(cp, r2, 4.16666667e-2f);
    cp = fmaf(cp, r2, -0.5f);
    float cr = fmaf(cp, r2, 1.0f);
    if (q & 1) { float t = sr; sr = cr; cr = -t; }
    if (q & 2) { sr = -sr; cr = -cr; }
    s = sr; c = cr;
}

#define TILE_B 16384

// ======== fp16 3-pass GEMM (QK projection) ========
#define BUF3   (4*TILE_B)
#define SMEM_G3 (2*BUF3)
__global__ void __launch_bounds__(256)
gemm3(const f16* __restrict__ Ah, const f16* __restrict__ Al,
      const f16* __restrict__ Bh, const f16* __restrict__ Bl,
      float* __restrict__ C, int M, int N, int K)
{
    extern __shared__ char smem[];
    const uint32_t sb = smem_to_u32(smem);
    const int tid = threadIdx.x, wid = tid >> 5, lane = tid & 31;
    const int bn = blockIdx.x << 7, bm = blockIdx.y << 7;
    const int wm = (wid >> 2) << 6, wn = (wid & 3) << 5;
    const int nchunk = K >> 6;
    const int lr = lane & 15, lc = lane >> 4, br = lane & 7, bk = (lane >> 3) & 1;
    float acc[4][4][4];
#pragma unroll
    for (int i = 0; i < 4; i++)
#pragma unroll
        for (int j = 0; j < 4; j++)
#pragma unroll
            for (int r = 0; r < 4; r++) acc[i][j][r] = 0.f;
    const f16* gs[4] = {Ah, Al, Bh, Bl};
    const int rb[4] = {bm, bm, bn, bn};
    auto load = [&](int kc, int buf) {
        uint32_t base = sb + buf * BUF3;
        int ke = kc << 6;
#pragma unroll
        for (int t = 0; t < 4; t++)
#pragma unroll
            for (int i = 0; i < 4; i++) {
                int idx = tid + (i << 8), r = idx >> 3, c = idx & 7;
                cp_async16(base + t * TILE_B + SWZ(r * 128 + c * 16),
                           gs[t] + (size_t)(rb[t] + r) * K + ke + c * 8);
            }
    };
    load(0, 0); cp_commit();
    for (int kc = 0; kc < nchunk; kc++) {
        int cur = kc & 1;
        if (kc + 1 < nchunk) { load(kc + 1, cur ^ 1); cp_commit(); cp_wait<1>(); }
        else cp_wait<0>();
        __syncthreads();
        uint32_t bA = sb + cur * BUF3;
#pragma unroll
        for (int ks = 0; ks < 4; ks++) {
            uint32_t a_h[4][4], a_l[4][4], b_h[4][2], b_l[4][2];
#pragma unroll
            for (int i = 0; i < 4; i++) {
                uint32_t o = SWZ((wm + i * 16 + lr) * 128 + ks * 32 + lc * 16);
                ldsm_x4(a_h[i][0], a_h[i][1], a_h[i][2], a_h[i][3], bA + o);
                ldsm_x4(a_l[i][0], a_l[i][1], a_l[i][2], a_l[i][3], bA + TILE_B + o);
            }
#pragma unroll
            for (int j = 0; j < 4; j++) {
                uint32_t o = SWZ((wn + j * 8 + br) * 128 + ks * 32 + bk * 16);
                ldsm_x2(b_h[j][0], b_h[j][1], bA + 2 * TILE_B + o);
                ldsm_x2(b_l[j][0], b_l[j][1], bA + 3 * TILE_B + o);
            }
#pragma unroll
            for (int i = 0; i < 4; i++)
#pragma unroll
                for (int j = 0; j < 4; j++) {
                    mma_f16(acc[i][j], a_h[i], b_h[j]);
                    mma_f16(acc[i][j], a_h[i], b_l[j]);
                    mma_f16(acc[i][j], a_l[i], b_h[j]);
                }
        }
        __syncthreads();
    }
#pragma unroll
    for (int i = 0; i < 4; i++) {
        int row = bm + wm + i * 16 + (lane >> 2);
#pragma unroll
        for (int j = 0; j < 4; j++) {
            int col = bn + wn + j * 8 + ((lane & 3) << 1);
            *(float2*)&C[(size_t)row * N + col]       = make_float2(acc[i][j][0], acc[i][j][1]);
            *(float2*)&C[(size_t)(row + 8) * N + col] = make_float2(acc[i][j][2], acc[i][j][3]);
        }
    }
}

// ======== fp16 2-pass GEMM: V projection with fused transpose (MODE 2 only now) ========
#define BUF2   (3*TILE_B)
#define SMEM_G2 (2*BUF2)
__global__ void __launch_bounds__(256)
gemm2v(const f16* __restrict__ Ah, const f16* __restrict__ Al,
       const f16* __restrict__ Bm, f16* __restrict__ VT, int M, int N, int K)
{
    extern __shared__ char smem[];
    const uint32_t sb = smem_to_u32(smem);
    const int tid = threadIdx.x, wid = tid >> 5, lane = tid & 31;
    const int bn = blockIdx.x << 7, bm = blockIdx.y << 7;
    const int wm = (wid >> 2) << 6, wn = (wid & 3) << 5;
    const int nchunk = K >> 6;
    const int lr = lane & 15, lc = lane >> 4, br = lane & 7, bk = (lane >> 3) & 1;
    float acc[4][4][4];
#pragma unroll
    for (int i = 0; i < 4; i++)
#pragma unroll
        for (int j = 0; j < 4; j++)
#pragma unroll
            for (int r = 0; r < 4; r++) acc[i][j][r] = 0.f;
    auto load = [&](int kc, int buf) {
        uint32_t base = sb + buf * BUF2;
        int ke = kc << 6;
#pragma unroll
        for (int i = 0; i < 4; i++) {
            int idx = tid + (i << 8), r = idx >> 3, c = idx & 7;
            uint32_t so = SWZ(r * 128 + c * 16);
            cp_async16(base + so,              Ah + (size_t)(bm + r) * K + ke + c * 8);
            cp_async16(base + TILE_B + so,     Al + (size_t)(bm + r) * K + ke + c * 8);
            cp_async16(base + 2 * TILE_B + so, Bm + (size_t)(bn + r) * K + ke + c * 8);
        }
    };
    load(0, 0); cp_commit();
    for (int kc = 0; kc < nchunk; kc++) {
        int cur = kc & 1;
        if (kc + 1 < nchunk) { load(kc + 1, cur ^ 1); cp_commit(); cp_wait<1>(); }
        else cp_wait<0>();
        __syncthreads();
        uint32_t bA = sb + cur * BUF2;
#pragma unroll
        for (int ks = 0; ks < 4; ks++) {
            uint32_t a_h[4][4], a_l[4][4], b_[4][2];
#pragma unroll
            for (int i = 0; i < 4; i++) {
                uint32_t o = SWZ((wm + i * 16 + lr) * 128 + ks * 32 + lc * 16);
                ldsm_x4(a_h[i][0], a_h[i][1], a_h[i][2], a_h[i][3], bA + o);
                ldsm_x4(a_l[i][0], a_l[i][1], a_l[i][2], a_l[i][3], bA + TILE_B + o);
            }
#pragma unroll
            for (int j = 0; j < 4; j++) {
                uint32_t o = SWZ((wn + j * 8 + br) * 128 + ks * 32 + bk * 16);
                ldsm_x2(b_[j][0], b_[j][1], bA + 2 * TILE_B + o);
            }
#pragma unroll
            for (int i = 0; i < 4; i++)
#pragma unroll
                for (int j = 0; j < 4; j++) {
                    mma_f16(acc[i][j], a_h[i], b_[j]);
                    mma_f16(acc[i][j], a_l[i], b_[j]);
                }
        }
        __syncthreads();
    }
    float* stage = (float*)smem;
#pragma unroll
    for (int i = 0; i < 4; i++) {
        int row = wm + i * 16 + (lane >> 2);
#pragma unroll
        for (int j = 0; j < 4; j++) {
            int col = wn + j * 8 + ((lane & 3) << 1);
            stage[col * 132 + row]           = acc[i][j][0];
            stage[(col + 1) * 132 + row]     = acc[i][j][1];
            stage[col * 132 + row + 8]       = acc[i][j][2];
            stage[(col + 1) * 132 + row + 8] = acc[i][j][3];
        }
    }
    __syncthreads();
    int b = bm >> 12;
    int dl = tid >> 1, ts = (tid & 1) << 6;
    int h = (bn + dl) >> 6, v = (bn + dl) & 63;
    size_t base = ((size_t)(b * H_ + h) * 80 + v) * T_ + (bm & 4095) + ts;
#pragma unroll
    for (int p = 0; p < 32; p++)
        store_h2(VT, base + p * 2, stage[dl * 132 + ts + p * 2], stage[dl * 132 + ts + p * 2 + 1]);
}

// ======== fp16 1-pass GEMM with row scale (O projection) ========
#define BUF1   (2*TILE_B)
#define SMEM_G1 (2*BUF1)
__global__ void __launch_bounds__(256)
gemm1(const f16* __restrict__ Am, const f16* __restrict__ Bm,
      const float* __restrict__ S, float* __restrict__ C, int M, int N, int K)
{
    extern __shared__ char smem[];
    const uint32_t sb = smem_to_u32(smem);
    const int tid = threadIdx.x, wid = tid >> 5, lane = tid & 31;
    const int bn = blockIdx.x << 7, bm = blockIdx.y << 7;
    const int wm = (wid >> 2) << 6, wn = (wid & 3) << 5;
    const int nchunk = K >> 6;
    const int lr = lane & 15, lc = lane >> 4, br = lane & 7, bk = (lane >> 3) & 1;
    float acc[4][4][4];
#pragma unroll
    for (int i = 0; i < 4; i++)
#pragma unroll
        for (int j = 0; j < 4; j++)
#pragma unroll
            for (int r = 0; r < 4; r++) acc[i][j][r] = 0.f;
    auto load = [&](int kc, int buf) {
        uint32_t base = sb + buf * BUF1;
        int ke = kc << 6;
#pragma unroll
        for (int i = 0; i < 4; i++) {
            int idx = tid + (i << 8), r = idx >> 3, c = idx & 7;
            uint32_t so = SWZ(r * 128 + c * 16);
            cp_async16(base + so,          Am + (size_t)(bm + r) * K + ke + c * 8);
            cp_async16(base + TILE_B + so, Bm + (size_t)(bn + r) * K + ke + c * 8);
        }
    };
    load(0, 0); cp_commit();
    for (int kc = 0; kc < nchunk; kc++) {
        int cur = kc & 1;
        if (kc + 1 < nchunk) { load(kc + 1, cur ^ 1); cp_commit(); cp_wait<1>(); }
        else cp_wait<0>();
        __syncthreads();
        uint32_t bA = sb + cur * BUF1;
#pragma unroll
        for (int ks = 0; ks < 4; ks++) {
            uint32_t a_[4][4], b_[4][2];
#pragma unroll
            for (int i = 0; i < 4; i++) {
                uint32_t o = SWZ((wm + i * 16 + lr) * 128 + ks * 32 + lc * 16);
                ldsm_x4(a_[i][0], a_[i][1], a_[i][2], a_[i][3], bA + o);
            }
#pragma unroll
            for (int j = 0; j < 4; j++) {
                uint32_t o = SWZ((wn + j * 8 + br) * 128 + ks * 32 + bk * 16);
                ldsm_x2(b_[j][0], b_[j][1], bA + TILE_B + o);
            }
#pragma unroll
            for (int i = 0; i < 4; i++)
#pragma unroll
                for (int j = 0; j < 4; j++)
                    mma_f16(acc[i][j], a_[i], b_[j]);
        }
        __syncthreads();
    }
#pragma unroll
    for (int i = 0; i < 4; i++) {
        int row = bm + wm + i * 16 + (lane >> 2);
        float s0 = S[row], s1 = S[row + 8];
#pragma unroll
        for (int j = 0; j < 4; j++) {
            int col = bn + wn + j * 8 + ((lane & 3) << 1);
            *(float2*)&C[(size_t)row * N + col]       = make_float2(acc[i][j][0] * s0, acc[i][j][1] * s0);
            *(float2*)&C[(size_t)(row + 8) * N + col] = make_float2(acc[i][j][2] * s1, acc[i][j][3] * s1);
        }
    }
}

// ======== conversions ========
__global__ void __launch_bounds__(256) split16_kernel(const float* __restrict__ in,
                                                      f16* __restrict__ hi, f16* __restrict__ lo, int n4)
{
    int i = blockIdx.x * 256 + threadIdx.x;
    if (i >= n4) return;
    float4 v = ((const float4*)in)[i];
    store_pair_h(hi, lo, (size_t)i * 4, v.x, v.y);
    store_pair_h(hi, lo, (size_t)i * 4 + 2, v.z, v.w);
}
__global__ void __launch_bounds__(256) conv16_kernel(const float* __restrict__ in,
                                                     f16* __restrict__ out, int n4)
{
    int i = blockIdx.x * 256 + threadIdx.x;
    if (i >= n4) return;
    float4 v = ((const float4*)in)[i];
    store_h2(out, (size_t)i * 4, v.x, v.y);
    store_h2(out, (size_t)i * 4 + 2, v.z, v.w);
}

// ======== phi kernels ========
#define PA  0
#define PAL 16384
#define PB  32768
#define PSC 49152
#define PNP 49664
#define SMEM_PHI 50688

__device__ __forceinline__ void conv_tile_h(const float* g, int ld, char* sm, int dstH, int dstL,
                                            float* np, int tid) {
    int r = tid >> 1, cb = (tid & 1) << 5;
    float s = 0.f;
    const float* gp = g + (size_t)r * ld + cb;
#pragma unroll
    for (int k = 0; k < 8; k++) {
        float4 v = *(const float4*)(gp + k * 4);
        s = fmaf(v.x, v.x, s); s = fmaf(v.y, v.y, s);
        s = fmaf(v.z, v.z, s); s = fmaf(v.w, v.w, s);
        uint32_t sw = SWZ((uint32_t)(r * 128 + (cb + k * 4) * 2));
        f16 h0 = __float2half_rn(v.x), h1 = __float2half_rn(v.y);
        f16 h2 = __float2half_rn(v.z), h3 = __float2half_rn(v.w);
        __half2 hp0 = __halves2half2(h0, h1), hp1 = __halves2half2(h2, h3);
        *(uint32_t*)(sm + dstH + sw) = *(uint32_t*)&hp0;
        *(uint32_t*)(sm + dstH + sw + 4) = *(uint32_t*)&hp1;
        __half2 lp0 = __halves2half2(__float2half_rn(v.x - __half2float(h0)),
                                     __float2half_rn(v.y - __half2float(h1)));
        __half2 lp1 = __halves2half2(__float2half_rn(v.z - __half2float(h2)),
                                     __float2half_rn(v.w - __half2float(h3)));
        *(uint32_t*)(sm + dstL + sw) = *(uint32_t*)&lp0;
        *(uint32_t*)(sm + dstL + sw + 4) = *(uint32_t*)&lp1;
    }
    np[tid] = s;
}

__global__ void __launch_bounds__(256) phi_q_kernel(
    const float* __restrict__ QK, const f16* __restrict__ rf16,
    f16* __restrict__ Qfh, f16* __restrict__ Qfl, float* __restrict__ scq)
{
    extern __shared__ char sm[];
    const uint32_t sb = smem_to_u32(sm);
    const int tid = threadIdx.x, wid = tid >> 5, lane = tid & 31;
    const int t0 = blockIdx.x << 7, m0c = blockIdx.y << 7, bh = blockIdx.z;
    const int b = bh >> 4, h = bh & 15;
    float* np = (float*)(sm + PNP);
#pragma unroll
    for (int i = 0; i < 4; i++) {
        int idx = tid + (i << 8), r = idx >> 3, c = idx & 7;
        cp_async16(sb + PB + SWZ(r * 128 + c * 16), rf16 + (size_t)(m0c + r) * DH_ + c * 8);
    }
    cp_commit();
    conv_tile_h(&QK[((size_t)(b * T_ + t0)) * 2048 + h * DH_], 2048, sm, PA, PAL, np, tid);
    __syncthreads();
    if (tid < 128 && blockIdx.y == 0)
        scq[(size_t)bh * T_ + t0 + tid] = __expf(-0.5f * (np[2 * tid] + np[2 * tid + 1])) * 0.0625f;
    cp_wait<0>();
    __syncthreads();
    const int wt = (wid >> 2) << 6, wm = (wid & 3) << 5;
    const int lr = lane & 15, lc = lane >> 4, br = lane & 7, bk = (lane >> 3) & 1;
    float acc[4][4][4];
#pragma unroll
    for (int i = 0; i < 4; i++)
#pragma unroll
        for (int j = 0; j < 4; j++)
#pragma unroll
            for (int r = 0; r < 4; r++) acc[i][j][r] = 0.f;
#pragma unroll
    for (int ks = 0; ks < 4; ks++) {
        uint32_t a_h[4][4], a_l[4][4], b_[4][2];
#pragma unroll
        for (int i = 0; i < 4; i++) {
            uint32_t o = SWZ((wt + i * 16 + lr) * 128 + ks * 32 + lc * 16);
            ldsm_x4(a_h[i][0], a_h[i][1], a_h[i][2], a_h[i][3], sb + PA + o);
            ldsm_x4(a_l[i][0], a_l[i][1], a_l[i][2], a_l[i][3], sb + PAL + o);
        }
#pragma unroll
        for (int j = 0; j < 4; j++) {
            uint32_t o = SWZ((wm + j * 8 + br) * 128 + ks * 32 + bk * 16);
            ldsm_x2(b_[j][0], b_[j][1], sb + PB + o);
        }
#pragma unroll
        for (int i = 0; i < 4; i++)
#pragma unroll
            for (int j = 0; j < 4; j++) {
                mma_f16(acc[i][j], a_h[i], b_[j]);
                mma_f16(acc[i][j], a_l[i], b_[j]);
            }
    }
#pragma unroll
    for (int i = 0; i < 4; i++) {
        int r0 = wt + i * 16 + (lane >> 2);
        size_t rb0 = ((size_t)bh * T_ + t0 + r0) * FD_ + m0c;
        size_t rb1 = rb0 + (size_t)8 * FD_;
#pragma unroll
        for (int j = 0; j < 4; j++) {
            int mc = wm + j * 8 + ((lane & 3) << 1);
            float sn0, cs0, sn1, cs1;
            fast_sincos(acc[i][j][0], sn0, cs0);
            fast_sincos(acc[i][j][1], sn1, cs1);
            store_pair_h(Qfh, Qfl, rb0 + mc, cs0, cs1);
            store_pair_h(Qfh, Qfl, rb0 + 256 + mc, sn0, sn1);
            fast_sincos(acc[i][j][2], sn0, cs0);
            fast_sincos(acc[i][j][3], sn1, cs1);
            store_pair_h(Qfh, Qfl, rb1 + mc, cs0, cs1);
            store_pair_h(Qfh, Qfl, rb1 + 256 + mc, sn0, sn1);
        }
    }
}

// phi_k: KfT' = phi_k / beta, SINGLE fp16
__global__ void __launch_bounds__(256) phi_k_kernel(
    const float* __restrict__ QK, const f16* __restrict__ rf16,
    const float* __restrict__ beta, f16* __restrict__ KfT)
{
    extern __shared__ char sm[];
    const uint32_t sb = smem_to_u32(sm);
    const int tid = threadIdx.x, wid = tid >> 5, lane = tid & 31;
    const int t0 = blockIdx.x << 7, m0c = blockIdx.y << 7, bh = blockIdx.z;
    const int b = bh >> 4, h = bh & 15;
    float* scale = (float*)(sm + PSC);
    float* np = (float*)(sm + PNP);
    const float gamma = 1.f / beta[bh];
#pragma unroll
    for (int i = 0; i < 4; i++) {
        int idx = tid + (i << 8), r = idx >> 3, c = idx & 7;
        cp_async16(sb + PA + SWZ(r * 128 + c * 16), rf16 + (size_t)(m0c + r) * DH_ + c * 8);
    }
    cp_commit();
    conv_tile_h(&QK[((size_t)(b * T_ + t0)) * 2048 + 1024 + h * DH_], 2048, sm, PAL, PB, np, tid);
    __syncthreads();
    if (tid < 128)
        scale[tid] = __expf(-0.5f * (np[2 * tid] + np[2 * tid + 1])) * 0.0625f * gamma;
    cp_wait<0>();
    __syncthreads();
    const int wm = (wid >> 2) << 6, wt = (wid & 3) << 5;
    const int lr = lane & 15, lc = lane >> 4, br = lane & 7, bk = (lane >> 3) & 1;
    float acc[4][4][4];
#pragma unroll
    for (int i = 0; i < 4; i++)
#pragma unroll
        for (int j = 0; j < 4; j++)
#pragma unroll
            for (int r = 0; r < 4; r++) acc[i][j][r] = 0.f;
#pragma unroll
    for (int ks = 0; ks < 4; ks++) {
        uint32_t a_[4][4], b_h[4][2], b_l[4][2];
#pragma unroll
        for (int i = 0; i < 4; i++) {
            uint32_t o = SWZ((wm + i * 16 + lr) * 128 + ks * 32 + lc * 16);
            ldsm_x4(a_[i][0], a_[i][1], a_[i][2], a_[i][3], sb + PA + o);
        }
#pragma unroll
        for (int j = 0; j < 4; j++) {
            uint32_t o = SWZ((wt + j * 8 + br) * 128 + ks * 32 + bk * 16);
            ldsm_x2(b_h[j][0], b_h[j][1], sb + PAL + o);
            ldsm_x2(b_l[j][0], b_l[j][1], sb + PB + o);
        }
#pragma unroll
        for (int i = 0; i < 4; i++)
#pragma unroll
            for (int j = 0; j < 4; j++) {
                mma_f16(acc[i][j], a_[i], b_h[j]);
                mma_f16(acc[i][j], a_[i], b_l[j]);
            }
    }
#pragma unroll
    for (int i = 0; i < 4; i++) {
        int r0 = wm + i * 16 + (lane >> 2);
        size_t rc0 = ((size_t)bh * FD_ + m0c + r0) * T_ + t0;
        size_t rs0 = rc0 + (size_t)256 * T_;
        size_t rc1 = rc0 + (size_t)8 * T_, rs1 = rs0 + (size_t)8 * T_;
#pragma unroll
        for (int j = 0; j < 4; j++) {
            int tc = wt + j * 8 + ((lane & 3) << 1);
            float sc0 = scale[tc], sc1 = scale[tc + 1];
            float sn0, cs0, sn1, cs1;
            fast_sincos(acc[i][j][0], sn0, cs0);
            fast_sincos(acc[i][j][1], sn1, cs1);
            store_h2(KfT, rc0 + tc, cs0 * sc0, cs1 * sc1);
            store_h2(KfT, rs0 + tc, sn0 * sc0, sn1 * sc1);
            fast_sincos(acc[i][j][2], sn0, cs0);
            fast_sincos(acc[i][j][3], sn1, cs1);
            store_h2(KfT, rc1 + tc, cs0 * sc0, cs1 * sc1);
            store_h2(KfT, rs1 + tc, sn0 * sc0, sn1 * sc1);
        }
    }
}

// ======== knorm / alphabeta / srow / vt_ones / zero_kvt ========
__global__ void __launch_bounds__(256) knorm_kernel(const float* __restrict__ QK,
                                                    float* __restrict__ sck)
{
    __shared__ float np[256];
    const int tid = threadIdx.x;
    const int t0 = blockIdx.x << 7, bh = blockIdx.y;
    const int b = bh >> 4, h = bh & 15;
    int r = tid >> 1, cb = (tid & 1) << 5;
    const float* gp = QK + ((size_t)(b * T_ + t0 + r)) * 2048 + 1024 + h * DH_ + cb;
    float s = 0.f;
#pragma unroll
    for (int k = 0; k < 8; k++) {
        float4 v = *(const float4*)(gp + k * 4);
        s = fmaf(v.x, v.x, s); s = fmaf(v.y, v.y, s);
        s = fmaf(v.z, v.z, s); s = fmaf(v.w, v.w, s);
    }
    np[tid] = s;
    __syncthreads();
    if (tid < 128)
        sck[(size_t)bh * T_ + t0 + tid] = __expf(-0.5f * (np[2 * tid] + np[2 * tid + 1])) * 0.0625f;
}

__global__ void __launch_bounds__(256) alphabeta_kernel(const float* __restrict__ sck,
                                                        float* __restrict__ alpha,
                                                        float* __restrict__ beta)
{
    __shared__ float rs[256], rm[256];
    const int bh = blockIdx.x, tid = threadIdx.x;
    float s = 0.f, m = 0.f;
    for (int i = tid; i < T_; i += 256) {
        float v = sck[(size_t)bh * T_ + i];
        s += v; m = fmaxf(m, v);
    }
    rs[tid] = s; rm[tid] = m;
    __syncthreads();
    for (int o = 128; o; o >>= 1) {
        if (tid < o) { rs[tid] += rs[tid + o]; rm[tid] = fmaxf(rm[tid], rm[tid + o]); }
        __syncthreads();
    }
    if (tid == 0) {
        alpha[bh] = 1.f / fmaxf(rs[0], 1e-30f);
        beta[bh]  = fmaxf(rm[0], 1e-37f);
    }
}

__global__ void __launch_bounds__(256) srow_kernel(const float* __restrict__ scq,
                                                   const float* __restrict__ alpha,
                                                   float* __restrict__ srow)
{
    int row = blockIdx.x * 256 + threadIdx.x;
    int b = row >> 12, t = row & 4095;
    float m = 0.f;
#pragma unroll
    for (int h = 0; h < H_; h++) {
        int bh = b * H_ + h;
        m = fmaxf(m, scq[(size_t)bh * T_ + t] / alpha[bh]);
    }
    srow[row] = fmaxf(m * 1e6f, 1e-30f);
}

__global__ void __launch_bounds__(256) vt_ones_kernel(f16* __restrict__ VT)
{
    const int bh = blockIdx.x;
    const f16 one = __float2half_rn(1.f), zero = __float2half_rn(0.f);
    for (int i = threadIdx.x; i < 8 * T_; i += 256) {
        int r = i >> 12, t = i & 4095;
        VT[((size_t)bh * 80 + 64 + r) * T_ + t] = (r == 0) ? one : zero;
    }
}

__global__ void __launch_bounds__(256) zero_kvt_kernel(f16* __restrict__ kvt)
{
    const int bh = blockIdx.x;
    for (int i = threadIdx.x; i < 15 * FD_; i += 256)
        kvt[((size_t)bh * 80 + 65) * FD_ + i] = __float2half_rn(0.f);
}

// ======== kv: KfT'(single fp16) x VT(fp16, 72 rows)^T, 1-pass, fused Ksum ========
#define KA   0
#define KB   16384
#define KBUF 26624
#define SMEM_KV (2*KBUF)

__global__ void __launch_bounds__(256) kv_gemm(
    const f16* __restrict__ Am, const f16* __restrict__ Bm,
    const float* __restrict__ alpha, const float* __restrict__ beta,
    f16* __restrict__ kvt)
{
    extern __shared__ char sm[];
    const uint32_t sb = smem_to_u32(sm);
    const int tid = threadIdx.x, wid = tid >> 5, lane = tid & 31;
    const int m0 = blockIdx.x << 7, bh = blockIdx.y;
    const size_t ab = (size_t)bh * FD_ + m0, bb = (size_t)bh * 80;
    const int wm = (wid >> 1) << 5, wn = (wid & 1) * 40;
    const int lr = lane & 15, lc = lane >> 4, br = lane & 7, bk = (lane >> 3) & 1;
    float acc[2][5][4];
#pragma unroll
    for (int i = 0; i < 2; i++)
#pragma unroll
        for (int j = 0; j < 5; j++)
#pragma unroll
            for (int r = 0; r < 4; r++) acc[i][j][r] = 0.f;
    auto load = [&](int kc, int buf) {
        uint32_t base = sb + buf * KBUF;
        int ke = kc << 6;
#pragma unroll
        for (int i = 0; i < 4; i++) {
            int idx = tid + (i << 8), r = idx >> 3, c = idx & 7;
            cp_async16(base + KA + SWZ(r * 128 + c * 16), Am + (ab + r) * T_ + ke + c * 8);
        }
#pragma unroll
        for (int i = 0; i < 3; i++) {
            int idx = tid + (i << 8);
            if (idx < 576) {
                int r = idx >> 3, c = idx & 7;
                cp_async16(base + KB + SWZ(r * 128 + c * 16), Bm + (bb + r) * T_ + ke + c * 8);
            }
        }
    };
    load(0, 0); cp_commit();
    for (int kc = 0; kc < T_ / 64; kc++) {
        int cur = kc & 1;
        if (kc + 1 < T_ / 64) { load(kc + 1, cur ^ 1); cp_commit(); cp_wait<1>(); }
        else cp_wait<0>();
        __syncthreads();
        uint32_t bA = sb + cur * KBUF;
#pragma unroll
        for (int ks = 0; ks < 4; ks++) {
            uint32_t a_[2][4], b_[5][2];
#pragma unroll
            for (int i = 0; i < 2; i++) {
                uint32_t o = SWZ((wm + i * 16 + lr) * 128 + ks * 32 + lc * 16);
                ldsm_x4(a_[i][0], a_[i][1], a_[i][2], a_[i][3], bA + KA + o);
            }
#pragma unroll
            for (int j = 0; j < 5; j++) {
                uint32_t o = SWZ((wn + j * 8 + br) * 128 + ks * 32 + bk * 16);
                ldsm_x2(b_[j][0], b_[j][1], bA + KB + o);
            }
#pragma unroll
            for (int i = 0; i < 2; i++)
#pragma unroll
                for (int j = 0; j < 5; j++)
                    mma_f16(acc[i][j], a_[i], b_[j]);
        }
        __syncthreads();
    }
    float* stage = (float*)sm;
#pragma unroll
    for (int i = 0; i < 2; i++) {
        int row = wm + i * 16 + (lane >> 2);
#pragma unroll
        for (int j = 0; j < 5; j++) {
            int col = wn + j * 8 + ((lane & 3) << 1);
            stage[col * 132 + row]           = acc[i][j][0];
            stage[(col + 1) * 132 + row]     = acc[i][j][1];
            stage[col * 132 + row + 8]       = acc[i][j][2];
            stage[(col + 1) * 132 + row + 8] = acc[i][j][3];
        }
    }
    __syncthreads();
    float av = alpha[bh] * beta[bh];
    int v = tid >> 2, fs = (tid & 3) << 5;
#pragma unroll
    for (int p = 0; p < 16; p++) {
        int f = fs + p * 2;
        store_h2(kvt, ((size_t)bh * 80 + v) * FD_ + m0 + f,
                 stage[v * 132 + f] * av, stage[v * 132 + f + 1] * av);
    }
    if (tid < 64) {
        int f = tid * 2;
        store_h2(kvt, ((size_t)bh * 80 + 64) * FD_ + m0 + f,
                 stage[64 * 132 + f] * av, stage[64 * 132 + f + 1] * av);
    }
}

// ======== qkv: Qf^(hi/lo) x KVT'[80], 2-pass; epilogue Z + scales; attn single fp16 ========
#define QA   0
#define QAL  16384
#define QB   32768
#define QBUF 43008
#define SMEM_QKV (2*QBUF)

__global__ void __launch_bounds__(256) qkv_gemm(
    const f16* __restrict__ Ah, const f16* __restrict__ Al,
    const f16* __restrict__ Bm, const float* __restrict__ scq,
    const float* __restrict__ alpha, const float* __restrict__ srow,
    f16* __restrict__ oh)
{
    extern __shared__ char sm[];
    __shared__ float zsm[128];
    const uint32_t sb = smem_to_u32(sm);
    const int tid = threadIdx.x, wid = tid >> 5, lane = tid & 31;
    const int t0 = blockIdx.x << 7, bh = blockIdx.y;
    const int b = bh >> 4, h = bh & 15;
    const size_t ab = (size_t)bh * T_ + t0, bb = (size_t)bh * 80;
    const int wm = (wid >> 1) << 5, wn = (wid & 1) * 40;
    const int lr = lane & 15, lc = lane >> 4, br = lane & 7, bk = (lane >> 3) & 1;
    float acc[2][5][4];
#pragma unroll
    for (int i = 0; i < 2; i++)
#pragma unroll
        for (int j = 0; j < 5; j++)
#pragma unroll
            for (int r = 0; r < 4; r++) acc[i][j][r] = 0.f;
    auto load = [&](int kc, int buf) {
        uint32_t base = sb + buf * QBUF;
        int ke = kc << 6;
#pragma unroll
        for (int i = 0; i < 4; i++) {
            int idx = tid + (i << 8), r = idx >> 3, c = idx & 7;
            uint32_t so = SWZ(r * 128 + c * 16);
            size_t g = (ab + r) * FD_ + ke + c * 8;
            cp_async16(base + QA + so, Ah + g);
            cp_async16(base + QAL + so, Al + g);
        }
#pragma unroll
        for (int i = 0; i < 3; i++) {
            int idx = tid + (i << 8);
            if (idx < 640) {
                int r = idx >> 3, c = idx & 7;
                cp_async16(base + QB + SWZ(r * 128 + c * 16), Bm + (bb + r) * FD_ + ke + c * 8);
            }
        }
    };
    load(0, 0); cp_commit();
    for (int kc = 0; kc < 8; kc++) {
        int cur = kc & 1;
        if (kc + 1 < 8) { load(kc + 1, cur ^ 1); cp_commit(); cp_wait<1>(); }
        else cp_wait<0>();
        __syncthreads();
        uint32_t bA = sb + cur * QBUF;
#pragma unroll
        for (int ks = 0; ks < 4; ks++) {
            uint32_t a_h[2][4], a_l[2][4], b_[5][2];
#pragma unroll
            for (int i = 0; i < 2; i++) {
                uint32_t o = SWZ((wm + i * 16 + lr) * 128 + ks * 32 + lc * 16);
                ldsm_x4(a_h[i][0], a_h[i][1], a_h[i][2], a_h[i][3], bA + QA + o);
                ldsm_x4(a_l[i][0], a_l[i][1], a_l[i][2], a_l[i][3], bA + QAL + o);
            }
#pragma unroll
            for (int j = 0; j < 5; j++) {
                uint32_t o = SWZ((wn + j * 8 + br) * 128 + ks * 32 + bk * 16);
                ldsm_x2(b_[j][0], b_[j][1], bA + QB + o);
            }
#pragma unroll
            for (int i = 0; i < 2; i++)
#pragma unroll
                for (int j = 0; j < 5; j++) {
                    mma_f16(acc[i][j], a_h[i], b_[j]);
                    mma_f16(acc[i][j], a_l[i], b_[j]);
                }
        }
        __syncthreads();
    }
    if (wn == 40 && (lane & 3) == 0) {
#pragma unroll
        for (int i = 0; i < 2; i++) {
            int row = wm + i * 16 + (lane >> 2);
            zsm[row] = acc[i][3][0];
            zsm[row + 8] = acc[i][3][2];
        }
    }
    __syncthreads();
    float av = alpha[bh];
#pragma unroll
    for (int i = 0; i < 2; i++) {
#pragma unroll
        for (int half = 0; half < 2; half++) {
            int row = wm + i * 16 + (lane >> 2) + half * 8;
            float sq = scq[ab + row];
            float Zt = sq * zsm[row] / av;
            float d = fmaxf(Zt, 1e-6f);
            float mult = sq / (av * d * srow[(size_t)b * T_ + t0 + row]);
#pragma unroll
            for (int j = 0; j < 5; j++) {
                int col = wn + j * 8 + ((lane & 3) << 1);
                if (col < 64) {
                    size_t g0 = ((size_t)(b * T_ + t0 + row)) * D_ + h * DH_ + col;
                    store_h2(oh, g0, acc[i][j][half * 2] * mult, acc[i][j][half * 2 + 1] * mult);
                }
            }
        }
    }
}

// ======== launch ========
extern "C" void kernel_launch(void* const* d_in, const int* in_sizes, int n_in,
                              void* d_out, int out_size)
{
    const float* x  = (const float*)d_in[0];
    const float* wq = (const float*)d_in[1];
    const float* wk = (const float*)d_in[2];
    const float* wv = (const float*)d_in[3];
    const float* wo = (const float*)d_in[4];
    const float* rf = (const float*)d_in[5];
    float* out = (float*)d_out;

    float* fb = nullptr; cudaGetSymbolAddress((void**)&fb, g_buf);
    bf16*  bb = nullptr; cudaGetSymbolAddress((void**)&bb, g_bf);

    float *QKp = fb + OFF_QK;
    float *SCQ = fb + OFF_SCQ, *SCK = fb + OFF_SCK;
    float *ALP = fb + OFF_AL, *BET = fb + OFF_BE, *SR = fb + OFF_SR;
    f16 *xh = (f16*)(bb + BO_XH), *xl = (f16*)(bb + BO_XL);
    f16 *wqkh = (f16*)(bb + BO_WQKH), *wqkl = (f16*)(bb + BO_WQKL);
    f16 *wv16 = (f16*)(bb + BO_WV), *wo16 = (f16*)(bb + BO_WO);
    f16 *rf16 = (f16*)(bb + BO_RF);
    f16 *Qfh = (f16*)(bb + BO_QFH), *Qfl = (f16*)(bb + BO_QFL);
    f16 *KfT = (f16*)(bb + BO_KFT);
    f16 *VT = (f16*)(bb + BO_VT);
    f16 *KVT = (f16*)(bb + BO_KVT);
    f16 *ah = (f16*)(bb + BO_AH);

    cudaFuncSetAttribute(gemm3, cudaFuncAttributeMaxDynamicSharedMemorySize, SMEM_G3);
    cudaFuncSetAttribute(gemm2v, cudaFuncAttributeMaxDynamicSharedMemorySize, SMEM_G2);
    cudaFuncSetAttribute(gemm1, cudaFuncAttributeMaxDynamicSharedMemorySize, SMEM_G1);
    cudaFuncSetAttribute(phi_q_kernel, cudaFuncAttributeMaxDynamicSharedMemorySize, SMEM_PHI);
    cudaFuncSetAttribute(phi_k_kernel, cudaFuncAttributeMaxDynamicSharedMemorySize, SMEM_PHI);
    cudaFuncSetAttribute(kv_gemm, cudaFuncAttributeMaxDynamicSharedMemorySize, SMEM_KV);
    cudaFuncSetAttribute(qkv_gemm, cudaFuncAttributeMaxDynamicSharedMemorySize, SMEM_QKV);

    int wn4 = D_ * D_ / 4;
    split16_kernel<<<(int)(SZ_BTD / 4 / 256), 256>>>(x, xh, xl, (int)(SZ_BTD / 4));
    split16_kernel<<<wn4 / 256, 256>>>(wq, wqkh, wqkl, wn4);
    split16_kernel<<<wn4 / 256, 256>>>(wk, wqkh + (size_t)D_ * D_, wqkl + (size_t)D_ * D_, wn4);
    conv16_kernel<<<wn4 / 256, 256>>>(wv, wv16, wn4);
    conv16_kernel<<<wn4 / 256, 256>>>(wo, wo16, wn4);
    conv16_kernel<<<16, 256>>>(rf, rf16, 4096);

    gemm3<<<dim3(16, 64), 256, SMEM_G3>>>(xh, xl, wqkh, wqkl, QKp, B_ * T_, 2048, D_);
    gemm2v<<<dim3(8, 64), 256, SMEM_G2>>>(xh, xl, wv16, VT, B_ * T_, D_, D_);
    vt_ones_kernel<<<BH_, 256>>>(VT);

    dim3 gPhi(T_ / 128, 2, BH_);
    phi_q_kernel<<<gPhi, 256, SMEM_PHI>>>(QKp, rf16, Qfh, Qfl, SCQ);
    knorm_kernel<<<dim3(T_ / 128, BH_), 256>>>(QKp, SCK);
    alphabeta_kernel<<<BH_, 256>>>(SCK, ALP, BET);
    phi_k_kernel<<<gPhi, 256, SMEM_PHI>>>(QKp, rf16, BET, KfT);

    zero_kvt_kernel<<<BH_, 256>>>(KVT);
    kv_gemm<<<dim3(FD_ / 128, BH_), 256, SMEM_KV>>>(KfT, VT, ALP, BET, KVT);
    srow_kernel<<<(B_ * T_) / 256, 256>>>(SCQ, ALP, SR);

    qkv_gemm<<<dim3(T_ / 128, BH_), 256, SMEM_QKV>>>(Qfh, Qfl, KVT, SCQ, ALP, SR, ah);

    gemm1<<<dim3(8, 64), 256, SMEM_G1>>>(ah, wo16, SR, out, B_ * T_, D_, D_);
}

// round 14
// speedup vs baseline: 3.7613x; 1.1995x over previous
#include <cuda_runtime.h>
#include <cuda_bf16.h>
#include <cuda_fp16.h>
#include <cstdint>
typedef __nv_bfloat16 bf16;
typedef __half f16;

#define B_   2
#define T_   4096
#define D_   1024
#define H_   16
#define DH_  64
#define FD_  512
#define BH_  (B_*H_)
#define SZ_BTD ((size_t)B_*T_*D_)
#define SZ_F   ((size_t)BH_*T_*FD_)

// fp32 scratch
#define OFF_QK  ((size_t)0)
#define OFF_SCQ (2*SZ_BTD)
#define OFF_SCK (OFF_SCQ + (size_t)BH_*T_)
#define OFF_AL  (OFF_SCK + (size_t)BH_*T_)
#define OFF_BE  (OFF_AL + BH_)
#define OFF_SR  (OFF_BE + BH_)
__device__ float g_buf[OFF_SR + (size_t)B_*T_];

// 2-byte scratch
#define BO_XH    ((size_t)0)
#define BO_XL    (SZ_BTD)
#define BO_WQKH  (2*SZ_BTD)
#define BO_WQKL  (BO_WQKH + 2*(size_t)D_*D_)
#define BO_WV    (BO_WQKL + 2*(size_t)D_*D_)
#define BO_WO    (BO_WV + (size_t)D_*D_)
#define BO_RF    (BO_WO + (size_t)D_*D_)
#define BO_QFH   (BO_RF + 16384)
#define BO_KFT   (BO_QFH + SZ_F)
#define BO_VT    (BO_KFT + SZ_F)                  // [bh][80][T]; row64=ones
#define BO_KVT   (BO_VT + (size_t)BH_*80*T_)
#define BO_AH    (BO_KVT + (size_t)BH_*80*FD_)
__device__ bf16 g_bf[BO_AH + SZ_BTD];

__device__ __forceinline__ uint32_t smem_to_u32(const void* p) {
    uint32_t a;
    asm("{ .reg .u64 t; cvta.to.shared.u64 t, %1; cvt.u32.u64 %0, t; }" : "=r"(a) : "l"(p));
    return a;
}
#define SWZ(o) ((o) ^ (((o) >> 3) & 0x70))
__device__ __forceinline__ void cp_async16(uint32_t s, const void* g) {
    asm volatile("cp.async.cg.shared.global [%0], [%1], 16;" :: "r"(s), "l"(g));
}
__device__ __forceinline__ void cp_commit() { asm volatile("cp.async.commit_group;" ::: "memory"); }
template <int N> __device__ __forceinline__ void cp_wait() {
    asm volatile("cp.async.wait_group %0;" :: "n"(N) : "memory");
}
__device__ __forceinline__ void ldsm_x4(uint32_t& r0, uint32_t& r1, uint32_t& r2, uint32_t& r3, uint32_t a) {
    asm volatile("ldmatrix.sync.aligned.m8n8.x4.shared.b16 {%0,%1,%2,%3}, [%4];"
                 : "=r"(r0), "=r"(r1), "=r"(r2), "=r"(r3) : "r"(a));
}
__device__ __forceinline__ void ldsm_x2(uint32_t& r0, uint32_t& r1, uint32_t a) {
    asm volatile("ldmatrix.sync.aligned.m8n8.x2.shared.b16 {%0,%1}, [%2];"
                 : "=r"(r0), "=r"(r1) : "r"(a));
}
__device__ __forceinline__ void mma_f16(float* c, const uint32_t* a, const uint32_t* b) {
    asm volatile("mma.sync.aligned.m16n8k16.row.col.f32.f16.f16.f32 "
                 "{%0,%1,%2,%3}, {%4,%5,%6,%7}, {%8,%9}, {%0,%1,%2,%3};"
                 : "+f"(c[0]), "+f"(c[1]), "+f"(c[2]), "+f"(c[3])
                 : "r"(a[0]), "r"(a[1]), "r"(a[2]), "r"(a[3]), "r"(b[0]), "r"(b[1]));
}
__device__ __forceinline__ void store_pair_h(f16* ph, f16* pl, size_t off, float x0, float x1) {
    f16 h0 = __float2half_rn(x0), h1 = __float2half_rn(x1);
    __half2 hp = __halves2half2(h0, h1);
    *(uint32_t*)(ph + off) = *(uint32_t*)&hp;
    __half2 lp = __halves2half2(__float2half_rn(x0 - __half2float(h0)),
                                __float2half_rn(x1 - __half2float(h1)));
    *(uint32_t*)(pl + off) = *(uint32_t*)&lp;
}
__device__ __forceinline__ void store_h2(f16* p, size_t off, float x0, float x1) {
    __half2 hp = __halves2half2(__float2half_rn(x0), __float2half_rn(x1));
    *(uint32_t*)(p + off) = *(uint32_t*)&hp;
}
__device__ __forceinline__ void fast_sincos(float x, float& s, float& c) {
    float kf = rintf(x * 0.63661977f);
    int q = (int)kf;
    float r = fmaf(kf, -1.5707963705062866f, x);
    r = fmaf(kf, 4.3711388286738e-8f, r);
    float r2 = r * r;
    float sp = fmaf(-1.98412698e-4f, r2, 8.33333333e-3f);
    sp = fmaf(sp, r2, -1.66666667e-1f) * r2;
    float sr = fmaf(sp, r, r);
    float cp = fmaf(2.48015873e-5f, r2, -1.38888889e-3f);
    cp = fmaf(cp, r2, 4.16666667e-2f);
    cp = fmaf(cp, r2, -0.5f);
    float cr = fmaf(cp, r2, 1.0f);
    if (q & 1) { float t = sr; sr = cr; cr = -t; }
    if (q & 2) { sr = -sr; cr = -cr; }
    s = sr; c = cr;
}

#define TILE_B 16384

// ======== fp16 3-pass GEMM (QK projection) ========
#define BUF3   (4*TILE_B)
#define SMEM_G3 (2*BUF3)
__global__ void __launch_bounds__(256)
gemm3(const f16* __restrict__ Ah, const f16* __restrict__ Al,
      const f16* __restrict__ Bh, const f16* __restrict__ Bl,
      float* __restrict__ C, int M, int N, int K)
{
    extern __shared__ char smem[];
    const uint32_t sb = smem_to_u32(smem);
    const int tid = threadIdx.x, wid = tid >> 5, lane = tid & 31;
    const int bn = blockIdx.x << 7, bm = blockIdx.y << 7;
    const int wm = (wid >> 2) << 6, wn = (wid & 3) << 5;
    const int nchunk = K >> 6;
    const int lr = lane & 15, lc = lane >> 4, br = lane & 7, bk = (lane >> 3) & 1;
    float acc[4][4][4];
#pragma unroll
    for (int i = 0; i < 4; i++)
#pragma unroll
        for (int j = 0; j < 4; j++)
#pragma unroll
            for (int r = 0; r < 4; r++) acc[i][j][r] = 0.f;
    const f16* gs[4] = {Ah, Al, Bh, Bl};
    const int rb[4] = {bm, bm, bn, bn};
    auto load = [&](int kc, int buf) {
        uint32_t base = sb + buf * BUF3;
        int ke = kc << 6;
#pragma unroll
        for (int t = 0; t < 4; t++)
#pragma unroll
            for (int i = 0; i < 4; i++) {
                int idx = tid + (i << 8), r = idx >> 3, c = idx & 7;
                cp_async16(base + t * TILE_B + SWZ(r * 128 + c * 16),
                           gs[t] + (size_t)(rb[t] + r) * K + ke + c * 8);
            }
    };
    load(0, 0); cp_commit();
    for (int kc = 0; kc < nchunk; kc++) {
        int cur = kc & 1;
        if (kc + 1 < nchunk) { load(kc + 1, cur ^ 1); cp_commit(); cp_wait<1>(); }
        else cp_wait<0>();
        __syncthreads();
        uint32_t bA = sb + cur * BUF3;
#pragma unroll
        for (int ks = 0; ks < 4; ks++) {
            uint32_t a_h[4][4], a_l[4][4], b_h[4][2], b_l[4][2];
#pragma unroll
            for (int i = 0; i < 4; i++) {
                uint32_t o = SWZ((wm + i * 16 + lr) * 128 + ks * 32 + lc * 16);
                ldsm_x4(a_h[i][0], a_h[i][1], a_h[i][2], a_h[i][3], bA + o);
                ldsm_x4(a_l[i][0], a_l[i][1], a_l[i][2], a_l[i][3], bA + TILE_B + o);
            }
#pragma unroll
            for (int j = 0; j < 4; j++) {
                uint32_t o = SWZ((wn + j * 8 + br) * 128 + ks * 32 + bk * 16);
                ldsm_x2(b_h[j][0], b_h[j][1], bA + 2 * TILE_B + o);
                ldsm_x2(b_l[j][0], b_l[j][1], bA + 3 * TILE_B + o);
            }
#pragma unroll
            for (int i = 0; i < 4; i++)
#pragma unroll
                for (int j = 0; j < 4; j++) {
                    mma_f16(acc[i][j], a_h[i], b_h[j]);
                    mma_f16(acc[i][j], a_h[i], b_l[j]);
                    mma_f16(acc[i][j], a_l[i], b_h[j]);
                }
        }
        __syncthreads();
    }
#pragma unroll
    for (int i = 0; i < 4; i++) {
        int row = bm + wm + i * 16 + (lane >> 2);
#pragma unroll
        for (int j = 0; j < 4; j++) {
            int col = bn + wn + j * 8 + ((lane & 3) << 1);
            *(float2*)&C[(size_t)row * N + col]       = make_float2(acc[i][j][0], acc[i][j][1]);
            *(float2*)&C[(size_t)(row + 8) * N + col] = make_float2(acc[i][j][2], acc[i][j][3]);
        }
    }
}

// ======== fp16 1-pass GEMM, V projection, fused VT transpose ========
#define BUF1   (2*TILE_B)
#define SMEM_G1V 69632     // max(2*BUF1=65536, stage 128*132*4=67584) padded
__global__ void __launch_bounds__(256)
gemm1v(const f16* __restrict__ Am, const f16* __restrict__ Bm,
       f16* __restrict__ VT, int M, int N, int K)
{
    extern __shared__ char smem[];
    const uint32_t sb = smem_to_u32(smem);
    const int tid = threadIdx.x, wid = tid >> 5, lane = tid & 31;
    const int bn = blockIdx.x << 7, bm = blockIdx.y << 7;
    const int wm = (wid >> 2) << 6, wn = (wid & 3) << 5;
    const int nchunk = K >> 6;
    const int lr = lane & 15, lc = lane >> 4, br = lane & 7, bk = (lane >> 3) & 1;
    float acc[4][4][4];
#pragma unroll
    for (int i = 0; i < 4; i++)
#pragma unroll
        for (int j = 0; j < 4; j++)
#pragma unroll
            for (int r = 0; r < 4; r++) acc[i][j][r] = 0.f;
    auto load = [&](int kc, int buf) {
        uint32_t base = sb + buf * BUF1;
        int ke = kc << 6;
#pragma unroll
        for (int i = 0; i < 4; i++) {
            int idx = tid + (i << 8), r = idx >> 3, c = idx & 7;
            uint32_t so = SWZ(r * 128 + c * 16);
            cp_async16(base + so,          Am + (size_t)(bm + r) * K + ke + c * 8);
            cp_async16(base + TILE_B + so, Bm + (size_t)(bn + r) * K + ke + c * 8);
        }
    };
    load(0, 0); cp_commit();
    for (int kc = 0; kc < nchunk; kc++) {
        int cur = kc & 1;
        if (kc + 1 < nchunk) { load(kc + 1, cur ^ 1); cp_commit(); cp_wait<1>(); }
        else cp_wait<0>();
        __syncthreads();
        uint32_t bA = sb + cur * BUF1;
#pragma unroll
        for (int ks = 0; ks < 4; ks++) {
            uint32_t a_[4][4], b_[4][2];
#pragma unroll
            for (int i = 0; i < 4; i++) {
                uint32_t o = SWZ((wm + i * 16 + lr) * 128 + ks * 32 + lc * 16);
                ldsm_x4(a_[i][0], a_[i][1], a_[i][2], a_[i][3], bA + o);
            }
#pragma unroll
            for (int j = 0; j < 4; j++) {
                uint32_t o = SWZ((wn + j * 8 + br) * 128 + ks * 32 + bk * 16);
                ldsm_x2(b_[j][0], b_[j][1], bA + TILE_B + o);
            }
#pragma unroll
            for (int i = 0; i < 4; i++)
#pragma unroll
                for (int j = 0; j < 4; j++)
                    mma_f16(acc[i][j], a_[i], b_[j]);
        }
        __syncthreads();
    }
    float* stage = (float*)smem;
#pragma unroll
    for (int i = 0; i < 4; i++) {
        int row = wm + i * 16 + (lane >> 2);
#pragma unroll
        for (int j = 0; j < 4; j++) {
            int col = wn + j * 8 + ((lane & 3) << 1);
            stage[col * 132 + row]           = acc[i][j][0];
            stage[(col + 1) * 132 + row]     = acc[i][j][1];
            stage[col * 132 + row + 8]       = acc[i][j][2];
            stage[(col + 1) * 132 + row + 8] = acc[i][j][3];
        }
    }
    __syncthreads();
    int b = bm >> 12;
    int dl = tid >> 1, ts = (tid & 1) << 6;
    int h = (bn + dl) >> 6, v = (bn + dl) & 63;
    size_t base = ((size_t)(b * H_ + h) * 80 + v) * T_ + (bm & 4095) + ts;
#pragma unroll
    for (int p = 0; p < 32; p++)
        store_h2(VT, base + p * 2, stage[dl * 132 + ts + p * 2], stage[dl * 132 + ts + p * 2 + 1]);
}

// ======== fp16 1-pass GEMM with row scale (O projection) ========
#define SMEM_G1 (2*BUF1)
__global__ void __launch_bounds__(256)
gemm1(const f16* __restrict__ Am, const f16* __restrict__ Bm,
      const float* __restrict__ S, float* __restrict__ C, int M, int N, int K)
{
    extern __shared__ char smem[];
    const uint32_t sb = smem_to_u32(smem);
    const int tid = threadIdx.x, wid = tid >> 5, lane = tid & 31;
    const int bn = blockIdx.x << 7, bm = blockIdx.y << 7;
    const int wm = (wid >> 2) << 6, wn = (wid & 3) << 5;
    const int nchunk = K >> 6;
    const int lr = lane & 15, lc = lane >> 4, br = lane & 7, bk = (lane >> 3) & 1;
    float acc[4][4][4];
#pragma unroll
    for (int i = 0; i < 4; i++)
#pragma unroll
        for (int j = 0; j < 4; j++)
#pragma unroll
            for (int r = 0; r < 4; r++) acc[i][j][r] = 0.f;
    auto load = [&](int kc, int buf) {
        uint32_t base = sb + buf * BUF1;
        int ke = kc << 6;
#pragma unroll
        for (int i = 0; i < 4; i++) {
            int idx = tid + (i << 8), r = idx >> 3, c = idx & 7;
            uint32_t so = SWZ(r * 128 + c * 16);
            cp_async16(base + so,          Am + (size_t)(bm + r) * K + ke + c * 8);
            cp_async16(base + TILE_B + so, Bm + (size_t)(bn + r) * K + ke + c * 8);
        }
    };
    load(0, 0); cp_commit();
    for (int kc = 0; kc < nchunk; kc++) {
        int cur = kc & 1;
        if (kc + 1 < nchunk) { load(kc + 1, cur ^ 1); cp_commit(); cp_wait<1>(); }
        else cp_wait<0>();
        __syncthreads();
        uint32_t bA = sb + cur * BUF1;
#pragma unroll
        for (int ks = 0; ks < 4; ks++) {
            uint32_t a_[4][4], b_[4][2];
#pragma unroll
            for (int i = 0; i < 4; i++) {
                uint32_t o = SWZ((wm + i * 16 + lr) * 128 + ks * 32 + lc * 16);
                ldsm_x4(a_[i][0], a_[i][1], a_[i][2], a_[i][3], bA + o);
            }
#pragma unroll
            for (int j = 0; j < 4; j++) {
                uint32_t o = SWZ((wn + j * 8 + br) * 128 + ks * 32 + bk * 16);
                ldsm_x2(b_[j][0], b_[j][1], bA + TILE_B + o);
            }
#pragma unroll
            for (int i = 0; i < 4; i++)
#pragma unroll
                for (int j = 0; j < 4; j++)
                    mma_f16(acc[i][j], a_[i], b_[j]);
        }
        __syncthreads();
    }
#pragma unroll
    for (int i = 0; i < 4; i++) {
        int row = bm + wm + i * 16 + (lane >> 2);
        float s0 = S[row], s1 = S[row + 8];
#pragma unroll
        for (int j = 0; j < 4; j++) {
            int col = bn + wn + j * 8 + ((lane & 3) << 1);
            *(float2*)&C[(size_t)row * N + col]       = make_float2(acc[i][j][0] * s0, acc[i][j][1] * s0);
            *(float2*)&C[(size_t)(row + 8) * N + col] = make_float2(acc[i][j][2] * s1, acc[i][j][3] * s1);
        }
    }
}

// ======== conversions ========
__global__ void __launch_bounds__(256) split16_kernel(const float* __restrict__ in,
                                                      f16* __restrict__ hi, f16* __restrict__ lo, int n4)
{
    int i = blockIdx.x * 256 + threadIdx.x;
    if (i >= n4) return;
    float4 v = ((const float4*)in)[i];
    store_pair_h(hi, lo, (size_t)i * 4, v.x, v.y);
    store_pair_h(hi, lo, (size_t)i * 4 + 2, v.z, v.w);
}
__global__ void __launch_bounds__(256) conv16_kernel(const float* __restrict__ in,
                                                     f16* __restrict__ out, int n4)
{
    int i = blockIdx.x * 256 + threadIdx.x;
    if (i >= n4) return;
    float4 v = ((const float4*)in)[i];
    store_h2(out, (size_t)i * 4, v.x, v.y);
    store_h2(out, (size_t)i * 4 + 2, v.z, v.w);
}

// ======== phi kernels ========
#define PA  0
#define PAL 16384
#define PB  32768
#define PSC 49152
#define PNP 49664
#define SMEM_PHI 50688

__device__ __forceinline__ void conv_tile_h(const float* g, int ld, char* sm, int dstH, int dstL,
                                            float* np, int tid) {
    int r = tid >> 1, cb = (tid & 1) << 5;
    float s = 0.f;
    const float* gp = g + (size_t)r * ld + cb;
#pragma unroll
    for (int k = 0; k < 8; k++) {
        float4 v = *(const float4*)(gp + k * 4);
        s = fmaf(v.x, v.x, s); s = fmaf(v.y, v.y, s);
        s = fmaf(v.z, v.z, s); s = fmaf(v.w, v.w, s);
        uint32_t sw = SWZ((uint32_t)(r * 128 + (cb + k * 4) * 2));
        f16 h0 = __float2half_rn(v.x), h1 = __float2half_rn(v.y);
        f16 h2 = __float2half_rn(v.z), h3 = __float2half_rn(v.w);
        __half2 hp0 = __halves2half2(h0, h1), hp1 = __halves2half2(h2, h3);
        *(uint32_t*)(sm + dstH + sw) = *(uint32_t*)&hp0;
        *(uint32_t*)(sm + dstH + sw + 4) = *(uint32_t*)&hp1;
        __half2 lp0 = __halves2half2(__float2half_rn(v.x - __half2float(h0)),
                                     __float2half_rn(v.y - __half2float(h1)));
        __half2 lp1 = __halves2half2(__float2half_rn(v.z - __half2float(h2)),
                                     __float2half_rn(v.w - __half2float(h3)));
        *(uint32_t*)(sm + dstL + sw) = *(uint32_t*)&lp0;
        *(uint32_t*)(sm + dstL + sw + 4) = *(uint32_t*)&lp1;
    }
    np[tid] = s;
}

// phi_q: Qf^ unscaled SINGLE fp16; scq fp32
__global__ void __launch_bounds__(256) phi_q_kernel(
    const float* __restrict__ QK, const f16* __restrict__ rf16,
    f16* __restrict__ Qf, float* __restrict__ scq)
{
    extern __shared__ char sm[];
    const uint32_t sb = smem_to_u32(sm);
    const int tid = threadIdx.x, wid = tid >> 5, lane = tid & 31;
    const int t0 = blockIdx.x << 7, m0c = blockIdx.y << 7, bh = blockIdx.z;
    const int b = bh >> 4, h = bh & 15;
    float* np = (float*)(sm + PNP);
#pragma unroll
    for (int i = 0; i < 4; i++) {
        int idx = tid + (i << 8), r = idx >> 3, c = idx & 7;
        cp_async16(sb + PB + SWZ(r * 128 + c * 16), rf16 + (size_t)(m0c + r) * DH_ + c * 8);
    }
    cp_commit();
    conv_tile_h(&QK[((size_t)(b * T_ + t0)) * 2048 + h * DH_], 2048, sm, PA, PAL, np, tid);
    __syncthreads();
    if (tid < 128 && blockIdx.y == 0)
        scq[(size_t)bh * T_ + t0 + tid] = __expf(-0.5f * (np[2 * tid] + np[2 * tid + 1])) * 0.0625f;
    cp_wait<0>();
    __syncthreads();
    const int wt = (wid >> 2) << 6, wm = (wid & 3) << 5;
    const int lr = lane & 15, lc = lane >> 4, br = lane & 7, bk = (lane >> 3) & 1;
    float acc[4][4][4];
#pragma unroll
    for (int i = 0; i < 4; i++)
#pragma unroll
        for (int j = 0; j < 4; j++)
#pragma unroll
            for (int r = 0; r < 4; r++) acc[i][j][r] = 0.f;
#pragma unroll
    for (int ks = 0; ks < 4; ks++) {
        uint32_t a_h[4][4], a_l[4][4], b_[4][2];
#pragma unroll
        for (int i = 0; i < 4; i++) {
            uint32_t o = SWZ((wt + i * 16 + lr) * 128 + ks * 32 + lc * 16);
            ldsm_x4(a_h[i][0], a_h[i][1], a_h[i][2], a_h[i][3], sb + PA + o);
            ldsm_x4(a_l[i][0], a_l[i][1], a_l[i][2], a_l[i][3], sb + PAL + o);
        }
#pragma unroll
        for (int j = 0; j < 4; j++) {
            uint32_t o = SWZ((wm + j * 8 + br) * 128 + ks * 32 + bk * 16);
            ldsm_x2(b_[j][0], b_[j][1], sb + PB + o);
        }
#pragma unroll
        for (int i = 0; i < 4; i++)
#pragma unroll
            for (int j = 0; j < 4; j++) {
                mma_f16(acc[i][j], a_h[i], b_[j]);
                mma_f16(acc[i][j], a_l[i], b_[j]);
            }
    }
#pragma unroll
    for (int i = 0; i < 4; i++) {
        int r0 = wt + i * 16 + (lane >> 2);
        size_t rb0 = ((size_t)bh * T_ + t0 + r0) * FD_ + m0c;
        size_t rb1 = rb0 + (size_t)8 * FD_;
#pragma unroll
        for (int j = 0; j < 4; j++) {
            int mc = wm + j * 8 + ((lane & 3) << 1);
            float sn0, cs0, sn1, cs1;
            fast_sincos(acc[i][j][0], sn0, cs0);
            fast_sincos(acc[i][j][1], sn1, cs1);
            store_h2(Qf, rb0 + mc, cs0, cs1);
            store_h2(Qf, rb0 + 256 + mc, sn0, sn1);
            fast_sincos(acc[i][j][2], sn0, cs0);
            fast_sincos(acc[i][j][3], sn1, cs1);
            store_h2(Qf, rb1 + mc, cs0, cs1);
            store_h2(Qf, rb1 + 256 + mc, sn0, sn1);
        }
    }
}

// phi_k: KfT' = phi_k / beta, SINGLE fp16
__global__ void __launch_bounds__(256) phi_k_kernel(
    const float* __restrict__ QK, const f16* __restrict__ rf16,
    const float* __restrict__ beta, f16* __restrict__ KfT)
{
    extern __shared__ char sm[];
    const uint32_t sb = smem_to_u32(sm);
    const int tid = threadIdx.x, wid = tid >> 5, lane = tid & 31;
    const int t0 = blockIdx.x << 7, m0c = blockIdx.y << 7, bh = blockIdx.z;
    const int b = bh >> 4, h = bh & 15;
    float* scale = (float*)(sm + PSC);
    float* np = (float*)(sm + PNP);
    const float gamma = 1.f / beta[bh];
#pragma unroll
    for (int i = 0; i < 4; i++) {
        int idx = tid + (i << 8), r = idx >> 3, c = idx & 7;
        cp_async16(sb + PA + SWZ(r * 128 + c * 16), rf16 + (size_t)(m0c + r) * DH_ + c * 8);
    }
    cp_commit();
    conv_tile_h(&QK[((size_t)(b * T_ + t0)) * 2048 + 1024 + h * DH_], 2048, sm, PAL, PB, np, tid);
    __syncthreads();
    if (tid < 128)
        scale[tid] = __expf(-0.5f * (np[2 * tid] + np[2 * tid + 1])) * 0.0625f * gamma;
    cp_wait<0>();
    __syncthreads();
    const int wm = (wid >> 2) << 6, wt = (wid & 3) << 5;
    const int lr = lane & 15, lc = lane >> 4, br = lane & 7, bk = (lane >> 3) & 1;
    float acc[4][4][4];
#pragma unroll
    for (int i = 0; i < 4; i++)
#pragma unroll
        for (int j = 0; j < 4; j++)
#pragma unroll
            for (int r = 0; r < 4; r++) acc[i][j][r] = 0.f;
#pragma unroll
    for (int ks = 0; ks < 4; ks++) {
        uint32_t a_[4][4], b_h[4][2], b_l[4][2];
#pragma unroll
        for (int i = 0; i < 4; i++) {
            uint32_t o = SWZ((wm + i * 16 + lr) * 128 + ks * 32 + lc * 16);
            ldsm_x4(a_[i][0], a_[i][1], a_[i][2], a_[i][3], sb + PA + o);
        }
#pragma unroll
        for (int j = 0; j < 4; j++) {
            uint32_t o = SWZ((wt + j * 8 + br) * 128 + ks * 32 + bk * 16);
            ldsm_x2(b_h[j][0], b_h[j][1], sb + PAL + o);
            ldsm_x2(b_l[j][0], b_l[j][1], sb + PB + o);
        }
#pragma unroll
        for (int i = 0; i < 4; i++)
#pragma unroll
            for (int j = 0; j < 4; j++) {
                mma_f16(acc[i][j], a_[i], b_h[j]);
                mma_f16(acc[i][j], a_[i], b_l[j]);
            }
    }
#pragma unroll
    for (int i = 0; i < 4; i++) {
        int r0 = wm + i * 16 + (lane >> 2);
        size_t rc0 = ((size_t)bh * FD_ + m0c + r0) * T_ + t0;
        size_t rs0 = rc0 + (size_t)256 * T_;
        size_t rc1 = rc0 + (size_t)8 * T_, rs1 = rs0 + (size_t)8 * T_;
#pragma unroll
        for (int j = 0; j < 4; j++) {
            int tc = wt + j * 8 + ((lane & 3) << 1);
            float sc0 = scale[tc], sc1 = scale[tc + 1];
            float sn0, cs0, sn1, cs1;
            fast_sincos(acc[i][j][0], sn0, cs0);
            fast_sincos(acc[i][j][1], sn1, cs1);
            store_h2(KfT, rc0 + tc, cs0 * sc0, cs1 * sc1);
            store_h2(KfT, rs0 + tc, sn0 * sc0, sn1 * sc1);
            fast_sincos(acc[i][j][2], sn0, cs0);
            fast_sincos(acc[i][j][3], sn1, cs1);
            store_h2(KfT, rc1 + tc, cs0 * sc0, cs1 * sc1);
            store_h2(KfT, rs1 + tc, sn0 * sc0, sn1 * sc1);
        }
    }
}

// ======== knorm / alphabeta / srow / vt_ones / zero_kvt ========
__global__ void __launch_bounds__(256) knorm_kernel(const float* __restrict__ QK,
                                                    float* __restrict__ sck)
{
    __shared__ float np[256];
    const int tid = threadIdx.x;
    const int t0 = blockIdx.x << 7, bh = blockIdx.y;
    const int b = bh >> 4, h = bh & 15;
    int r = tid >> 1, cb = (tid & 1) << 5;
    const float* gp = QK + ((size_t)(b * T_ + t0 + r)) * 2048 + 1024 + h * DH_ + cb;
    float s = 0.f;
#pragma unroll
    for (int k = 0; k < 8; k++) {
        float4 v = *(const float4*)(gp + k * 4);
        s = fmaf(v.x, v.x, s); s = fmaf(v.y, v.y, s);
        s = fmaf(v.z, v.z, s); s = fmaf(v.w, v.w, s);
    }
    np[tid] = s;
    __syncthreads();
    if (tid < 128)
        sck[(size_t)bh * T_ + t0 + tid] = __expf(-0.5f * (np[2 * tid] + np[2 * tid + 1])) * 0.0625f;
}

__global__ void __launch_bounds__(256) alphabeta_kernel(const float* __restrict__ sck,
                                                        float* __restrict__ alpha,
                                                        float* __restrict__ beta)
{
    __shared__ float rs[256], rm[256];
    const int bh = blockIdx.x, tid = threadIdx.x;
    float s = 0.f, m = 0.f;
    for (int i = tid; i < T_; i += 256) {
        float v = sck[(size_t)bh * T_ + i];
        s += v; m = fmaxf(m, v);
    }
    rs[tid] = s; rm[tid] = m;
    __syncthreads();
    for (int o = 128; o; o >>= 1) {
        if (tid < o) { rs[tid] += rs[tid + o]; rm[tid] = fmaxf(rm[tid], rm[tid + o]); }
        __syncthreads();
    }
    if (tid == 0) {
        alpha[bh] = 1.f / fmaxf(rs[0], 1e-30f);
        beta[bh]  = fmaxf(rm[0], 1e-37f);
    }
}

__global__ void __launch_bounds__(256) srow_kernel(const float* __restrict__ scq,
                                                   const float* __restrict__ alpha,
                                                   float* __restrict__ srow)
{
    int row = blockIdx.x * 256 + threadIdx.x;
    int b = row >> 12, t = row & 4095;
    float m = 0.f;
#pragma unroll
    for (int h = 0; h < H_; h++) {
        int bh = b * H_ + h;
        m = fmaxf(m, scq[(size_t)bh * T_ + t] / alpha[bh]);
    }
    srow[row] = fmaxf(m * 1e6f, 1e-30f);
}

__global__ void __launch_bounds__(256) vt_ones_kernel(f16* __restrict__ VT)
{
    const int bh = blockIdx.x;
    const f16 one = __float2half_rn(1.f), zero = __float2half_rn(0.f);
    for (int i = threadIdx.x; i < 8 * T_; i += 256) {
        int r = i >> 12, t = i & 4095;
        VT[((size_t)bh * 80 + 64 + r) * T_ + t] = (r == 0) ? one : zero;
    }
}

__global__ void __launch_bounds__(256) zero_kvt_kernel(f16* __restrict__ kvt)
{
    const int bh = blockIdx.x;
    for (int i = threadIdx.x; i < 15 * FD_; i += 256)
        kvt[((size_t)bh * 80 + 65) * FD_ + i] = __float2half_rn(0.f);
}

// ======== kv: KfT'(fp16) x VT(fp16, 72 rows)^T, 1-pass, fused Ksum ========
#define KA   0
#define KB   16384
#define KBUF 26624
#define SMEM_KV (2*KBUF)

__global__ void __launch_bounds__(256) kv_gemm(
    const f16* __restrict__ Am, const f16* __restrict__ Bm,
    const float* __restrict__ alpha, const float* __restrict__ beta,
    f16* __restrict__ kvt)
{
    extern __shared__ char sm[];
    const uint32_t sb = smem_to_u32(sm);
    const int tid = threadIdx.x, wid = tid >> 5, lane = tid & 31;
    const int m0 = blockIdx.x << 7, bh = blockIdx.y;
    const size_t ab = (size_t)bh * FD_ + m0, bb = (size_t)bh * 80;
    const int wm = (wid >> 1) << 5, wn = (wid & 1) * 40;
    const int lr = lane & 15, lc = lane >> 4, br = lane & 7, bk = (lane >> 3) & 1;
    float acc[2][5][4];
#pragma unroll
    for (int i = 0; i < 2; i++)
#pragma unroll
        for (int j = 0; j < 5; j++)
#pragma unroll
            for (int r = 0; r < 4; r++) acc[i][j][r] = 0.f;
    auto load = [&](int kc, int buf) {
        uint32_t base = sb + buf * KBUF;
        int ke = kc << 6;
#pragma unroll
        for (int i = 0; i < 4; i++) {
            int idx = tid + (i << 8), r = idx >> 3, c = idx & 7;
            cp_async16(base + KA + SWZ(r * 128 + c * 16), Am + (ab + r) * T_ + ke + c * 8);
        }
#pragma unroll
        for (int i = 0; i < 3; i++) {
            int idx = tid + (i << 8);
            if (idx < 576) {
                int r = idx >> 3, c = idx & 7;
                cp_async16(base + KB + SWZ(r * 128 + c * 16), Bm + (bb + r) * T_ + ke + c * 8);
            }
        }
    };
    load(0, 0); cp_commit();
    for (int kc = 0; kc < T_ / 64; kc++) {
        int cur = kc & 1;
        if (kc + 1 < T_ / 64) { load(kc + 1, cur ^ 1); cp_commit(); cp_wait<1>(); }
        else cp_wait<0>();
        __syncthreads();
        uint32_t bA = sb + cur * KBUF;
#pragma unroll
        for (int ks = 0; ks < 4; ks++) {
            uint32_t a_[2][4], b_[5][2];
#pragma unroll
            for (int i = 0; i < 2; i++) {
                uint32_t o = SWZ((wm + i * 16 + lr) * 128 + ks * 32 + lc * 16);
                ldsm_x4(a_[i][0], a_[i][1], a_[i][2], a_[i][3], bA + KA + o);
            }
#pragma unroll
            for (int j = 0; j < 5; j++) {
                uint32_t o = SWZ((wn + j * 8 + br) * 128 + ks * 32 + bk * 16);
                ldsm_x2(b_[j][0], b_[j][1], bA + KB + o);
            }
#pragma unroll
            for (int i = 0; i < 2; i++)
#pragma unroll
                for (int j = 0; j < 5; j++)
                    mma_f16(acc[i][j], a_[i], b_[j]);
        }
        __syncthreads();
    }
    float* stage = (float*)sm;
#pragma unroll
    for (int i = 0; i < 2; i++) {
        int row = wm + i * 16 + (lane >> 2);
#pragma unroll
        for (int j = 0; j < 5; j++) {
            int col = wn + j * 8 + ((lane & 3) << 1);
            stage[col * 132 + row]           = acc[i][j][0];
            stage[(col + 1) * 132 + row]     = acc[i][j][1];
            stage[col * 132 + row + 8]       = acc[i][j][2];
            stage[(col + 1) * 132 + row + 8] = acc[i][j][3];
        }
    }
    __syncthreads();
    float av = alpha[bh] * beta[bh];
    int v = tid >> 2, fs = (tid & 3) << 5;
#pragma unroll
    for (int p = 0; p < 16; p++) {
        int f = fs + p * 2;
        store_h2(kvt, ((size_t)bh * 80 + v) * FD_ + m0 + f,
                 stage[v * 132 + f] * av, stage[v * 132 + f + 1] * av);
    }
    if (tid < 64) {
        int f = tid * 2;
        store_h2(kvt, ((size_t)bh * 80 + 64) * FD_ + m0 + f,
                 stage[64 * 132 + f] * av, stage[64 * 132 + f + 1] * av);
    }
}

// ======== qkv: Qf(single) x KVT'[80], 1-pass; epilogue Z + scales ========
#define QA   0
#define QB   16384
#define QBUF 26624
#define SMEM_QKV (2*QBUF)

__global__ void __launch_bounds__(256) qkv_gemm(
    const f16* __restrict__ Am, const f16* __restrict__ Bm,
    const float* __restrict__ scq, const float* __restrict__ alpha,
    const float* __restrict__ srow, f16* __restrict__ oh)
{
    extern __shared__ char sm[];
    __shared__ float zsm[128];
    const uint32_t sb = smem_to_u32(sm);
    const int tid = threadIdx.x, wid = tid >> 5, lane = tid & 31;
    const int t0 = blockIdx.x << 7, bh = blockIdx.y;
    const int b = bh >> 4, h = bh & 15;
    const size_t ab = (size_t)bh * T_ + t0, bb = (size_t)bh * 80;
    const int wm = (wid >> 1) << 5, wn = (wid & 1) * 40;
    const int lr = lane & 15, lc = lane >> 4, br = lane & 7, bk = (lane >> 3) & 1;
    float acc[2][5][4];
#pragma unroll
    for (int i = 0; i < 2; i++)
#pragma unroll
        for (int j = 0; j < 5; j++)
#pragma unroll
            for (int r = 0; r < 4; r++) acc[i][j][r] = 0.f;
    auto load = [&](int kc, int buf) {
        uint32_t base = sb + buf * QBUF;
        int ke = kc << 6;
#pragma unroll
        for (int i = 0; i < 4; i++) {
            int idx = tid + (i << 8), r = idx >> 3, c = idx & 7;
            cp_async16(base + QA + SWZ(r * 128 + c * 16), Am + (ab + r) * FD_ + ke + c * 8);
        }
#pragma unroll
        for (int i = 0; i < 3; i++) {
            int idx = tid + (i << 8);
            if (idx < 640) {
                int r = idx >> 3, c = idx & 7;
                cp_async16(base + QB + SWZ(r * 128 + c * 16), Bm + (bb + r) * FD_ + ke + c * 8);
            }
        }
    };
    load(0, 0); cp_commit();
    for (int kc = 0; kc < 8; kc++) {
        int cur = kc & 1;
        if (kc + 1 < 8) { load(kc + 1, cur ^ 1); cp_commit(); cp_wait<1>(); }
        else cp_wait<0>();
        __syncthreads();
        uint32_t bA = sb + cur * QBUF;
#pragma unroll
        for (int ks = 0; ks < 4; ks++) {
            uint32_t a_[2][4], b_[5][2];
#pragma unroll
            for (int i = 0; i < 2; i++) {
                uint32_t o = SWZ((wm + i * 16 + lr) * 128 + ks * 32 + lc * 16);
                ldsm_x4(a_[i][0], a_[i][1], a_[i][2], a_[i][3], bA + QA + o);
            }
#pragma unroll
            for (int j = 0; j < 5; j++) {
                uint32_t o = SWZ((wn + j * 8 + br) * 128 + ks * 32 + bk * 16);
                ldsm_x2(b_[j][0], b_[j][1], bA + QB + o);
            }
#pragma unroll
            for (int i = 0; i < 2; i++)
#pragma unroll
                for (int j = 0; j < 5; j++)
                    mma_f16(acc[i][j], a_[i], b_[j]);
        }
        __syncthreads();
    }
    if (wn == 40 && (lane & 3) == 0) {
#pragma unroll
        for (int i = 0; i < 2; i++) {
            int row = wm + i * 16 + (lane >> 2);
            zsm[row] = acc[i][3][0];
            zsm[row + 8] = acc[i][3][2];
        }
    }
    __syncthreads();
    float av = alpha[bh];
#pragma unroll
    for (int i = 0; i < 2; i++) {
#pragma unroll
        for (int half = 0; half < 2; half++) {
            int row = wm + i * 16 + (lane >> 2) + half * 8;
            float sq = scq[ab + row];
            float Zt = sq * zsm[row] / av;
            float d = fmaxf(Zt, 1e-6f);
            float mult = sq / (av * d * srow[(size_t)b * T_ + t0 + row]);
#pragma unroll
            for (int j = 0; j < 5; j++) {
                int col = wn + j * 8 + ((lane & 3) << 1);
                if (col < 64) {
                    size_t g0 = ((size_t)(b * T_ + t0 + row)) * D_ + h * DH_ + col;
                    store_h2(oh, g0, acc[i][j][half * 2] * mult, acc[i][j][half * 2 + 1] * mult);
                }
            }
        }
    }
}

// ======== launch ========
extern "C" void kernel_launch(void* const* d_in, const int* in_sizes, int n_in,
                              void* d_out, int out_size)
{
    const float* x  = (const float*)d_in[0];
    const float* wq = (const float*)d_in[1];
    const float* wk = (const float*)d_in[2];
    const float* wv = (const float*)d_in[3];
    const float* wo = (const float*)d_in[4];
    const float* rf = (const float*)d_in[5];
    float* out = (float*)d_out;

    float* fb = nullptr; cudaGetSymbolAddress((void**)&fb, g_buf);
    bf16*  bb = nullptr; cudaGetSymbolAddress((void**)&bb, g_bf);

    float *QKp = fb + OFF_QK;
    float *SCQ = fb + OFF_SCQ, *SCK = fb + OFF_SCK;
    float *ALP = fb + OFF_AL, *BET = fb + OFF_BE, *SR = fb + OFF_SR;
    f16 *xh = (f16*)(bb + BO_XH), *xl = (f16*)(bb + BO_XL);
    f16 *wqkh = (f16*)(bb + BO_WQKH), *wqkl = (f16*)(bb + BO_WQKL);
    f16 *wv16 = (f16*)(bb + BO_WV), *wo16 = (f16*)(bb + BO_WO);
    f16 *rf16 = (f16*)(bb + BO_RF);
    f16 *Qf = (f16*)(bb + BO_QFH);
    f16 *KfT = (f16*)(bb + BO_KFT);
    f16 *VT = (f16*)(bb + BO_VT);
    f16 *KVT = (f16*)(bb + BO_KVT);
    f16 *ah = (f16*)(bb + BO_AH);

    cudaFuncSetAttribute(gemm3, cudaFuncAttributeMaxDynamicSharedMemorySize, SMEM_G3);
    cudaFuncSetAttribute(gemm1v, cudaFuncAttributeMaxDynamicSharedMemorySize, SMEM_G1V);
    cudaFuncSetAttribute(gemm1, cudaFuncAttributeMaxDynamicSharedMemorySize, SMEM_G1);
    cudaFuncSetAttribute(phi_q_kernel, cudaFuncAttributeMaxDynamicSharedMemorySize, SMEM_PHI);
    cudaFuncSetAttribute(phi_k_kernel, cudaFuncAttributeMaxDynamicSharedMemorySize, SMEM_PHI);
    cudaFuncSetAttribute(kv_gemm, cudaFuncAttributeMaxDynamicSharedMemorySize, SMEM_KV);
    cudaFuncSetAttribute(qkv_gemm, cudaFuncAttributeMaxDynamicSharedMemorySize, SMEM_QKV);

    int wn4 = D_ * D_ / 4;
    split16_kernel<<<(int)(SZ_BTD / 4 / 256), 256>>>(x, xh, xl, (int)(SZ_BTD / 4));
    split16_kernel<<<wn4 / 256, 256>>>(wq, wqkh, wqkl, wn4);
    split16_kernel<<<wn4 / 256, 256>>>(wk, wqkh + (size_t)D_ * D_, wqkl + (size_t)D_ * D_, wn4);
    conv16_kernel<<<wn4 / 256, 256>>>(wv, wv16, wn4);
    conv16_kernel<<<wn4 / 256, 256>>>(wo, wo16, wn4);
    conv16_kernel<<<16, 256>>>(rf, rf16, 4096);

    gemm3<<<dim3(16, 64), 256, SMEM_G3>>>(xh, xl, wqkh, wqkl, QKp, B_ * T_, 2048, D_);
    gemm1v<<<dim3(8, 64), 256, SMEM_G1V>>>(xh, wv16, VT, B_ * T_, D_, D_);
    vt_ones_kernel<<<BH_, 256>>>(VT);

    dim3 gPhi(T_ / 128, 2, BH_);
    phi_q_kernel<<<gPhi, 256, SMEM_PHI>>>(QKp, rf16, Qf, SCQ);
    knorm_kernel<<<dim3(T_ / 128, BH_), 256>>>(QKp, SCK);
    alphabeta_kernel<<<BH_, 256>>>(SCK, ALP, BET);
    phi_k_kernel<<<gPhi, 256, SMEM_PHI>>>(QKp, rf16, BET, KfT);

    zero_kvt_kernel<<<BH_, 256>>>(KVT);
    kv_gemm<<<dim3(FD_ / 128, BH_), 256, SMEM_KV>>>(KfT, VT, ALP, BET, KVT);
    srow_kernel<<<(B_ * T_) / 256, 256>>>(SCQ, ALP, SR);

    qkv_gemm<<<dim3(T_ / 128, BH_), 256, SMEM_QKV>>>(Qf, KVT, SCQ, ALP, SR, ah);

    gemm1<<<dim3(8, 64), 256, SMEM_G1>>>(ah, wo16, SR, out, B_ * T_, D_, D_);
}

// round 15
// speedup vs baseline: 3.9011x; 1.0372x over previous
#include <cuda_runtime.h>
#include <cuda_bf16.h>
#include <cuda_fp16.h>
#include <cstdint>
typedef __nv_bfloat16 bf16;
typedef __half f16;

#define B_   2
#define T_   4096
#define D_   1024
#define H_   16
#define DH_  64
#define FD_  512
#define BH_  (B_*H_)
#define SZ_BTD ((size_t)B_*T_*D_)
#define SZ_F   ((size_t)BH_*T_*FD_)

// fp32 scratch
#define OFF_Q   ((size_t)0)
#define OFF_K   (SZ_BTD)
#define OFF_SCQ (2*SZ_BTD)
#define OFF_SCK (OFF_SCQ + (size_t)BH_*T_)
#define OFF_AL  (OFF_SCK + (size_t)BH_*T_)
#define OFF_BE  (OFF_AL + BH_)
#define OFF_SR  (OFF_BE + BH_)
__device__ float g_buf[OFF_SR + (size_t)B_*T_];

// 2-byte scratch
#define BO_XH    ((size_t)0)
#define BO_XL    (SZ_BTD)
#define BO_WQH   (2*SZ_BTD)
#define BO_WQL   (BO_WQH + (size_t)D_*D_)
#define BO_WK    (BO_WQL + (size_t)D_*D_)
#define BO_WV    (BO_WK + (size_t)D_*D_)
#define BO_WO    (BO_WV + (size_t)D_*D_)
#define BO_RF    (BO_WO + (size_t)D_*D_)
#define BO_QF    (BO_RF + 16384)
#define BO_KFT   (BO_QF + SZ_F)
#define BO_VT    (BO_KFT + SZ_F)                  // [bh][80][T]; row64=ones
#define BO_KVT   (BO_VT + (size_t)BH_*80*T_)
#define BO_AH    (BO_KVT + (size_t)BH_*80*FD_)
__device__ bf16 g_bf[BO_AH + SZ_BTD];

__device__ __forceinline__ uint32_t smem_to_u32(const void* p) {
    uint32_t a;
    asm("{ .reg .u64 t; cvta.to.shared.u64 t, %1; cvt.u32.u64 %0, t; }" : "=r"(a) : "l"(p));
    return a;
}
#define SWZ(o) ((o) ^ (((o) >> 3) & 0x70))
__device__ __forceinline__ void cp_async16(uint32_t s, const void* g) {
    asm volatile("cp.async.cg.shared.global [%0], [%1], 16;" :: "r"(s), "l"(g));
}
__device__ __forceinline__ void cp_commit() { asm volatile("cp.async.commit_group;" ::: "memory"); }
template <int N> __device__ __forceinline__ void cp_wait() {
    asm volatile("cp.async.wait_group %0;" :: "n"(N) : "memory");
}
__device__ __forceinline__ void ldsm_x4(uint32_t& r0, uint32_t& r1, uint32_t& r2, uint32_t& r3, uint32_t a) {
    asm volatile("ldmatrix.sync.aligned.m8n8.x4.shared.b16 {%0,%1,%2,%3}, [%4];"
                 : "=r"(r0), "=r"(r1), "=r"(r2), "=r"(r3) : "r"(a));
}
__device__ __forceinline__ void ldsm_x2(uint32_t& r0, uint32_t& r1, uint32_t a) {
    asm volatile("ldmatrix.sync.aligned.m8n8.x2.shared.b16 {%0,%1}, [%2];"
                 : "=r"(r0), "=r"(r1) : "r"(a));
}
__device__ __forceinline__ void mma_f16(float* c, const uint32_t* a, const uint32_t* b) {
    asm volatile("mma.sync.aligned.m16n8k16.row.col.f32.f16.f16.f32 "
                 "{%0,%1,%2,%3}, {%4,%5,%6,%7}, {%8,%9}, {%0,%1,%2,%3};"
                 : "+f"(c[0]), "+f"(c[1]), "+f"(c[2]), "+f"(c[3])
                 : "r"(a[0]), "r"(a[1]), "r"(a[2]), "r"(a[3]), "r"(b[0]), "r"(b[1]));
}
__device__ __forceinline__ void store_pair_h(f16* ph, f16* pl, size_t off, float x0, float x1) {
    f16 h0 = __float2half_rn(x0), h1 = __float2half_rn(x1);
    __half2 hp = __halves2half2(h0, h1);
    *(uint32_t*)(ph + off) = *(uint32_t*)&hp;
    __half2 lp = __halves2half2(__float2half_rn(x0 - __half2float(h0)),
                                __float2half_rn(x1 - __half2float(h1)));
    *(uint32_t*)(pl + off) = *(uint32_t*)&lp;
}
__device__ __forceinline__ void store_h2(f16* p, size_t off, float x0, float x1) {
    __half2 hp = __halves2half2(__float2half_rn(x0), __float2half_rn(x1));
    *(uint32_t*)(p + off) = *(uint32_t*)&hp;
}
__device__ __forceinline__ void fast_sincos(float x, float& s, float& c) {
    float kf = rintf(x * 0.63661977f);
    int q = (int)kf;
    float r = fmaf(kf, -1.5707963705062866f, x);
    r = fmaf(kf, 4.3711388286738e-8f, r);
    float r2 = r * r;
    float sp = fmaf(-1.98412698e-4f, r2, 8.33333333e-3f);
    sp = fmaf(sp, r2, -1.66666667e-1f) * r2;
    float sr = fmaf(sp, r, r);
    float cp = fmaf(2.48015873e-5f, r2, -1.38888889e-3f);
    cp = fmaf(cp, r2, 4.16666667e-2f);
    cp = fmaf(cp, r2, -0.5f);
    float cr = fmaf(cp, r2, 1.0f);
    if (q & 1) { float t = sr; sr = cr; cr = -t; }
    if (q & 2) { sr = -sr; cr = -cr; }
    s = sr; c = cr;
}

#define TILE_B 16384

// ======== fp16 3-pass GEMM (Q projection) ========
#define BUF3   (4*TILE_B)
#define SMEM_G3 (2*BUF3)
__global__ void __launch_bounds__(256)
gemm3(const f16* __restrict__ Ah, const f16* __restrict__ Al,
      const f16* __restrict__ Bh, const f16* __restrict__ Bl,
      float* __restrict__ C, int M, int N, int K)
{
    extern __shared__ char smem[];
    const uint32_t sb = smem_to_u32(smem);
    const int tid = threadIdx.x, wid = tid >> 5, lane = tid & 31;
    const int bn = blockIdx.x << 7, bm = blockIdx.y << 7;
    const int wm = (wid >> 2) << 6, wn = (wid & 3) << 5;
    const int nchunk = K >> 6;
    const int lr = lane & 15, lc = lane >> 4, br = lane & 7, bk = (lane >> 3) & 1;
    float acc[4][4][4];
#pragma unroll
    for (int i = 0; i < 4; i++)
#pragma unroll
        for (int j = 0; j < 4; j++)
#pragma unroll
            for (int r = 0; r < 4; r++) acc[i][j][r] = 0.f;
    const f16* gs[4] = {Ah, Al, Bh, Bl};
    const int rb[4] = {bm, bm, bn, bn};
    auto load = [&](int kc, int buf) {
        uint32_t base = sb + buf * BUF3;
        int ke = kc << 6;
#pragma unroll
        for (int t = 0; t < 4; t++)
#pragma unroll
            for (int i = 0; i < 4; i++) {
                int idx = tid + (i << 8), r = idx >> 3, c = idx & 7;
                cp_async16(base + t * TILE_B + SWZ(r * 128 + c * 16),
                           gs[t] + (size_t)(rb[t] + r) * K + ke + c * 8);
            }
    };
    load(0, 0); cp_commit();
    for (int kc = 0; kc < nchunk; kc++) {
        int cur = kc & 1;
        if (kc + 1 < nchunk) { load(kc + 1, cur ^ 1); cp_commit(); cp_wait<1>(); }
        else cp_wait<0>();
        __syncthreads();
        uint32_t bA = sb + cur * BUF3;
#pragma unroll
        for (int ks = 0; ks < 4; ks++) {
            uint32_t a_h[4][4], a_l[4][4], b_h[4][2], b_l[4][2];
#pragma unroll
            for (int i = 0; i < 4; i++) {
                uint32_t o = SWZ((wm + i * 16 + lr) * 128 + ks * 32 + lc * 16);
                ldsm_x4(a_h[i][0], a_h[i][1], a_h[i][2], a_h[i][3], bA + o);
                ldsm_x4(a_l[i][0], a_l[i][1], a_l[i][2], a_l[i][3], bA + TILE_B + o);
            }
#pragma unroll
            for (int j = 0; j < 4; j++) {
                uint32_t o = SWZ((wn + j * 8 + br) * 128 + ks * 32 + bk * 16);
                ldsm_x2(b_h[j][0], b_h[j][1], bA + 2 * TILE_B + o);
                ldsm_x2(b_l[j][0], b_l[j][1], bA + 3 * TILE_B + o);
            }
#pragma unroll
            for (int i = 0; i < 4; i++)
#pragma unroll
                for (int j = 0; j < 4; j++) {
                    mma_f16(acc[i][j], a_h[i], b_h[j]);
                    mma_f16(acc[i][j], a_h[i], b_l[j]);
                    mma_f16(acc[i][j], a_l[i], b_h[j]);
                }
        }
        __syncthreads();
    }
#pragma unroll
    for (int i = 0; i < 4; i++) {
        int row = bm + wm + i * 16 + (lane >> 2);
#pragma unroll
        for (int j = 0; j < 4; j++) {
            int col = bn + wn + j * 8 + ((lane & 3) << 1);
            *(float2*)&C[(size_t)row * N + col]       = make_float2(acc[i][j][0], acc[i][j][1]);
            *(float2*)&C[(size_t)(row + 8) * N + col] = make_float2(acc[i][j][2], acc[i][j][3]);
        }
    }
}

// ======== fp16 2-pass GEMM (K projection): A hi/lo, B single ========
#define BUF2   (3*TILE_B)
#define SMEM_G2 (2*BUF2)
__global__ void __launch_bounds__(256)
gemm2(const f16* __restrict__ Ah, const f16* __restrict__ Al,
      const f16* __restrict__ Bm, float* __restrict__ C, int M, int N, int K)
{
    extern __shared__ char smem[];
    const uint32_t sb = smem_to_u32(smem);
    const int tid = threadIdx.x, wid = tid >> 5, lane = tid & 31;
    const int bn = blockIdx.x << 7, bm = blockIdx.y << 7;
    const int wm = (wid >> 2) << 6, wn = (wid & 3) << 5;
    const int nchunk = K >> 6;
    const int lr = lane & 15, lc = lane >> 4, br = lane & 7, bk = (lane >> 3) & 1;
    float acc[4][4][4];
#pragma unroll
    for (int i = 0; i < 4; i++)
#pragma unroll
        for (int j = 0; j < 4; j++)
#pragma unroll
            for (int r = 0; r < 4; r++) acc[i][j][r] = 0.f;
    auto load = [&](int kc, int buf) {
        uint32_t base = sb + buf * BUF2;
        int ke = kc << 6;
#pragma unroll
        for (int i = 0; i < 4; i++) {
            int idx = tid + (i << 8), r = idx >> 3, c = idx & 7;
            uint32_t so = SWZ(r * 128 + c * 16);
            cp_async16(base + so,              Ah + (size_t)(bm + r) * K + ke + c * 8);
            cp_async16(base + TILE_B + so,     Al + (size_t)(bm + r) * K + ke + c * 8);
            cp_async16(base + 2 * TILE_B + so, Bm + (size_t)(bn + r) * K + ke + c * 8);
        }
    };
    load(0, 0); cp_commit();
    for (int kc = 0; kc < nchunk; kc++) {
        int cur = kc & 1;
        if (kc + 1 < nchunk) { load(kc + 1, cur ^ 1); cp_commit(); cp_wait<1>(); }
        else cp_wait<0>();
        __syncthreads();
        uint32_t bA = sb + cur * BUF2;
#pragma unroll
        for (int ks = 0; ks < 4; ks++) {
            uint32_t a_h[4][4], a_l[4][4], b_[4][2];
#pragma unroll
            for (int i = 0; i < 4; i++) {
                uint32_t o = SWZ((wm + i * 16 + lr) * 128 + ks * 32 + lc * 16);
                ldsm_x4(a_h[i][0], a_h[i][1], a_h[i][2], a_h[i][3], bA + o);
                ldsm_x4(a_l[i][0], a_l[i][1], a_l[i][2], a_l[i][3], bA + TILE_B + o);
            }
#pragma unroll
            for (int j = 0; j < 4; j++) {
                uint32_t o = SWZ((wn + j * 8 + br) * 128 + ks * 32 + bk * 16);
                ldsm_x2(b_[j][0], b_[j][1], bA + 2 * TILE_B + o);
            }
#pragma unroll
            for (int i = 0; i < 4; i++)
#pragma unroll
                for (int j = 0; j < 4; j++) {
                    mma_f16(acc[i][j], a_h[i], b_[j]);
                    mma_f16(acc[i][j], a_l[i], b_[j]);
                }
        }
        __syncthreads();
    }
#pragma unroll
    for (int i = 0; i < 4; i++) {
        int row = bm + wm + i * 16 + (lane >> 2);
#pragma unroll
        for (int j = 0; j < 4; j++) {
            int col = bn + wn + j * 8 + ((lane & 3) << 1);
            *(float2*)&C[(size_t)row * N + col]       = make_float2(acc[i][j][0], acc[i][j][1]);
            *(float2*)&C[(size_t)(row + 8) * N + col] = make_float2(acc[i][j][2], acc[i][j][3]);
        }
    }
}

// ======== fp16 1-pass GEMM, V projection, fused VT transpose ========
#define BUF1   (2*TILE_B)
#define SMEM_G1V 69632
__global__ void __launch_bounds__(256)
gemm1v(const f16* __restrict__ Am, const f16* __restrict__ Bm,
       f16* __restrict__ VT, int M, int N, int K)
{
    extern __shared__ char smem[];
    const uint32_t sb = smem_to_u32(smem);
    const int tid = threadIdx.x, wid = tid >> 5, lane = tid & 31;
    const int bn = blockIdx.x << 7, bm = blockIdx.y << 7;
    const int wm = (wid >> 2) << 6, wn = (wid & 3) << 5;
    const int nchunk = K >> 6;
    const int lr = lane & 15, lc = lane >> 4, br = lane & 7, bk = (lane >> 3) & 1;
    float acc[4][4][4];
#pragma unroll
    for (int i = 0; i < 4; i++)
#pragma unroll
        for (int j = 0; j < 4; j++)
#pragma unroll
            for (int r = 0; r < 4; r++) acc[i][j][r] = 0.f;
    auto load = [&](int kc, int buf) {
        uint32_t base = sb + buf * BUF1;
        int ke = kc << 6;
#pragma unroll
        for (int i = 0; i < 4; i++) {
            int idx = tid + (i << 8), r = idx >> 3, c = idx & 7;
            uint32_t so = SWZ(r * 128 + c * 16);
            cp_async16(base + so,          Am + (size_t)(bm + r) * K + ke + c * 8);
            cp_async16(base + TILE_B + so, Bm + (size_t)(bn + r) * K + ke + c * 8);
        }
    };
    load(0, 0); cp_commit();
    for (int kc = 0; kc < nchunk; kc++) {
        int cur = kc & 1;
        if (kc + 1 < nchunk) { load(kc + 1, cur ^ 1); cp_commit(); cp_wait<1>(); }
        else cp_wait<0>();
        __syncthreads();
        uint32_t bA = sb + cur * BUF1;
#pragma unroll
        for (int ks = 0; ks < 4; ks++) {
            uint32_t a_[4][4], b_[4][2];
#pragma unroll
            for (int i = 0; i < 4; i++) {
                uint32_t o = SWZ((wm + i * 16 + lr) * 128 + ks * 32 + lc * 16);
                ldsm_x4(a_[i][0], a_[i][1], a_[i][2], a_[i][3], bA + o);
            }
#pragma unroll
            for (int j = 0; j < 4; j++) {
                uint32_t o = SWZ((wn + j * 8 + br) * 128 + ks * 32 + bk * 16);
                ldsm_x2(b_[j][0], b_[j][1], bA + TILE_B + o);
            }
#pragma unroll
            for (int i = 0; i < 4; i++)
#pragma unroll
                for (int j = 0; j < 4; j++)
                    mma_f16(acc[i][j], a_[i], b_[j]);
        }
        __syncthreads();
    }
    float* stage = (float*)smem;
#pragma unroll
    for (int i = 0; i < 4; i++) {
        int row = wm + i * 16 + (lane >> 2);
#pragma unroll
        for (int j = 0; j < 4; j++) {
            int col = wn + j * 8 + ((lane & 3) << 1);
            stage[col * 132 + row]           = acc[i][j][0];
            stage[(col + 1) * 132 + row]     = acc[i][j][1];
            stage[col * 132 + row + 8]       = acc[i][j][2];
            stage[(col + 1) * 132 + row + 8] = acc[i][j][3];
        }
    }
    __syncthreads();
    int b = bm >> 12;
    int dl = tid >> 1, ts = (tid & 1) << 6;
    int h = (bn + dl) >> 6, v = (bn + dl) & 63;
    size_t base = ((size_t)(b * H_ + h) * 80 + v) * T_ + (bm & 4095) + ts;
#pragma unroll
    for (int p = 0; p < 32; p++)
        store_h2(VT, base + p * 2, stage[dl * 132 + ts + p * 2], stage[dl * 132 + ts + p * 2 + 1]);
}

// ======== fp16 1-pass GEMM with row scale (O projection) ========
#define SMEM_G1 (2*BUF1)
__global__ void __launch_bounds__(256)
gemm1(const f16* __restrict__ Am, const f16* __restrict__ Bm,
      const float* __restrict__ S, float* __restrict__ C, int M, int N, int K)
{
    extern __shared__ char smem[];
    const uint32_t sb = smem_to_u32(smem);
    const int tid = threadIdx.x, wid = tid >> 5, lane = tid & 31;
    const int bn = blockIdx.x << 7, bm = blockIdx.y << 7;
    const int wm = (wid >> 2) << 6, wn = (wid & 3) << 5;
    const int nchunk = K >> 6;
    const int lr = lane & 15, lc = lane >> 4, br = lane & 7, bk = (lane >> 3) & 1;
    float acc[4][4][4];
#pragma unroll
    for (int i = 0; i < 4; i++)
#pragma unroll
        for (int j = 0; j < 4; j++)
#pragma unroll
            for (int r = 0; r < 4; r++) acc[i][j][r] = 0.f;
    auto load = [&](int kc, int buf) {
        uint32_t base = sb + buf * BUF1;
        int ke = kc << 6;
#pragma unroll
        for (int i = 0; i < 4; i++) {
            int idx = tid + (i << 8), r = idx >> 3, c = idx & 7;
            uint32_t so = SWZ(r * 128 + c * 16);
            cp_async16(base + so,          Am + (size_t)(bm + r) * K + ke + c * 8);
            cp_async16(base + TILE_B + so, Bm + (size_t)(bn + r) * K + ke + c * 8);
        }
    };
    load(0, 0); cp_commit();
    for (int kc = 0; kc < nchunk; kc++) {
        int cur = kc & 1;
        if (kc + 1 < nchunk) { load(kc + 1, cur ^ 1); cp_commit(); cp_wait<1>(); }
        else cp_wait<0>();
        __syncthreads();
        uint32_t bA = sb + cur * BUF1;
#pragma unroll
        for (int ks = 0; ks < 4; ks++) {
            uint32_t a_[4][4], b_[4][2];
#pragma unroll
            for (int i = 0; i < 4; i++) {
                uint32_t o = SWZ((wm + i * 16 + lr) * 128 + ks * 32 + lc * 16);
                ldsm_x4(a_[i][0], a_[i][1], a_[i][2], a_[i][3], bA + o);
            }
#pragma unroll
            for (int j = 0; j < 4; j++) {
                uint32_t o = SWZ((wn + j * 8 + br) * 128 + ks * 32 + bk * 16);
                ldsm_x2(b_[j][0], b_[j][1], bA + TILE_B + o);
            }
#pragma unroll
            for (int i = 0; i < 4; i++)
#pragma unroll
                for (int j = 0; j < 4; j++)
                    mma_f16(acc[i][j], a_[i], b_[j]);
        }
        __syncthreads();
    }
#pragma unroll
    for (int i = 0; i < 4; i++) {
        int row = bm + wm + i * 16 + (lane >> 2);
        float s0 = S[row], s1 = S[row + 8];
#pragma unroll
        for (int j = 0; j < 4; j++) {
            int col = bn + wn + j * 8 + ((lane & 3) << 1);
            *(float2*)&C[(size_t)row * N + col]       = make_float2(acc[i][j][0] * s0, acc[i][j][1] * s0);
            *(float2*)&C[(size_t)(row + 8) * N + col] = make_float2(acc[i][j][2] * s1, acc[i][j][3] * s1);
        }
    }
}

// ======== conversions ========
__global__ void __launch_bounds__(256) split16_kernel(const float* __restrict__ in,
                                                      f16* __restrict__ hi, f16* __restrict__ lo, int n4)
{
    int i = blockIdx.x * 256 + threadIdx.x;
    if (i >= n4) return;
    float4 v = ((const float4*)in)[i];
    store_pair_h(hi, lo, (size_t)i * 4, v.x, v.y);
    store_pair_h(hi, lo, (size_t)i * 4 + 2, v.z, v.w);
}
__global__ void __launch_bounds__(256) conv16_kernel(const float* __restrict__ in,
                                                     f16* __restrict__ out, int n4)
{
    int i = blockIdx.x * 256 + threadIdx.x;
    if (i >= n4) return;
    float4 v = ((const float4*)in)[i];
    store_h2(out, (size_t)i * 4, v.x, v.y);
    store_h2(out, (size_t)i * 4 + 2, v.z, v.w);
}

// ======== phi kernels (1-pass MMA; tiles single fp16, norms fp32) ========
#define PA  0
#define PB  16384
#define PSC 32768
#define PNP 33280
#define SMEM_PHI 34304

__device__ __forceinline__ void conv_tile_h1(const float* g, int ld, char* sm, int dst,
                                             float* np, int tid) {
    int r = tid >> 1, cb = (tid & 1) << 5;
    float s = 0.f;
    const float* gp = g + (size_t)r * ld + cb;
#pragma unroll
    for (int k = 0; k < 8; k++) {
        float4 v = *(const float4*)(gp + k * 4);
        s = fmaf(v.x, v.x, s); s = fmaf(v.y, v.y, s);
        s = fmaf(v.z, v.z, s); s = fmaf(v.w, v.w, s);
        uint32_t sw = SWZ((uint32_t)(r * 128 + (cb + k * 4) * 2));
        __half2 hp0 = __halves2half2(__float2half_rn(v.x), __float2half_rn(v.y));
        __half2 hp1 = __halves2half2(__float2half_rn(v.z), __float2half_rn(v.w));
        *(uint32_t*)(sm + dst + sw) = *(uint32_t*)&hp0;
        *(uint32_t*)(sm + dst + sw + 4) = *(uint32_t*)&hp1;
    }
    np[tid] = s;
}

// phi_q: A = Q tile (single fp16) at PA, B = rf at PB; Qf single fp16
__global__ void __launch_bounds__(256) phi_q_kernel(
    const float* __restrict__ Q, const f16* __restrict__ rf16,
    f16* __restrict__ Qf, float* __restrict__ scq)
{
    extern __shared__ char sm[];
    const uint32_t sb = smem_to_u32(sm);
    const int tid = threadIdx.x, wid = tid >> 5, lane = tid & 31;
    const int t0 = blockIdx.x << 7, m0c = blockIdx.y << 7, bh = blockIdx.z;
    const int b = bh >> 4, h = bh & 15;
    float* np = (float*)(sm + PNP);
#pragma unroll
    for (int i = 0; i < 4; i++) {
        int idx = tid + (i << 8), r = idx >> 3, c = idx & 7;
        cp_async16(sb + PB + SWZ(r * 128 + c * 16), rf16 + (size_t)(m0c + r) * DH_ + c * 8);
    }
    cp_commit();
    conv_tile_h1(&Q[((size_t)(b * T_ + t0)) * D_ + h * DH_], D_, sm, PA, np, tid);
    __syncthreads();
    if (tid < 128 && blockIdx.y == 0)
        scq[(size_t)bh * T_ + t0 + tid] = __expf(-0.5f * (np[2 * tid] + np[2 * tid + 1])) * 0.0625f;
    cp_wait<0>();
    __syncthreads();
    const int wt = (wid >> 2) << 6, wm = (wid & 3) << 5;
    const int lr = lane & 15, lc = lane >> 4, br = lane & 7, bk = (lane >> 3) & 1;
    float acc[4][4][4];
#pragma unroll
    for (int i = 0; i < 4; i++)
#pragma unroll
        for (int j = 0; j < 4; j++)
#pragma unroll
            for (int r = 0; r < 4; r++) acc[i][j][r] = 0.f;
#pragma unroll
    for (int ks = 0; ks < 4; ks++) {
        uint32_t a_[4][4], b_[4][2];
#pragma unroll
        for (int i = 0; i < 4; i++) {
            uint32_t o = SWZ((wt + i * 16 + lr) * 128 + ks * 32 + lc * 16);
            ldsm_x4(a_[i][0], a_[i][1], a_[i][2], a_[i][3], sb + PA + o);
        }
#pragma unroll
        for (int j = 0; j < 4; j++) {
            uint32_t o = SWZ((wm + j * 8 + br) * 128 + ks * 32 + bk * 16);
            ldsm_x2(b_[j][0], b_[j][1], sb + PB + o);
        }
#pragma unroll
        for (int i = 0; i < 4; i++)
#pragma unroll
            for (int j = 0; j < 4; j++)
                mma_f16(acc[i][j], a_[i], b_[j]);
    }
#pragma unroll
    for (int i = 0; i < 4; i++) {
        int r0 = wt + i * 16 + (lane >> 2);
        size_t rb0 = ((size_t)bh * T_ + t0 + r0) * FD_ + m0c;
        size_t rb1 = rb0 + (size_t)8 * FD_;
#pragma unroll
        for (int j = 0; j < 4; j++) {
            int mc = wm + j * 8 + ((lane & 3) << 1);
            float sn0, cs0, sn1, cs1;
            fast_sincos(acc[i][j][0], sn0, cs0);
            fast_sincos(acc[i][j][1], sn1, cs1);
            store_h2(Qf, rb0 + mc, cs0, cs1);
            store_h2(Qf, rb0 + 256 + mc, sn0, sn1);
            fast_sincos(acc[i][j][2], sn0, cs0);
            fast_sincos(acc[i][j][3], sn1, cs1);
            store_h2(Qf, rb1 + mc, cs0, cs1);
            store_h2(Qf, rb1 + 256 + mc, sn0, sn1);
        }
    }
}

// phi_k: A = rf at PA, B = K tile (single fp16) at PB; KfT' = phi_k/beta single fp16
__global__ void __launch_bounds__(256) phi_k_kernel(
    const float* __restrict__ Kg, const f16* __restrict__ rf16,
    const float* __restrict__ beta, f16* __restrict__ KfT)
{
    extern __shared__ char sm[];
    const uint32_t sb = smem_to_u32(sm);
    const int tid = threadIdx.x, wid = tid >> 5, lane = tid & 31;
    const int t0 = blockIdx.x << 7, m0c = blockIdx.y << 7, bh = blockIdx.z;
    const int b = bh >> 4, h = bh & 15;
    float* scale = (float*)(sm + PSC);
    float* np = (float*)(sm + PNP);
    const float gamma = 1.f / beta[bh];
#pragma unroll
    for (int i = 0; i < 4; i++) {
        int idx = tid + (i << 8), r = idx >> 3, c = idx & 7;
        cp_async16(sb + PA + SWZ(r * 128 + c * 16), rf16 + (size_t)(m0c + r) * DH_ + c * 8);
    }
    cp_commit();
    conv_tile_h1(&Kg[((size_t)(b * T_ + t0)) * D_ + h * DH_], D_, sm, PB, np, tid);
    __syncthreads();
    if (tid < 128)
        scale[tid] = __expf(-0.5f * (np[2 * tid] + np[2 * tid + 1])) * 0.0625f * gamma;
    cp_wait<0>();
    __syncthreads();
    const int wm = (wid >> 2) << 6, wt = (wid & 3) << 5;
    const int lr = lane & 15, lc = lane >> 4, br = lane & 7, bk = (lane >> 3) & 1;
    float acc[4][4][4];
#pragma unroll
    for (int i = 0; i < 4; i++)
#pragma unroll
        for (int j = 0; j < 4; j++)
#pragma unroll
            for (int r = 0; r < 4; r++) acc[i][j][r] = 0.f;
#pragma unroll
    for (int ks = 0; ks < 4; ks++) {
        uint32_t a_[4][4], b_[4][2];
#pragma unroll
        for (int i = 0; i < 4; i++) {
            uint32_t o = SWZ((wm + i * 16 + lr) * 128 + ks * 32 + lc * 16);
            ldsm_x4(a_[i][0], a_[i][1], a_[i][2], a_[i][3], sb + PA + o);
        }
#pragma unroll
        for (int j = 0; j < 4; j++) {
            uint32_t o = SWZ((wt + j * 8 + br) * 128 + ks * 32 + bk * 16);
            ldsm_x2(b_[j][0], b_[j][1], sb + PB + o);
        }
#pragma unroll
        for (int i = 0; i < 4; i++)
#pragma unroll
            for (int j = 0; j < 4; j++)
                mma_f16(acc[i][j], a_[i], b_[j]);
    }
#pragma unroll
    for (int i = 0; i < 4; i++) {
        int r0 = wm + i * 16 + (lane >> 2);
        size_t rc0 = ((size_t)bh * FD_ + m0c + r0) * T_ + t0;
        size_t rs0 = rc0 + (size_t)256 * T_;
        size_t rc1 = rc0 + (size_t)8 * T_, rs1 = rs0 + (size_t)8 * T_;
#pragma unroll
        for (int j = 0; j < 4; j++) {
            int tc = wt + j * 8 + ((lane & 3) << 1);
            float sc0 = scale[tc], sc1 = scale[tc + 1];
            float sn0, cs0, sn1, cs1;
            fast_sincos(acc[i][j][0], sn0, cs0);
            fast_sincos(acc[i][j][1], sn1, cs1);
            store_h2(KfT, rc0 + tc, cs0 * sc0, cs1 * sc1);
            store_h2(KfT, rs0 + tc, sn0 * sc0, sn1 * sc1);
            fast_sincos(acc[i][j][2], sn0, cs0);
            fast_sincos(acc[i][j][3], sn1, cs1);
            store_h2(KfT, rc1 + tc, cs0 * sc0, cs1 * sc1);
            store_h2(KfT, rs1 + tc, sn0 * sc0, sn1 * sc1);
        }
    }
}

// ======== knorm / alphabeta / srow / vt_ones / zero_kvt ========
__global__ void __launch_bounds__(256) knorm_kernel(const float* __restrict__ Kg,
                                                    float* __restrict__ sck)
{
    __shared__ float np[256];
    const int tid = threadIdx.x;
    const int t0 = blockIdx.x << 7, bh = blockIdx.y;
    const int b = bh >> 4, h = bh & 15;
    int r = tid >> 1, cb = (tid & 1) << 5;
    const float* gp = Kg + ((size_t)(b * T_ + t0 + r)) * D_ + h * DH_ + cb;
    float s = 0.f;
#pragma unroll
    for (int k = 0; k < 8; k++) {
        float4 v = *(const float4*)(gp + k * 4);
        s = fmaf(v.x, v.x, s); s = fmaf(v.y, v.y, s);
        s = fmaf(v.z, v.z, s); s = fmaf(v.w, v.w, s);
    }
    np[tid] = s;
    __syncthreads();
    if (tid < 128)
        sck[(size_t)bh * T_ + t0 + tid] = __expf(-0.5f * (np[2 * tid] + np[2 * tid + 1])) * 0.0625f;
}

__global__ void __launch_bounds__(256) alphabeta_kernel(const float* __restrict__ sck,
                                                        float* __restrict__ alpha,
                                                        float* __restrict__ beta)
{
    __shared__ float rs[256], rm[256];
    const int bh = blockIdx.x, tid = threadIdx.x;
    float s = 0.f, m = 0.f;
    for (int i = tid; i < T_; i += 256) {
        float v = sck[(size_t)bh * T_ + i];
        s += v; m = fmaxf(m, v);
    }
    rs[tid] = s; rm[tid] = m;
    __syncthreads();
    for (int o = 128; o; o >>= 1) {
        if (tid < o) { rs[tid] += rs[tid + o]; rm[tid] = fmaxf(rm[tid], rm[tid + o]); }
        __syncthreads();
    }
    if (tid == 0) {
        alpha[bh] = 1.f / fmaxf(rs[0], 1e-30f);
        beta[bh]  = fmaxf(rm[0], 1e-37f);
    }
}

__global__ void __launch_bounds__(256) srow_kernel(const float* __restrict__ scq,
                                                   const float* __restrict__ alpha,
                                                   float* __restrict__ srow)
{
    int row = blockIdx.x * 256 + threadIdx.x;
    int b = row >> 12, t = row & 4095;
    float m = 0.f;
#pragma unroll
    for (int h = 0; h < H_; h++) {
        int bh = b * H_ + h;
        m = fmaxf(m, scq[(size_t)bh * T_ + t] / alpha[bh]);
    }
    srow[row] = fmaxf(m * 1e6f, 1e-30f);
}

__global__ void __launch_bounds__(256) vt_ones_kernel(f16* __restrict__ VT)
{
    const int bh = blockIdx.x;
    const f16 one = __float2half_rn(1.f), zero = __float2half_rn(0.f);
    for (int i = threadIdx.x; i < 8 * T_; i += 256) {
        int r = i >> 12, t = i & 4095;
        VT[((size_t)bh * 80 + 64 + r) * T_ + t] = (r == 0) ? one : zero;
    }
}

__global__ void __launch_bounds__(256) zero_kvt_kernel(f16* __restrict__ kvt)
{
    const int bh = blockIdx.x;
    for (int i = threadIdx.x; i < 15 * FD_; i += 256)
        kvt[((size_t)bh * 80 + 65) * FD_ + i] = __float2half_rn(0.f);
}

// ======== kv: KfT'(fp16) x VT(fp16, 72 rows)^T, 1-pass, fused Ksum ========
#define KA   0
#define KB   16384
#define KBUF 26624
#define SMEM_KV (2*KBUF)

__global__ void __launch_bounds__(256) kv_gemm(
    const f16* __restrict__ Am, const f16* __restrict__ Bm,
    const float* __restrict__ alpha, const float* __restrict__ beta,
    f16* __restrict__ kvt)
{
    extern __shared__ char sm[];
    const uint32_t sb = smem_to_u32(sm);
    const int tid = threadIdx.x, wid = tid >> 5, lane = tid & 31;
    const int m0 = blockIdx.x << 7, bh = blockIdx.y;
    const size_t ab = (size_t)bh * FD_ + m0, bb = (size_t)bh * 80;
    const int wm = (wid >> 1) << 5, wn = (wid & 1) * 40;
    const int lr = lane & 15, lc = lane >> 4, br = lane & 7, bk = (lane >> 3) & 1;
    float acc[2][5][4];
#pragma unroll
    for (int i = 0; i < 2; i++)
#pragma unroll
        for (int j = 0; j < 5; j++)
#pragma unroll
            for (int r = 0; r < 4; r++) acc[i][j][r] = 0.f;
    auto load = [&](int kc, int buf) {
        uint32_t base = sb + buf * KBUF;
        int ke = kc << 6;
#pragma unroll
        for (int i = 0; i < 4; i++) {
            int idx = tid + (i << 8), r = idx >> 3, c = idx & 7;
            cp_async16(base + KA + SWZ(r * 128 + c * 16), Am + (ab + r) * T_ + ke + c * 8);
        }
#pragma unroll
        for (int i = 0; i < 3; i++) {
            int idx = tid + (i << 8);
            if (idx < 576) {
                int r = idx >> 3, c = idx & 7;
                cp_async16(base + KB + SWZ(r * 128 + c * 16), Bm + (bb + r) * T_ + ke + c * 8);
            }
        }
    };
    load(0, 0); cp_commit();
    for (int kc = 0; kc < T_ / 64; kc++) {
        int cur = kc & 1;
        if (kc + 1 < T_ / 64) { load(kc + 1, cur ^ 1); cp_commit(); cp_wait<1>(); }
        else cp_wait<0>();
        __syncthreads();
        uint32_t bA = sb + cur * KBUF;
#pragma unroll
        for (int ks = 0; ks < 4; ks++) {
            uint32_t a_[2][4], b_[5][2];
#pragma unroll
            for (int i = 0; i < 2; i++) {
                uint32_t o = SWZ((wm + i * 16 + lr) * 128 + ks * 32 + lc * 16);
                ldsm_x4(a_[i][0], a_[i][1], a_[i][2], a_[i][3], bA + KA + o);
            }
#pragma unroll
            for (int j = 0; j < 5; j++) {
                uint32_t o = SWZ((wn + j * 8 + br) * 128 + ks * 32 + bk * 16);
                ldsm_x2(b_[j][0], b_[j][1], bA + KB + o);
            }
#pragma unroll
            for (int i = 0; i < 2; i++)
#pragma unroll
                for (int j = 0; j < 5; j++)
                    mma_f16(acc[i][j], a_[i], b_[j]);
        }
        __syncthreads();
    }
    float* stage = (float*)sm;
#pragma unroll
    for (int i = 0; i < 2; i++) {
        int row = wm + i * 16 + (lane >> 2);
#pragma unroll
        for (int j = 0; j < 5; j++) {
            int col = wn + j * 8 + ((lane & 3) << 1);
            stage[col * 132 + row]           = acc[i][j][0];
            stage[(col + 1) * 132 + row]     = acc[i][j][1];
            stage[col * 132 + row + 8]       = acc[i][j][2];
            stage[(col + 1) * 132 + row + 8] = acc[i][j][3];
        }
    }
    __syncthreads();
    float av = alpha[bh] * beta[bh];
    int v = tid >> 2, fs = (tid & 3) << 5;
#pragma unroll
    for (int p = 0; p < 16; p++) {
        int f = fs + p * 2;
        store_h2(kvt, ((size_t)bh * 80 + v) * FD_ + m0 + f,
                 stage[v * 132 + f] * av, stage[v * 132 + f + 1] * av);
    }
    if (tid < 64) {
        int f = tid * 2;
        store_h2(kvt, ((size_t)bh * 80 + 64) * FD_ + m0 + f,
                 stage[64 * 132 + f] * av, stage[64 * 132 + f + 1] * av);
    }
}

// ======== qkv: Qf(single) x KVT'[80], 1-pass; epilogue Z + scales ========
#define QA   0
#define QB   16384
#define QBUF 26624
#define SMEM_QKV (2*QBUF)

__global__ void __launch_bounds__(256) qkv_gemm(
    const f16* __restrict__ Am, const f16* __restrict__ Bm,
    const float* __restrict__ scq, const float* __restrict__ alpha,
    const float* __restrict__ srow, f16* __restrict__ oh)
{
    extern __shared__ char sm[];
    __shared__ float zsm[128];
    const uint32_t sb = smem_to_u32(sm);
    const int tid = threadIdx.x, wid = tid >> 5, lane = tid & 31;
    const int t0 = blockIdx.x << 7, bh = blockIdx.y;
    const int b = bh >> 4, h = bh & 15;
    const size_t ab = (size_t)bh * T_ + t0, bb = (size_t)bh * 80;
    const int wm = (wid >> 1) << 5, wn = (wid & 1) * 40;
    const int lr = lane & 15, lc = lane >> 4, br = lane & 7, bk = (lane >> 3) & 1;
    float acc[2][5][4];
#pragma unroll
    for (int i = 0; i < 2; i++)
#pragma unroll
        for (int j = 0; j < 5; j++)
#pragma unroll
            for (int r = 0; r < 4; r++) acc[i][j][r] = 0.f;
    auto load = [&](int kc, int buf) {
        uint32_t base = sb + buf * QBUF;
        int ke = kc << 6;
#pragma unroll
        for (int i = 0; i < 4; i++) {
            int idx = tid + (i << 8), r = idx >> 3, c = idx & 7;
            cp_async16(base + QA + SWZ(r * 128 + c * 16), Am + (ab + r) * FD_ + ke + c * 8);
        }
#pragma unroll
        for (int i = 0; i < 3; i++) {
            int idx = tid + (i << 8);
            if (idx < 640) {
                int r = idx >> 3, c = idx & 7;
                cp_async16(base + QB + SWZ(r * 128 + c * 16), Bm + (bb + r) * FD_ + ke + c * 8);
            }
        }
    };
    load(0, 0); cp_commit();
    for (int kc = 0; kc < 8; kc++) {
        int cur = kc & 1;
        if (kc + 1 < 8) { load(kc + 1, cur ^ 1); cp_commit(); cp_wait<1>(); }
        else cp_wait<0>();
        __syncthreads();
        uint32_t bA = sb + cur * QBUF;
#pragma unroll
        for (int ks = 0; ks < 4; ks++) {
            uint32_t a_[2][4], b_[5][2];
#pragma unroll
            for (int i = 0; i < 2; i++) {
                uint32_t o = SWZ((wm + i * 16 + lr) * 128 + ks * 32 + lc * 16);
                ldsm_x4(a_[i][0], a_[i][1], a_[i][2], a_[i][3], bA + QA + o);
            }
#pragma unroll
            for (int j = 0; j < 5; j++) {
                uint32_t o = SWZ((wn + j * 8 + br) * 128 + ks * 32 + bk * 16);
                ldsm_x2(b_[j][0], b_[j][1], bA + QB + o);
            }
#pragma unroll
            for (int i = 0; i < 2; i++)
#pragma unroll
                for (int j = 0; j < 5; j++)
                    mma_f16(acc[i][j], a_[i], b_[j]);
        }
        __syncthreads();
    }
    if (wn == 40 && (lane & 3) == 0) {
#pragma unroll
        for (int i = 0; i < 2; i++) {
            int row = wm + i * 16 + (lane >> 2);
            zsm[row] = acc[i][3][0];
            zsm[row + 8] = acc[i][3][2];
        }
    }
    __syncthreads();
    float av = alpha[bh];
#pragma unroll
    for (int i = 0; i < 2; i++) {
#pragma unroll
        for (int half = 0; half < 2; half++) {
            int row = wm + i * 16 + (lane >> 2) + half * 8;
            float sq = scq[ab + row];
            float Zt = sq * zsm[row] / av;
            float d = fmaxf(Zt, 1e-6f);
            float mult = sq / (av * d * srow[(size_t)b * T_ + t0 + row]);
#pragma unroll
            for (int j = 0; j < 5; j++) {
                int col = wn + j * 8 + ((lane & 3) << 1);
                if (col < 64) {
                    size_t g0 = ((size_t)(b * T_ + t0 + row)) * D_ + h * DH_ + col;
                    store_h2(oh, g0, acc[i][j][half * 2] * mult, acc[i][j][half * 2 + 1] * mult);
                }
            }
        }
    }
}

// ======== launch ========
extern "C" void kernel_launch(void* const* d_in, const int* in_sizes, int n_in,
                              void* d_out, int out_size)
{
    const float* x  = (const float*)d_in[0];
    const float* wq = (const float*)d_in[1];
    const float* wk = (const float*)d_in[2];
    const float* wv = (const float*)d_in[3];
    const float* wo = (const float*)d_in[4];
    const float* rf = (const float*)d_in[5];
    float* out = (float*)d_out;

    float* fb = nullptr; cudaGetSymbolAddress((void**)&fb, g_buf);
    bf16*  bb = nullptr; cudaGetSymbolAddress((void**)&bb, g_bf);

    float *Qp = fb + OFF_Q, *Kp = fb + OFF_K;
    float *SCQ = fb + OFF_SCQ, *SCK = fb + OFF_SCK;
    float *ALP = fb + OFF_AL, *BET = fb + OFF_BE, *SR = fb + OFF_SR;
    f16 *xh = (f16*)(bb + BO_XH), *xl = (f16*)(bb + BO_XL);
    f16 *wqh = (f16*)(bb + BO_WQH), *wql = (f16*)(bb + BO_WQL);
    f16 *wk16 = (f16*)(bb + BO_WK);
    f16 *wv16 = (f16*)(bb + BO_WV), *wo16 = (f16*)(bb + BO_WO);
    f16 *rf16 = (f16*)(bb + BO_RF);
    f16 *Qf = (f16*)(bb + BO_QF);
    f16 *KfT = (f16*)(bb + BO_KFT);
    f16 *VT = (f16*)(bb + BO_VT);
    f16 *KVT = (f16*)(bb + BO_KVT);
    f16 *ah = (f16*)(bb + BO_AH);

    cudaFuncSetAttribute(gemm3, cudaFuncAttributeMaxDynamicSharedMemorySize, SMEM_G3);
    cudaFuncSetAttribute(gemm2, cudaFuncAttributeMaxDynamicSharedMemorySize, SMEM_G2);
    cudaFuncSetAttribute(gemm1v, cudaFuncAttributeMaxDynamicSharedMemorySize, SMEM_G1V);
    cudaFuncSetAttribute(gemm1, cudaFuncAttributeMaxDynamicSharedMemorySize, SMEM_G1);
    cudaFuncSetAttribute(phi_q_kernel, cudaFuncAttributeMaxDynamicSharedMemorySize, SMEM_PHI);
    cudaFuncSetAttribute(phi_k_kernel, cudaFuncAttributeMaxDynamicSharedMemorySize, SMEM_PHI);
    cudaFuncSetAttribute(kv_gemm, cudaFuncAttributeMaxDynamicSharedMemorySize, SMEM_KV);
    cudaFuncSetAttribute(qkv_gemm, cudaFuncAttributeMaxDynamicSharedMemorySize, SMEM_QKV);

    int wn4 = D_ * D_ / 4;
    split16_kernel<<<(int)(SZ_BTD / 4 / 256), 256>>>(x, xh, xl, (int)(SZ_BTD / 4));
    split16_kernel<<<wn4 / 256, 256>>>(wq, wqh, wql, wn4);
    conv16_kernel<<<wn4 / 256, 256>>>(wk, wk16, wn4);
    conv16_kernel<<<wn4 / 256, 256>>>(wv, wv16, wn4);
    conv16_kernel<<<wn4 / 256, 256>>>(wo, wo16, wn4);
    conv16_kernel<<<16, 256>>>(rf, rf16, 4096);

    gemm3<<<dim3(8, 64), 256, SMEM_G3>>>(xh, xl, wqh, wql, Qp, B_ * T_, D_, D_);
    gemm2<<<dim3(8, 64), 256, SMEM_G2>>>(xh, xl, wk16, Kp, B_ * T_, D_, D_);
    gemm1v<<<dim3(8, 64), 256, SMEM_G1V>>>(xh, wv16, VT, B_ * T_, D_, D_);
    vt_ones_kernel<<<BH_, 256>>>(VT);

    dim3 gPhi(T_ / 128, 2, BH_);
    phi_q_kernel<<<gPhi, 256, SMEM_PHI>>>(Qp, rf16, Qf, SCQ);
    knorm_kernel<<<dim3(T_ / 128, BH_), 256>>>(Kp, SCK);
    alphabeta_kernel<<<BH_, 256>>>(SCK, ALP, BET);
    phi_k_kernel<<<gPhi, 256, SMEM_PHI>>>(Kp, rf16, BET, KfT);

    zero_kvt_kernel<<<BH_, 256>>>(KVT);
    kv_gemm<<<dim3(FD_ / 128, BH_), 256, SMEM_KV>>>(KfT, VT, ALP, BET, KVT);
    srow_kernel<<<(B_ * T_) / 256, 256>>>(SCQ, ALP, SR);

    qkv_gemm<<<dim3(T_ / 128, BH_), 256, SMEM_QKV>>>(Qf, KVT, SCQ, ALP, SR, ah);

    gemm1<<<dim3(8, 64), 256, SMEM_G1>>>(ah, wo16, SR, out, B_ * T_, D_, D_);
}

// round 16
// speedup vs baseline: 4.0251x; 1.0318x over previous
#include <cuda_runtime.h>
#include <cuda_bf16.h>
#include <cuda_fp16.h>
#include <cstdint>
typedef __nv_bfloat16 bf16;
typedef __half f16;

#define B_   2
#define T_   4096
#define D_   1024
#define H_   16
#define DH_  64
#define FD_  512
#define BH_  (B_*H_)
#define SZ_BTD ((size_t)B_*T_*D_)
#define SZ_F   ((size_t)BH_*T_*FD_)

// fp32 scratch
#define OFF_Q   ((size_t)0)
#define OFF_K   (SZ_BTD)
#define OFF_SCQ (2*SZ_BTD)
#define OFF_SCK (OFF_SCQ + (size_t)BH_*T_)
#define OFF_AL  (OFF_SCK + (size_t)BH_*T_)
#define OFF_BE  (OFF_AL + BH_)
#define OFF_SR  (OFF_BE + BH_)
__device__ float g_buf[OFF_SR + (size_t)B_*T_];

// 2-byte scratch
#define BO_XH    ((size_t)0)
#define BO_XL    (SZ_BTD)
#define BO_WQH   (2*SZ_BTD)
#define BO_WQL   (BO_WQH + (size_t)D_*D_)
#define BO_WK    (BO_WQL + (size_t)D_*D_)
#define BO_WV    (BO_WK + (size_t)D_*D_)
#define BO_WO    (BO_WV + (size_t)D_*D_)
#define BO_RF    (BO_WO + (size_t)D_*D_)
#define BO_QF    (BO_RF + 16384)
#define BO_KFT   (BO_QF + SZ_F)
#define BO_VT    (BO_KFT + SZ_F)                  // [bh][80][T]; row64=ones
#define BO_KVT   (BO_VT + (size_t)BH_*80*T_)
#define BO_AH    (BO_KVT + (size_t)BH_*80*FD_)
__device__ bf16 g_bf[BO_AH + SZ_BTD];

__device__ __forceinline__ uint32_t smem_to_u32(const void* p) {
    uint32_t a;
    asm("{ .reg .u64 t; cvta.to.shared.u64 t, %1; cvt.u32.u64 %0, t; }" : "=r"(a) : "l"(p));
    return a;
}
#define SWZ(o) ((o) ^ (((o) >> 3) & 0x70))
__device__ __forceinline__ void cp_async16(uint32_t s, const void* g) {
    asm volatile("cp.async.cg.shared.global [%0], [%1], 16;" :: "r"(s), "l"(g));
}
__device__ __forceinline__ void cp_commit() { asm volatile("cp.async.commit_group;" ::: "memory"); }
template <int N> __device__ __forceinline__ void cp_wait() {
    asm volatile("cp.async.wait_group %0;" :: "n"(N) : "memory");
}
__device__ __forceinline__ void ldsm_x4(uint32_t& r0, uint32_t& r1, uint32_t& r2, uint32_t& r3, uint32_t a) {
    asm volatile("ldmatrix.sync.aligned.m8n8.x4.shared.b16 {%0,%1,%2,%3}, [%4];"
                 : "=r"(r0), "=r"(r1), "=r"(r2), "=r"(r3) : "r"(a));
}
__device__ __forceinline__ void ldsm_x2(uint32_t& r0, uint32_t& r1, uint32_t a) {
    asm volatile("ldmatrix.sync.aligned.m8n8.x2.shared.b16 {%0,%1}, [%2];"
                 : "=r"(r0), "=r"(r1) : "r"(a));
}
__device__ __forceinline__ void mma_f16(float* c, const uint32_t* a, const uint32_t* b) {
    asm volatile("mma.sync.aligned.m16n8k16.row.col.f32.f16.f16.f32 "
                 "{%0,%1,%2,%3}, {%4,%5,%6,%7}, {%8,%9}, {%0,%1,%2,%3};"
                 : "+f"(c[0]), "+f"(c[1]), "+f"(c[2]), "+f"(c[3])
                 : "r"(a[0]), "r"(a[1]), "r"(a[2]), "r"(a[3]), "r"(b[0]), "r"(b[1]));
}
__device__ __forceinline__ void store_pair_h(f16* ph, f16* pl, size_t off, float x0, float x1) {
    f16 h0 = __float2half_rn(x0), h1 = __float2half_rn(x1);
    __half2 hp = __halves2half2(h0, h1);
    *(uint32_t*)(ph + off) = *(uint32_t*)&hp;
    __half2 lp = __halves2half2(__float2half_rn(x0 - __half2float(h0)),
                                __float2half_rn(x1 - __half2float(h1)));
    *(uint32_t*)(pl + off) = *(uint32_t*)&lp;
}
__device__ __forceinline__ void store_h2(f16* p, size_t off, float x0, float x1) {
    __half2 hp = __halves2half2(__float2half_rn(x0), __float2half_rn(x1));
    *(uint32_t*)(p + off) = *(uint32_t*)&hp;
}
__device__ __forceinline__ void fast_sincos(float x, float& s, float& c) {
    float kf = rintf(x * 0.63661977f);
    int q = (int)kf;
    float r = fmaf(kf, -1.5707963705062866f, x);
    r = fmaf(kf, 4.3711388286738e-8f, r);
    float r2 = r * r;
    float sp = fmaf(-1.98412698e-4f, r2, 8.33333333e-3f);
    sp = fmaf(sp, r2, -1.66666667e-1f) * r2;
    float sr = fmaf(sp, r, r);
    float cp = fmaf(2.48015873e-5f, r2, -1.38888889e-3f);
    cp = fmaf(cp, r2, 4.16666667e-2f);
    cp = fmaf(cp, r2, -0.5f);
    float cr = fmaf(cp, r2, 1.0f);
    if (q & 1) { float t = sr; sr = cr; cr = -t; }
    if (q & 2) { sr = -sr; cr = -cr; }
    s = sr; c = cr;
}

#define TILE_B 16384
#define BUF3   (4*TILE_B)
#define BUF2   (3*TILE_B)
#define BUF1   (2*TILE_B)
#define SMEM_PROJ (2*BUF3)      // 128KB; covers all three paths

// ======== uber projection kernel: z=0 Q(3-pass), z=1 K(2-pass), z=2 V(1-pass + VT) ========
__global__ void __launch_bounds__(256)
proj_all(const f16* __restrict__ xh, const f16* __restrict__ xl,
         const f16* __restrict__ wqh, const f16* __restrict__ wql,
         const f16* __restrict__ wk16, const f16* __restrict__ wv16,
         float* __restrict__ Qp, float* __restrict__ Kp, f16* __restrict__ VT)
{
    extern __shared__ char smem[];
    const uint32_t sb = smem_to_u32(smem);
    const int tid = threadIdx.x, wid = tid >> 5, lane = tid & 31;
    const int bn = blockIdx.x << 7, bm = blockIdx.y << 7;
    const int wm = (wid >> 2) << 6, wn = (wid & 3) << 5;
    const int K = D_, N = D_;
    const int nchunk = K >> 6;
    const int lr = lane & 15, lc = lane >> 4, br = lane & 7, bk = (lane >> 3) & 1;
    float acc[4][4][4];
#pragma unroll
    for (int i = 0; i < 4; i++)
#pragma unroll
        for (int j = 0; j < 4; j++)
#pragma unroll
            for (int r = 0; r < 4; r++) acc[i][j][r] = 0.f;

    if (blockIdx.z == 0) {
        // ---- Q projection: 3-pass (x hi/lo, wq hi/lo) ----
        const f16* gs[4] = {xh, xl, wqh, wql};
        const int rb[4] = {bm, bm, bn, bn};
        auto load = [&](int kc, int buf) {
            uint32_t base = sb + buf * BUF3;
            int ke = kc << 6;
#pragma unroll
            for (int t = 0; t < 4; t++)
#pragma unroll
                for (int i = 0; i < 4; i++) {
                    int idx = tid + (i << 8), r = idx >> 3, c = idx & 7;
                    cp_async16(base + t * TILE_B + SWZ(r * 128 + c * 16),
                               gs[t] + (size_t)(rb[t] + r) * K + ke + c * 8);
                }
        };
        load(0, 0); cp_commit();
        for (int kc = 0; kc < nchunk; kc++) {
            int cur = kc & 1;
            if (kc + 1 < nchunk) { load(kc + 1, cur ^ 1); cp_commit(); cp_wait<1>(); }
            else cp_wait<0>();
            __syncthreads();
            uint32_t bA = sb + cur * BUF3;
#pragma unroll
            for (int ks = 0; ks < 4; ks++) {
                uint32_t a_h[4][4], a_l[4][4], b_h[4][2], b_l[4][2];
#pragma unroll
                for (int i = 0; i < 4; i++) {
                    uint32_t o = SWZ((wm + i * 16 + lr) * 128 + ks * 32 + lc * 16);
                    ldsm_x4(a_h[i][0], a_h[i][1], a_h[i][2], a_h[i][3], bA + o);
                    ldsm_x4(a_l[i][0], a_l[i][1], a_l[i][2], a_l[i][3], bA + TILE_B + o);
                }
#pragma unroll
                for (int j = 0; j < 4; j++) {
                    uint32_t o = SWZ((wn + j * 8 + br) * 128 + ks * 32 + bk * 16);
                    ldsm_x2(b_h[j][0], b_h[j][1], bA + 2 * TILE_B + o);
                    ldsm_x2(b_l[j][0], b_l[j][1], bA + 3 * TILE_B + o);
                }
#pragma unroll
                for (int i = 0; i < 4; i++)
#pragma unroll
                    for (int j = 0; j < 4; j++) {
                        mma_f16(acc[i][j], a_h[i], b_h[j]);
                        mma_f16(acc[i][j], a_h[i], b_l[j]);
                        mma_f16(acc[i][j], a_l[i], b_h[j]);
                    }
            }
            __syncthreads();
        }
#pragma unroll
        for (int i = 0; i < 4; i++) {
            int row = bm + wm + i * 16 + (lane >> 2);
#pragma unroll
            for (int j = 0; j < 4; j++) {
                int col = bn + wn + j * 8 + ((lane & 3) << 1);
                *(float2*)&Qp[(size_t)row * N + col]       = make_float2(acc[i][j][0], acc[i][j][1]);
                *(float2*)&Qp[(size_t)(row + 8) * N + col] = make_float2(acc[i][j][2], acc[i][j][3]);
            }
        }
    } else if (blockIdx.z == 1) {
        // ---- K projection: 2-pass (x hi/lo, wk single) ----
        auto load = [&](int kc, int buf) {
            uint32_t base = sb + buf * BUF2;
            int ke = kc << 6;
#pragma unroll
            for (int i = 0; i < 4; i++) {
                int idx = tid + (i << 8), r = idx >> 3, c = idx & 7;
                uint32_t so = SWZ(r * 128 + c * 16);
                cp_async16(base + so,              xh + (size_t)(bm + r) * K + ke + c * 8);
                cp_async16(base + TILE_B + so,     xl + (size_t)(bm + r) * K + ke + c * 8);
                cp_async16(base + 2 * TILE_B + so, wk16 + (size_t)(bn + r) * K + ke + c * 8);
            }
        };
        load(0, 0); cp_commit();
        for (int kc = 0; kc < nchunk; kc++) {
            int cur = kc & 1;
            if (kc + 1 < nchunk) { load(kc + 1, cur ^ 1); cp_commit(); cp_wait<1>(); }
            else cp_wait<0>();
            __syncthreads();
            uint32_t bA = sb + cur * BUF2;
#pragma unroll
            for (int ks = 0; ks < 4; ks++) {
                uint32_t a_h[4][4], a_l[4][4], b_[4][2];
#pragma unroll
                for (int i = 0; i < 4; i++) {
                    uint32_t o = SWZ((wm + i * 16 + lr) * 128 + ks * 32 + lc * 16);
                    ldsm_x4(a_h[i][0], a_h[i][1], a_h[i][2], a_h[i][3], bA + o);
                    ldsm_x4(a_l[i][0], a_l[i][1], a_l[i][2], a_l[i][3], bA + TILE_B + o);
                }
#pragma unroll
                for (int j = 0; j < 4; j++) {
                    uint32_t o = SWZ((wn + j * 8 + br) * 128 + ks * 32 + bk * 16);
                    ldsm_x2(b_[j][0], b_[j][1], bA + 2 * TILE_B + o);
                }
#pragma unroll
                for (int i = 0; i < 4; i++)
#pragma unroll
                    for (int j = 0; j < 4; j++) {
                        mma_f16(acc[i][j], a_h[i], b_[j]);
                        mma_f16(acc[i][j], a_l[i], b_[j]);
                    }
            }
            __syncthreads();
        }
#pragma unroll
        for (int i = 0; i < 4; i++) {
            int row = bm + wm + i * 16 + (lane >> 2);
#pragma unroll
            for (int j = 0; j < 4; j++) {
                int col = bn + wn + j * 8 + ((lane & 3) << 1);
                *(float2*)&Kp[(size_t)row * N + col]       = make_float2(acc[i][j][0], acc[i][j][1]);
                *(float2*)&Kp[(size_t)(row + 8) * N + col] = make_float2(acc[i][j][2], acc[i][j][3]);
            }
        }
    } else {
        // ---- V projection: 1-pass, fused VT transpose ----
        auto load = [&](int kc, int buf) {
            uint32_t base = sb + buf * BUF1;
            int ke = kc << 6;
#pragma unroll
            for (int i = 0; i < 4; i++) {
                int idx = tid + (i << 8), r = idx >> 3, c = idx & 7;
                uint32_t so = SWZ(r * 128 + c * 16);
                cp_async16(base + so,          xh + (size_t)(bm + r) * K + ke + c * 8);
                cp_async16(base + TILE_B + so, wv16 + (size_t)(bn + r) * K + ke + c * 8);
            }
        };
        load(0, 0); cp_commit();
        for (int kc = 0; kc < nchunk; kc++) {
            int cur = kc & 1;
            if (kc + 1 < nchunk) { load(kc + 1, cur ^ 1); cp_commit(); cp_wait<1>(); }
            else cp_wait<0>();
            __syncthreads();
            uint32_t bA = sb + cur * BUF1;
#pragma unroll
            for (int ks = 0; ks < 4; ks++) {
                uint32_t a_[4][4], b_[4][2];
#pragma unroll
                for (int i = 0; i < 4; i++) {
                    uint32_t o = SWZ((wm + i * 16 + lr) * 128 + ks * 32 + lc * 16);
                    ldsm_x4(a_[i][0], a_[i][1], a_[i][2], a_[i][3], bA + o);
                }
#pragma unroll
                for (int j = 0; j < 4; j++) {
                    uint32_t o = SWZ((wn + j * 8 + br) * 128 + ks * 32 + bk * 16);
                    ldsm_x2(b_[j][0], b_[j][1], bA + TILE_B + o);
                }
#pragma unroll
                for (int i = 0; i < 4; i++)
#pragma unroll
                    for (int j = 0; j < 4; j++)
                        mma_f16(acc[i][j], a_[i], b_[j]);
            }
            __syncthreads();
        }
        float* stage = (float*)smem;
#pragma unroll
        for (int i = 0; i < 4; i++) {
            int row = wm + i * 16 + (lane >> 2);
#pragma unroll
            for (int j = 0; j < 4; j++) {
                int col = wn + j * 8 + ((lane & 3) << 1);
                stage[col * 132 + row]           = acc[i][j][0];
                stage[(col + 1) * 132 + row]     = acc[i][j][1];
                stage[col * 132 + row + 8]       = acc[i][j][2];
                stage[(col + 1) * 132 + row + 8] = acc[i][j][3];
            }
        }
        __syncthreads();
        int b = bm >> 12;
        int dl = tid >> 1, ts = (tid & 1) << 6;
        int h = (bn + dl) >> 6, v = (bn + dl) & 63;
        size_t base = ((size_t)(b * H_ + h) * 80 + v) * T_ + (bm & 4095) + ts;
#pragma unroll
        for (int p = 0; p < 32; p++)
            store_h2(VT, base + p * 2, stage[dl * 132 + ts + p * 2], stage[dl * 132 + ts + p * 2 + 1]);
    }
}

// ======== fp16 1-pass GEMM with row scale (O projection) ========
#define SMEM_G1 (2*BUF1)
__global__ void __launch_bounds__(256)
gemm1(const f16* __restrict__ Am, const f16* __restrict__ Bm,
      const float* __restrict__ S, float* __restrict__ C, int M, int N, int K)
{
    extern __shared__ char smem[];
    const uint32_t sb = smem_to_u32(smem);
    const int tid = threadIdx.x, wid = tid >> 5, lane = tid & 31;
    const int bn = blockIdx.x << 7, bm = blockIdx.y << 7;
    const int wm = (wid >> 2) << 6, wn = (wid & 3) << 5;
    const int nchunk = K >> 6;
    const int lr = lane & 15, lc = lane >> 4, br = lane & 7, bk = (lane >> 3) & 1;
    float acc[4][4][4];
#pragma unroll
    for (int i = 0; i < 4; i++)
#pragma unroll
        for (int j = 0; j < 4; j++)
#pragma unroll
            for (int r = 0; r < 4; r++) acc[i][j][r] = 0.f;
    auto load = [&](int kc, int buf) {
        uint32_t base = sb + buf * BUF1;
        int ke = kc << 6;
#pragma unroll
        for (int i = 0; i < 4; i++) {
            int idx = tid + (i << 8), r = idx >> 3, c = idx & 7;
            uint32_t so = SWZ(r * 128 + c * 16);
            cp_async16(base + so,          Am + (size_t)(bm + r) * K + ke + c * 8);
            cp_async16(base + TILE_B + so, Bm + (size_t)(bn + r) * K + ke + c * 8);
        }
    };
    load(0, 0); cp_commit();
    for (int kc = 0; kc < nchunk; kc++) {
        int cur = kc & 1;
        if (kc + 1 < nchunk) { load(kc + 1, cur ^ 1); cp_commit(); cp_wait<1>(); }
        else cp_wait<0>();
        __syncthreads();
        uint32_t bA = sb + cur * BUF1;
#pragma unroll
        for (int ks = 0; ks < 4; ks++) {
            uint32_t a_[4][4], b_[4][2];
#pragma unroll
            for (int i = 0; i < 4; i++) {
                uint32_t o = SWZ((wm + i * 16 + lr) * 128 + ks * 32 + lc * 16);
                ldsm_x4(a_[i][0], a_[i][1], a_[i][2], a_[i][3], bA + o);
            }
#pragma unroll
            for (int j = 0; j < 4; j++) {
                uint32_t o = SWZ((wn + j * 8 + br) * 128 + ks * 32 + bk * 16);
                ldsm_x2(b_[j][0], b_[j][1], bA + TILE_B + o);
            }
#pragma unroll
            for (int i = 0; i < 4; i++)
#pragma unroll
                for (int j = 0; j < 4; j++)
                    mma_f16(acc[i][j], a_[i], b_[j]);
        }
        __syncthreads();
    }
#pragma unroll
    for (int i = 0; i < 4; i++) {
        int row = bm + wm + i * 16 + (lane >> 2);
        float s0 = S[row], s1 = S[row + 8];
#pragma unroll
        for (int j = 0; j < 4; j++) {
            int col = bn + wn + j * 8 + ((lane & 3) << 1);
            *(float2*)&C[(size_t)row * N + col]       = make_float2(acc[i][j][0] * s0, acc[i][j][1] * s0);
            *(float2*)&C[(size_t)(row + 8) * N + col] = make_float2(acc[i][j][2] * s1, acc[i][j][3] * s1);
        }
    }
}

// ======== conversions ========
__global__ void __launch_bounds__(256) split16_kernel(const float* __restrict__ in,
                                                      f16* __restrict__ hi, f16* __restrict__ lo, int n4)
{
    int i = blockIdx.x * 256 + threadIdx.x;
    if (i >= n4) return;
    float4 v = ((const float4*)in)[i];
    store_pair_h(hi, lo, (size_t)i * 4, v.x, v.y);
    store_pair_h(hi, lo, (size_t)i * 4 + 2, v.z, v.w);
}
__global__ void __launch_bounds__(256) conv16_kernel(const float* __restrict__ in,
                                                     f16* __restrict__ out, int n4)
{
    int i = blockIdx.x * 256 + threadIdx.x;
    if (i >= n4) return;
    float4 v = ((const float4*)in)[i];
    store_h2(out, (size_t)i * 4, v.x, v.y);
    store_h2(out, (size_t)i * 4 + 2, v.z, v.w);
}

// ======== phi kernels (1-pass MMA; both rf halves per CTA) ========
// phi_q layout: Q tile 16KB @0, rf full 32KB @16384, np @49152
#define PQ_A   0
#define PQ_B   16384
#define PQ_NP  49152
#define SMEM_PHIQ 50176
// phi_k layout: rf full 32KB @0, K tile 16KB @32768, scale @49152, np @49664
#define PK_A   0
#define PK_B   32768
#define PK_SC  49152
#define PK_NP  49664
#define SMEM_PHIK 50688

__device__ __forceinline__ void conv_tile_h1(const float* g, int ld, char* sm, int dst,
                                             float* np, int tid) {
    int r = tid >> 1, cb = (tid & 1) << 5;
    float s = 0.f;
    const float* gp = g + (size_t)r * ld + cb;
#pragma unroll
    for (int k = 0; k < 8; k++) {
        float4 v = *(const float4*)(gp + k * 4);
        s = fmaf(v.x, v.x, s); s = fmaf(v.y, v.y, s);
        s = fmaf(v.z, v.z, s); s = fmaf(v.w, v.w, s);
        uint32_t sw = SWZ((uint32_t)(r * 128 + (cb + k * 4) * 2));
        __half2 hp0 = __halves2half2(__float2half_rn(v.x), __float2half_rn(v.y));
        __half2 hp1 = __halves2half2(__float2half_rn(v.z), __float2half_rn(v.w));
        *(uint32_t*)(sm + dst + sw) = *(uint32_t*)&hp0;
        *(uint32_t*)(sm + dst + sw + 4) = *(uint32_t*)&hp1;
    }
    np[tid] = s;
}

// phi_q: A = Q tile @PQ_A, B = rf full (256 rows) @PQ_B; loop both halves
__global__ void __launch_bounds__(256) phi_q_kernel(
    const float* __restrict__ Q, const f16* __restrict__ rf16,
    f16* __restrict__ Qf, float* __restrict__ scq)
{
    extern __shared__ char sm[];
    const uint32_t sb = smem_to_u32(sm);
    const int tid = threadIdx.x, wid = tid >> 5, lane = tid & 31;
    const int t0 = blockIdx.x << 7, bh = blockIdx.y;
    const int b = bh >> 4, h = bh & 15;
    float* np = (float*)(sm + PQ_NP);
#pragma unroll
    for (int i = 0; i < 8; i++) {
        int idx = tid + (i << 8), r = idx >> 3, c = idx & 7;
        cp_async16(sb + PQ_B + SWZ(r * 128 + c * 16), rf16 + (size_t)r * DH_ + c * 8);
    }
    cp_commit();
    conv_tile_h1(&Q[((size_t)(b * T_ + t0)) * D_ + h * DH_], D_, sm, PQ_A, np, tid);
    __syncthreads();
    if (tid < 128)
        scq[(size_t)bh * T_ + t0 + tid] = __expf(-0.5f * (np[2 * tid] + np[2 * tid + 1])) * 0.0625f;
    cp_wait<0>();
    __syncthreads();
    const int wt = (wid >> 2) << 6, wm = (wid & 3) << 5;
    const int lr = lane & 15, lc = lane >> 4, br = lane & 7, bk = (lane >> 3) & 1;
    for (int half = 0; half < 2; half++) {
        const int m0c = half << 7;
        const uint32_t bB = sb + PQ_B + (half << 14);
        float acc[4][4][4];
#pragma unroll
        for (int i = 0; i < 4; i++)
#pragma unroll
            for (int j = 0; j < 4; j++)
#pragma unroll
                for (int r = 0; r < 4; r++) acc[i][j][r] = 0.f;
#pragma unroll
        for (int ks = 0; ks < 4; ks++) {
            uint32_t a_[4][4], b_[4][2];
#pragma unroll
            for (int i = 0; i < 4; i++) {
                uint32_t o = SWZ((wt + i * 16 + lr) * 128 + ks * 32 + lc * 16);
                ldsm_x4(a_[i][0], a_[i][1], a_[i][2], a_[i][3], sb + PQ_A + o);
            }
#pragma unroll
            for (int j = 0; j < 4; j++) {
                uint32_t o = SWZ((wm + j * 8 + br) * 128 + ks * 32 + bk * 16);
                ldsm_x2(b_[j][0], b_[j][1], bB + o);
            }
#pragma unroll
            for (int i = 0; i < 4; i++)
#pragma unroll
                for (int j = 0; j < 4; j++)
                    mma_f16(acc[i][j], a_[i], b_[j]);
        }
#pragma unroll
        for (int i = 0; i < 4; i++) {
            int r0 = wt + i * 16 + (lane >> 2);
            size_t rb0 = ((size_t)bh * T_ + t0 + r0) * FD_ + m0c;
            size_t rb1 = rb0 + (size_t)8 * FD_;
#pragma unroll
            for (int j = 0; j < 4; j++) {
                int mc = wm + j * 8 + ((lane & 3) << 1);
                float sn0, cs0, sn1, cs1;
                fast_sincos(acc[i][j][0], sn0, cs0);
                fast_sincos(acc[i][j][1], sn1, cs1);
                store_h2(Qf, rb0 + mc, cs0, cs1);
                store_h2(Qf, rb0 + 256 + mc, sn0, sn1);
                fast_sincos(acc[i][j][2], sn0, cs0);
                fast_sincos(acc[i][j][3], sn1, cs1);
                store_h2(Qf, rb1 + mc, cs0, cs1);
                store_h2(Qf, rb1 + 256 + mc, sn0, sn1);
            }
        }
    }
}

// phi_k: A = rf full @PK_A, B = K tile @PK_B; loop both rf halves
__global__ void __launch_bounds__(256) phi_k_kernel(
    const float* __restrict__ Kg, const f16* __restrict__ rf16,
    const float* __restrict__ beta, f16* __restrict__ KfT)
{
    extern __shared__ char sm[];
    const uint32_t sb = smem_to_u32(sm);
    const int tid = threadIdx.x, wid = tid >> 5, lane = tid & 31;
    const int t0 = blockIdx.x << 7, bh = blockIdx.y;
    const int b = bh >> 4, h = bh & 15;
    float* scale = (float*)(sm + PK_SC);
    float* np = (float*)(sm + PK_NP);
    const float gamma = 1.f / beta[bh];
#pragma unroll
    for (int i = 0; i < 8; i++) {
        int idx = tid + (i << 8), r = idx >> 3, c = idx & 7;
        cp_async16(sb + PK_A + SWZ(r * 128 + c * 16), rf16 + (size_t)r * DH_ + c * 8);
    }
    cp_commit();
    conv_tile_h1(&Kg[((size_t)(b * T_ + t0)) * D_ + h * DH_], D_, sm, PK_B, np, tid);
    __syncthreads();
    if (tid < 128)
        scale[tid] = __expf(-0.5f * (np[2 * tid] + np[2 * tid + 1])) * 0.0625f * gamma;
    cp_wait<0>();
    __syncthreads();
    const int wm = (wid >> 2) << 6, wt = (wid & 3) << 5;
    const int lr = lane & 15, lc = lane >> 4, br = lane & 7, bk = (lane >> 3) & 1;
    for (int half = 0; half < 2; half++) {
        const int m0c = half << 7;
        const uint32_t bA = sb + PK_A + (half << 14);
        float acc[4][4][4];
#pragma unroll
        for (int i = 0; i < 4; i++)
#pragma unroll
            for (int j = 0; j < 4; j++)
#pragma unroll
                for (int r = 0; r < 4; r++) acc[i][j][r] = 0.f;
#pragma unroll
        for (int ks = 0; ks < 4; ks++) {
            uint32_t a_[4][4], b_[4][2];
#pragma unroll
            for (int i = 0; i < 4; i++) {
                uint32_t o = SWZ((wm + i * 16 + lr) * 128 + ks * 32 + lc * 16);
                ldsm_x4(a_[i][0], a_[i][1], a_[i][2], a_[i][3], bA + o);
            }
#pragma unroll
            for (int j = 0; j < 4; j++) {
                uint32_t o = SWZ((wt + j * 8 + br) * 128 + ks * 32 + bk * 16);
                ldsm_x2(b_[j][0], b_[j][1], sb + PK_B + o);
            }
#pragma unroll
            for (int i = 0; i < 4; i++)
#pragma unroll
                for (int j = 0; j < 4; j++)
                    mma_f16(acc[i][j], a_[i], b_[j]);
        }
#pragma unroll
        for (int i = 0; i < 4; i++) {
            int r0 = wm + i * 16 + (lane >> 2);
            size_t rc0 = ((size_t)bh * FD_ + m0c + r0) * T_ + t0;
            size_t rs0 = rc0 + (size_t)256 * T_;
            size_t rc1 = rc0 + (size_t)8 * T_, rs1 = rs0 + (size_t)8 * T_;
#pragma unroll
            for (int j = 0; j < 4; j++) {
                int tc = wt + j * 8 + ((lane & 3) << 1);
                float sc0 = scale[tc], sc1 = scale[tc + 1];
                float sn0, cs0, sn1, cs1;
                fast_sincos(acc[i][j][0], sn0, cs0);
                fast_sincos(acc[i][j][1], sn1, cs1);
                store_h2(KfT, rc0 + tc, cs0 * sc0, cs1 * sc1);
                store_h2(KfT, rs0 + tc, sn0 * sc0, sn1 * sc1);
                fast_sincos(acc[i][j][2], sn0, cs0);
                fast_sincos(acc[i][j][3], sn1, cs1);
                store_h2(KfT, rc1 + tc, cs0 * sc0, cs1 * sc1);
                store_h2(KfT, rs1 + tc, sn0 * sc0, sn1 * sc1);
            }
        }
    }
}

// ======== knorm / alphabeta / srow / vt_ones / zero_kvt ========
__global__ void __launch_bounds__(256) knorm_kernel(const float* __restrict__ Kg,
                                                    float* __restrict__ sck)
{
    __shared__ float np[256];
    const int tid = threadIdx.x;
    const int t0 = blockIdx.x << 7, bh = blockIdx.y;
    const int b = bh >> 4, h = bh & 15;
    int r = tid >> 1, cb = (tid & 1) << 5;
    const float* gp = Kg + ((size_t)(b * T_ + t0 + r)) * D_ + h * DH_ + cb;
    float s = 0.f;
#pragma unroll
    for (int k = 0; k < 8; k++) {
        float4 v = *(const float4*)(gp + k * 4);
        s = fmaf(v.x, v.x, s); s = fmaf(v.y, v.y, s);
        s = fmaf(v.z, v.z, s); s = fmaf(v.w, v.w, s);
    }
    np[tid] = s;
    __syncthreads();
    if (tid < 128)
        sck[(size_t)bh * T_ + t0 + tid] = __expf(-0.5f * (np[2 * tid] + np[2 * tid + 1])) * 0.0625f;
}

__global__ void __launch_bounds__(256) alphabeta_kernel(const float* __restrict__ sck,
                                                        float* __restrict__ alpha,
                                                        float* __restrict__ beta)
{
    __shared__ float rs[256], rm[256];
    const int bh = blockIdx.x, tid = threadIdx.x;
    float s = 0.f, m = 0.f;
    for (int i = tid; i < T_; i += 256) {
        float v = sck[(size_t)bh * T_ + i];
        s += v; m = fmaxf(m, v);
    }
    rs[tid] = s; rm[tid] = m;
    __syncthreads();
    for (int o = 128; o; o >>= 1) {
        if (tid < o) { rs[tid] += rs[tid + o]; rm[tid] = fmaxf(rm[tid], rm[tid + o]); }
        __syncthreads();
    }
    if (tid == 0) {
        alpha[bh] = 1.f / fmaxf(rs[0], 1e-30f);
        beta[bh]  = fmaxf(rm[0], 1e-37f);
    }
}

__global__ void __launch_bounds__(256) srow_kernel(const float* __restrict__ scq,
                                                   const float* __restrict__ alpha,
                                                   float* __restrict__ srow)
{
    int row = blockIdx.x * 256 + threadIdx.x;
    int b = row >> 12, t = row & 4095;
    float m = 0.f;
#pragma unroll
    for (int h = 0; h < H_; h++) {
        int bh = b * H_ + h;
        m = fmaxf(m, scq[(size_t)bh * T_ + t] / alpha[bh]);
    }
    srow[row] = fmaxf(m * 1e6f, 1e-30f);
}

__global__ void __launch_bounds__(256) vt_ones_kernel(f16* __restrict__ VT)
{
    const int bh = blockIdx.x;
    const f16 one = __float2half_rn(1.f), zero = __float2half_rn(0.f);
    for (int i = threadIdx.x; i < 8 * T_; i += 256) {
        int r = i >> 12, t = i & 4095;
        VT[((size_t)bh * 80 + 64 + r) * T_ + t] = (r == 0) ? one : zero;
    }
}

__global__ void __launch_bounds__(256) zero_kvt_kernel(f16* __restrict__ kvt)
{
    const int bh = blockIdx.x;
    for (int i = threadIdx.x; i < 15 * FD_; i += 256)
        kvt[((size_t)bh * 80 + 65) * FD_ + i] = __float2half_rn(0.f);
}

// ======== kv: KfT'(fp16) x VT(fp16, 72 rows)^T, 1-pass, fused Ksum ========
#define KA   0
#define KB   16384
#define KBUF 26624
#define SMEM_KV (2*KBUF)

__global__ void __launch_bounds__(256) kv_gemm(
    const f16* __restrict__ Am, const f16* __restrict__ Bm,
    const float* __restrict__ alpha, const float* __restrict__ beta,
    f16* __restrict__ kvt)
{
    extern __shared__ char sm[];
    const uint32_t sb = smem_to_u32(sm);
    const int tid = threadIdx.x, wid = tid >> 5, lane = tid & 31;
    const int m0 = blockIdx.x << 7, bh = blockIdx.y;
    const size_t ab = (size_t)bh * FD_ + m0, bb = (size_t)bh * 80;
    const int wm = (wid >> 1) << 5, wn = (wid & 1) * 40;
    const int lr = lane & 15, lc = lane >> 4, br = lane & 7, bk = (lane >> 3) & 1;
    float acc[2][5][4];
#pragma unroll
    for (int i = 0; i < 2; i++)
#pragma unroll
        for (int j = 0; j < 5; j++)
#pragma unroll
            for (int r = 0; r < 4; r++) acc[i][j][r] = 0.f;
    auto load = [&](int kc, int buf) {
        uint32_t base = sb + buf * KBUF;
        int ke = kc << 6;
#pragma unroll
        for (int i = 0; i < 4; i++) {
            int idx = tid + (i << 8), r = idx >> 3, c = idx & 7;
            cp_async16(base + KA + SWZ(r * 128 + c * 16), Am + (ab + r) * T_ + ke + c * 8);
        }
#pragma unroll
        for (int i = 0; i < 3; i++) {
            int idx = tid + (i << 8);
            if (idx < 576) {
                int r = idx >> 3, c = idx & 7;
                cp_async16(base + KB + SWZ(r * 128 + c * 16), Bm + (bb + r) * T_ + ke + c * 8);
            }
        }
    };
    load(0, 0); cp_commit();
    for (int kc = 0; kc < T_ / 64; kc++) {
        int cur = kc & 1;
        if (kc + 1 < T_ / 64) { load(kc + 1, cur ^ 1); cp_commit(); cp_wait<1>(); }
        else cp_wait<0>();
        __syncthreads();
        uint32_t bA = sb + cur * KBUF;
#pragma unroll
        for (int ks = 0; ks < 4; ks++) {
            uint32_t a_[2][4], b_[5][2];
#pragma unroll
            for (int i = 0; i < 2; i++) {
                uint32_t o = SWZ((wm + i * 16 + lr) * 128 + ks * 32 + lc * 16);
                ldsm_x4(a_[i][0], a_[i][1], a_[i][2], a_[i][3], bA + KA + o);
            }
#pragma unroll
            for (int j = 0; j < 5; j++) {
                uint32_t o = SWZ((wn + j * 8 + br) * 128 + ks * 32 + bk * 16);
                ldsm_x2(b_[j][0], b_[j][1], bA + KB + o);
            }
#pragma unroll
            for (int i = 0; i < 2; i++)
#pragma unroll
                for (int j = 0; j < 5; j++)
                    mma_f16(acc[i][j], a_[i], b_[j]);
        }
        __syncthreads();
    }
    float* stage = (float*)sm;
#pragma unroll
    for (int i = 0; i < 2; i++) {
        int row = wm + i * 16 + (lane >> 2);
#pragma unroll
        for (int j = 0; j < 5; j++) {
            int col = wn + j * 8 + ((lane & 3) << 1);
            stage[col * 132 + row]           = acc[i][j][0];
            stage[(col + 1) * 132 + row]     = acc[i][j][1];
            stage[col * 132 + row + 8]       = acc[i][j][2];
            stage[(col + 1) * 132 + row + 8] = acc[i][j][3];
        }
    }
    __syncthreads();
    float av = alpha[bh] * beta[bh];
    int v = tid >> 2, fs = (tid & 3) << 5;
#pragma unroll
    for (int p = 0; p < 16; p++) {
        int f = fs + p * 2;
        store_h2(kvt, ((size_t)bh * 80 + v) * FD_ + m0 + f,
                 stage[v * 132 + f] * av, stage[v * 132 + f + 1] * av);
    }
    if (tid < 64) {
        int f = tid * 2;
        store_h2(kvt, ((size_t)bh * 80 + 64) * FD_ + m0 + f,
                 stage[64 * 132 + f] * av, stage[64 * 132 + f + 1] * av);
    }
}

// ======== qkv: Qf(single) x KVT'[80], 1-pass; epilogue Z + scales ========
#define QA   0
#define QB   16384
#define QBUF 26624
#define SMEM_QKV (2*QBUF)

__global__ void __launch_bounds__(256) qkv_gemm(
    const f16* __restrict__ Am, const f16* __restrict__ Bm,
    const float* __restrict__ scq, const float* __restrict__ alpha,
    const float* __restrict__ srow, f16* __restrict__ oh)
{
    extern __shared__ char sm[];
    __shared__ float zsm[128];
    const uint32_t sb = smem_to_u32(sm);
    const int tid = threadIdx.x, wid = tid >> 5, lane = tid & 31;
    const int t0 = blockIdx.x << 7, bh = blockIdx.y;
    const int b = bh >> 4, h = bh & 15;
    const size_t ab = (size_t)bh * T_ + t0, bb = (size_t)bh * 80;
    const int wm = (wid >> 1) << 5, wn = (wid & 1) * 40;
    const int lr = lane & 15, lc = lane >> 4, br = lane & 7, bk = (lane >> 3) & 1;
    float acc[2][5][4];
#pragma unroll
    for (int i = 0; i < 2; i++)
#pragma unroll
        for (int j = 0; j < 5; j++)
#pragma unroll
            for (int r = 0; r < 4; r++) acc[i][j][r] = 0.f;
    auto load = [&](int kc, int buf) {
        uint32_t base = sb + buf * QBUF;
        int ke = kc << 6;
#pragma unroll
        for (int i = 0; i < 4; i++) {
            int idx = tid + (i << 8), r = idx >> 3, c = idx & 7;
            cp_async16(base + QA + SWZ(r * 128 + c * 16), Am + (ab + r) * FD_ + ke + c * 8);
        }
#pragma unroll
        for (int i = 0; i < 3; i++) {
            int idx = tid + (i << 8);
            if (idx < 640) {
                int r = idx >> 3, c = idx & 7;
                cp_async16(base + QB + SWZ(r * 128 + c * 16), Bm + (bb + r) * FD_ + ke + c * 8);
            }
        }
    };
    load(0, 0); cp_commit();
    for (int kc = 0; kc < 8; kc++) {
        int cur = kc & 1;
        if (kc + 1 < 8) { load(kc + 1, cur ^ 1); cp_commit(); cp_wait<1>(); }
        else cp_wait<0>();
        __syncthreads();
        uint32_t bA = sb + cur * QBUF;
#pragma unroll
        for (int ks = 0; ks < 4; ks++) {
            uint32_t a_[2][4], b_[5][2];
#pragma unroll
            for (int i = 0; i < 2; i++) {
                uint32_t o = SWZ((wm + i * 16 + lr) * 128 + ks * 32 + lc * 16);
                ldsm_x4(a_[i][0], a_[i][1], a_[i][2], a_[i][3], bA + QA + o);
            }
#pragma unroll
            for (int j = 0; j < 5; j++) {
                uint32_t o = SWZ((wn + j * 8 + br) * 128 + ks * 32 + bk * 16);
                ldsm_x2(b_[j][0], b_[j][1], bA + QB + o);
            }
#pragma unroll
            for (int i = 0; i < 2; i++)
#pragma unroll
                for (int j = 0; j < 5; j++)
                    mma_f16(acc[i][j], a_[i], b_[j]);
        }
        __syncthreads();
    }
    if (wn == 40 && (lane & 3) == 0) {
#pragma unroll
        for (int i = 0; i < 2; i++) {
            int row = wm + i * 16 + (lane >> 2);
            zsm[row] = acc[i][3][0];
            zsm[row + 8] = acc[i][3][2];
        }
    }
    __syncthreads();
    float av = alpha[bh];
#pragma unroll
    for (int i = 0; i < 2; i++) {
#pragma unroll
        for (int half = 0; half < 2; half++) {
            int row = wm + i * 16 + (lane >> 2) + half * 8;
            float sq = scq[ab + row];
            float Zt = sq * zsm[row] / av;
            float d = fmaxf(Zt, 1e-6f);
            float mult = sq / (av * d * srow[(size_t)b * T_ + t0 + row]);
#pragma unroll
            for (int j = 0; j < 5; j++) {
                int col = wn + j * 8 + ((lane & 3) << 1);
                if (col < 64) {
                    size_t g0 = ((size_t)(b * T_ + t0 + row)) * D_ + h * DH_ + col;
                    store_h2(oh, g0, acc[i][j][half * 2] * mult, acc[i][j][half * 2 + 1] * mult);
                }
            }
        }
    }
}

// ======== launch ========
extern "C" void kernel_launch(void* const* d_in, const int* in_sizes, int n_in,
                              void* d_out, int out_size)
{
    const float* x  = (const float*)d_in[0];
    const float* wq = (const float*)d_in[1];
    const float* wk = (const float*)d_in[2];
    const float* wv = (const float*)d_in[3];
    const float* wo = (const float*)d_in[4];
    const float* rf = (const float*)d_in[5];
    float* out = (float*)d_out;

    float* fb = nullptr; cudaGetSymbolAddress((void**)&fb, g_buf);
    bf16*  bb = nullptr; cudaGetSymbolAddress((void**)&bb, g_bf);

    float *Qp = fb + OFF_Q, *Kp = fb + OFF_K;
    float *SCQ = fb + OFF_SCQ, *SCK = fb + OFF_SCK;
    float *ALP = fb + OFF_AL, *BET = fb + OFF_BE, *SR = fb + OFF_SR;
    f16 *xh = (f16*)(bb + BO_XH), *xl = (f16*)(bb + BO_XL);
    f16 *wqh = (f16*)(bb + BO_WQH), *wql = (f16*)(bb + BO_WQL);
    f16 *wk16 = (f16*)(bb + BO_WK);
    f16 *wv16 = (f16*)(bb + BO_WV), *wo16 = (f16*)(bb + BO_WO);
    f16 *rf16 = (f16*)(bb + BO_RF);
    f16 *Qf = (f16*)(bb + BO_QF);
    f16 *KfT = (f16*)(bb + BO_KFT);
    f16 *VT = (f16*)(bb + BO_VT);
    f16 *KVT = (f16*)(bb + BO_KVT);
    f16 *ah = (f16*)(bb + BO_AH);

    cudaFuncSetAttribute(proj_all, cudaFuncAttributeMaxDynamicSharedMemorySize, SMEM_PROJ);
    cudaFuncSetAttribute(gemm1, cudaFuncAttributeMaxDynamicSharedMemorySize, SMEM_G1);
    cudaFuncSetAttribute(phi_q_kernel, cudaFuncAttributeMaxDynamicSharedMemorySize, SMEM_PHIQ);
    cudaFuncSetAttribute(phi_k_kernel, cudaFuncAttributeMaxDynamicSharedMemorySize, SMEM_PHIK);
    cudaFuncSetAttribute(kv_gemm, cudaFuncAttributeMaxDynamicSharedMemorySize, SMEM_KV);
    cudaFuncSetAttribute(qkv_gemm, cudaFuncAttributeMaxDynamicSharedMemorySize, SMEM_QKV);

    int wn4 = D_ * D_ / 4;
    split16_kernel<<<(int)(SZ_BTD / 4 / 256), 256>>>(x, xh, xl, (int)(SZ_BTD / 4));
    split16_kernel<<<wn4 / 256, 256>>>(wq, wqh, wql, wn4);
    conv16_kernel<<<wn4 / 256, 256>>>(wk, wk16, wn4);
    conv16_kernel<<<wn4 / 256, 256>>>(wv, wv16, wn4);
    conv16_kernel<<<wn4 / 256, 256>>>(wo, wo16, wn4);
    conv16_kernel<<<16, 256>>>(rf, rf16, 4096);

    // fused Q/K/V projections (z = 0/1/2) — fills inter-kernel wave tails
    proj_all<<<dim3(8, 64, 3), 256, SMEM_PROJ>>>(xh, xl, wqh, wql, wk16, wv16, Qp, Kp, VT);
    vt_ones_kernel<<<BH_, 256>>>(VT);

    dim3 gPhi(T_ / 128, BH_);
    phi_q_kernel<<<gPhi, 256, SMEM_PHIQ>>>(Qp, rf16, Qf, SCQ);
    knorm_kernel<<<gPhi, 256>>>(Kp, SCK);
    alphabeta_kernel<<<BH_, 256>>>(SCK, ALP, BET);
    phi_k_kernel<<<gPhi, 256, SMEM_PHIK>>>(Kp, rf16, BET, KfT);

    zero_kvt_kernel<<<BH_, 256>>>(KVT);
    kv_gemm<<<dim3(FD_ / 128, BH_), 256, SMEM_KV>>>(KfT, VT, ALP, BET, KVT);
    srow_kernel<<<(B_ * T_) / 256, 256>>>(SCQ, ALP, SR);

    qkv_gemm<<<dim3(T_ / 128, BH_), 256, SMEM_QKV>>>(Qf, KVT, SCQ, ALP, SR, ah);

    gemm1<<<dim3(8, 64), 256, SMEM_G1>>>(ah, wo16, SR, out, B_ * T_, D_, D_);
}